// round 1
// baseline (speedup 1.0000x reference)
#include <cuda_runtime.h>
#include <cuda_bf16.h>
#include <cstddef>

#define BB 2
#define SS 2048
#define DD 4096
#define HH 32
#define HD 128
#define NEG_INF -1000000000.0f

// Scratch (device globals; allocation APIs are forbidden)
__device__ float g_qk[(size_t)BB * SS * DD];  // K projection, RoPE'd in place. layout (b,s,h,hd)
__device__ float g_v [(size_t)BB * SS * DD];  // V projection.                 layout (b,s,h,hd)
__device__ float g_qr[(size_t)BB * SS * DD];  // RoPE'd + scaled Q (=hidden).  layout (b,s,h,hd)
__device__ float g_ao[(size_t)BB * HH * SS * HD]; // attn out, layout (b,h,s,hd)

// ---------------------------------------------------------------------------
// Tiled fp32 GEMM: C[M=4096][N=4096] = A @ W^T (+bias). W row-major [N][K].
// GATHER=true reads A from g_ao's (b,h,s,hd) layout as the logical (b*s, h*hd)
// matrix for the output projection.
// ---------------------------------------------------------------------------
template<bool GATHER>
__global__ __launch_bounds__(256) void gemm_kernel(
    const float* __restrict__ A, const float* __restrict__ W,
    const float* __restrict__ bias, float* __restrict__ C)
{
    const int K = DD;
    __shared__ float As[16][128];
    __shared__ float Ws[16][128];
    int bm = blockIdx.y << 7, bn = blockIdx.x << 7;
    int t = threadIdx.x, tx = t & 15, ty = t >> 4;
    float acc[8][8] = {};

    for (int k0 = 0; k0 < K; k0 += 16) {
#pragma unroll
        for (int i = 0; i < 2; i++) {
            int slot = t + (i << 8);          // 0..511
            int row = slot >> 2;              // 0..127
            int c4 = (slot & 3) << 2;         // 0,4,8,12
            size_t aidx;
            if (GATHER) {
                int m = bm + row, k = k0 + c4;
                int b = m >> 11, s = m & (SS - 1);
                int h = k >> 7,  d = k & (HD - 1);
                aidx = ((((size_t)b * HH + h) * SS + s) << 7) + d;
            } else {
                aidx = (size_t)(bm + row) * K + k0 + c4;
            }
            float4 va = *(const float4*)(A + aidx);
            As[c4 + 0][row] = va.x; As[c4 + 1][row] = va.y;
            As[c4 + 2][row] = va.z; As[c4 + 3][row] = va.w;
            float4 vw = *(const float4*)(W + (size_t)(bn + row) * K + k0 + c4);
            Ws[c4 + 0][row] = vw.x; Ws[c4 + 1][row] = vw.y;
            Ws[c4 + 2][row] = vw.z; Ws[c4 + 3][row] = vw.w;
        }
        __syncthreads();
#pragma unroll
        for (int kk = 0; kk < 16; kk++) {
            float a[8], b[8];
#pragma unroll
            for (int i = 0; i < 8; i++) a[i] = As[kk][(ty << 3) + i];
#pragma unroll
            for (int j = 0; j < 8; j++) b[j] = Ws[kk][(tx << 3) + j];
#pragma unroll
            for (int i = 0; i < 8; i++)
#pragma unroll
                for (int j = 0; j < 8; j++)
                    acc[i][j] = fmaf(a[i], b[j], acc[i][j]);
        }
        __syncthreads();
    }
#pragma unroll
    for (int i = 0; i < 8; i++) {
        int m = bm + (ty << 3) + i;
#pragma unroll
        for (int j = 0; j < 8; j++) {
            int n = bn + (tx << 3) + j;
            float v = acc[i][j];
            if (bias) v += bias[n];
            C[(size_t)m * DD + n] = v;
        }
    }
}

// ---------------------------------------------------------------------------
// RoPE: dst[b,s,h,d] = rope(src[b,s,h,d]) * scale. One thread per (b,s,h, d<64) pair.
// ---------------------------------------------------------------------------
__global__ void rope_kernel(const float* __restrict__ src, float* __restrict__ dst,
                            const float* __restrict__ cosp, const float* __restrict__ sinp,
                            float scale)
{
    int idx = blockIdx.x * blockDim.x + threadIdx.x;
    const int total = BB * SS * HH * (HD / 2);
    if (idx >= total) return;
    int d  = idx & 63;
    int h  = (idx >> 6) & (HH - 1);
    int bs = idx >> 11;
    size_t base = (size_t)bs * DD + (h << 7);
    size_t cbase = (size_t)bs * HD;
    float c0 = cosp[cbase + d],      s0 = sinp[cbase + d];
    float c1 = cosp[cbase + d + 64], s1 = sinp[cbase + d + 64];
    float x0 = src[base + d], x1 = src[base + d + 64];
    dst[base + d]      = (x0 * c0 - x1 * s0) * scale;
    dst[base + d + 64] = (x1 * c1 + x0 * s1) * scale;
}

// ---------------------------------------------------------------------------
// Scores: P[bh,q,k] = (Qr . Kr) with causal mask (NEG_INF). Scale folded into Qr.
// 64x64 tiles, K=128 in two 32-wide chunks. Fully-masked tiles skip compute.
// ---------------------------------------------------------------------------
__global__ __launch_bounds__(256) void score_kernel(
    const float* __restrict__ Qr, const float* __restrict__ Kr, float* __restrict__ P)
{
    int bh = blockIdx.z;
    int b = bh >> 5, h = bh & 31;
    int q0 = blockIdx.y << 6, k0 = blockIdx.x << 6;
    size_t pbase = ((size_t)bh * SS + q0) * SS + k0;
    int t = threadIdx.x;

    if (k0 > q0) {                       // whole 64x64 tile above the diagonal
        for (int i = t; i < 64 * 64; i += 256) {
            int r = i >> 6, c = i & 63;
            P[pbase + (size_t)r * SS + c] = NEG_INF;
        }
        return;
    }

    __shared__ float Qs[32][64];
    __shared__ float Ks[32][64];
    int tx = t & 15, ty = t >> 4;
    float acc[4][4] = {};
    const float* Qp = Qr + (size_t)(b * SS + q0) * DD + (h << 7);
    const float* Kp = Kr + (size_t)(b * SS + k0) * DD + (h << 7);

    for (int kc = 0; kc < HD; kc += 32) {
#pragma unroll
        for (int i = 0; i < 2; i++) {
            int slot = t + (i << 8);      // 0..511
            int row = slot >> 3;          // 0..63
            int c4 = (slot & 7) << 2;     // 0..28
            float4 vq = *(const float4*)(Qp + (size_t)row * DD + kc + c4);
            Qs[c4 + 0][row] = vq.x; Qs[c4 + 1][row] = vq.y;
            Qs[c4 + 2][row] = vq.z; Qs[c4 + 3][row] = vq.w;
            float4 vk = *(const float4*)(Kp + (size_t)row * DD + kc + c4);
            Ks[c4 + 0][row] = vk.x; Ks[c4 + 1][row] = vk.y;
            Ks[c4 + 2][row] = vk.z; Ks[c4 + 3][row] = vk.w;
        }
        __syncthreads();
#pragma unroll
        for (int kk = 0; kk < 32; kk++) {
            float a[4], bb[4];
#pragma unroll
            for (int i = 0; i < 4; i++) a[i] = Qs[kk][(ty << 2) + i];
#pragma unroll
            for (int j = 0; j < 4; j++) bb[j] = Ks[kk][(tx << 2) + j];
#pragma unroll
            for (int i = 0; i < 4; i++)
#pragma unroll
                for (int j = 0; j < 4; j++)
                    acc[i][j] = fmaf(a[i], bb[j], acc[i][j]);
        }
        __syncthreads();
    }
#pragma unroll
    for (int i = 0; i < 4; i++) {
        int q = q0 + (ty << 2) + i;
#pragma unroll
        for (int j = 0; j < 4; j++) {
            int k = k0 + (tx << 2) + j;
            P[pbase + (size_t)((ty << 2) + i) * SS + (tx << 2) + j] =
                (k <= q) ? acc[i][j] : NEG_INF;
        }
    }
}

// ---------------------------------------------------------------------------
// Row softmax in place. One 256-thread block per row of 2048; values in regs.
// ---------------------------------------------------------------------------
__global__ __launch_bounds__(256) void softmax_kernel(float* __restrict__ P)
{
    size_t row = blockIdx.x;
    float* p = P + row * (size_t)SS;
    int t = threadIdx.x;
    float v[8];
    float mx = -3.4e38f;
#pragma unroll
    for (int i = 0; i < 8; i++) { v[i] = p[t + (i << 8)]; mx = fmaxf(mx, v[i]); }
#pragma unroll
    for (int o = 16; o; o >>= 1) mx = fmaxf(mx, __shfl_xor_sync(0xffffffffu, mx, o));
    __shared__ float rmax[8], rsum[8];
    if ((t & 31) == 0) rmax[t >> 5] = mx;
    __syncthreads();
    mx = rmax[0];
#pragma unroll
    for (int i = 1; i < 8; i++) mx = fmaxf(mx, rmax[i]);
    float sum = 0.f;
#pragma unroll
    for (int i = 0; i < 8; i++) { v[i] = __expf(v[i] - mx); sum += v[i]; }
#pragma unroll
    for (int o = 16; o; o >>= 1) sum += __shfl_xor_sync(0xffffffffu, sum, o);
    if ((t & 31) == 0) rsum[t >> 5] = sum;
    __syncthreads();
    sum = rsum[0];
#pragma unroll
    for (int i = 1; i < 8; i++) sum += rsum[i];
    float inv = 1.0f / sum;
#pragma unroll
    for (int i = 0; i < 8; i++) p[t + (i << 8)] = v[i] * inv;
}

// ---------------------------------------------------------------------------
// AO[bh,q,:] = sum_k P[bh,q,k] * V[b,k,h,:].  Causal: only k < q0+64 contribute
// (masked P entries are exactly 0 after softmax).
// ---------------------------------------------------------------------------
__global__ __launch_bounds__(256) void pv_kernel(
    const float* __restrict__ P, const float* __restrict__ V, float* __restrict__ AO)
{
    int bh = blockIdx.y;
    int b = bh >> 5, h = bh & 31;
    int q0 = blockIdx.x << 6;
    int t = threadIdx.x, tx = t & 15, ty = t >> 4;
    __shared__ float Ps[32][64];    // [k][q]
    __shared__ float Vs[32][128];   // [k][d]
    float acc[4][8] = {};
    const float* Pp = P + ((size_t)bh * SS + q0) * SS;
    const float* Vp = V + (size_t)b * SS * DD + (h << 7);
    int kend = q0 + 64;

    for (int k0 = 0; k0 < kend; k0 += 32) {
#pragma unroll
        for (int i = 0; i < 2; i++) {
            int slot = t + (i << 8);
            int row = slot >> 3;           // q row 0..63
            int c4 = (slot & 7) << 2;      // k 0..28
            float4 vp = *(const float4*)(Pp + (size_t)row * SS + k0 + c4);
            Ps[c4 + 0][row] = vp.x; Ps[c4 + 1][row] = vp.y;
            Ps[c4 + 2][row] = vp.z; Ps[c4 + 3][row] = vp.w;
        }
#pragma unroll
        for (int i = 0; i < 4; i++) {
            int slot = t + (i << 8);       // 0..1023
            int row = slot >> 5;           // k 0..31
            int c4 = (slot & 31) << 2;     // d 0..124
            *(float4*)&Vs[row][c4] = *(const float4*)(Vp + (size_t)(k0 + row) * DD + c4);
        }
        __syncthreads();
#pragma unroll
        for (int kk = 0; kk < 32; kk++) {
            float a[4], bb[8];
#pragma unroll
            for (int i = 0; i < 4; i++) a[i] = Ps[kk][(ty << 2) + i];
#pragma unroll
            for (int j = 0; j < 8; j++) bb[j] = Vs[kk][(tx << 3) + j];
#pragma unroll
            for (int i = 0; i < 4; i++)
#pragma unroll
                for (int j = 0; j < 8; j++)
                    acc[i][j] = fmaf(a[i], bb[j], acc[i][j]);
        }
        __syncthreads();
    }
#pragma unroll
    for (int i = 0; i < 4; i++) {
        size_t obase = ((size_t)bh * SS + q0 + (ty << 2) + i) * HD;
#pragma unroll
        for (int j = 0; j < 8; j++)
            AO[obase + (tx << 3) + j] = acc[i][j];
    }
}

// ---------------------------------------------------------------------------
extern "C" void kernel_launch(void* const* d_in, const int* in_sizes, int n_in,
                              void* d_out, int out_size)
{
    (void)in_sizes; (void)n_in; (void)out_size;
    const float* hidden = (const float*)d_in[0];
    const float* Wqk    = (const float*)d_in[1];
    const float* bqk    = (const float*)d_in[2];
    const float* Wv     = (const float*)d_in[3];
    const float* bv     = (const float*)d_in[4];
    const float* Wo     = (const float*)d_in[5];
    const float* cosp   = (const float*)d_in[6];
    const float* sinp   = (const float*)d_in[7];
    // d_in[8] = attention_mask: pure causal, applied analytically.

    float* out   = (float*)d_out;                       // attn_output: B*S*D
    float* attnw = out + (size_t)BB * SS * DD;          // attn_weights: B*H*S*S

    float *qk_p, *v_p, *qr_p, *ao_p;
    cudaGetSymbolAddress((void**)&qk_p, g_qk);
    cudaGetSymbolAddress((void**)&v_p,  g_v);
    cudaGetSymbolAddress((void**)&qr_p, g_qr);
    cudaGetSymbolAddress((void**)&ao_p, g_ao);

    dim3 gemm_grid(DD / 128, (BB * SS) / 128);
    // 1) K and V projections
    gemm_kernel<false><<<gemm_grid, 256>>>(hidden, Wqk, bqk, qk_p);
    gemm_kernel<false><<<gemm_grid, 256>>>(hidden, Wv,  bv,  v_p);

    // 2) RoPE: Q from hidden (softmax scale folded in), K in place
    const int rope_total = BB * SS * HH * (HD / 2);
    const float scale = 0.088388347648318447f;  // 128^-0.5
    rope_kernel<<<(rope_total + 255) / 256, 256>>>(hidden, qr_p, cosp, sinp, scale);
    rope_kernel<<<(rope_total + 255) / 256, 256>>>(qk_p,   qk_p, cosp, sinp, 1.0f);

    // 3) Scores (masked) -> attn_weights region, then softmax in place
    score_kernel<<<dim3(SS / 64, SS / 64, BB * HH), 256>>>(qr_p, qk_p, attnw);
    softmax_kernel<<<BB * HH * SS, 256>>>(attnw);

    // 4) P @ V
    pv_kernel<<<dim3(SS / 64, BB * HH), 256>>>(attnw, v_p, ao_p);

    // 5) Output projection (gathered A from (b,h,s,hd) layout)
    gemm_kernel<true><<<gemm_grid, 256>>>(ao_p, Wo, nullptr, out);
}

// round 3
// speedup vs baseline: 1.9118x; 1.9118x over previous
#include <cuda_runtime.h>
#include <cuda_bf16.h>
#include <cstdint>
#include <cstddef>

#define BB 2
#define SS 2048
#define DD 4096
#define HH 32
#define HD 128
#define NEG_INF -1000000000.0f

#define NELT ((size_t)BB * SS * DD)   // 16,777,216

// ---------------- scratch (device globals; alloc APIs forbidden) ----------
__device__ float g_qk[NELT];   // K projection, RoPE'd in place. (b,s,h,hd)
__device__ float g_v [NELT];   // V projection.                  (b,s,h,hd)
__device__ float g_qr[NELT];   // RoPE'd + scaled Q (=hidden).   (b,s,h,hd)
__device__ float g_ao[NELT];   // attn out, (b,h,s,hd)

__device__ __nv_bfloat16 g_hh[NELT],  g_hl[NELT];    // hidden hi/lo
__device__ __nv_bfloat16 g_qkh[NELT], g_qkl[NELT];   // Wqk hi/lo
__device__ __nv_bfloat16 g_vh[NELT],  g_vl[NELT];    // Wv  hi/lo
__device__ __nv_bfloat16 g_oh[NELT],  g_ol[NELT];    // Wo  hi/lo
__device__ __nv_bfloat16 g_aoh[NELT], g_aol[NELT];   // attn-out (gathered) hi/lo

// ---------------- helpers ---------------------------------------------------
__device__ __forceinline__ uint32_t smem_u32(const void* p) {
    uint32_t a;
    asm("{ .reg .u64 t; cvta.to.shared.u64 t, %1; cvt.u32.u64 %0, t; }" : "=r"(a) : "l"(p));
    return a;
}
__device__ __forceinline__ void cp_async16(uint32_t dst, const void* src) {
    asm volatile("cp.async.cg.shared.global [%0], [%1], 16;" :: "r"(dst), "l"(src));
}
#define CP_COMMIT() asm volatile("cp.async.commit_group;" ::: "memory")
#define CP_WAIT2()  asm volatile("cp.async.wait_group 2;" ::: "memory")

__device__ __forceinline__ void ldmx4(uint32_t* r, uint32_t addr) {
    asm volatile("ldmatrix.sync.aligned.m8n8.x4.shared.b16 {%0,%1,%2,%3}, [%4];"
                 : "=r"(r[0]), "=r"(r[1]), "=r"(r[2]), "=r"(r[3]) : "r"(addr));
}
__device__ __forceinline__ void mma16816(float* d, const uint32_t* a, const uint32_t* b) {
    asm volatile(
        "mma.sync.aligned.m16n8k16.row.col.f32.bf16.bf16.f32 "
        "{%0,%1,%2,%3}, {%4,%5,%6,%7}, {%8,%9}, {%0,%1,%2,%3};"
        : "+f"(d[0]), "+f"(d[1]), "+f"(d[2]), "+f"(d[3])
        : "r"(a[0]), "r"(a[1]), "r"(a[2]), "r"(a[3]), "r"(b[0]), "r"(b[1]));
}

// GEMM config: BM=BN=128, BK=64, 3-stage cp.async pipeline.
#define NSTAGE 3
#define TILE_BYTES 16384            // 128 rows x 128B
#define STAGE_BYTES (4 * TILE_BYTES)
#define GEMM_SMEM (NSTAGE * STAGE_BYTES)   // 196608

// ---------------------------------------------------------------------------
// HMMA bf16 hi/lo GEMM: C[4096][4096] = A @ W^T (+bias), fp32-accurate.
// A,W as bf16 hi/lo pairs, K-major rows (ld = 4096).
// ---------------------------------------------------------------------------
__global__ __launch_bounds__(256) void gemm_tc(
    const __nv_bfloat16* __restrict__ Ah, const __nv_bfloat16* __restrict__ Al,
    const __nv_bfloat16* __restrict__ Bh, const __nv_bfloat16* __restrict__ Bl,
    const float* __restrict__ bias, float* __restrict__ C)
{
    extern __shared__ char smem[];
    const uint32_t sbase = smem_u32(smem);
    const int t = threadIdx.x;
    const int wid = t >> 5, lane = t & 31;
    const int bm = blockIdx.y << 7, bn = blockIdx.x << 7;

    // per-thread loader assignment: 4 tiles (Ah,Al,Bh,Bl), 64 threads each
    const int ltile = t >> 6, ltid = t & 63;
    const __nv_bfloat16* lsrc =
        (ltile == 0) ? Ah + (size_t)bm * DD :
        (ltile == 1) ? Al + (size_t)bm * DD :
        (ltile == 2) ? Bh + (size_t)bn * DD :
                       Bl + (size_t)bn * DD;

    auto load_stage = [&](int stg, int kc) {
        uint32_t dbase = sbase + stg * STAGE_BYTES + (ltile << 14);
#pragma unroll
        for (int q = 0; q < 16; q++) {
            int idx = ltid + (q << 6);           // 0..1023
            int r = idx >> 3, c = idx & 7;       // row, 16B-chunk
            const void* src = lsrc + (size_t)r * DD + kc + (c << 3);
            uint32_t dst = dbase + (r << 7) + (((c ^ (r & 7)) << 4));
            cp_async16(dst, src);
        }
        CP_COMMIT();
    };

    load_stage(0, 0);
    load_stage(1, 64);
    load_stage(2, 128);

    const int wm = (wid & 1) << 6;     // 0 / 64
    const int wn = (wid >> 1) << 5;    // 0 / 32 / 64 / 96
    const int lr = lane & 15, lc = lane >> 4;

    float acc[4][4][4] = {};

    for (int it = 0; it < DD / 64; it++) {
        int stg = it % NSTAGE;
        CP_WAIT2();
        __syncthreads();
        uint32_t sb = sbase + stg * STAGE_BYTES;

#pragma unroll
        for (int ks = 0; ks < 4; ks++) {
            uint32_t ah[4][4], al[4][4], bh[4][2], bl[4][2];
#pragma unroll
            for (int mi = 0; mi < 4; mi++) {
                int r = wm + mi * 16 + lr;
                uint32_t off = (uint32_t)(r << 7) + ((((ks * 2 + lc) ^ (r & 7)) << 4));
                ldmx4(ah[mi], sb + off);                 // Ah tile at +0
                ldmx4(al[mi], sb + TILE_BYTES + off);    // Al tile
            }
#pragma unroll
            for (int g = 0; g < 2; g++) {
                int r = wn + g * 16 + lr;
                uint32_t off = (uint32_t)(r << 7) + ((((ks * 2 + lc) ^ (r & 7)) << 4));
                uint32_t rb[4];
                ldmx4(rb, sb + 2 * TILE_BYTES + off);    // Bh tile
                bh[g*2+0][0] = rb[0]; bh[g*2+0][1] = rb[2];
                bh[g*2+1][0] = rb[1]; bh[g*2+1][1] = rb[3];
                ldmx4(rb, sb + 3 * TILE_BYTES + off);    // Bl tile
                bl[g*2+0][0] = rb[0]; bl[g*2+0][1] = rb[2];
                bl[g*2+1][0] = rb[1]; bl[g*2+1][1] = rb[3];
            }
#pragma unroll
            for (int mi = 0; mi < 4; mi++)
#pragma unroll
                for (int ni = 0; ni < 4; ni++) {
                    mma16816(acc[mi][ni], ah[mi], bh[ni]);
                    mma16816(acc[mi][ni], ah[mi], bl[ni]);
                    mma16816(acc[mi][ni], al[mi], bh[ni]);
                }
        }
        __syncthreads();
        if (it + NSTAGE < DD / 64) load_stage(stg, (it + NSTAGE) * 64);
    }

    // epilogue: direct global stores (float2), optional bias
    const int qr = lane >> 2, qc = (lane & 3) << 1;
#pragma unroll
    for (int mi = 0; mi < 4; mi++) {
#pragma unroll
        for (int ni = 0; ni < 4; ni++) {
            int col = bn + wn + ni * 8 + qc;
            float bx = 0.f, by = 0.f;
            if (bias) { bx = bias[col]; by = bias[col + 1]; }
            int row0 = bm + wm + mi * 16 + qr;
            float2 v0 = { acc[mi][ni][0] + bx, acc[mi][ni][1] + by };
            float2 v1 = { acc[mi][ni][2] + bx, acc[mi][ni][3] + by };
            *(float2*)&C[(size_t)row0 * DD + col] = v0;
            *(float2*)&C[(size_t)(row0 + 8) * DD + col] = v1;
        }
    }
}

// ---------------------------------------------------------------------------
// fp32 -> bf16 hi/lo split
// ---------------------------------------------------------------------------
__global__ void conv_kernel(const float* __restrict__ x,
                            __nv_bfloat16* __restrict__ hi, __nv_bfloat16* __restrict__ lo)
{
    size_t i = (size_t)blockIdx.x * blockDim.x + threadIdx.x;
    if (i >= NELT / 4) return;
    float4 v = ((const float4*)x)[i];
    float f[4] = { v.x, v.y, v.z, v.w };
    __nv_bfloat16 h[4], l[4];
#pragma unroll
    for (int k = 0; k < 4; k++) {
        h[k] = __float2bfloat16(f[k]);
        l[k] = __float2bfloat16(f[k] - __bfloat162float(h[k]));
    }
    ((__nv_bfloat162*)hi)[i * 2]     = __nv_bfloat162(h[0], h[1]);
    ((__nv_bfloat162*)hi)[i * 2 + 1] = __nv_bfloat162(h[2], h[3]);
    ((__nv_bfloat162*)lo)[i * 2]     = __nv_bfloat162(l[0], l[1]);
    ((__nv_bfloat162*)lo)[i * 2 + 1] = __nv_bfloat162(l[2], l[3]);
}

// gather (b,h,s,hd) -> row-major (m = b*S+s, k = h*HD+hd) + hi/lo split
__global__ void conv_gather_kernel(const float* __restrict__ ao,
                                   __nv_bfloat16* __restrict__ hi, __nv_bfloat16* __restrict__ lo)
{
    size_t i = (size_t)blockIdx.x * blockDim.x + threadIdx.x;
    if (i >= NELT / 4) return;
    int m = (int)(i >> 10);
    int kq = ((int)i & 1023) << 2;
    int b = m >> 11, s = m & (SS - 1);
    int h = kq >> 7, d = kq & (HD - 1);
    size_t in = ((((size_t)b * HH + h) * SS + s) << 7) + d;
    float4 v = *(const float4*)(ao + in);
    float f[4] = { v.x, v.y, v.z, v.w };
    __nv_bfloat16 hh[4], ll[4];
#pragma unroll
    for (int k = 0; k < 4; k++) {
        hh[k] = __float2bfloat16(f[k]);
        ll[k] = __float2bfloat16(f[k] - __bfloat162float(hh[k]));
    }
    ((__nv_bfloat162*)hi)[i * 2]     = __nv_bfloat162(hh[0], hh[1]);
    ((__nv_bfloat162*)hi)[i * 2 + 1] = __nv_bfloat162(hh[2], hh[3]);
    ((__nv_bfloat162*)lo)[i * 2]     = __nv_bfloat162(ll[0], ll[1]);
    ((__nv_bfloat162*)lo)[i * 2 + 1] = __nv_bfloat162(ll[2], ll[3]);
}

// ---------------------------------------------------------------------------
// RoPE
// ---------------------------------------------------------------------------
__global__ void rope_kernel(const float* __restrict__ src, float* __restrict__ dst,
                            const float* __restrict__ cosp, const float* __restrict__ sinp,
                            float scale)
{
    int idx = blockIdx.x * blockDim.x + threadIdx.x;
    const int total = BB * SS * HH * (HD / 2);
    if (idx >= total) return;
    int d  = idx & 63;
    int h  = (idx >> 6) & (HH - 1);
    int bs = idx >> 11;
    size_t base = (size_t)bs * DD + (h << 7);
    size_t cbase = (size_t)bs * HD;
    float c0 = cosp[cbase + d],      s0 = sinp[cbase + d];
    float c1 = cosp[cbase + d + 64], s1 = sinp[cbase + d + 64];
    float x0 = src[base + d], x1 = src[base + d + 64];
    dst[base + d]      = (x0 * c0 - x1 * s0) * scale;
    dst[base + d + 64] = (x1 * c1 + x0 * s1) * scale;
}

// ---------------------------------------------------------------------------
// Scores (fp32 SIMT, causal-aware)
// ---------------------------------------------------------------------------
__global__ __launch_bounds__(256) void score_kernel(
    const float* __restrict__ Qr, const float* __restrict__ Kr, float* __restrict__ P)
{
    int bh = blockIdx.z;
    int b = bh >> 5, h = bh & 31;
    int q0 = blockIdx.y << 6, k0 = blockIdx.x << 6;
    size_t pbase = ((size_t)bh * SS + q0) * SS + k0;
    int t = threadIdx.x;

    if (k0 > q0) {
        for (int i = t; i < 64 * 64; i += 256) {
            int r = i >> 6, c = i & 63;
            P[pbase + (size_t)r * SS + c] = NEG_INF;
        }
        return;
    }

    __shared__ float Qs[32][64];
    __shared__ float Ks[32][64];
    int tx = t & 15, ty = t >> 4;
    float acc[4][4] = {};
    const float* Qp = Qr + (size_t)(b * SS + q0) * DD + (h << 7);
    const float* Kp = Kr + (size_t)(b * SS + k0) * DD + (h << 7);

    for (int kc = 0; kc < HD; kc += 32) {
#pragma unroll
        for (int i = 0; i < 2; i++) {
            int slot = t + (i << 8);
            int row = slot >> 3;
            int c4 = (slot & 7) << 2;
            float4 vq = *(const float4*)(Qp + (size_t)row * DD + kc + c4);
            Qs[c4 + 0][row] = vq.x; Qs[c4 + 1][row] = vq.y;
            Qs[c4 + 2][row] = vq.z; Qs[c4 + 3][row] = vq.w;
            float4 vk = *(const float4*)(Kp + (size_t)row * DD + kc + c4);
            Ks[c4 + 0][row] = vk.x; Ks[c4 + 1][row] = vk.y;
            Ks[c4 + 2][row] = vk.z; Ks[c4 + 3][row] = vk.w;
        }
        __syncthreads();
#pragma unroll
        for (int kk = 0; kk < 32; kk++) {
            float a[4], bb[4];
#pragma unroll
            for (int i = 0; i < 4; i++) a[i] = Qs[kk][(ty << 2) + i];
#pragma unroll
            for (int j = 0; j < 4; j++) bb[j] = Ks[kk][(tx << 2) + j];
#pragma unroll
            for (int i = 0; i < 4; i++)
#pragma unroll
                for (int j = 0; j < 4; j++)
                    acc[i][j] = fmaf(a[i], bb[j], acc[i][j]);
        }
        __syncthreads();
    }
#pragma unroll
    for (int i = 0; i < 4; i++) {
        int q = q0 + (ty << 2) + i;
#pragma unroll
        for (int j = 0; j < 4; j++) {
            int k = k0 + (tx << 2) + j;
            P[pbase + (size_t)((ty << 2) + i) * SS + (tx << 2) + j] =
                (k <= q) ? acc[i][j] : NEG_INF;
        }
    }
}

// ---------------------------------------------------------------------------
// Softmax (in place, one block per row)
// ---------------------------------------------------------------------------
__global__ __launch_bounds__(256) void softmax_kernel(float* __restrict__ P)
{
    size_t row = blockIdx.x;
    float* p = P + row * (size_t)SS;
    int t = threadIdx.x;
    float v[8];
    float mx = -3.4e38f;
#pragma unroll
    for (int i = 0; i < 8; i++) { v[i] = p[t + (i << 8)]; mx = fmaxf(mx, v[i]); }
#pragma unroll
    for (int o = 16; o; o >>= 1) mx = fmaxf(mx, __shfl_xor_sync(0xffffffffu, mx, o));
    __shared__ float rmax[8], rsum[8];
    if ((t & 31) == 0) rmax[t >> 5] = mx;
    __syncthreads();
    mx = rmax[0];
#pragma unroll
    for (int i = 1; i < 8; i++) mx = fmaxf(mx, rmax[i]);
    float sum = 0.f;
#pragma unroll
    for (int i = 0; i < 8; i++) { v[i] = __expf(v[i] - mx); sum += v[i]; }
#pragma unroll
    for (int o = 16; o; o >>= 1) sum += __shfl_xor_sync(0xffffffffu, sum, o);
    if ((t & 31) == 0) rsum[t >> 5] = sum;
    __syncthreads();
    sum = rsum[0];
#pragma unroll
    for (int i = 1; i < 8; i++) sum += rsum[i];
    float inv = 1.0f / sum;
#pragma unroll
    for (int i = 0; i < 8; i++) p[t + (i << 8)] = v[i] * inv;
}

// ---------------------------------------------------------------------------
// PV (fp32 SIMT, causal-aware)
// ---------------------------------------------------------------------------
__global__ __launch_bounds__(256) void pv_kernel(
    const float* __restrict__ P, const float* __restrict__ V, float* __restrict__ AO)
{
    int bh = blockIdx.y;
    int b = bh >> 5, h = bh & 31;
    int q0 = blockIdx.x << 6;
    int t = threadIdx.x, tx = t & 15, ty = t >> 4;
    __shared__ float Ps[32][64];
    __shared__ float Vs[32][128];
    float acc[4][8] = {};
    const float* Pp = P + ((size_t)bh * SS + q0) * SS;
    const float* Vp = V + (size_t)b * SS * DD + (h << 7);
    int kend = q0 + 64;

    for (int k0 = 0; k0 < kend; k0 += 32) {
#pragma unroll
        for (int i = 0; i < 2; i++) {
            int slot = t + (i << 8);
            int row = slot >> 3;
            int c4 = (slot & 7) << 2;
            float4 vp = *(const float4*)(Pp + (size_t)row * SS + k0 + c4);
            Ps[c4 + 0][row] = vp.x; Ps[c4 + 1][row] = vp.y;
            Ps[c4 + 2][row] = vp.z; Ps[c4 + 3][row] = vp.w;
        }
#pragma unroll
        for (int i = 0; i < 4; i++) {
            int slot = t + (i << 8);
            int row = slot >> 5;
            int c4 = (slot & 31) << 2;
            *(float4*)&Vs[row][c4] = *(const float4*)(Vp + (size_t)(k0 + row) * DD + c4);
        }
        __syncthreads();
#pragma unroll
        for (int kk = 0; kk < 32; kk++) {
            float a[4], bb[8];
#pragma unroll
            for (int i = 0; i < 4; i++) a[i] = Ps[kk][(ty << 2) + i];
#pragma unroll
            for (int j = 0; j < 8; j++) bb[j] = Vs[kk][(tx << 3) + j];
#pragma unroll
            for (int i = 0; i < 4; i++)
#pragma unroll
                for (int j = 0; j < 8; j++)
                    acc[i][j] = fmaf(a[i], bb[j], acc[i][j]);
        }
        __syncthreads();
    }
#pragma unroll
    for (int i = 0; i < 4; i++) {
        size_t obase = ((size_t)bh * SS + q0 + (ty << 2) + i) * HD;
#pragma unroll
        for (int j = 0; j < 8; j++)
            AO[obase + (tx << 3) + j] = acc[i][j];
    }
}

// ---------------------------------------------------------------------------
extern "C" void kernel_launch(void* const* d_in, const int* in_sizes, int n_in,
                              void* d_out, int out_size)
{
    (void)in_sizes; (void)n_in; (void)out_size;
    const float* hidden = (const float*)d_in[0];
    const float* Wqk    = (const float*)d_in[1];
    const float* bqk    = (const float*)d_in[2];
    const float* Wv     = (const float*)d_in[3];
    const float* bv     = (const float*)d_in[4];
    const float* Wo     = (const float*)d_in[5];
    const float* cosp   = (const float*)d_in[6];
    const float* sinp   = (const float*)d_in[7];

    float* out   = (float*)d_out;
    float* attnw = out + (size_t)BB * SS * DD;

    float *qk_p, *v_p, *qr_p, *ao_p;
    cudaGetSymbolAddress((void**)&qk_p, g_qk);
    cudaGetSymbolAddress((void**)&v_p,  g_v);
    cudaGetSymbolAddress((void**)&qr_p, g_qr);
    cudaGetSymbolAddress((void**)&ao_p, g_ao);

    __nv_bfloat16 *hh, *hl, *qkh, *qkl, *vh, *vl, *oh, *ol, *aoh, *aol;
    cudaGetSymbolAddress((void**)&hh,  g_hh);  cudaGetSymbolAddress((void**)&hl,  g_hl);
    cudaGetSymbolAddress((void**)&qkh, g_qkh); cudaGetSymbolAddress((void**)&qkl, g_qkl);
    cudaGetSymbolAddress((void**)&vh,  g_vh);  cudaGetSymbolAddress((void**)&vl,  g_vl);
    cudaGetSymbolAddress((void**)&oh,  g_oh);  cudaGetSymbolAddress((void**)&ol,  g_ol);
    cudaGetSymbolAddress((void**)&aoh, g_aoh); cudaGetSymbolAddress((void**)&aol, g_aol);

    cudaFuncSetAttribute(gemm_tc, cudaFuncAttributeMaxDynamicSharedMemorySize, GEMM_SMEM);

    const int cvblk = (int)((NELT / 4 + 255) / 256);
    conv_kernel<<<cvblk, 256>>>(hidden, hh, hl);
    conv_kernel<<<cvblk, 256>>>(Wqk, qkh, qkl);
    conv_kernel<<<cvblk, 256>>>(Wv,  vh,  vl);
    conv_kernel<<<cvblk, 256>>>(Wo,  oh,  ol);

    dim3 gg(DD / 128, (BB * SS) / 128);
    gemm_tc<<<gg, 256, GEMM_SMEM>>>(hh, hl, qkh, qkl, bqk, qk_p);
    gemm_tc<<<gg, 256, GEMM_SMEM>>>(hh, hl, vh,  vl,  bv,  v_p);

    const int rope_total = BB * SS * HH * (HD / 2);
    const float scale = 0.088388347648318447f;  // 128^-0.5
    rope_kernel<<<(rope_total + 255) / 256, 256>>>(hidden, qr_p, cosp, sinp, scale);
    rope_kernel<<<(rope_total + 255) / 256, 256>>>(qk_p,   qk_p, cosp, sinp, 1.0f);

    score_kernel<<<dim3(SS / 64, SS / 64, BB * HH), 256>>>(qr_p, qk_p, attnw);
    softmax_kernel<<<BB * HH * SS, 256>>>(attnw);
    pv_kernel<<<dim3(SS / 64, BB * HH), 256>>>(attnw, v_p, ao_p);

    conv_gather_kernel<<<cvblk, 256>>>(ao_p, aoh, aol);
    gemm_tc<<<gg, 256, GEMM_SMEM>>>(aoh, aol, oh, ol, nullptr, out);
}

// round 4
// speedup vs baseline: 2.6063x; 1.3633x over previous
#include <cuda_runtime.h>
#include <cuda_bf16.h>
#include <cstdint>
#include <cstddef>

#define BB 2
#define SS 2048
#define DD 4096
#define HH 32
#define HD 128
#define NEG_INF -1000000000.0f

#define NELT ((size_t)BB * SS * DD)          // 16,777,216
#define NP   ((size_t)BB * HH * SS * SS)     // 268,435,456

// ---------------- scratch (device globals; alloc APIs forbidden) ----------
__device__ float g_qk[NELT];   // K projection (b,s,h,hd) fp32
__device__ float g_v [NELT];   // V projection (b,s,h,hd) fp32

__device__ __nv_bfloat16 g_hh[NELT],  g_hl[NELT];    // hidden hi/lo
__device__ __nv_bfloat16 g_qkh[NELT], g_qkl[NELT];   // Wqk hi/lo
__device__ __nv_bfloat16 g_vh[NELT],  g_vl[NELT];    // Wv hi/lo
__device__ __nv_bfloat16 g_oh[NELT],  g_ol[NELT];    // Wo hi/lo
__device__ __nv_bfloat16 g_qh[NELT],  g_ql[NELT];    // roped Q hi/lo (b,s,h,hd)
__device__ __nv_bfloat16 g_kh[NELT],  g_kl[NELT];    // roped K hi/lo (b,s,h,hd)
__device__ __nv_bfloat16 g_vth[NELT], g_vtl[NELT];   // V^T hi/lo (b,h,d,k)
__device__ __nv_bfloat16 g_aoh[NELT], g_aol[NELT];   // attn-out gathered hi/lo
__device__ __nv_bfloat16 g_ph[NP],    g_pl[NP];      // softmax P hi/lo

// ---------------- helpers ---------------------------------------------------
__device__ __forceinline__ uint32_t smem_u32(const void* p) {
    uint32_t a;
    asm("{ .reg .u64 t; cvta.to.shared.u64 t, %1; cvt.u32.u64 %0, t; }" : "=r"(a) : "l"(p));
    return a;
}
__device__ __forceinline__ void cp_async16(uint32_t dst, const void* src) {
    asm volatile("cp.async.cg.shared.global [%0], [%1], 16;" :: "r"(dst), "l"(src));
}
#define CP_COMMIT() asm volatile("cp.async.commit_group;" ::: "memory")
#define CP_WAIT2()  asm volatile("cp.async.wait_group 2;" ::: "memory")
#define CP_WAIT0()  asm volatile("cp.async.wait_group 0;" ::: "memory")

__device__ __forceinline__ void ldmx4(uint32_t* r, uint32_t addr) {
    asm volatile("ldmatrix.sync.aligned.m8n8.x4.shared.b16 {%0,%1,%2,%3}, [%4];"
                 : "=r"(r[0]), "=r"(r[1]), "=r"(r[2]), "=r"(r[3]) : "r"(addr));
}
__device__ __forceinline__ void mma16816(float* d, const uint32_t* a, const uint32_t* b) {
    asm volatile(
        "mma.sync.aligned.m16n8k16.row.col.f32.bf16.bf16.f32 "
        "{%0,%1,%2,%3}, {%4,%5,%6,%7}, {%8,%9}, {%0,%1,%2,%3};"
        : "+f"(d[0]), "+f"(d[1]), "+f"(d[2]), "+f"(d[3])
        : "r"(a[0]), "r"(a[1]), "r"(a[2]), "r"(a[3]), "r"(b[0]), "r"(b[1]));
}

// one 128x64 bf16 subtile loaded by 64 threads (ltid 0..63), XOR-swizzled
__device__ __forceinline__ void load_subtile(uint32_t dbase, const __nv_bfloat16* src,
                                             int ld, int ltid)
{
#pragma unroll
    for (int q = 0; q < 16; q++) {
        int idx = ltid + (q << 6);
        int r = idx >> 3, c = idx & 7;
        cp_async16(dbase + (r << 7) + ((c ^ (r & 7)) << 4),
                   src + (size_t)r * ld + (c << 3));
    }
}

// one K=16 MMA step for the 128x128 CTA tile with hi/lo 3-product accumulate.
// Tile bases: A-hi, A-lo, B-hi, B-lo (each a 128x64 swizzled subtile).
__device__ __forceinline__ void hmma_block(
    uint32_t tAh, uint32_t tAl, uint32_t tBh, uint32_t tBl,
    int ksl, int wm, int wn, int lr, int lc, float (&acc)[4][4][4])
{
    uint32_t ah[4][4], al[4][4], bh[4][2], bl[4][2];
#pragma unroll
    for (int mi = 0; mi < 4; mi++) {
        int r = wm + mi * 16 + lr;
        uint32_t off = (uint32_t)(r << 7) + ((((ksl * 2 + lc) ^ (r & 7)) << 4));
        ldmx4(ah[mi], tAh + off);
        ldmx4(al[mi], tAl + off);
    }
#pragma unroll
    for (int g = 0; g < 2; g++) {
        int r = wn + g * 16 + lr;
        uint32_t off = (uint32_t)(r << 7) + ((((ksl * 2 + lc) ^ (r & 7)) << 4));
        uint32_t rb[4];
        ldmx4(rb, tBh + off);
        bh[g*2+0][0] = rb[0]; bh[g*2+0][1] = rb[2];
        bh[g*2+1][0] = rb[1]; bh[g*2+1][1] = rb[3];
        ldmx4(rb, tBl + off);
        bl[g*2+0][0] = rb[0]; bl[g*2+0][1] = rb[2];
        bl[g*2+1][0] = rb[1]; bl[g*2+1][1] = rb[3];
    }
#pragma unroll
    for (int mi = 0; mi < 4; mi++)
#pragma unroll
        for (int ni = 0; ni < 4; ni++) {
            mma16816(acc[mi][ni], ah[mi], bh[ni]);
            mma16816(acc[mi][ni], ah[mi], bl[ni]);
            mma16816(acc[mi][ni], al[mi], bh[ni]);
        }
}

__device__ __forceinline__ void split_hi_lo(float f, __nv_bfloat16& h, __nv_bfloat16& l) {
    h = __float2bfloat16(f);
    l = __float2bfloat16(f - __bfloat162float(h));
}

// GEMM config: BM=BN=128, BK=64, 3-stage cp.async pipeline.
#define NSTAGE 3
#define TILE_BYTES 16384            // 128 rows x 128B
#define STAGE_BYTES (4 * TILE_BYTES)
#define GEMM_SMEM (NSTAGE * STAGE_BYTES)   // 196608
#define SCORE_SMEM 131072

// ---------------------------------------------------------------------------
// HMMA bf16 hi/lo GEMM: C[4096][4096] = A @ W^T (+bias), fp32-accurate.
// ---------------------------------------------------------------------------
__global__ __launch_bounds__(256) void gemm_tc(
    const __nv_bfloat16* __restrict__ Ah, const __nv_bfloat16* __restrict__ Al,
    const __nv_bfloat16* __restrict__ Bh, const __nv_bfloat16* __restrict__ Bl,
    const float* __restrict__ bias, float* __restrict__ C)
{
    extern __shared__ char smem[];
    const uint32_t sbase = smem_u32(smem);
    const int t = threadIdx.x;
    const int wid = t >> 5, lane = t & 31;
    const int bm = blockIdx.y << 7, bn = blockIdx.x << 7;

    const int ltile = t >> 6, ltid = t & 63;
    const __nv_bfloat16* lsrc =
        (ltile == 0) ? Ah + (size_t)bm * DD :
        (ltile == 1) ? Al + (size_t)bm * DD :
        (ltile == 2) ? Bh + (size_t)bn * DD :
                       Bl + (size_t)bn * DD;

    auto load_stage = [&](int stg, int kc) {
        load_subtile(sbase + stg * STAGE_BYTES + (ltile << 14), lsrc + kc, DD, ltid);
        CP_COMMIT();
    };

    load_stage(0, 0);
    load_stage(1, 64);
    load_stage(2, 128);

    const int wm = (wid & 1) << 6;
    const int wn = (wid >> 1) << 5;
    const int lr = lane & 15, lc = lane >> 4;

    float acc[4][4][4] = {};
    const int iters = DD / 64;

    for (int it = 0; it < iters; it++) {
        int stg = it % NSTAGE;
        CP_WAIT2();
        __syncthreads();
        uint32_t sb = sbase + stg * STAGE_BYTES;
#pragma unroll
        for (int ks = 0; ks < 4; ks++)
            hmma_block(sb, sb + TILE_BYTES, sb + 2 * TILE_BYTES, sb + 3 * TILE_BYTES,
                       ks, wm, wn, lr, lc, acc);
        __syncthreads();
        if (it + NSTAGE < iters) load_stage(stg, (it + NSTAGE) * 64);
        else CP_COMMIT();
    }

    const int qr = lane >> 2, qc = (lane & 3) << 1;
#pragma unroll
    for (int mi = 0; mi < 4; mi++) {
#pragma unroll
        for (int ni = 0; ni < 4; ni++) {
            int col = bn + wn + ni * 8 + qc;
            float bx = 0.f, by = 0.f;
            if (bias) { bx = bias[col]; by = bias[col + 1]; }
            int row0 = bm + wm + mi * 16 + qr;
            float2 v0 = { acc[mi][ni][0] + bx, acc[mi][ni][1] + by };
            float2 v1 = { acc[mi][ni][2] + bx, acc[mi][ni][3] + by };
            *(float2*)&C[(size_t)row0 * DD + col] = v0;
            *(float2*)&C[(size_t)(row0 + 8) * DD + col] = v1;
        }
    }
}

// ---------------------------------------------------------------------------
// score_tc: P[bh, q, k] = Q . K (hi/lo HMMA), causal mask, fp32 out.
// 128x128 tile per CTA; K-dim = HD = 128 single shot.
// ---------------------------------------------------------------------------
__global__ __launch_bounds__(256) void score_tc(
    const __nv_bfloat16* __restrict__ Qh, const __nv_bfloat16* __restrict__ Ql,
    const __nv_bfloat16* __restrict__ Kh, const __nv_bfloat16* __restrict__ Kl,
    float* __restrict__ P)
{
    extern __shared__ char smem[];
    const int bh = blockIdx.z;
    const int b = bh >> 5, h = bh & 31;
    const int q0 = blockIdx.y << 7, k0 = blockIdx.x << 7;
    const size_t pbase = ((size_t)bh * SS + q0) * SS + k0;
    const int t = threadIdx.x;

    if (k0 > q0) {               // fully-masked tile
        const float4 nf = { NEG_INF, NEG_INF, NEG_INF, NEG_INF };
#pragma unroll
        for (int q = 0; q < 16; q++) {
            int i = t + (q << 8);          // 0..4095 float4 slots
            int r = i >> 5, c4 = (i & 31) << 2;
            *(float4*)&P[pbase + (size_t)r * SS + c4] = nf;
        }
        return;
    }

    const uint32_t sbase = smem_u32(smem);
    const int wid = t >> 5, lane = t & 31;

    const int ltile = t >> 6, ltid = t & 63;
    const __nv_bfloat16* lsrc =
        (ltile == 0) ? Qh + (size_t)(b * SS + q0) * DD + (h << 7) :
        (ltile == 1) ? Ql + (size_t)(b * SS + q0) * DD + (h << 7) :
        (ltile == 2) ? Kh + (size_t)(b * SS + k0) * DD + (h << 7) :
                       Kl + (size_t)(b * SS + k0) * DD + (h << 7);

    // 4 tensors x 2 halves of 16KB; tensor stride 32KB
    load_subtile(sbase + (ltile << 15),         lsrc,      DD, ltid);
    load_subtile(sbase + (ltile << 15) + 16384, lsrc + 64, DD, ltid);
    CP_COMMIT();
    CP_WAIT0();
    __syncthreads();

    const int wm = (wid & 1) << 6;
    const int wn = (wid >> 1) << 5;
    const int lr = lane & 15, lc = lane >> 4;
    float acc[4][4][4] = {};

#pragma unroll
    for (int ks = 0; ks < 8; ks++) {
        uint32_t hb = sbase + (ks >> 2) * 16384;
        hmma_block(hb, hb + 32768, hb + 65536, hb + 98304, ks & 3, wm, wn, lr, lc, acc);
    }

    const int qr = lane >> 2, qc = (lane & 3) << 1;
#pragma unroll
    for (int mi = 0; mi < 4; mi++) {
#pragma unroll
        for (int ni = 0; ni < 4; ni++) {
            int rl = wm + mi * 16 + qr;
            int cl = wn + ni * 8 + qc;
            int k = k0 + cl;
            int qA = q0 + rl, qB = qA + 8;
            float2 v0 = { (k <= qA) ? acc[mi][ni][0] : NEG_INF,
                          (k + 1 <= qA) ? acc[mi][ni][1] : NEG_INF };
            float2 v1 = { (k <= qB) ? acc[mi][ni][2] : NEG_INF,
                          (k + 1 <= qB) ? acc[mi][ni][3] : NEG_INF };
            *(float2*)&P[pbase + (size_t)rl * SS + cl] = v0;
            *(float2*)&P[pbase + (size_t)(rl + 8) * SS + cl] = v1;
        }
    }
}

// ---------------------------------------------------------------------------
// pv_tc: AO[b, q, h*128+d] = sum_k P[bh,q,k] * Vt[bh,d,k]; causal k-bound.
// Output written directly as gathered bf16 hi/lo for the final GEMM.
// ---------------------------------------------------------------------------
__global__ __launch_bounds__(256) void pv_tc(
    const __nv_bfloat16* __restrict__ Ph, const __nv_bfloat16* __restrict__ Pl,
    const __nv_bfloat16* __restrict__ Vth, const __nv_bfloat16* __restrict__ Vtl,
    __nv_bfloat16* __restrict__ AOh, __nv_bfloat16* __restrict__ AOl)
{
    extern __shared__ char smem[];
    const uint32_t sbase = smem_u32(smem);
    const int t = threadIdx.x;
    const int wid = t >> 5, lane = t & 31;
    const int q0 = blockIdx.x << 7;
    const int bh = blockIdx.y;
    const int b = bh >> 5, h = bh & 31;

    const int ltile = t >> 6, ltid = t & 63;
    const __nv_bfloat16* lsrc =
        (ltile == 0) ? Ph  + ((size_t)bh * SS + q0) * SS :
        (ltile == 1) ? Pl  + ((size_t)bh * SS + q0) * SS :
        (ltile == 2) ? Vth + (size_t)bh * HD * SS :
                       Vtl + (size_t)bh * HD * SS;

    const int iters = (q0 >> 6) + 2;

    auto load_stage = [&](int stg, int kc) {
        load_subtile(sbase + stg * STAGE_BYTES + (ltile << 14), lsrc + kc, SS, ltid);
        CP_COMMIT();
    };

#pragma unroll
    for (int s = 0; s < NSTAGE; s++) {
        if (s < iters) load_stage(s, s * 64);
        else CP_COMMIT();
    }

    const int wm = (wid & 1) << 6;
    const int wn = (wid >> 1) << 5;
    const int lr = lane & 15, lc = lane >> 4;
    float acc[4][4][4] = {};

    for (int it = 0; it < iters; it++) {
        int stg = it % NSTAGE;
        CP_WAIT2();
        __syncthreads();
        uint32_t sb = sbase + stg * STAGE_BYTES;
#pragma unroll
        for (int ks = 0; ks < 4; ks++)
            hmma_block(sb, sb + TILE_BYTES, sb + 2 * TILE_BYTES, sb + 3 * TILE_BYTES,
                       ks, wm, wn, lr, lc, acc);
        __syncthreads();
        if (it + NSTAGE < iters) load_stage(stg, (it + NSTAGE) * 64);
        else CP_COMMIT();
    }

    const int qr = lane >> 2, qc = (lane & 3) << 1;
#pragma unroll
    for (int mi = 0; mi < 4; mi++) {
#pragma unroll
        for (int ni = 0; ni < 4; ni++) {
            int row = q0 + wm + mi * 16 + qr;
            int col = (h << 7) + wn + ni * 8 + qc;
            size_t m0 = ((size_t)b * SS + row) * DD + col;
            size_t m1 = m0 + (size_t)8 * DD;
            __nv_bfloat16 h0, l0, h1, l1;
            split_hi_lo(acc[mi][ni][0], h0, l0);
            split_hi_lo(acc[mi][ni][1], h1, l1);
            *(__nv_bfloat162*)&AOh[m0] = __nv_bfloat162(h0, h1);
            *(__nv_bfloat162*)&AOl[m0] = __nv_bfloat162(l0, l1);
            split_hi_lo(acc[mi][ni][2], h0, l0);
            split_hi_lo(acc[mi][ni][3], h1, l1);
            *(__nv_bfloat162*)&AOh[m1] = __nv_bfloat162(h0, h1);
            *(__nv_bfloat162*)&AOl[m1] = __nv_bfloat162(l0, l1);
        }
    }
}

// ---------------------------------------------------------------------------
// fp32 -> bf16 hi/lo split (weights / hidden)
// ---------------------------------------------------------------------------
__global__ void conv_kernel(const float* __restrict__ x,
                            __nv_bfloat16* __restrict__ hi, __nv_bfloat16* __restrict__ lo)
{
    size_t i = (size_t)blockIdx.x * blockDim.x + threadIdx.x;
    if (i >= NELT / 4) return;
    float4 v = ((const float4*)x)[i];
    float f[4] = { v.x, v.y, v.z, v.w };
    __nv_bfloat16 h[4], l[4];
#pragma unroll
    for (int k = 0; k < 4; k++) split_hi_lo(f[k], h[k], l[k]);
    ((__nv_bfloat162*)hi)[i * 2]     = __nv_bfloat162(h[0], h[1]);
    ((__nv_bfloat162*)hi)[i * 2 + 1] = __nv_bfloat162(h[2], h[3]);
    ((__nv_bfloat162*)lo)[i * 2]     = __nv_bfloat162(l[0], l[1]);
    ((__nv_bfloat162*)lo)[i * 2 + 1] = __nv_bfloat162(l[2], l[3]);
}

// ---------------------------------------------------------------------------
// RoPE fused with bf16 hi/lo split: dst = rope(src) * scale
// ---------------------------------------------------------------------------
__global__ void rope_bf16_kernel(const float* __restrict__ src,
                                 __nv_bfloat16* __restrict__ dh, __nv_bfloat16* __restrict__ dl,
                                 const float* __restrict__ cosp, const float* __restrict__ sinp,
                                 float scale)
{
    int idx = blockIdx.x * blockDim.x + threadIdx.x;
    const int total = BB * SS * HH * (HD / 2);
    if (idx >= total) return;
    int d  = idx & 63;
    int h  = (idx >> 6) & (HH - 1);
    int bs = idx >> 11;
    size_t base = (size_t)bs * DD + (h << 7);
    size_t cbase = (size_t)bs * HD;
    float c0 = cosp[cbase + d],      s0 = sinp[cbase + d];
    float c1 = cosp[cbase + d + 64], s1 = sinp[cbase + d + 64];
    float x0 = src[base + d], x1 = src[base + d + 64];
    float y0 = (x0 * c0 - x1 * s0) * scale;
    float y1 = (x1 * c1 + x0 * s1) * scale;
    __nv_bfloat16 hh, ll;
    split_hi_lo(y0, hh, ll); dh[base + d] = hh;      dl[base + d] = ll;
    split_hi_lo(y1, hh, ll); dh[base + d + 64] = hh; dl[base + d + 64] = ll;
}

// ---------------------------------------------------------------------------
// V transpose + hi/lo split: (b,s,h,hd) fp32 -> (b,h,d,k=s) bf16 x2
// ---------------------------------------------------------------------------
__global__ __launch_bounds__(256) void vt_conv_kernel(
    const float* __restrict__ V,
    __nv_bfloat16* __restrict__ Vh, __nv_bfloat16* __restrict__ Vl)
{
    __shared__ float tile[32][33];
    int bh = blockIdx.z;
    int b = bh >> 5, h = bh & 31;
    int s0 = blockIdx.x << 5, d0 = blockIdx.y << 5;
    int t = threadIdx.x;
    int row = t >> 3, c4 = (t & 7) << 2;

    float4 v = *(const float4*)(V + ((size_t)(b * SS + s0 + row)) * DD + (h << 7) + d0 + c4);
    tile[row][c4 + 0] = v.x; tile[row][c4 + 1] = v.y;
    tile[row][c4 + 2] = v.z; tile[row][c4 + 3] = v.w;
    __syncthreads();

    size_t obase = ((size_t)bh * HD + d0 + row) * SS + s0 + c4;
    float f[4] = { tile[c4 + 0][row], tile[c4 + 1][row], tile[c4 + 2][row], tile[c4 + 3][row] };
    __nv_bfloat16 hh[4], ll[4];
#pragma unroll
    for (int k = 0; k < 4; k++) split_hi_lo(f[k], hh[k], ll[k]);
    *(__nv_bfloat162*)&Vh[obase]     = __nv_bfloat162(hh[0], hh[1]);
    *(__nv_bfloat162*)&Vh[obase + 2] = __nv_bfloat162(hh[2], hh[3]);
    *(__nv_bfloat162*)&Vl[obase]     = __nv_bfloat162(ll[0], ll[1]);
    *(__nv_bfloat162*)&Vl[obase + 2] = __nv_bfloat162(ll[2], ll[3]);
}

// ---------------------------------------------------------------------------
// Softmax in place + fused bf16 hi/lo emission of P
// ---------------------------------------------------------------------------
__global__ __launch_bounds__(256) void softmax_pconv_kernel(
    float* __restrict__ P, __nv_bfloat16* __restrict__ Ph, __nv_bfloat16* __restrict__ Pl)
{
    size_t row = blockIdx.x;
    float* p = P + row * (size_t)SS;
    __nv_bfloat16* ph = Ph + row * (size_t)SS;
    __nv_bfloat16* pl = Pl + row * (size_t)SS;
    int t = threadIdx.x;
    float v[8];
    float mx = -3.4e38f;
#pragma unroll
    for (int i = 0; i < 8; i++) { v[i] = p[t + (i << 8)]; mx = fmaxf(mx, v[i]); }
#pragma unroll
    for (int o = 16; o; o >>= 1) mx = fmaxf(mx, __shfl_xor_sync(0xffffffffu, mx, o));
    __shared__ float rmax[8], rsum[8];
    if ((t & 31) == 0) rmax[t >> 5] = mx;
    __syncthreads();
    mx = rmax[0];
#pragma unroll
    for (int i = 1; i < 8; i++) mx = fmaxf(mx, rmax[i]);
    float sum = 0.f;
#pragma unroll
    for (int i = 0; i < 8; i++) { v[i] = __expf(v[i] - mx); sum += v[i]; }
#pragma unroll
    for (int o = 16; o; o >>= 1) sum += __shfl_xor_sync(0xffffffffu, sum, o);
    if ((t & 31) == 0) rsum[t >> 5] = sum;
    __syncthreads();
    sum = rsum[0];
#pragma unroll
    for (int i = 1; i < 8; i++) sum += rsum[i];
    float inv = 1.0f / sum;
#pragma unroll
    for (int i = 0; i < 8; i++) {
        float pv = v[i] * inv;
        int off = t + (i << 8);
        p[off] = pv;
        __nv_bfloat16 hh, ll;
        split_hi_lo(pv, hh, ll);
        ph[off] = hh;
        pl[off] = ll;
    }
}

// ---------------------------------------------------------------------------
extern "C" void kernel_launch(void* const* d_in, const int* in_sizes, int n_in,
                              void* d_out, int out_size)
{
    (void)in_sizes; (void)n_in; (void)out_size;
    const float* hidden = (const float*)d_in[0];
    const float* Wqk    = (const float*)d_in[1];
    const float* bqk    = (const float*)d_in[2];
    const float* Wv     = (const float*)d_in[3];
    const float* bv     = (const float*)d_in[4];
    const float* Wo     = (const float*)d_in[5];
    const float* cosp   = (const float*)d_in[6];
    const float* sinp   = (const float*)d_in[7];

    float* out   = (float*)d_out;
    float* attnw = out + (size_t)BB * SS * DD;

    float *qk_p, *v_p;
    cudaGetSymbolAddress((void**)&qk_p, g_qk);
    cudaGetSymbolAddress((void**)&v_p,  g_v);

    __nv_bfloat16 *hh, *hl, *qkh, *qkl, *vh, *vl, *oh, *ol;
    __nv_bfloat16 *qh, *ql, *kh, *kl, *vth, *vtl, *aoh, *aol, *ph, *pl;
    cudaGetSymbolAddress((void**)&hh,  g_hh);  cudaGetSymbolAddress((void**)&hl,  g_hl);
    cudaGetSymbolAddress((void**)&qkh, g_qkh); cudaGetSymbolAddress((void**)&qkl, g_qkl);
    cudaGetSymbolAddress((void**)&vh,  g_vh);  cudaGetSymbolAddress((void**)&vl,  g_vl);
    cudaGetSymbolAddress((void**)&oh,  g_oh);  cudaGetSymbolAddress((void**)&ol,  g_ol);
    cudaGetSymbolAddress((void**)&qh,  g_qh);  cudaGetSymbolAddress((void**)&ql,  g_ql);
    cudaGetSymbolAddress((void**)&kh,  g_kh);  cudaGetSymbolAddress((void**)&kl,  g_kl);
    cudaGetSymbolAddress((void**)&vth, g_vth); cudaGetSymbolAddress((void**)&vtl, g_vtl);
    cudaGetSymbolAddress((void**)&aoh, g_aoh); cudaGetSymbolAddress((void**)&aol, g_aol);
    cudaGetSymbolAddress((void**)&ph,  g_ph);  cudaGetSymbolAddress((void**)&pl,  g_pl);

    cudaFuncSetAttribute(gemm_tc,  cudaFuncAttributeMaxDynamicSharedMemorySize, GEMM_SMEM);
    cudaFuncSetAttribute(score_tc, cudaFuncAttributeMaxDynamicSharedMemorySize, SCORE_SMEM);
    cudaFuncSetAttribute(pv_tc,    cudaFuncAttributeMaxDynamicSharedMemorySize, GEMM_SMEM);

    const int cvblk = (int)((NELT / 4 + 255) / 256);
    conv_kernel<<<cvblk, 256>>>(hidden, hh, hl);
    conv_kernel<<<cvblk, 256>>>(Wqk, qkh, qkl);
    conv_kernel<<<cvblk, 256>>>(Wv,  vh,  vl);
    conv_kernel<<<cvblk, 256>>>(Wo,  oh,  ol);

    dim3 gg(DD / 128, (BB * SS) / 128);
    gemm_tc<<<gg, 256, GEMM_SMEM>>>(hh, hl, qkh, qkl, bqk, qk_p);
    gemm_tc<<<gg, 256, GEMM_SMEM>>>(hh, hl, vh,  vl,  bv,  v_p);

    const int rope_total = BB * SS * HH * (HD / 2);
    const float scale = 0.088388347648318447f;  // 128^-0.5
    rope_bf16_kernel<<<(rope_total + 255) / 256, 256>>>(hidden, qh, ql, cosp, sinp, scale);
    rope_bf16_kernel<<<(rope_total + 255) / 256, 256>>>(qk_p,   kh, kl, cosp, sinp, 1.0f);

    vt_conv_kernel<<<dim3(SS / 32, HD / 32, BB * HH), 256>>>(v_p, vth, vtl);

    score_tc<<<dim3(SS / 128, SS / 128, BB * HH), 256, SCORE_SMEM>>>(qh, ql, kh, kl, attnw);
    softmax_pconv_kernel<<<BB * HH * SS, 256>>>(attnw, ph, pl);
    pv_tc<<<dim3(SS / 128, BB * HH), 256, GEMM_SMEM>>>(ph, pl, vth, vtl, aoh, aol);

    gemm_tc<<<gg, 256, GEMM_SMEM>>>(aoh, aol, oh, ol, nullptr, out);
}

// round 5
// speedup vs baseline: 2.6835x; 1.0296x over previous
#include <cuda_runtime.h>
#include <cuda_bf16.h>
#include <cstdint>
#include <cstddef>

#define BB 2
#define SS 2048
#define DD 4096
#define HH 32
#define HD 128
#define NEG_INF -1000000000.0f

#define NELT ((size_t)BB * SS * DD)          // 16,777,216
#define NP   ((size_t)BB * HH * SS * SS)     // 268,435,456

// ---------------- scratch (device globals; alloc APIs forbidden) ----------
__device__ float g_qk[NELT];   // K projection (b,s,h,hd) fp32
__device__ float g_v [NELT];   // V projection (b,s,h,hd) fp32

__device__ __nv_bfloat16 g_hh[NELT],  g_hl[NELT];    // hidden hi/lo
__device__ __nv_bfloat16 g_qkh[NELT], g_qkl[NELT];   // Wqk hi/lo
__device__ __nv_bfloat16 g_vh[NELT],  g_vl[NELT];    // Wv hi/lo
__device__ __nv_bfloat16 g_oh[NELT],  g_ol[NELT];    // Wo hi/lo
__device__ __nv_bfloat16 g_qh[NELT],  g_ql[NELT];    // roped Q hi/lo (b,s,h,hd)
__device__ __nv_bfloat16 g_kh[NELT],  g_kl[NELT];    // roped K hi/lo (b,s,h,hd)
__device__ __nv_bfloat16 g_vth[NELT], g_vtl[NELT];   // V^T hi/lo (b,h,d,k)
__device__ __nv_bfloat16 g_aoh[NELT], g_aol[NELT];   // attn-out gathered hi/lo
__device__ __nv_bfloat16 g_ph[NP],    g_pl[NP];      // softmax P hi/lo

// ---------------- helpers ---------------------------------------------------
__device__ __forceinline__ uint32_t smem_u32(const void* p) {
    uint32_t a;
    asm("{ .reg .u64 t; cvta.to.shared.u64 t, %1; cvt.u32.u64 %0, t; }" : "=r"(a) : "l"(p));
    return a;
}
__device__ __forceinline__ void cp_async16(uint32_t dst, const void* src) {
    asm volatile("cp.async.cg.shared.global [%0], [%1], 16;" :: "r"(dst), "l"(src));
}
#define CP_COMMIT() asm volatile("cp.async.commit_group;" ::: "memory")
#define CP_WAIT2()  asm volatile("cp.async.wait_group 2;" ::: "memory")
#define CP_WAIT0()  asm volatile("cp.async.wait_group 0;" ::: "memory")

__device__ __forceinline__ void ldmx4(uint32_t* r, uint32_t addr) {
    asm volatile("ldmatrix.sync.aligned.m8n8.x4.shared.b16 {%0,%1,%2,%3}, [%4];"
                 : "=r"(r[0]), "=r"(r[1]), "=r"(r[2]), "=r"(r[3]) : "r"(addr));
}
__device__ __forceinline__ void mma16816(float* d, const uint32_t* a, const uint32_t* b) {
    asm volatile(
        "mma.sync.aligned.m16n8k16.row.col.f32.bf16.bf16.f32 "
        "{%0,%1,%2,%3}, {%4,%5,%6,%7}, {%8,%9}, {%0,%1,%2,%3};"
        : "+f"(d[0]), "+f"(d[1]), "+f"(d[2]), "+f"(d[3])
        : "r"(a[0]), "r"(a[1]), "r"(a[2]), "r"(a[3]), "r"(b[0]), "r"(b[1]));
}

// one 128x64 bf16 subtile loaded by 64 threads (ltid 0..63), XOR-swizzled
__device__ __forceinline__ void load_subtile(uint32_t dbase, const __nv_bfloat16* src,
                                             int ld, int ltid)
{
#pragma unroll
    for (int q = 0; q < 16; q++) {
        int idx = ltid + (q << 6);
        int r = idx >> 3, c = idx & 7;
        cp_async16(dbase + (r << 7) + ((c ^ (r & 7)) << 4),
                   src + (size_t)r * ld + (c << 3));
    }
}

// one K=16 MMA step for the 128x128 CTA tile with hi/lo 3-product accumulate.
__device__ __forceinline__ void hmma_block(
    uint32_t tAh, uint32_t tAl, uint32_t tBh, uint32_t tBl,
    int ksl, int wm, int wn, int lr, int lc, float (&acc)[4][4][4])
{
    uint32_t ah[4][4], al[4][4], bh[4][2], bl[4][2];
#pragma unroll
    for (int mi = 0; mi < 4; mi++) {
        int r = wm + mi * 16 + lr;
        uint32_t off = (uint32_t)(r << 7) + ((((ksl * 2 + lc) ^ (r & 7)) << 4));
        ldmx4(ah[mi], tAh + off);
        ldmx4(al[mi], tAl + off);
    }
#pragma unroll
    for (int g = 0; g < 2; g++) {
        int r = wn + g * 16 + lr;
        uint32_t off = (uint32_t)(r << 7) + ((((ksl * 2 + lc) ^ (r & 7)) << 4));
        uint32_t rb[4];
        ldmx4(rb, tBh + off);
        bh[g*2+0][0] = rb[0]; bh[g*2+0][1] = rb[2];
        bh[g*2+1][0] = rb[1]; bh[g*2+1][1] = rb[3];
        ldmx4(rb, tBl + off);
        bl[g*2+0][0] = rb[0]; bl[g*2+0][1] = rb[2];
        bl[g*2+1][0] = rb[1]; bl[g*2+1][1] = rb[3];
    }
#pragma unroll
    for (int mi = 0; mi < 4; mi++)
#pragma unroll
        for (int ni = 0; ni < 4; ni++) {
            mma16816(acc[mi][ni], ah[mi], bh[ni]);
            mma16816(acc[mi][ni], ah[mi], bl[ni]);
            mma16816(acc[mi][ni], al[mi], bh[ni]);
        }
}

__device__ __forceinline__ void split_hi_lo(float f, __nv_bfloat16& h, __nv_bfloat16& l) {
    h = __float2bfloat16(f);
    l = __float2bfloat16(f - __bfloat162float(h));
}

#define NSTAGE 3
#define TILE_BYTES 16384            // 128 rows x 128B
#define STAGE_BYTES (4 * TILE_BYTES)
#define GEMM_SMEM (NSTAGE * STAGE_BYTES)   // 196608
#define SCORE_SMEM 131072

// ---------------------------------------------------------------------------
// HMMA bf16 hi/lo GEMM: C[4096][4096] = A @ W^T (+bias), fp32-accurate.
// ---------------------------------------------------------------------------
__global__ __launch_bounds__(256) void gemm_tc(
    const __nv_bfloat16* __restrict__ Ah, const __nv_bfloat16* __restrict__ Al,
    const __nv_bfloat16* __restrict__ Bh, const __nv_bfloat16* __restrict__ Bl,
    const float* __restrict__ bias, float* __restrict__ C)
{
    extern __shared__ char smem[];
    const uint32_t sbase = smem_u32(smem);
    const int t = threadIdx.x;
    const int wid = t >> 5, lane = t & 31;
    const int bm = blockIdx.y << 7, bn = blockIdx.x << 7;

    const int ltile = t >> 6, ltid = t & 63;
    const __nv_bfloat16* lsrc =
        (ltile == 0) ? Ah + (size_t)bm * DD :
        (ltile == 1) ? Al + (size_t)bm * DD :
        (ltile == 2) ? Bh + (size_t)bn * DD :
                       Bl + (size_t)bn * DD;

    auto load_stage = [&](int stg, int kc) {
        load_subtile(sbase + stg * STAGE_BYTES + (ltile << 14), lsrc + kc, DD, ltid);
        CP_COMMIT();
    };

    load_stage(0, 0);
    load_stage(1, 64);
    load_stage(2, 128);

    const int wm = (wid & 1) << 6;
    const int wn = (wid >> 1) << 5;
    const int lr = lane & 15, lc = lane >> 4;

    float acc[4][4][4] = {};
    const int iters = DD / 64;

    for (int it = 0; it < iters; it++) {
        int stg = it % NSTAGE;
        CP_WAIT2();
        __syncthreads();
        uint32_t sb = sbase + stg * STAGE_BYTES;
#pragma unroll
        for (int ks = 0; ks < 4; ks++)
            hmma_block(sb, sb + TILE_BYTES, sb + 2 * TILE_BYTES, sb + 3 * TILE_BYTES,
                       ks, wm, wn, lr, lc, acc);
        __syncthreads();
        if (it + NSTAGE < iters) load_stage(stg, (it + NSTAGE) * 64);
        else CP_COMMIT();
    }

    const int qr = lane >> 2, qc = (lane & 3) << 1;
#pragma unroll
    for (int mi = 0; mi < 4; mi++) {
#pragma unroll
        for (int ni = 0; ni < 4; ni++) {
            int col = bn + wn + ni * 8 + qc;
            float bx = 0.f, by = 0.f;
            if (bias) { bx = bias[col]; by = bias[col + 1]; }
            int row0 = bm + wm + mi * 16 + qr;
            float2 v0 = { acc[mi][ni][0] + bx, acc[mi][ni][1] + by };
            float2 v1 = { acc[mi][ni][2] + bx, acc[mi][ni][3] + by };
            *(float2*)&C[(size_t)row0 * DD + col] = v0;
            *(float2*)&C[(size_t)(row0 + 8) * DD + col] = v1;
        }
    }
}

// ---------------------------------------------------------------------------
// score_tc: P[bh, q, k] = Q . K (hi/lo HMMA), causal mask, fp32 out.
// Above-diagonal tiles write NOTHING (softmax synthesizes the suffix).
// ---------------------------------------------------------------------------
__global__ __launch_bounds__(256) void score_tc(
    const __nv_bfloat16* __restrict__ Qh, const __nv_bfloat16* __restrict__ Ql,
    const __nv_bfloat16* __restrict__ Kh, const __nv_bfloat16* __restrict__ Kl,
    float* __restrict__ P)
{
    extern __shared__ char smem[];
    const int q0 = blockIdx.y << 7, k0 = blockIdx.x << 7;
    if (k0 > q0) return;          // softmax handles the suffix analytically

    const int bh = blockIdx.z;
    const int b = bh >> 5, h = bh & 31;
    const size_t pbase = ((size_t)bh * SS + q0) * SS + k0;
    const int t = threadIdx.x;
    const uint32_t sbase = smem_u32(smem);
    const int wid = t >> 5, lane = t & 31;

    const int ltile = t >> 6, ltid = t & 63;
    const __nv_bfloat16* lsrc =
        (ltile == 0) ? Qh + (size_t)(b * SS + q0) * DD + (h << 7) :
        (ltile == 1) ? Ql + (size_t)(b * SS + q0) * DD + (h << 7) :
        (ltile == 2) ? Kh + (size_t)(b * SS + k0) * DD + (h << 7) :
                       Kl + (size_t)(b * SS + k0) * DD + (h << 7);

    load_subtile(sbase + (ltile << 15),         lsrc,      DD, ltid);
    load_subtile(sbase + (ltile << 15) + 16384, lsrc + 64, DD, ltid);
    CP_COMMIT();
    CP_WAIT0();
    __syncthreads();

    const int wm = (wid & 1) << 6;
    const int wn = (wid >> 1) << 5;
    const int lr = lane & 15, lc = lane >> 4;
    float acc[4][4][4] = {};

#pragma unroll
    for (int ks = 0; ks < 8; ks++) {
        uint32_t hb = sbase + (ks >> 2) * 16384;
        hmma_block(hb, hb + 32768, hb + 65536, hb + 98304, ks & 3, wm, wn, lr, lc, acc);
    }

    const int qr = lane >> 2, qc = (lane & 3) << 1;
#pragma unroll
    for (int mi = 0; mi < 4; mi++) {
#pragma unroll
        for (int ni = 0; ni < 4; ni++) {
            int rl = wm + mi * 16 + qr;
            int cl = wn + ni * 8 + qc;
            int k = k0 + cl;
            int qA = q0 + rl, qB = qA + 8;
            float2 v0 = { (k <= qA) ? acc[mi][ni][0] : NEG_INF,
                          (k + 1 <= qA) ? acc[mi][ni][1] : NEG_INF };
            float2 v1 = { (k <= qB) ? acc[mi][ni][2] : NEG_INF,
                          (k + 1 <= qB) ? acc[mi][ni][3] : NEG_INF };
            *(float2*)&P[pbase + (size_t)rl * SS + cl] = v0;
            *(float2*)&P[pbase + (size_t)(rl + 8) * SS + cl] = v1;
        }
    }
}

// ---------------------------------------------------------------------------
// pv_tc: AO[b, q, h*128+d] = sum_k P[bh,q,k] * Vt[bh,d,k]; causal k-bound.
// ---------------------------------------------------------------------------
__global__ __launch_bounds__(256) void pv_tc(
    const __nv_bfloat16* __restrict__ Ph, const __nv_bfloat16* __restrict__ Pl,
    const __nv_bfloat16* __restrict__ Vth, const __nv_bfloat16* __restrict__ Vtl,
    __nv_bfloat16* __restrict__ AOh, __nv_bfloat16* __restrict__ AOl)
{
    extern __shared__ char smem[];
    const uint32_t sbase = smem_u32(smem);
    const int t = threadIdx.x;
    const int wid = t >> 5, lane = t & 31;
    const int q0 = blockIdx.x << 7;
    const int bh = blockIdx.y;
    const int b = bh >> 5, h = bh & 31;

    const int ltile = t >> 6, ltid = t & 63;
    const __nv_bfloat16* lsrc =
        (ltile == 0) ? Ph  + ((size_t)bh * SS + q0) * SS :
        (ltile == 1) ? Pl  + ((size_t)bh * SS + q0) * SS :
        (ltile == 2) ? Vth + (size_t)bh * HD * SS :
                       Vtl + (size_t)bh * HD * SS;

    const int iters = (q0 >> 6) + 2;

    auto load_stage = [&](int stg, int kc) {
        load_subtile(sbase + stg * STAGE_BYTES + (ltile << 14), lsrc + kc, SS, ltid);
        CP_COMMIT();
    };

#pragma unroll
    for (int s = 0; s < NSTAGE; s++) {
        if (s < iters) load_stage(s, s * 64);
        else CP_COMMIT();
    }

    const int wm = (wid & 1) << 6;
    const int wn = (wid >> 1) << 5;
    const int lr = lane & 15, lc = lane >> 4;
    float acc[4][4][4] = {};

    for (int it = 0; it < iters; it++) {
        int stg = it % NSTAGE;
        CP_WAIT2();
        __syncthreads();
        uint32_t sb = sbase + stg * STAGE_BYTES;
#pragma unroll
        for (int ks = 0; ks < 4; ks++)
            hmma_block(sb, sb + TILE_BYTES, sb + 2 * TILE_BYTES, sb + 3 * TILE_BYTES,
                       ks, wm, wn, lr, lc, acc);
        __syncthreads();
        if (it + NSTAGE < iters) load_stage(stg, (it + NSTAGE) * 64);
        else CP_COMMIT();
    }

    const int qr = lane >> 2, qc = (lane & 3) << 1;
#pragma unroll
    for (int mi = 0; mi < 4; mi++) {
#pragma unroll
        for (int ni = 0; ni < 4; ni++) {
            int row = q0 + wm + mi * 16 + qr;
            int col = (h << 7) + wn + ni * 8 + qc;
            size_t m0 = ((size_t)b * SS + row) * DD + col;
            size_t m1 = m0 + (size_t)8 * DD;
            __nv_bfloat16 h0, l0, h1, l1;
            split_hi_lo(acc[mi][ni][0], h0, l0);
            split_hi_lo(acc[mi][ni][1], h1, l1);
            *(__nv_bfloat162*)&AOh[m0] = __nv_bfloat162(h0, h1);
            *(__nv_bfloat162*)&AOl[m0] = __nv_bfloat162(l0, l1);
            split_hi_lo(acc[mi][ni][2], h0, l0);
            split_hi_lo(acc[mi][ni][3], h1, l1);
            *(__nv_bfloat162*)&AOh[m1] = __nv_bfloat162(h0, h1);
            *(__nv_bfloat162*)&AOl[m1] = __nv_bfloat162(l0, l1);
        }
    }
}

// ---------------------------------------------------------------------------
// fp32 -> bf16 hi/lo split (weights / hidden)
// ---------------------------------------------------------------------------
__global__ void conv_kernel(const float* __restrict__ x,
                            __nv_bfloat16* __restrict__ hi, __nv_bfloat16* __restrict__ lo)
{
    size_t i = (size_t)blockIdx.x * blockDim.x + threadIdx.x;
    if (i >= NELT / 4) return;
    float4 v = ((const float4*)x)[i];
    float f[4] = { v.x, v.y, v.z, v.w };
    __nv_bfloat16 h[4], l[4];
#pragma unroll
    for (int k = 0; k < 4; k++) split_hi_lo(f[k], h[k], l[k]);
    ((__nv_bfloat162*)hi)[i * 2]     = __nv_bfloat162(h[0], h[1]);
    ((__nv_bfloat162*)hi)[i * 2 + 1] = __nv_bfloat162(h[2], h[3]);
    ((__nv_bfloat162*)lo)[i * 2]     = __nv_bfloat162(l[0], l[1]);
    ((__nv_bfloat162*)lo)[i * 2 + 1] = __nv_bfloat162(l[2], l[3]);
}

// ---------------------------------------------------------------------------
// RoPE fused with bf16 hi/lo split
// ---------------------------------------------------------------------------
__global__ void rope_bf16_kernel(const float* __restrict__ src,
                                 __nv_bfloat16* __restrict__ dh, __nv_bfloat16* __restrict__ dl,
                                 const float* __restrict__ cosp, const float* __restrict__ sinp,
                                 float scale)
{
    int idx = blockIdx.x * blockDim.x + threadIdx.x;
    const int total = BB * SS * HH * (HD / 2);
    if (idx >= total) return;
    int d  = idx & 63;
    int h  = (idx >> 6) & (HH - 1);
    int bs = idx >> 11;
    size_t base = (size_t)bs * DD + (h << 7);
    size_t cbase = (size_t)bs * HD;
    float c0 = cosp[cbase + d],      s0 = sinp[cbase + d];
    float c1 = cosp[cbase + d + 64], s1 = sinp[cbase + d + 64];
    float x0 = src[base + d], x1 = src[base + d + 64];
    float y0 = (x0 * c0 - x1 * s0) * scale;
    float y1 = (x1 * c1 + x0 * s1) * scale;
    __nv_bfloat16 hh, ll;
    split_hi_lo(y0, hh, ll); dh[base + d] = hh;      dl[base + d] = ll;
    split_hi_lo(y1, hh, ll); dh[base + d + 64] = hh; dl[base + d + 64] = ll;
}

// ---------------------------------------------------------------------------
// V transpose + hi/lo split: (b,s,h,hd) fp32 -> (b,h,d,k=s) bf16 x2
// ---------------------------------------------------------------------------
__global__ __launch_bounds__(256) void vt_conv_kernel(
    const float* __restrict__ V,
    __nv_bfloat16* __restrict__ Vh, __nv_bfloat16* __restrict__ Vl)
{
    __shared__ float tile[32][33];
    int bh = blockIdx.z;
    int b = bh >> 5, h = bh & 31;
    int s0 = blockIdx.x << 5, d0 = blockIdx.y << 5;
    int t = threadIdx.x;
    int row = t >> 3, c4 = (t & 7) << 2;

    float4 v = *(const float4*)(V + ((size_t)(b * SS + s0 + row)) * DD + (h << 7) + d0 + c4);
    tile[row][c4 + 0] = v.x; tile[row][c4 + 1] = v.y;
    tile[row][c4 + 2] = v.z; tile[row][c4 + 3] = v.w;
    __syncthreads();

    size_t obase = ((size_t)bh * HD + d0 + row) * SS + s0 + c4;
    float f[4] = { tile[c4 + 0][row], tile[c4 + 1][row], tile[c4 + 2][row], tile[c4 + 3][row] };
    __nv_bfloat16 hh[4], ll[4];
#pragma unroll
    for (int k = 0; k < 4; k++) split_hi_lo(f[k], hh[k], ll[k]);
    *(__nv_bfloat162*)&Vh[obase]     = __nv_bfloat162(hh[0], hh[1]);
    *(__nv_bfloat162*)&Vh[obase + 2] = __nv_bfloat162(hh[2], hh[3]);
    *(__nv_bfloat162*)&Vl[obase]     = __nv_bfloat162(ll[0], ll[1]);
    *(__nv_bfloat162*)&Vl[obase + 2] = __nv_bfloat162(ll[2], ll[3]);
}

// ---------------------------------------------------------------------------
// Causal softmax in place + bf16 hi/lo emission.
// Reads only k <= q; writes full fp32 row (zeros past q); writes bf16 P only
// up to the row's 128-aligned causal bound (all pv_tc ever reads).
// ---------------------------------------------------------------------------
__global__ __launch_bounds__(256) void softmax_pconv_kernel(
    float* __restrict__ P, __nv_bfloat16* __restrict__ Ph, __nv_bfloat16* __restrict__ Pl)
{
    size_t row = blockIdx.x;
    int q = (int)(row & (SS - 1));
    int kend = ((q >> 7) + 1) << 7;            // 128-aligned causal bound
    float* p = P + row * (size_t)SS;
    __nv_bfloat16* ph = Ph + row * (size_t)SS;
    __nv_bfloat16* pl = Pl + row * (size_t)SS;
    int t = threadIdx.x;
    float v[8];
    float mx = -3.4e38f;
#pragma unroll
    for (int i = 0; i < 8; i++) {
        int off = t + (i << 8);
        v[i] = (off <= q) ? p[off] : -3.4e38f;
        mx = fmaxf(mx, v[i]);
    }
#pragma unroll
    for (int o = 16; o; o >>= 1) mx = fmaxf(mx, __shfl_xor_sync(0xffffffffu, mx, o));
    __shared__ float rmax[8], rsum[8];
    if ((t & 31) == 0) rmax[t >> 5] = mx;
    __syncthreads();
    mx = rmax[0];
#pragma unroll
    for (int i = 1; i < 8; i++) mx = fmaxf(mx, rmax[i]);
    float sum = 0.f;
#pragma unroll
    for (int i = 0; i < 8; i++) {
        int off = t + (i << 8);
        v[i] = (off <= q) ? __expf(v[i] - mx) : 0.f;
        sum += v[i];
    }
#pragma unroll
    for (int o = 16; o; o >>= 1) sum += __shfl_xor_sync(0xffffffffu, sum, o);
    if ((t & 31) == 0) rsum[t >> 5] = sum;
    __syncthreads();
    sum = rsum[0];
#pragma unroll
    for (int i = 1; i < 8; i++) sum += rsum[i];
    float inv = 1.0f / sum;
#pragma unroll
    for (int i = 0; i < 8; i++) {
        int off = t + (i << 8);
        float pv = v[i] * inv;                 // exactly 0 past q
        p[off] = pv;
        if (off < kend) {
            __nv_bfloat16 hh, ll;
            split_hi_lo(pv, hh, ll);
            ph[off] = hh;
            pl[off] = ll;
        }
    }
}

// ---------------------------------------------------------------------------
extern "C" void kernel_launch(void* const* d_in, const int* in_sizes, int n_in,
                              void* d_out, int out_size)
{
    (void)in_sizes; (void)n_in; (void)out_size;
    const float* hidden = (const float*)d_in[0];
    const float* Wqk    = (const float*)d_in[1];
    const float* bqk    = (const float*)d_in[2];
    const float* Wv     = (const float*)d_in[3];
    const float* bv     = (const float*)d_in[4];
    const float* Wo     = (const float*)d_in[5];
    const float* cosp   = (const float*)d_in[6];
    const float* sinp   = (const float*)d_in[7];

    float* out   = (float*)d_out;
    float* attnw = out + (size_t)BB * SS * DD;

    float *qk_p, *v_p;
    cudaGetSymbolAddress((void**)&qk_p, g_qk);
    cudaGetSymbolAddress((void**)&v_p,  g_v);

    __nv_bfloat16 *hh, *hl, *qkh, *qkl, *vh, *vl, *oh, *ol;
    __nv_bfloat16 *qh, *ql, *kh, *kl, *vth, *vtl, *aoh, *aol, *ph, *pl;
    cudaGetSymbolAddress((void**)&hh,  g_hh);  cudaGetSymbolAddress((void**)&hl,  g_hl);
    cudaGetSymbolAddress((void**)&qkh, g_qkh); cudaGetSymbolAddress((void**)&qkl, g_qkl);
    cudaGetSymbolAddress((void**)&vh,  g_vh);  cudaGetSymbolAddress((void**)&vl,  g_vl);
    cudaGetSymbolAddress((void**)&oh,  g_oh);  cudaGetSymbolAddress((void**)&ol,  g_ol);
    cudaGetSymbolAddress((void**)&qh,  g_qh);  cudaGetSymbolAddress((void**)&ql,  g_ql);
    cudaGetSymbolAddress((void**)&kh,  g_kh);  cudaGetSymbolAddress((void**)&kl,  g_kl);
    cudaGetSymbolAddress((void**)&vth, g_vth); cudaGetSymbolAddress((void**)&vtl, g_vtl);
    cudaGetSymbolAddress((void**)&aoh, g_aoh); cudaGetSymbolAddress((void**)&aol, g_aol);
    cudaGetSymbolAddress((void**)&ph,  g_ph);  cudaGetSymbolAddress((void**)&pl,  g_pl);

    cudaFuncSetAttribute(gemm_tc,  cudaFuncAttributeMaxDynamicSharedMemorySize, GEMM_SMEM);
    cudaFuncSetAttribute(score_tc, cudaFuncAttributeMaxDynamicSharedMemorySize, SCORE_SMEM);
    cudaFuncSetAttribute(pv_tc,    cudaFuncAttributeMaxDynamicSharedMemorySize, GEMM_SMEM);

    const int cvblk = (int)((NELT / 4 + 255) / 256);
    conv_kernel<<<cvblk, 256>>>(hidden, hh, hl);
    conv_kernel<<<cvblk, 256>>>(Wqk, qkh, qkl);
    conv_kernel<<<cvblk, 256>>>(Wv,  vh,  vl);
    conv_kernel<<<cvblk, 256>>>(Wo,  oh,  ol);

    dim3 gg(DD / 128, (BB * SS) / 128);
    gemm_tc<<<gg, 256, GEMM_SMEM>>>(hh, hl, qkh, qkl, bqk, qk_p);
    gemm_tc<<<gg, 256, GEMM_SMEM>>>(hh, hl, vh,  vl,  bv,  v_p);

    const int rope_total = BB * SS * HH * (HD / 2);
    const float scale = 0.088388347648318447f;  // 128^-0.5
    rope_bf16_kernel<<<(rope_total + 255) / 256, 256>>>(hidden, qh, ql, cosp, sinp, scale);
    rope_bf16_kernel<<<(rope_total + 255) / 256, 256>>>(qk_p,   kh, kl, cosp, sinp, 1.0f);

    vt_conv_kernel<<<dim3(SS / 32, HD / 32, BB * HH), 256>>>(v_p, vth, vtl);

    score_tc<<<dim3(SS / 128, SS / 128, BB * HH), 256, SCORE_SMEM>>>(qh, ql, kh, kl, attnw);
    softmax_pconv_kernel<<<BB * HH * SS, 256>>>(attnw, ph, pl);
    pv_tc<<<dim3(SS / 128, BB * HH), 256, GEMM_SMEM>>>(ph, pl, vth, vtl, aoh, aol);

    gemm_tc<<<gg, 256, GEMM_SMEM>>>(aoh, aol, oh, ol, nullptr, out);
}

// round 6
// speedup vs baseline: 2.8232x; 1.0521x over previous
#include <cuda_runtime.h>
#include <cuda_bf16.h>
#include <cstdint>
#include <cstddef>

#define BB 2
#define SS 2048
#define DD 4096
#define HH 32
#define HD 128
#define NEG_INF -1000000000.0f

#define NELT ((size_t)BB * SS * DD)          // 16,777,216
#define NP   ((size_t)BB * HH * SS * SS)     // 268,435,456

// ---------------- scratch (device globals; alloc APIs forbidden) ----------
__device__ float g_qk[NELT];   // K projection (b,s,h,hd) fp32
__device__ float g_v [NELT];   // V projection (b,s,h,hd) fp32

__device__ __nv_bfloat16 g_hh[NELT],  g_hl[NELT];    // hidden hi/lo
__device__ __nv_bfloat16 g_qkh[NELT], g_qkl[NELT];   // Wqk hi/lo
__device__ __nv_bfloat16 g_vh[NELT],  g_vl[NELT];    // Wv hi/lo
__device__ __nv_bfloat16 g_oh[NELT],  g_ol[NELT];    // Wo hi/lo
__device__ __nv_bfloat16 g_qh[NELT],  g_ql[NELT];    // roped Q hi/lo (b,s,h,hd)
__device__ __nv_bfloat16 g_kh[NELT],  g_kl[NELT];    // roped K hi/lo (b,s,h,hd)
__device__ __nv_bfloat16 g_vth[NELT], g_vtl[NELT];   // V^T hi/lo (b,h,d,k)
__device__ __nv_bfloat16 g_aoh[NELT], g_aol[NELT];   // attn-out gathered hi/lo
__device__ __nv_bfloat16 g_ph[NP],    g_pl[NP];      // softmax P hi/lo

// ---------------- helpers ---------------------------------------------------
__device__ __forceinline__ uint32_t smem_u32(const void* p) {
    uint32_t a;
    asm("{ .reg .u64 t; cvta.to.shared.u64 t, %1; cvt.u32.u64 %0, t; }" : "=r"(a) : "l"(p));
    return a;
}
__device__ __forceinline__ void cp_async16(uint32_t dst, const void* src) {
    asm volatile("cp.async.cg.shared.global [%0], [%1], 16;" :: "r"(dst), "l"(src));
}
#define CP_COMMIT() asm volatile("cp.async.commit_group;" ::: "memory")
#define CP_WAIT2()  asm volatile("cp.async.wait_group 2;" ::: "memory")

__device__ __forceinline__ void ldmx4(uint32_t* r, uint32_t addr) {
    asm volatile("ldmatrix.sync.aligned.m8n8.x4.shared.b16 {%0,%1,%2,%3}, [%4];"
                 : "=r"(r[0]), "=r"(r[1]), "=r"(r[2]), "=r"(r[3]) : "r"(addr));
}
__device__ __forceinline__ void mma16816(float* d, const uint32_t* a, const uint32_t* b) {
    asm volatile(
        "mma.sync.aligned.m16n8k16.row.col.f32.bf16.bf16.f32 "
        "{%0,%1,%2,%3}, {%4,%5,%6,%7}, {%8,%9}, {%0,%1,%2,%3};"
        : "+f"(d[0]), "+f"(d[1]), "+f"(d[2]), "+f"(d[3])
        : "r"(a[0]), "r"(a[1]), "r"(a[2]), "r"(a[3]), "r"(b[0]), "r"(b[1]));
}
__device__ __forceinline__ void split_hi_lo(float f, __nv_bfloat16& h, __nv_bfloat16& l) {
    h = __float2bfloat16(f);
    l = __float2bfloat16(f - __bfloat162float(h));
}

// ---- BK=32 pipeline config: 2 CTAs/SM --------------------------------------
#define NSTAGE 3
#define TILE_B 8192                    // 128 rows x 64B (32 bf16)
#define STAGE_B (4 * TILE_B)           // 32 KB (Ah, Al, Bh, Bl)
#define PIPE_SMEM (NSTAGE * STAGE_B)   // 96 KB -> 2 CTAs/SM

// swizzled byte offset within a 128x32 tile (64B rows)
__device__ __forceinline__ uint32_t sw_off32(int r, int chunk) {
    return (uint32_t)(r << 6) + (((chunk ^ ((r >> 1) & 3)) << 4));
}

// one 128x32 bf16 subtile loaded by 64 threads (ltid 0..63)
__device__ __forceinline__ void load_subtile32(uint32_t dbase, const __nv_bfloat16* src,
                                               int ld, int ltid)
{
#pragma unroll
    for (int q = 0; q < 8; q++) {
        int idx = ltid + (q << 6);           // 0..511
        int r = idx >> 2, c = idx & 3;
        cp_async16(dbase + sw_off32(r, c), src + (size_t)r * ld + (c << 3));
    }
}

// one K=16 MMA step (ks in 0..1) for a 128x128 tile; register-lean: B frags
// resident, A frags loaded per-mi.
__device__ __forceinline__ void hmma_block32(
    uint32_t sb, int ks, int wm, int wn, int lr, int lc, float (&acc)[4][4][4])
{
    const int chunk = ks * 2 + lc;
    uint32_t bh[4][2], bl[4][2];
#pragma unroll
    for (int g = 0; g < 2; g++) {
        int r = wn + g * 16 + lr;
        uint32_t off = sw_off32(r, chunk);
        uint32_t rb[4];
        ldmx4(rb, sb + 2 * TILE_B + off);    // Bh
        bh[g*2+0][0] = rb[0]; bh[g*2+0][1] = rb[2];
        bh[g*2+1][0] = rb[1]; bh[g*2+1][1] = rb[3];
        ldmx4(rb, sb + 3 * TILE_B + off);    // Bl
        bl[g*2+0][0] = rb[0]; bl[g*2+0][1] = rb[2];
        bl[g*2+1][0] = rb[1]; bl[g*2+1][1] = rb[3];
    }
#pragma unroll
    for (int mi = 0; mi < 4; mi++) {
        int r = wm + mi * 16 + lr;
        uint32_t off = sw_off32(r, chunk);
        uint32_t ah[4], al[4];
        ldmx4(ah, sb + off);                 // Ah
        ldmx4(al, sb + TILE_B + off);        // Al
#pragma unroll
        for (int ni = 0; ni < 4; ni++) {
            mma16816(acc[mi][ni], ah, bh[ni]);
            mma16816(acc[mi][ni], ah, bl[ni]);
            mma16816(acc[mi][ni], al, bh[ni]);
        }
    }
}

// ---------------------------------------------------------------------------
// HMMA bf16 hi/lo GEMM: C[4096][4096] = A @ W^T (+bias), fp32-accurate.
// ---------------------------------------------------------------------------
__global__ __launch_bounds__(256, 2) void gemm_tc(
    const __nv_bfloat16* __restrict__ Ah, const __nv_bfloat16* __restrict__ Al,
    const __nv_bfloat16* __restrict__ Bh, const __nv_bfloat16* __restrict__ Bl,
    const float* __restrict__ bias, float* __restrict__ C)
{
    extern __shared__ char smem[];
    const uint32_t sbase = smem_u32(smem);
    const int t = threadIdx.x;
    const int wid = t >> 5, lane = t & 31;
    const int bm = blockIdx.y << 7, bn = blockIdx.x << 7;

    const int ltile = t >> 6, ltid = t & 63;
    const __nv_bfloat16* lsrc =
        (ltile == 0) ? Ah + (size_t)bm * DD :
        (ltile == 1) ? Al + (size_t)bm * DD :
        (ltile == 2) ? Bh + (size_t)bn * DD :
                       Bl + (size_t)bn * DD;

    auto load_stage = [&](int stg, int kc) {
        load_subtile32(sbase + stg * STAGE_B + ltile * TILE_B, lsrc + kc, DD, ltid);
        CP_COMMIT();
    };

    load_stage(0, 0);
    load_stage(1, 32);
    load_stage(2, 64);

    const int wm = (wid & 1) << 6;
    const int wn = (wid >> 1) << 5;
    const int lr = lane & 15, lc = lane >> 4;

    float acc[4][4][4] = {};
    const int iters = DD / 32;

    for (int it = 0; it < iters; it++) {
        int stg = it % NSTAGE;
        CP_WAIT2();
        __syncthreads();
        uint32_t sb = sbase + stg * STAGE_B;
        hmma_block32(sb, 0, wm, wn, lr, lc, acc);
        hmma_block32(sb, 1, wm, wn, lr, lc, acc);
        __syncthreads();
        if (it + NSTAGE < iters) load_stage(stg, (it + NSTAGE) * 32);
        else CP_COMMIT();
    }

    const int qr = lane >> 2, qc = (lane & 3) << 1;
#pragma unroll
    for (int mi = 0; mi < 4; mi++) {
#pragma unroll
        for (int ni = 0; ni < 4; ni++) {
            int col = bn + wn + ni * 8 + qc;
            float bx = 0.f, by = 0.f;
            if (bias) { bx = bias[col]; by = bias[col + 1]; }
            int row0 = bm + wm + mi * 16 + qr;
            float2 v0 = { acc[mi][ni][0] + bx, acc[mi][ni][1] + by };
            float2 v1 = { acc[mi][ni][2] + bx, acc[mi][ni][3] + by };
            *(float2*)&C[(size_t)row0 * DD + col] = v0;
            *(float2*)&C[(size_t)(row0 + 8) * DD + col] = v1;
        }
    }
}

// ---------------------------------------------------------------------------
// score_tc: P[bh, q, k] = Q . K (hi/lo HMMA), causal mask, fp32 out.
// Above-diagonal tiles write NOTHING (softmax synthesizes the suffix).
// ---------------------------------------------------------------------------
__global__ __launch_bounds__(256, 2) void score_tc(
    const __nv_bfloat16* __restrict__ Qh, const __nv_bfloat16* __restrict__ Ql,
    const __nv_bfloat16* __restrict__ Kh, const __nv_bfloat16* __restrict__ Kl,
    float* __restrict__ P)
{
    extern __shared__ char smem[];
    const int q0 = blockIdx.y << 7, k0 = blockIdx.x << 7;
    if (k0 > q0) return;

    const int bh = blockIdx.z;
    const int b = bh >> 5, h = bh & 31;
    const size_t pbase = ((size_t)bh * SS + q0) * SS + k0;
    const int t = threadIdx.x;
    const uint32_t sbase = smem_u32(smem);
    const int wid = t >> 5, lane = t & 31;

    const int ltile = t >> 6, ltid = t & 63;
    const __nv_bfloat16* lsrc =
        (ltile == 0) ? Qh + (size_t)(b * SS + q0) * DD + (h << 7) :
        (ltile == 1) ? Ql + (size_t)(b * SS + q0) * DD + (h << 7) :
        (ltile == 2) ? Kh + (size_t)(b * SS + k0) * DD + (h << 7) :
                       Kl + (size_t)(b * SS + k0) * DD + (h << 7);

    auto load_stage = [&](int stg, int kc) {
        load_subtile32(sbase + stg * STAGE_B + ltile * TILE_B, lsrc + kc, DD, ltid);
        CP_COMMIT();
    };

    load_stage(0, 0);
    load_stage(1, 32);
    load_stage(2, 64);

    const int wm = (wid & 1) << 6;
    const int wn = (wid >> 1) << 5;
    const int lr = lane & 15, lc = lane >> 4;
    float acc[4][4][4] = {};
    const int iters = HD / 32;    // 4

    for (int it = 0; it < iters; it++) {
        int stg = it % NSTAGE;
        CP_WAIT2();
        __syncthreads();
        uint32_t sb = sbase + stg * STAGE_B;
        hmma_block32(sb, 0, wm, wn, lr, lc, acc);
        hmma_block32(sb, 1, wm, wn, lr, lc, acc);
        __syncthreads();
        if (it + NSTAGE < iters) load_stage(stg, (it + NSTAGE) * 32);
        else CP_COMMIT();
    }

    const int qr = lane >> 2, qc = (lane & 3) << 1;
#pragma unroll
    for (int mi = 0; mi < 4; mi++) {
#pragma unroll
        for (int ni = 0; ni < 4; ni++) {
            int rl = wm + mi * 16 + qr;
            int cl = wn + ni * 8 + qc;
            int k = k0 + cl;
            int qA = q0 + rl, qB = qA + 8;
            float2 v0 = { (k <= qA) ? acc[mi][ni][0] : NEG_INF,
                          (k + 1 <= qA) ? acc[mi][ni][1] : NEG_INF };
            float2 v1 = { (k <= qB) ? acc[mi][ni][2] : NEG_INF,
                          (k + 1 <= qB) ? acc[mi][ni][3] : NEG_INF };
            *(float2*)&P[pbase + (size_t)rl * SS + cl] = v0;
            *(float2*)&P[pbase + (size_t)(rl + 8) * SS + cl] = v1;
        }
    }
}

// ---------------------------------------------------------------------------
// pv_tc: AO[b, q, h*128+d] = sum_k P[bh,q,k] * Vt[bh,d,k]; causal k-bound.
// ---------------------------------------------------------------------------
__global__ __launch_bounds__(256, 2) void pv_tc(
    const __nv_bfloat16* __restrict__ Ph, const __nv_bfloat16* __restrict__ Pl,
    const __nv_bfloat16* __restrict__ Vth, const __nv_bfloat16* __restrict__ Vtl,
    __nv_bfloat16* __restrict__ AOh, __nv_bfloat16* __restrict__ AOl)
{
    extern __shared__ char smem[];
    const uint32_t sbase = smem_u32(smem);
    const int t = threadIdx.x;
    const int wid = t >> 5, lane = t & 31;
    const int q0 = blockIdx.x << 7;
    const int bh = blockIdx.y;
    const int b = bh >> 5, h = bh & 31;

    const int ltile = t >> 6, ltid = t & 63;
    const __nv_bfloat16* lsrc =
        (ltile == 0) ? Ph  + ((size_t)bh * SS + q0) * SS :
        (ltile == 1) ? Pl  + ((size_t)bh * SS + q0) * SS :
        (ltile == 2) ? Vth + (size_t)bh * HD * SS :
                       Vtl + (size_t)bh * HD * SS;

    const int iters = (q0 >> 5) + 4;

    auto load_stage = [&](int stg, int kc) {
        load_subtile32(sbase + stg * STAGE_B + ltile * TILE_B, lsrc + kc, SS, ltid);
        CP_COMMIT();
    };

#pragma unroll
    for (int s = 0; s < NSTAGE; s++) load_stage(s, s * 32);

    const int wm = (wid & 1) << 6;
    const int wn = (wid >> 1) << 5;
    const int lr = lane & 15, lc = lane >> 4;
    float acc[4][4][4] = {};

    for (int it = 0; it < iters; it++) {
        int stg = it % NSTAGE;
        CP_WAIT2();
        __syncthreads();
        uint32_t sb = sbase + stg * STAGE_B;
        hmma_block32(sb, 0, wm, wn, lr, lc, acc);
        hmma_block32(sb, 1, wm, wn, lr, lc, acc);
        __syncthreads();
        if (it + NSTAGE < iters) load_stage(stg, (it + NSTAGE) * 32);
        else CP_COMMIT();
    }

    const int qr = lane >> 2, qc = (lane & 3) << 1;
#pragma unroll
    for (int mi = 0; mi < 4; mi++) {
#pragma unroll
        for (int ni = 0; ni < 4; ni++) {
            int row = q0 + wm + mi * 16 + qr;
            int col = (h << 7) + wn + ni * 8 + qc;
            size_t m0 = ((size_t)b * SS + row) * DD + col;
            size_t m1 = m0 + (size_t)8 * DD;
            __nv_bfloat16 h0, l0, h1, l1;
            split_hi_lo(acc[mi][ni][0], h0, l0);
            split_hi_lo(acc[mi][ni][1], h1, l1);
            *(__nv_bfloat162*)&AOh[m0] = __nv_bfloat162(h0, h1);
            *(__nv_bfloat162*)&AOl[m0] = __nv_bfloat162(l0, l1);
            split_hi_lo(acc[mi][ni][2], h0, l0);
            split_hi_lo(acc[mi][ni][3], h1, l1);
            *(__nv_bfloat162*)&AOh[m1] = __nv_bfloat162(h0, h1);
            *(__nv_bfloat162*)&AOl[m1] = __nv_bfloat162(l0, l1);
        }
    }
}

// ---------------------------------------------------------------------------
// fp32 -> bf16 hi/lo split (weights / hidden)
// ---------------------------------------------------------------------------
__global__ void conv_kernel(const float* __restrict__ x,
                            __nv_bfloat16* __restrict__ hi, __nv_bfloat16* __restrict__ lo)
{
    size_t i = (size_t)blockIdx.x * blockDim.x + threadIdx.x;
    if (i >= NELT / 4) return;
    float4 v = ((const float4*)x)[i];
    float f[4] = { v.x, v.y, v.z, v.w };
    __nv_bfloat16 h[4], l[4];
#pragma unroll
    for (int k = 0; k < 4; k++) split_hi_lo(f[k], h[k], l[k]);
    ((__nv_bfloat162*)hi)[i * 2]     = __nv_bfloat162(h[0], h[1]);
    ((__nv_bfloat162*)hi)[i * 2 + 1] = __nv_bfloat162(h[2], h[3]);
    ((__nv_bfloat162*)lo)[i * 2]     = __nv_bfloat162(l[0], l[1]);
    ((__nv_bfloat162*)lo)[i * 2 + 1] = __nv_bfloat162(l[2], l[3]);
}

// ---------------------------------------------------------------------------
// RoPE fused with bf16 hi/lo split
// ---------------------------------------------------------------------------
__global__ void rope_bf16_kernel(const float* __restrict__ src,
                                 __nv_bfloat16* __restrict__ dh, __nv_bfloat16* __restrict__ dl,
                                 const float* __restrict__ cosp, const float* __restrict__ sinp,
                                 float scale)
{
    int idx = blockIdx.x * blockDim.x + threadIdx.x;
    const int total = BB * SS * HH * (HD / 2);
    if (idx >= total) return;
    int d  = idx & 63;
    int h  = (idx >> 6) & (HH - 1);
    int bs = idx >> 11;
    size_t base = (size_t)bs * DD + (h << 7);
    size_t cbase = (size_t)bs * HD;
    float c0 = cosp[cbase + d],      s0 = sinp[cbase + d];
    float c1 = cosp[cbase + d + 64], s1 = sinp[cbase + d + 64];
    float x0 = src[base + d], x1 = src[base + d + 64];
    float y0 = (x0 * c0 - x1 * s0) * scale;
    float y1 = (x1 * c1 + x0 * s1) * scale;
    __nv_bfloat16 hh, ll;
    split_hi_lo(y0, hh, ll); dh[base + d] = hh;      dl[base + d] = ll;
    split_hi_lo(y1, hh, ll); dh[base + d + 64] = hh; dl[base + d + 64] = ll;
}

// ---------------------------------------------------------------------------
// V transpose + hi/lo split: (b,s,h,hd) fp32 -> (b,h,d,k=s) bf16 x2
// ---------------------------------------------------------------------------
__global__ __launch_bounds__(256) void vt_conv_kernel(
    const float* __restrict__ V,
    __nv_bfloat16* __restrict__ Vh, __nv_bfloat16* __restrict__ Vl)
{
    __shared__ float tile[32][33];
    int bh = blockIdx.z;
    int b = bh >> 5, h = bh & 31;
    int s0 = blockIdx.x << 5, d0 = blockIdx.y << 5;
    int t = threadIdx.x;
    int row = t >> 3, c4 = (t & 7) << 2;

    float4 v = *(const float4*)(V + ((size_t)(b * SS + s0 + row)) * DD + (h << 7) + d0 + c4);
    tile[row][c4 + 0] = v.x; tile[row][c4 + 1] = v.y;
    tile[row][c4 + 2] = v.z; tile[row][c4 + 3] = v.w;
    __syncthreads();

    size_t obase = ((size_t)bh * HD + d0 + row) * SS + s0 + c4;
    float f[4] = { tile[c4 + 0][row], tile[c4 + 1][row], tile[c4 + 2][row], tile[c4 + 3][row] };
    __nv_bfloat16 hh[4], ll[4];
#pragma unroll
    for (int k = 0; k < 4; k++) split_hi_lo(f[k], hh[k], ll[k]);
    *(__nv_bfloat162*)&Vh[obase]     = __nv_bfloat162(hh[0], hh[1]);
    *(__nv_bfloat162*)&Vh[obase + 2] = __nv_bfloat162(hh[2], hh[3]);
    *(__nv_bfloat162*)&Vl[obase]     = __nv_bfloat162(ll[0], ll[1]);
    *(__nv_bfloat162*)&Vl[obase + 2] = __nv_bfloat162(ll[2], ll[3]);
}

// ---------------------------------------------------------------------------
// Causal softmax in place + bf16 hi/lo emission.
// ---------------------------------------------------------------------------
__global__ __launch_bounds__(256) void softmax_pconv_kernel(
    float* __restrict__ P, __nv_bfloat16* __restrict__ Ph, __nv_bfloat16* __restrict__ Pl)
{
    size_t row = blockIdx.x;
    int q = (int)(row & (SS - 1));
    int kend = ((q >> 7) + 1) << 7;
    float* p = P + row * (size_t)SS;
    __nv_bfloat16* ph = Ph + row * (size_t)SS;
    __nv_bfloat16* pl = Pl + row * (size_t)SS;
    int t = threadIdx.x;
    float v[8];
    float mx = -3.4e38f;
#pragma unroll
    for (int i = 0; i < 8; i++) {
        int off = t + (i << 8);
        v[i] = (off <= q) ? p[off] : -3.4e38f;
        mx = fmaxf(mx, v[i]);
    }
#pragma unroll
    for (int o = 16; o; o >>= 1) mx = fmaxf(mx, __shfl_xor_sync(0xffffffffu, mx, o));
    __shared__ float rmax[8], rsum[8];
    if ((t & 31) == 0) rmax[t >> 5] = mx;
    __syncthreads();
    mx = rmax[0];
#pragma unroll
    for (int i = 1; i < 8; i++) mx = fmaxf(mx, rmax[i]);
    float sum = 0.f;
#pragma unroll
    for (int i = 0; i < 8; i++) {
        int off = t + (i << 8);
        v[i] = (off <= q) ? __expf(v[i] - mx) : 0.f;
        sum += v[i];
    }
#pragma unroll
    for (int o = 16; o; o >>= 1) sum += __shfl_xor_sync(0xffffffffu, sum, o);
    if ((t & 31) == 0) rsum[t >> 5] = sum;
    __syncthreads();
    sum = rsum[0];
#pragma unroll
    for (int i = 1; i < 8; i++) sum += rsum[i];
    float inv = 1.0f / sum;
#pragma unroll
    for (int i = 0; i < 8; i++) {
        int off = t + (i << 8);
        float pv = v[i] * inv;
        p[off] = pv;
        if (off < kend) {
            __nv_bfloat16 hh, ll;
            split_hi_lo(pv, hh, ll);
            ph[off] = hh;
            pl[off] = ll;
        }
    }
}

// ---------------------------------------------------------------------------
extern "C" void kernel_launch(void* const* d_in, const int* in_sizes, int n_in,
                              void* d_out, int out_size)
{
    (void)in_sizes; (void)n_in; (void)out_size;
    const float* hidden = (const float*)d_in[0];
    const float* Wqk    = (const float*)d_in[1];
    const float* bqk    = (const float*)d_in[2];
    const float* Wv     = (const float*)d_in[3];
    const float* bv     = (const float*)d_in[4];
    const float* Wo     = (const float*)d_in[5];
    const float* cosp   = (const float*)d_in[6];
    const float* sinp   = (const float*)d_in[7];

    float* out   = (float*)d_out;
    float* attnw = out + (size_t)BB * SS * DD;

    float *qk_p, *v_p;
    cudaGetSymbolAddress((void**)&qk_p, g_qk);
    cudaGetSymbolAddress((void**)&v_p,  g_v);

    __nv_bfloat16 *hh, *hl, *qkh, *qkl, *vh, *vl, *oh, *ol;
    __nv_bfloat16 *qh, *ql, *kh, *kl, *vth, *vtl, *aoh, *aol, *ph, *pl;
    cudaGetSymbolAddress((void**)&hh,  g_hh);  cudaGetSymbolAddress((void**)&hl,  g_hl);
    cudaGetSymbolAddress((void**)&qkh, g_qkh); cudaGetSymbolAddress((void**)&qkl, g_qkl);
    cudaGetSymbolAddress((void**)&vh,  g_vh);  cudaGetSymbolAddress((void**)&vl,  g_vl);
    cudaGetSymbolAddress((void**)&oh,  g_oh);  cudaGetSymbolAddress((void**)&ol,  g_ol);
    cudaGetSymbolAddress((void**)&qh,  g_qh);  cudaGetSymbolAddress((void**)&ql,  g_ql);
    cudaGetSymbolAddress((void**)&kh,  g_kh);  cudaGetSymbolAddress((void**)&kl,  g_kl);
    cudaGetSymbolAddress((void**)&vth, g_vth); cudaGetSymbolAddress((void**)&vtl, g_vtl);
    cudaGetSymbolAddress((void**)&aoh, g_aoh); cudaGetSymbolAddress((void**)&aol, g_aol);
    cudaGetSymbolAddress((void**)&ph,  g_ph);  cudaGetSymbolAddress((void**)&pl,  g_pl);

    cudaFuncSetAttribute(gemm_tc,  cudaFuncAttributeMaxDynamicSharedMemorySize, PIPE_SMEM);
    cudaFuncSetAttribute(score_tc, cudaFuncAttributeMaxDynamicSharedMemorySize, PIPE_SMEM);
    cudaFuncSetAttribute(pv_tc,    cudaFuncAttributeMaxDynamicSharedMemorySize, PIPE_SMEM);

    const int cvblk = (int)((NELT / 4 + 255) / 256);
    conv_kernel<<<cvblk, 256>>>(hidden, hh, hl);
    conv_kernel<<<cvblk, 256>>>(Wqk, qkh, qkl);
    conv_kernel<<<cvblk, 256>>>(Wv,  vh,  vl);
    conv_kernel<<<cvblk, 256>>>(Wo,  oh,  ol);

    dim3 gg(DD / 128, (BB * SS) / 128);
    gemm_tc<<<gg, 256, PIPE_SMEM>>>(hh, hl, qkh, qkl, bqk, qk_p);
    gemm_tc<<<gg, 256, PIPE_SMEM>>>(hh, hl, vh,  vl,  bv,  v_p);

    const int rope_total = BB * SS * HH * (HD / 2);
    const float scale = 0.088388347648318447f;  // 128^-0.5
    rope_bf16_kernel<<<(rope_total + 255) / 256, 256>>>(hidden, qh, ql, cosp, sinp, scale);
    rope_bf16_kernel<<<(rope_total + 255) / 256, 256>>>(qk_p,   kh, kl, cosp, sinp, 1.0f);

    vt_conv_kernel<<<dim3(SS / 32, HD / 32, BB * HH), 256>>>(v_p, vth, vtl);

    score_tc<<<dim3(SS / 128, SS / 128, BB * HH), 256, PIPE_SMEM>>>(qh, ql, kh, kl, attnw);
    softmax_pconv_kernel<<<BB * HH * SS, 256>>>(attnw, ph, pl);
    pv_tc<<<dim3(SS / 128, BB * HH), 256, PIPE_SMEM>>>(ph, pl, vth, vtl, aoh, aol);

    gemm_tc<<<gg, 256, PIPE_SMEM>>>(aoh, aol, oh, ol, nullptr, out);
}

// round 7
// speedup vs baseline: 3.7206x; 1.3179x over previous
#include <cuda_runtime.h>
#include <cuda_fp16.h>
#include <cstdint>
#include <cstddef>

#define BB 2
#define SS 2048
#define DD 4096
#define HH 32
#define HD 128
#define NEG_INF -1000000000.0f

#define NELT ((size_t)BB * SS * DD)          // 16,777,216
#define NP   ((size_t)BB * HH * SS * SS)     // 268,435,456

// ---------------- scratch (device globals; alloc APIs forbidden) ----------
__device__ float g_qk[NELT];   // K projection (b,s,h,hd) fp32
__device__ float g_v [NELT];   // V projection (b,s,h,hd) fp32

__device__ __half g_hh[NELT],  g_hl[NELT];    // hidden hi/lo
__device__ __half g_qkh[NELT];                // Wqk hi
__device__ __half g_vh[NELT];                 // Wv hi
__device__ __half g_oh[NELT];                 // Wo hi
__device__ __half g_qh[NELT],  g_ql[NELT];    // roped Q hi/lo (b,s,h,hd)
__device__ __half g_kh[NELT],  g_kl[NELT];    // roped K hi/lo (b,s,h,hd)
__device__ __half g_vth[NELT];                // V^T hi (b,h,d,k)
__device__ __half g_aoh[NELT], g_aol[NELT];   // attn-out gathered hi/lo
__device__ __half g_ph[NP],    g_pl[NP];      // softmax P hi/lo

// ---------------- helpers ---------------------------------------------------
__device__ __forceinline__ uint32_t smem_u32(const void* p) {
    uint32_t a;
    asm("{ .reg .u64 t; cvta.to.shared.u64 t, %1; cvt.u32.u64 %0, t; }" : "=r"(a) : "l"(p));
    return a;
}
__device__ __forceinline__ void cp_async16(uint32_t dst, const void* src) {
    asm volatile("cp.async.cg.shared.global [%0], [%1], 16;" :: "r"(dst), "l"(src));
}
#define CP_COMMIT() asm volatile("cp.async.commit_group;" ::: "memory")
#define CP_WAIT2()  asm volatile("cp.async.wait_group 2;" ::: "memory")
#define CP_WAIT3()  asm volatile("cp.async.wait_group 3;" ::: "memory")

__device__ __forceinline__ void ldmx4(uint32_t* r, uint32_t addr) {
    asm volatile("ldmatrix.sync.aligned.m8n8.x4.shared.b16 {%0,%1,%2,%3}, [%4];"
                 : "=r"(r[0]), "=r"(r[1]), "=r"(r[2]), "=r"(r[3]) : "r"(addr));
}
__device__ __forceinline__ void mma16816(float* d, const uint32_t* a, const uint32_t* b) {
    asm volatile(
        "mma.sync.aligned.m16n8k16.row.col.f32.f16.f16.f32 "
        "{%0,%1,%2,%3}, {%4,%5,%6,%7}, {%8,%9}, {%0,%1,%2,%3};"
        : "+f"(d[0]), "+f"(d[1]), "+f"(d[2]), "+f"(d[3])
        : "r"(a[0]), "r"(a[1]), "r"(a[2]), "r"(a[3]), "r"(b[0]), "r"(b[1]));
}
__device__ __forceinline__ void split_hi_lo(float f, __half& h, __half& l) {
    h = __float2half_rn(f);
    l = __float2half_rn(f - __half2float(h));
}

// ---- BK=32 tiles ------------------------------------------------------------
#define TILE_B 8192                     // 128 rows x 64B (32 fp16)
#define STAGE2 (3 * TILE_B)             // gemm/pv: Ah, Al, Bh
#define STAGE3 (4 * TILE_B)             // score:  Qh, Ql, Kh, Kl
#define NSTAGE_G 4                      // gemm/pv pipeline depth
#define NSTAGE_S 3                      // score pipeline depth
#define SMEM_G (NSTAGE_G * STAGE2)      // 98304
#define SMEM_S (NSTAGE_S * STAGE3)      // 98304

// swizzled byte offset within a 128x32 tile (64B rows)
__device__ __forceinline__ uint32_t sw_off32(int r, int chunk) {
    return (uint32_t)(r << 6) + (((chunk ^ ((r >> 1) & 3)) << 4));
}

// ---- 2-product K=16 MMA step: A(hi+lo) x B(hi). Tiles: [Ah|Al|Bh] -----------
__device__ __forceinline__ void hmma2(
    uint32_t sb, int ks, int wm, int wn, int lr, int lc, float (&acc)[4][4][4])
{
    const int chunk = ks * 2 + lc;
    uint32_t bh[4][2];
#pragma unroll
    for (int g = 0; g < 2; g++) {
        int r = wn + g * 16 + lr;
        uint32_t rb[4];
        ldmx4(rb, sb + 2 * TILE_B + sw_off32(r, chunk));
        bh[g*2+0][0] = rb[0]; bh[g*2+0][1] = rb[2];
        bh[g*2+1][0] = rb[1]; bh[g*2+1][1] = rb[3];
    }
#pragma unroll
    for (int mi = 0; mi < 4; mi++) {
        int r = wm + mi * 16 + lr;
        uint32_t off = sw_off32(r, chunk);
        uint32_t ah[4], al[4];
        ldmx4(ah, sb + off);
        ldmx4(al, sb + TILE_B + off);
#pragma unroll
        for (int ni = 0; ni < 4; ni++) {
            mma16816(acc[mi][ni], ah, bh[ni]);
            mma16816(acc[mi][ni], al, bh[ni]);
        }
    }
}

// ---- 3-product K=16 MMA step (score): tiles [Qh|Ql|Kh|Kl] -------------------
__device__ __forceinline__ void hmma3(
    uint32_t sb, int ks, int wm, int wn, int lr, int lc, float (&acc)[4][4][4])
{
    const int chunk = ks * 2 + lc;
    uint32_t bh[4][2], bl[4][2];
#pragma unroll
    for (int g = 0; g < 2; g++) {
        int r = wn + g * 16 + lr;
        uint32_t off = sw_off32(r, chunk);
        uint32_t rb[4];
        ldmx4(rb, sb + 2 * TILE_B + off);
        bh[g*2+0][0] = rb[0]; bh[g*2+0][1] = rb[2];
        bh[g*2+1][0] = rb[1]; bh[g*2+1][1] = rb[3];
        ldmx4(rb, sb + 3 * TILE_B + off);
        bl[g*2+0][0] = rb[0]; bl[g*2+0][1] = rb[2];
        bl[g*2+1][0] = rb[1]; bl[g*2+1][1] = rb[3];
    }
#pragma unroll
    for (int mi = 0; mi < 4; mi++) {
        int r = wm + mi * 16 + lr;
        uint32_t off = sw_off32(r, chunk);
        uint32_t ah[4], al[4];
        ldmx4(ah, sb + off);
        ldmx4(al, sb + TILE_B + off);
#pragma unroll
        for (int ni = 0; ni < 4; ni++) {
            mma16816(acc[mi][ni], ah, bh[ni]);
            mma16816(acc[mi][ni], ah, bl[ni]);
            mma16816(acc[mi][ni], al, bh[ni]);
        }
    }
}

// ---------------------------------------------------------------------------
// HMMA fp16 2-product GEMM: C[4096][4096] = A @ W^T (+bias).
// ---------------------------------------------------------------------------
__global__ __launch_bounds__(256, 2) void gemm_tc(
    const __half* __restrict__ Ah, const __half* __restrict__ Al,
    const __half* __restrict__ Bh,
    const float* __restrict__ bias, float* __restrict__ C)
{
    extern __shared__ char smem[];
    const uint32_t sbase = smem_u32(smem);
    const int t = threadIdx.x;
    const int wid = t >> 5, lane = t & 31;
    const int bm = blockIdx.y << 7, bn = blockIdx.x << 7;

    const __half* base0 = Ah + (size_t)bm * DD;
    const __half* base1 = Al + (size_t)bm * DD;
    const __half* base2 = Bh + (size_t)bn * DD;

    auto load_stage = [&](int stg, int kc) {
        uint32_t db = sbase + stg * STAGE2;
#pragma unroll
        for (int i = 0; i < 6; i++) {
            int idx = t + (i << 8);              // 0..1535
            int tile = idx >> 9;                 // 0..2
            int w = idx & 511;
            int r = w >> 2, c = w & 3;
            const __half* src = (tile == 0 ? base0 : tile == 1 ? base1 : base2)
                                + (size_t)r * DD + kc + (c << 3);
            cp_async16(db + tile * TILE_B + sw_off32(r, c), src);
        }
        CP_COMMIT();
    };

    load_stage(0, 0);
    load_stage(1, 32);
    load_stage(2, 64);
    load_stage(3, 96);

    const int wm = (wid & 1) << 6;
    const int wn = (wid >> 1) << 5;
    const int lr = lane & 15, lc = lane >> 4;

    float acc[4][4][4] = {};
    const int iters = DD / 32;

    for (int it = 0; it < iters; it++) {
        int stg = it % NSTAGE_G;
        CP_WAIT3();
        __syncthreads();
        uint32_t sb = sbase + stg * STAGE2;
        hmma2(sb, 0, wm, wn, lr, lc, acc);
        hmma2(sb, 1, wm, wn, lr, lc, acc);
        __syncthreads();
        if (it + NSTAGE_G < iters) load_stage(stg, (it + NSTAGE_G) * 32);
        else CP_COMMIT();
    }

    const int qr = lane >> 2, qc = (lane & 3) << 1;
#pragma unroll
    for (int mi = 0; mi < 4; mi++) {
#pragma unroll
        for (int ni = 0; ni < 4; ni++) {
            int col = bn + wn + ni * 8 + qc;
            float bx = 0.f, by = 0.f;
            if (bias) { bx = bias[col]; by = bias[col + 1]; }
            int row0 = bm + wm + mi * 16 + qr;
            float2 v0 = { acc[mi][ni][0] + bx, acc[mi][ni][1] + by };
            float2 v1 = { acc[mi][ni][2] + bx, acc[mi][ni][3] + by };
            *(float2*)&C[(size_t)row0 * DD + col] = v0;
            *(float2*)&C[(size_t)(row0 + 8) * DD + col] = v1;
        }
    }
}

// ---------------------------------------------------------------------------
// score_tc: P = Q.K (fp16 3-product), causal; above-diagonal tiles untouched.
// ---------------------------------------------------------------------------
__global__ __launch_bounds__(256, 2) void score_tc(
    const __half* __restrict__ Qh, const __half* __restrict__ Ql,
    const __half* __restrict__ Kh, const __half* __restrict__ Kl,
    float* __restrict__ P)
{
    extern __shared__ char smem[];
    const int q0 = blockIdx.y << 7, k0 = blockIdx.x << 7;
    if (k0 > q0) return;

    const int bh = blockIdx.z;
    const int b = bh >> 5, h = bh & 31;
    const size_t pbase = ((size_t)bh * SS + q0) * SS + k0;
    const int t = threadIdx.x;
    const uint32_t sbase = smem_u32(smem);
    const int wid = t >> 5, lane = t & 31;

    const __half* base0 = Qh + (size_t)(b * SS + q0) * DD + (h << 7);
    const __half* base1 = Ql + (size_t)(b * SS + q0) * DD + (h << 7);
    const __half* base2 = Kh + (size_t)(b * SS + k0) * DD + (h << 7);
    const __half* base3 = Kl + (size_t)(b * SS + k0) * DD + (h << 7);

    auto load_stage = [&](int stg, int kc) {
        uint32_t db = sbase + stg * STAGE3;
#pragma unroll
        for (int i = 0; i < 8; i++) {
            int idx = t + (i << 8);              // 0..2047
            int tile = idx >> 9;                 // 0..3
            int w = idx & 511;
            int r = w >> 2, c = w & 3;
            const __half* src = (tile == 0 ? base0 : tile == 1 ? base1 :
                                 tile == 2 ? base2 : base3)
                                + (size_t)r * DD + kc + (c << 3);
            cp_async16(db + tile * TILE_B + sw_off32(r, c), src);
        }
        CP_COMMIT();
    };

    load_stage(0, 0);
    load_stage(1, 32);
    load_stage(2, 64);

    const int wm = (wid & 1) << 6;
    const int wn = (wid >> 1) << 5;
    const int lr = lane & 15, lc = lane >> 4;
    float acc[4][4][4] = {};
    const int iters = HD / 32;   // 4

    for (int it = 0; it < iters; it++) {
        int stg = it % NSTAGE_S;
        CP_WAIT2();
        __syncthreads();
        uint32_t sb = sbase + stg * STAGE3;
        hmma3(sb, 0, wm, wn, lr, lc, acc);
        hmma3(sb, 1, wm, wn, lr, lc, acc);
        __syncthreads();
        if (it + NSTAGE_S < iters) load_stage(stg, (it + NSTAGE_S) * 32);
        else CP_COMMIT();
    }

    const int qr = lane >> 2, qc = (lane & 3) << 1;
#pragma unroll
    for (int mi = 0; mi < 4; mi++) {
#pragma unroll
        for (int ni = 0; ni < 4; ni++) {
            int rl = wm + mi * 16 + qr;
            int cl = wn + ni * 8 + qc;
            int k = k0 + cl;
            int qA = q0 + rl, qB = qA + 8;
            float2 v0 = { (k <= qA) ? acc[mi][ni][0] : NEG_INF,
                          (k + 1 <= qA) ? acc[mi][ni][1] : NEG_INF };
            float2 v1 = { (k <= qB) ? acc[mi][ni][2] : NEG_INF,
                          (k + 1 <= qB) ? acc[mi][ni][3] : NEG_INF };
            *(float2*)&P[pbase + (size_t)rl * SS + cl] = v0;
            *(float2*)&P[pbase + (size_t)(rl + 8) * SS + cl] = v1;
        }
    }
}

// ---------------------------------------------------------------------------
// pv_tc: AO = P @ V^T (fp16 2-product), causal k-bound; gathered hi/lo out.
// ---------------------------------------------------------------------------
__global__ __launch_bounds__(256, 2) void pv_tc(
    const __half* __restrict__ Ph, const __half* __restrict__ Pl,
    const __half* __restrict__ Vth,
    __half* __restrict__ AOh, __half* __restrict__ AOl)
{
    extern __shared__ char smem[];
    const uint32_t sbase = smem_u32(smem);
    const int t = threadIdx.x;
    const int wid = t >> 5, lane = t & 31;
    const int q0 = blockIdx.x << 7;
    const int bh = blockIdx.y;
    const int b = bh >> 5, h = bh & 31;

    const __half* base0 = Ph  + ((size_t)bh * SS + q0) * SS;
    const __half* base1 = Pl  + ((size_t)bh * SS + q0) * SS;
    const __half* base2 = Vth + (size_t)bh * HD * SS;

    const int iters = (q0 >> 5) + 4;

    auto load_stage = [&](int stg, int kc) {
        uint32_t db = sbase + stg * STAGE2;
#pragma unroll
        for (int i = 0; i < 6; i++) {
            int idx = t + (i << 8);
            int tile = idx >> 9;
            int w = idx & 511;
            int r = w >> 2, c = w & 3;
            const __half* src = (tile == 0 ? base0 : tile == 1 ? base1 : base2)
                                + (size_t)r * SS + kc + (c << 3);
            cp_async16(db + tile * TILE_B + sw_off32(r, c), src);
        }
        CP_COMMIT();
    };

    load_stage(0, 0);
    load_stage(1, 32);
    load_stage(2, 64);
    load_stage(3, 96);

    const int wm = (wid & 1) << 6;
    const int wn = (wid >> 1) << 5;
    const int lr = lane & 15, lc = lane >> 4;
    float acc[4][4][4] = {};

    for (int it = 0; it < iters; it++) {
        int stg = it % NSTAGE_G;
        CP_WAIT3();
        __syncthreads();
        uint32_t sb = sbase + stg * STAGE2;
        hmma2(sb, 0, wm, wn, lr, lc, acc);
        hmma2(sb, 1, wm, wn, lr, lc, acc);
        __syncthreads();
        if (it + NSTAGE_G < iters) load_stage(stg, (it + NSTAGE_G) * 32);
        else CP_COMMIT();
    }

    const int qr = lane >> 2, qc = (lane & 3) << 1;
#pragma unroll
    for (int mi = 0; mi < 4; mi++) {
#pragma unroll
        for (int ni = 0; ni < 4; ni++) {
            int row = q0 + wm + mi * 16 + qr;
            int col = (h << 7) + wn + ni * 8 + qc;
            size_t m0 = ((size_t)b * SS + row) * DD + col;
            size_t m1 = m0 + (size_t)8 * DD;
            __half h0, l0, h1, l1;
            split_hi_lo(acc[mi][ni][0], h0, l0);
            split_hi_lo(acc[mi][ni][1], h1, l1);
            *(__half2*)&AOh[m0] = __halves2half2(h0, h1);
            *(__half2*)&AOl[m0] = __halves2half2(l0, l1);
            split_hi_lo(acc[mi][ni][2], h0, l0);
            split_hi_lo(acc[mi][ni][3], h1, l1);
            *(__half2*)&AOh[m1] = __halves2half2(h0, h1);
            *(__half2*)&AOl[m1] = __halves2half2(l0, l1);
        }
    }
}

// ---------------------------------------------------------------------------
// fp32 -> fp16 hi/lo split (hidden)
// ---------------------------------------------------------------------------
__global__ void conv_hilo(const float* __restrict__ x,
                          __half* __restrict__ hi, __half* __restrict__ lo)
{
    size_t i = (size_t)blockIdx.x * blockDim.x + threadIdx.x;
    if (i >= NELT / 4) return;
    float4 v = ((const float4*)x)[i];
    float f[4] = { v.x, v.y, v.z, v.w };
    __half h[4], l[4];
#pragma unroll
    for (int k = 0; k < 4; k++) split_hi_lo(f[k], h[k], l[k]);
    ((__half2*)hi)[i * 2]     = __halves2half2(h[0], h[1]);
    ((__half2*)hi)[i * 2 + 1] = __halves2half2(h[2], h[3]);
    ((__half2*)lo)[i * 2]     = __halves2half2(l[0], l[1]);
    ((__half2*)lo)[i * 2 + 1] = __halves2half2(l[2], l[3]);
}

// fp32 -> fp16 hi only (weights)
__global__ void conv_hi(const float* __restrict__ x, __half* __restrict__ hi)
{
    size_t i = (size_t)blockIdx.x * blockDim.x + threadIdx.x;
    if (i >= NELT / 4) return;
    float4 v = ((const float4*)x)[i];
    ((__half2*)hi)[i * 2]     = __halves2half2(__float2half_rn(v.x), __float2half_rn(v.y));
    ((__half2*)hi)[i * 2 + 1] = __halves2half2(__float2half_rn(v.z), __float2half_rn(v.w));
}

// ---------------------------------------------------------------------------
// RoPE fused with fp16 hi/lo split
// ---------------------------------------------------------------------------
__global__ void rope_half_kernel(const float* __restrict__ src,
                                 __half* __restrict__ dh, __half* __restrict__ dl,
                                 const float* __restrict__ cosp, const float* __restrict__ sinp,
                                 float scale)
{
    int idx = blockIdx.x * blockDim.x + threadIdx.x;
    const int total = BB * SS * HH * (HD / 2);
    if (idx >= total) return;
    int d  = idx & 63;
    int h  = (idx >> 6) & (HH - 1);
    int bs = idx >> 11;
    size_t base = (size_t)bs * DD + (h << 7);
    size_t cbase = (size_t)bs * HD;
    float c0 = cosp[cbase + d],      s0 = sinp[cbase + d];
    float c1 = cosp[cbase + d + 64], s1 = sinp[cbase + d + 64];
    float x0 = src[base + d], x1 = src[base + d + 64];
    float y0 = (x0 * c0 - x1 * s0) * scale;
    float y1 = (x1 * c1 + x0 * s1) * scale;
    __half hh, ll;
    split_hi_lo(y0, hh, ll); dh[base + d] = hh;      dl[base + d] = ll;
    split_hi_lo(y1, hh, ll); dh[base + d + 64] = hh; dl[base + d + 64] = ll;
}

// ---------------------------------------------------------------------------
// V transpose + fp16 hi: (b,s,h,hd) fp32 -> (b,h,d,k=s)
// ---------------------------------------------------------------------------
__global__ __launch_bounds__(256) void vt_conv_kernel(
    const float* __restrict__ V, __half* __restrict__ Vh)
{
    __shared__ float tile[32][33];
    int bh = blockIdx.z;
    int b = bh >> 5, h = bh & 31;
    int s0 = blockIdx.x << 5, d0 = blockIdx.y << 5;
    int t = threadIdx.x;
    int row = t >> 3, c4 = (t & 7) << 2;

    float4 v = *(const float4*)(V + ((size_t)(b * SS + s0 + row)) * DD + (h << 7) + d0 + c4);
    tile[row][c4 + 0] = v.x; tile[row][c4 + 1] = v.y;
    tile[row][c4 + 2] = v.z; tile[row][c4 + 3] = v.w;
    __syncthreads();

    size_t obase = ((size_t)bh * HD + d0 + row) * SS + s0 + c4;
    *(__half2*)&Vh[obase]     = __halves2half2(__float2half_rn(tile[c4 + 0][row]),
                                               __float2half_rn(tile[c4 + 1][row]));
    *(__half2*)&Vh[obase + 2] = __halves2half2(__float2half_rn(tile[c4 + 2][row]),
                                               __float2half_rn(tile[c4 + 3][row]));
}

// ---------------------------------------------------------------------------
// Causal softmax in place + fp16 hi/lo emission (up to 128-aligned bound).
// ---------------------------------------------------------------------------
__global__ __launch_bounds__(256) void softmax_pconv_kernel(
    float* __restrict__ P, __half* __restrict__ Ph, __half* __restrict__ Pl)
{
    size_t row = blockIdx.x;
    int q = (int)(row & (SS - 1));
    int kend = ((q >> 7) + 1) << 7;
    float* p = P + row * (size_t)SS;
    __half* ph = Ph + row * (size_t)SS;
    __half* pl = Pl + row * (size_t)SS;
    int t = threadIdx.x;
    float v[8];
    float mx = -3.4e38f;
#pragma unroll
    for (int i = 0; i < 8; i++) {
        int off = t + (i << 8);
        v[i] = (off <= q) ? p[off] : -3.4e38f;
        mx = fmaxf(mx, v[i]);
    }
#pragma unroll
    for (int o = 16; o; o >>= 1) mx = fmaxf(mx, __shfl_xor_sync(0xffffffffu, mx, o));
    __shared__ float rmax[8], rsum[8];
    if ((t & 31) == 0) rmax[t >> 5] = mx;
    __syncthreads();
    mx = rmax[0];
#pragma unroll
    for (int i = 1; i < 8; i++) mx = fmaxf(mx, rmax[i]);
    float sum = 0.f;
#pragma unroll
    for (int i = 0; i < 8; i++) {
        int off = t + (i << 8);
        v[i] = (off <= q) ? __expf(v[i] - mx) : 0.f;
        sum += v[i];
    }
#pragma unroll
    for (int o = 16; o; o >>= 1) sum += __shfl_xor_sync(0xffffffffu, sum, o);
    if ((t & 31) == 0) rsum[t >> 5] = sum;
    __syncthreads();
    sum = rsum[0];
#pragma unroll
    for (int i = 1; i < 8; i++) sum += rsum[i];
    float inv = 1.0f / sum;
#pragma unroll
    for (int i = 0; i < 8; i++) {
        int off = t + (i << 8);
        float pv = v[i] * inv;
        p[off] = pv;
        if (off < kend) {
            __half hh, ll;
            split_hi_lo(pv, hh, ll);
            ph[off] = hh;
            pl[off] = ll;
        }
    }
}

// ---------------------------------------------------------------------------
extern "C" void kernel_launch(void* const* d_in, const int* in_sizes, int n_in,
                              void* d_out, int out_size)
{
    (void)in_sizes; (void)n_in; (void)out_size;
    const float* hidden = (const float*)d_in[0];
    const float* Wqk    = (const float*)d_in[1];
    const float* bqk    = (const float*)d_in[2];
    const float* Wv     = (const float*)d_in[3];
    const float* bv     = (const float*)d_in[4];
    const float* Wo     = (const float*)d_in[5];
    const float* cosp   = (const float*)d_in[6];
    const float* sinp   = (const float*)d_in[7];

    float* out   = (float*)d_out;
    float* attnw = out + (size_t)BB * SS * DD;

    float *qk_p, *v_p;
    cudaGetSymbolAddress((void**)&qk_p, g_qk);
    cudaGetSymbolAddress((void**)&v_p,  g_v);

    __half *hh, *hl, *qkh, *vh, *oh;
    __half *qh, *ql, *kh, *kl, *vth, *aoh, *aol, *ph, *pl;
    cudaGetSymbolAddress((void**)&hh,  g_hh);  cudaGetSymbolAddress((void**)&hl,  g_hl);
    cudaGetSymbolAddress((void**)&qkh, g_qkh);
    cudaGetSymbolAddress((void**)&vh,  g_vh);
    cudaGetSymbolAddress((void**)&oh,  g_oh);
    cudaGetSymbolAddress((void**)&qh,  g_qh);  cudaGetSymbolAddress((void**)&ql,  g_ql);
    cudaGetSymbolAddress((void**)&kh,  g_kh);  cudaGetSymbolAddress((void**)&kl,  g_kl);
    cudaGetSymbolAddress((void**)&vth, g_vth);
    cudaGetSymbolAddress((void**)&aoh, g_aoh); cudaGetSymbolAddress((void**)&aol, g_aol);
    cudaGetSymbolAddress((void**)&ph,  g_ph);  cudaGetSymbolAddress((void**)&pl,  g_pl);

    cudaFuncSetAttribute(gemm_tc,  cudaFuncAttributeMaxDynamicSharedMemorySize, SMEM_G);
    cudaFuncSetAttribute(score_tc, cudaFuncAttributeMaxDynamicSharedMemorySize, SMEM_S);
    cudaFuncSetAttribute(pv_tc,    cudaFuncAttributeMaxDynamicSharedMemorySize, SMEM_G);

    const int cvblk = (int)((NELT / 4 + 255) / 256);
    conv_hilo<<<cvblk, 256>>>(hidden, hh, hl);
    conv_hi<<<cvblk, 256>>>(Wqk, qkh);
    conv_hi<<<cvblk, 256>>>(Wv,  vh);
    conv_hi<<<cvblk, 256>>>(Wo,  oh);

    dim3 gg(DD / 128, (BB * SS) / 128);
    gemm_tc<<<gg, 256, SMEM_G>>>(hh, hl, qkh, bqk, qk_p);
    gemm_tc<<<gg, 256, SMEM_G>>>(hh, hl, vh,  bv,  v_p);

    const int rope_total = BB * SS * HH * (HD / 2);
    const float scale = 0.088388347648318447f;  // 128^-0.5
    rope_half_kernel<<<(rope_total + 255) / 256, 256>>>(hidden, qh, ql, cosp, sinp, scale);
    rope_half_kernel<<<(rope_total + 255) / 256, 256>>>(qk_p,   kh, kl, cosp, sinp, 1.0f);

    vt_conv_kernel<<<dim3(SS / 32, HD / 32, BB * HH), 256>>>(v_p, vth);

    score_tc<<<dim3(SS / 128, SS / 128, BB * HH), 256, SMEM_S>>>(qh, ql, kh, kl, attnw);
    softmax_pconv_kernel<<<BB * HH * SS, 256>>>(attnw, ph, pl);
    pv_tc<<<dim3(SS / 128, BB * HH), 256, SMEM_G>>>(ph, pl, vth, aoh, aol);

    gemm_tc<<<gg, 256, SMEM_G>>>(aoh, aol, oh, nullptr, out);
}

// round 8
// speedup vs baseline: 3.7560x; 1.0095x over previous
#include <cuda_runtime.h>
#include <cuda_fp16.h>
#include <cstdint>
#include <cstddef>

#define BB 2
#define SS 2048
#define DD 4096
#define HH 32
#define HD 128
#define NEG_INF -1000000000.0f

#define NELT ((size_t)BB * SS * DD)          // 16,777,216
#define NP   ((size_t)BB * HH * SS * SS)     // 268,435,456

// ---------------- scratch (device globals; alloc APIs forbidden) ----------
__device__ __half g_hh[NELT],  g_hl[NELT];    // hidden hi/lo
__device__ __half g_qkh[NELT];                // Wqk hi
__device__ __half g_vh[NELT];                 // Wv hi
__device__ __half g_oh[NELT];                 // Wo hi
__device__ __half g_qh[NELT],  g_ql[NELT];    // roped Q hi/lo (b,s,h,hd)
__device__ __half g_kh[NELT],  g_kl[NELT];    // roped K hi/lo (b,s,h,hd)
__device__ __half g_vth[NELT];                // V^T hi (b,h,d,k)
__device__ __half g_aoh[NELT], g_aol[NELT];   // attn-out gathered hi/lo
__device__ __half g_ph[NP],    g_pl[NP];      // softmax P hi/lo

// ---------------- helpers ---------------------------------------------------
__device__ __forceinline__ uint32_t smem_u32(const void* p) {
    uint32_t a;
    asm("{ .reg .u64 t; cvta.to.shared.u64 t, %1; cvt.u32.u64 %0, t; }" : "=r"(a) : "l"(p));
    return a;
}
__device__ __forceinline__ void cp_async16(uint32_t dst, const void* src) {
    asm volatile("cp.async.cg.shared.global [%0], [%1], 16;" :: "r"(dst), "l"(src));
}
#define CP_COMMIT() asm volatile("cp.async.commit_group;" ::: "memory")
#define CP_WAIT2()  asm volatile("cp.async.wait_group 2;" ::: "memory")
#define CP_WAIT3()  asm volatile("cp.async.wait_group 3;" ::: "memory")

__device__ __forceinline__ void ldmx4(uint32_t* r, uint32_t addr) {
    asm volatile("ldmatrix.sync.aligned.m8n8.x4.shared.b16 {%0,%1,%2,%3}, [%4];"
                 : "=r"(r[0]), "=r"(r[1]), "=r"(r[2]), "=r"(r[3]) : "r"(addr));
}
__device__ __forceinline__ void mma16816(float* d, const uint32_t* a, const uint32_t* b) {
    asm volatile(
        "mma.sync.aligned.m16n8k16.row.col.f32.f16.f16.f32 "
        "{%0,%1,%2,%3}, {%4,%5,%6,%7}, {%8,%9}, {%0,%1,%2,%3};"
        : "+f"(d[0]), "+f"(d[1]), "+f"(d[2]), "+f"(d[3])
        : "r"(a[0]), "r"(a[1]), "r"(a[2]), "r"(a[3]), "r"(b[0]), "r"(b[1]));
}
__device__ __forceinline__ void split_hi_lo(float f, __half& h, __half& l) {
    h = __float2half_rn(f);
    l = __float2half_rn(f - __half2float(h));
}

// ---- BK=32 tiles ------------------------------------------------------------
#define TILE_B 8192                     // 128 rows x 64B (32 fp16)
#define STAGE2 (3 * TILE_B)             // gemm/pv: Ah, Al, Bh
#define STAGE3 (4 * TILE_B)             // score:  Qh, Ql, Kh, Kl
#define NSTAGE_G 4
#define NSTAGE_S 3
#define SMEM_G (NSTAGE_G * STAGE2)      // 98304
#define SMEM_S (NSTAGE_S * STAGE3)      // 98304

__device__ __forceinline__ uint32_t sw_off32(int r, int chunk) {
    return (uint32_t)(r << 6) + (((chunk ^ ((r >> 1) & 3)) << 4));
}

// ---- 2-product K=16 MMA step: A(hi+lo) x B(hi). Tiles: [Ah|Al|Bh] -----------
__device__ __forceinline__ void hmma2(
    uint32_t sb, int ks, int wm, int wn, int lr, int lc, float (&acc)[4][4][4])
{
    const int chunk = ks * 2 + lc;
    uint32_t bh[4][2];
#pragma unroll
    for (int g = 0; g < 2; g++) {
        int r = wn + g * 16 + lr;
        uint32_t rb[4];
        ldmx4(rb, sb + 2 * TILE_B + sw_off32(r, chunk));
        bh[g*2+0][0] = rb[0]; bh[g*2+0][1] = rb[2];
        bh[g*2+1][0] = rb[1]; bh[g*2+1][1] = rb[3];
    }
#pragma unroll
    for (int mi = 0; mi < 4; mi++) {
        int r = wm + mi * 16 + lr;
        uint32_t off = sw_off32(r, chunk);
        uint32_t ah[4], al[4];
        ldmx4(ah, sb + off);
        ldmx4(al, sb + TILE_B + off);
#pragma unroll
        for (int ni = 0; ni < 4; ni++) {
            mma16816(acc[mi][ni], ah, bh[ni]);
            mma16816(acc[mi][ni], al, bh[ni]);
        }
    }
}

// ---- 3-product K=16 MMA step (score): tiles [Qh|Ql|Kh|Kl] -------------------
__device__ __forceinline__ void hmma3(
    uint32_t sb, int ks, int wm, int wn, int lr, int lc, float (&acc)[4][4][4])
{
    const int chunk = ks * 2 + lc;
    uint32_t bh[4][2], bl[4][2];
#pragma unroll
    for (int g = 0; g < 2; g++) {
        int r = wn + g * 16 + lr;
        uint32_t off = sw_off32(r, chunk);
        uint32_t rb[4];
        ldmx4(rb, sb + 2 * TILE_B + off);
        bh[g*2+0][0] = rb[0]; bh[g*2+0][1] = rb[2];
        bh[g*2+1][0] = rb[1]; bh[g*2+1][1] = rb[3];
        ldmx4(rb, sb + 3 * TILE_B + off);
        bl[g*2+0][0] = rb[0]; bl[g*2+0][1] = rb[2];
        bl[g*2+1][0] = rb[1]; bl[g*2+1][1] = rb[3];
    }
#pragma unroll
    for (int mi = 0; mi < 4; mi++) {
        int r = wm + mi * 16 + lr;
        uint32_t off = sw_off32(r, chunk);
        uint32_t ah[4], al[4];
        ldmx4(ah, sb + off);
        ldmx4(al, sb + TILE_B + off);
#pragma unroll
        for (int ni = 0; ni < 4; ni++) {
            mma16816(acc[mi][ni], ah, bh[ni]);
            mma16816(acc[mi][ni], ah, bl[ni]);
            mma16816(acc[mi][ni], al, bh[ni]);
        }
    }
}

// ---------------------------------------------------------------------------
// HMMA fp16 2-product GEMM with fused epilogues.
//  MODE 0: C = fp32 out (final projection)
//  MODE 1: QK projection -> +bias -> RoPE -> fp16 hi/lo (kh=O1, kl=O2)
//  MODE 2: V projection  -> +bias -> transpose to (b,h,d,s) fp16 hi (O1)
// ---------------------------------------------------------------------------
template<int MODE>
__global__ __launch_bounds__(256, 2) void gemm_tc(
    const __half* __restrict__ Ah, const __half* __restrict__ Al,
    const __half* __restrict__ Bh,
    const float* __restrict__ bias,
    const float* __restrict__ cosp, const float* __restrict__ sinp,
    float* __restrict__ C, __half* __restrict__ O1, __half* __restrict__ O2)
{
    extern __shared__ char smem[];
    const uint32_t sbase = smem_u32(smem);
    const int t = threadIdx.x;
    const int wid = t >> 5, lane = t & 31;
    const int bm = blockIdx.y << 7, bn = blockIdx.x << 7;

    const __half* base0 = Ah + (size_t)bm * DD;
    const __half* base1 = Al + (size_t)bm * DD;
    const __half* base2 = Bh + (size_t)bn * DD;

    auto load_stage = [&](int stg, int kc) {
        uint32_t db = sbase + stg * STAGE2;
#pragma unroll
        for (int i = 0; i < 6; i++) {
            int idx = t + (i << 8);
            int tile = idx >> 9;
            int w = idx & 511;
            int r = w >> 2, c = w & 3;
            const __half* src = (tile == 0 ? base0 : tile == 1 ? base1 : base2)
                                + (size_t)r * DD + kc + (c << 3);
            cp_async16(db + tile * TILE_B + sw_off32(r, c), src);
        }
        CP_COMMIT();
    };

    load_stage(0, 0);
    load_stage(1, 32);
    load_stage(2, 64);
    load_stage(3, 96);

    const int wm = (wid & 1) << 6;
    const int wn = (wid >> 1) << 5;
    const int lr = lane & 15, lc = lane >> 4;

    float acc[4][4][4] = {};
    const int iters = DD / 32;

    for (int it = 0; it < iters; it++) {
        int stg = it % NSTAGE_G;
        CP_WAIT3();
        __syncthreads();
        uint32_t sb = sbase + stg * STAGE2;
        hmma2(sb, 0, wm, wn, lr, lc, acc);
        hmma2(sb, 1, wm, wn, lr, lc, acc);
        __syncthreads();
        if (it + NSTAGE_G < iters) load_stage(stg, (it + NSTAGE_G) * 32);
        else CP_COMMIT();
    }

    const int qr = lane >> 2, qc = (lane & 3) << 1;

    if (MODE == 0) {
#pragma unroll
        for (int mi = 0; mi < 4; mi++) {
#pragma unroll
            for (int ni = 0; ni < 4; ni++) {
                int col = bn + wn + ni * 8 + qc;
                int row0 = bm + wm + mi * 16 + qr;
                float2 v0 = { acc[mi][ni][0], acc[mi][ni][1] };
                float2 v1 = { acc[mi][ni][2], acc[mi][ni][3] };
                *(float2*)&C[(size_t)row0 * DD + col] = v0;
                *(float2*)&C[(size_t)(row0 + 8) * DD + col] = v1;
            }
        }
        return;
    }

    // staged epilogues: write acc (+bias) into padded fp32 smem tile
    __syncthreads();
    const int PAD = (MODE == 1) ? 132 : 133;
    float* eps = (float*)smem;
#pragma unroll
    for (int mi = 0; mi < 4; mi++) {
#pragma unroll
        for (int ni = 0; ni < 4; ni++) {
            int cl = wn + ni * 8 + qc;
            float b0 = bias ? bias[bn + cl] : 0.f;
            float b1 = bias ? bias[bn + cl + 1] : 0.f;
            int r0 = wm + mi * 16 + qr;
            eps[r0 * PAD + cl]           = acc[mi][ni][0] + b0;
            eps[r0 * PAD + cl + 1]       = acc[mi][ni][1] + b1;
            eps[(r0 + 8) * PAD + cl]     = acc[mi][ni][2] + b0;
            eps[(r0 + 8) * PAD + cl + 1] = acc[mi][ni][3] + b1;
        }
    }
    __syncthreads();

    if (MODE == 1) {
        // RoPE within the head tile (N-tile == one head): pairs (d, d+64)
#pragma unroll
        for (int q8 = 0; q8 < 32; q8++) {
            int idx = t + (q8 << 8);          // 0..8191
            int d = idx & 63, r = idx >> 6;
            int m = bm + r;
            size_t cb = (size_t)m * HD;
            float c0 = cosp[cb + d],      s0 = sinp[cb + d];
            float c1 = cosp[cb + d + 64], s1 = sinp[cb + d + 64];
            float x0 = eps[r * 132 + d], x1 = eps[r * 132 + d + 64];
            float y0 = x0 * c0 - x1 * s0;
            float y1 = x1 * c1 + x0 * s1;
            size_t o = (size_t)m * DD + bn + d;
            __half hh, ll;
            split_hi_lo(y0, hh, ll); O1[o] = hh;      O2[o] = ll;
            split_hi_lo(y1, hh, ll); O1[o + 64] = hh; O2[o + 64] = ll;
        }
    } else {
        // MODE 2: transpose tile (s x d) -> Vt (b,h,d,s) fp16 hi
        int bh = ((bm >> 11) << 5) + (bn >> 7);
        int sbase_g = bm & (SS - 1);
#pragma unroll
        for (int q8 = 0; q8 < 16; q8++) {
            int qi = t + (q8 << 8);           // 0..4095 quads
            int d = qi >> 5;
            int sq = (qi & 31) << 2;
            float f0 = eps[(sq + 0) * 133 + d];
            float f1 = eps[(sq + 1) * 133 + d];
            float f2 = eps[(sq + 2) * 133 + d];
            float f3 = eps[(sq + 3) * 133 + d];
            size_t o = ((size_t)bh * HD + d) * SS + sbase_g + sq;
            *(__half2*)&O1[o]     = __halves2half2(__float2half_rn(f0), __float2half_rn(f1));
            *(__half2*)&O1[o + 2] = __halves2half2(__float2half_rn(f2), __float2half_rn(f3));
        }
    }
}

// ---------------------------------------------------------------------------
// score_tc: P = Q.K (fp16 3-product), causal; above-diagonal tiles untouched.
// ---------------------------------------------------------------------------
__global__ __launch_bounds__(256, 2) void score_tc(
    const __half* __restrict__ Qh, const __half* __restrict__ Ql,
    const __half* __restrict__ Kh, const __half* __restrict__ Kl,
    float* __restrict__ P)
{
    extern __shared__ char smem[];
    const int q0 = blockIdx.y << 7, k0 = blockIdx.x << 7;
    if (k0 > q0) return;

    const int bh = blockIdx.z;
    const int b = bh >> 5, h = bh & 31;
    const size_t pbase = ((size_t)bh * SS + q0) * SS + k0;
    const int t = threadIdx.x;
    const uint32_t sbase = smem_u32(smem);
    const int wid = t >> 5, lane = t & 31;

    const __half* base0 = Qh + (size_t)(b * SS + q0) * DD + (h << 7);
    const __half* base1 = Ql + (size_t)(b * SS + q0) * DD + (h << 7);
    const __half* base2 = Kh + (size_t)(b * SS + k0) * DD + (h << 7);
    const __half* base3 = Kl + (size_t)(b * SS + k0) * DD + (h << 7);

    auto load_stage = [&](int stg, int kc) {
        uint32_t db = sbase + stg * STAGE3;
#pragma unroll
        for (int i = 0; i < 8; i++) {
            int idx = t + (i << 8);
            int tile = idx >> 9;
            int w = idx & 511;
            int r = w >> 2, c = w & 3;
            const __half* src = (tile == 0 ? base0 : tile == 1 ? base1 :
                                 tile == 2 ? base2 : base3)
                                + (size_t)r * DD + kc + (c << 3);
            cp_async16(db + tile * TILE_B + sw_off32(r, c), src);
        }
        CP_COMMIT();
    };

    load_stage(0, 0);
    load_stage(1, 32);
    load_stage(2, 64);

    const int wm = (wid & 1) << 6;
    const int wn = (wid >> 1) << 5;
    const int lr = lane & 15, lc = lane >> 4;
    float acc[4][4][4] = {};
    const int iters = HD / 32;

    for (int it = 0; it < iters; it++) {
        int stg = it % NSTAGE_S;
        CP_WAIT2();
        __syncthreads();
        uint32_t sb = sbase + stg * STAGE3;
        hmma3(sb, 0, wm, wn, lr, lc, acc);
        hmma3(sb, 1, wm, wn, lr, lc, acc);
        __syncthreads();
        if (it + NSTAGE_S < iters) load_stage(stg, (it + NSTAGE_S) * 32);
        else CP_COMMIT();
    }

    const int qr = lane >> 2, qc = (lane & 3) << 1;
#pragma unroll
    for (int mi = 0; mi < 4; mi++) {
#pragma unroll
        for (int ni = 0; ni < 4; ni++) {
            int rl = wm + mi * 16 + qr;
            int cl = wn + ni * 8 + qc;
            int k = k0 + cl;
            int qA = q0 + rl, qB = qA + 8;
            float2 v0 = { (k <= qA) ? acc[mi][ni][0] : NEG_INF,
                          (k + 1 <= qA) ? acc[mi][ni][1] : NEG_INF };
            float2 v1 = { (k <= qB) ? acc[mi][ni][2] : NEG_INF,
                          (k + 1 <= qB) ? acc[mi][ni][3] : NEG_INF };
            *(float2*)&P[pbase + (size_t)rl * SS + cl] = v0;
            *(float2*)&P[pbase + (size_t)(rl + 8) * SS + cl] = v1;
        }
    }
}

// ---------------------------------------------------------------------------
// pv_tc: AO = P @ V^T (fp16 2-product), causal k-bound; gathered hi/lo out.
// ---------------------------------------------------------------------------
__global__ __launch_bounds__(256, 2) void pv_tc(
    const __half* __restrict__ Ph, const __half* __restrict__ Pl,
    const __half* __restrict__ Vth,
    __half* __restrict__ AOh, __half* __restrict__ AOl)
{
    extern __shared__ char smem[];
    const uint32_t sbase = smem_u32(smem);
    const int t = threadIdx.x;
    const int wid = t >> 5, lane = t & 31;
    const int q0 = blockIdx.x << 7;
    const int bh = blockIdx.y;
    const int b = bh >> 5, h = bh & 31;

    const __half* base0 = Ph  + ((size_t)bh * SS + q0) * SS;
    const __half* base1 = Pl  + ((size_t)bh * SS + q0) * SS;
    const __half* base2 = Vth + (size_t)bh * HD * SS;

    const int iters = (q0 >> 5) + 4;

    auto load_stage = [&](int stg, int kc) {
        uint32_t db = sbase + stg * STAGE2;
#pragma unroll
        for (int i = 0; i < 6; i++) {
            int idx = t + (i << 8);
            int tile = idx >> 9;
            int w = idx & 511;
            int r = w >> 2, c = w & 3;
            const __half* src = (tile == 0 ? base0 : tile == 1 ? base1 : base2)
                                + (size_t)r * SS + kc + (c << 3);
            cp_async16(db + tile * TILE_B + sw_off32(r, c), src);
        }
        CP_COMMIT();
    };

    load_stage(0, 0);
    load_stage(1, 32);
    load_stage(2, 64);
    load_stage(3, 96);

    const int wm = (wid & 1) << 6;
    const int wn = (wid >> 1) << 5;
    const int lr = lane & 15, lc = lane >> 4;
    float acc[4][4][4] = {};

    for (int it = 0; it < iters; it++) {
        int stg = it % NSTAGE_G;
        CP_WAIT3();
        __syncthreads();
        uint32_t sb = sbase + stg * STAGE2;
        hmma2(sb, 0, wm, wn, lr, lc, acc);
        hmma2(sb, 1, wm, wn, lr, lc, acc);
        __syncthreads();
        if (it + NSTAGE_G < iters) load_stage(stg, (it + NSTAGE_G) * 32);
        else CP_COMMIT();
    }

    const int qr = lane >> 2, qc = (lane & 3) << 1;
#pragma unroll
    for (int mi = 0; mi < 4; mi++) {
#pragma unroll
        for (int ni = 0; ni < 4; ni++) {
            int row = q0 + wm + mi * 16 + qr;
            int col = (h << 7) + wn + ni * 8 + qc;
            size_t m0 = ((size_t)b * SS + row) * DD + col;
            size_t m1 = m0 + (size_t)8 * DD;
            __half h0, l0, h1, l1;
            split_hi_lo(acc[mi][ni][0], h0, l0);
            split_hi_lo(acc[mi][ni][1], h1, l1);
            *(__half2*)&AOh[m0] = __halves2half2(h0, h1);
            *(__half2*)&AOl[m0] = __halves2half2(l0, l1);
            split_hi_lo(acc[mi][ni][2], h0, l0);
            split_hi_lo(acc[mi][ni][3], h1, l1);
            *(__half2*)&AOh[m1] = __halves2half2(h0, h1);
            *(__half2*)&AOl[m1] = __halves2half2(l0, l1);
        }
    }
}

// ---------------------------------------------------------------------------
// prep_hidden: one pass over hidden -> hh/hl (raw split) + qh/ql (roped Q)
// ---------------------------------------------------------------------------
__global__ void prep_hidden(const float* __restrict__ src,
                            __half* __restrict__ hh, __half* __restrict__ hl,
                            __half* __restrict__ qh, __half* __restrict__ ql,
                            const float* __restrict__ cosp, const float* __restrict__ sinp,
                            float scale)
{
    int idx = blockIdx.x * blockDim.x + threadIdx.x;
    const int total = BB * SS * HH * (HD / 2);
    if (idx >= total) return;
    int d  = idx & 63;
    int h  = (idx >> 6) & (HH - 1);
    int bs = idx >> 11;
    size_t base = (size_t)bs * DD + (h << 7);
    size_t cbase = (size_t)bs * HD;
    float c0 = cosp[cbase + d],      s0 = sinp[cbase + d];
    float c1 = cosp[cbase + d + 64], s1 = sinp[cbase + d + 64];
    float x0 = src[base + d], x1 = src[base + d + 64];
    __half a, b;
    split_hi_lo(x0, a, b); hh[base + d] = a;      hl[base + d] = b;
    split_hi_lo(x1, a, b); hh[base + d + 64] = a; hl[base + d + 64] = b;
    float y0 = (x0 * c0 - x1 * s0) * scale;
    float y1 = (x1 * c1 + x0 * s1) * scale;
    split_hi_lo(y0, a, b); qh[base + d] = a;      ql[base + d] = b;
    split_hi_lo(y1, a, b); qh[base + d + 64] = a; ql[base + d + 64] = b;
}

// fp32 -> fp16 hi only (weights)
__global__ void conv_hi(const float* __restrict__ x, __half* __restrict__ hi)
{
    size_t i = (size_t)blockIdx.x * blockDim.x + threadIdx.x;
    if (i >= NELT / 4) return;
    float4 v = ((const float4*)x)[i];
    ((__half2*)hi)[i * 2]     = __halves2half2(__float2half_rn(v.x), __float2half_rn(v.y));
    ((__half2*)hi)[i * 2 + 1] = __halves2half2(__float2half_rn(v.z), __float2half_rn(v.w));
}

// ---------------------------------------------------------------------------
// Causal softmax in place + fp16 hi/lo emission — float4 vectorized.
// ---------------------------------------------------------------------------
__global__ __launch_bounds__(256) void softmax_pconv_kernel(
    float* __restrict__ P, __half* __restrict__ Ph, __half* __restrict__ Pl)
{
    size_t row = blockIdx.x;
    int q = (int)(row & (SS - 1));
    int kend = ((q >> 7) + 1) << 7;
    float4* p4 = (float4*)(P + row * (size_t)SS);
    __half* ph = Ph + row * (size_t)SS;
    __half* pl = Pl + row * (size_t)SS;
    int t = threadIdx.x;

    float v[8];
    {
        float4 va = p4[t], vb = p4[t + 256];
        int oa = t << 2, ob = 1024 + (t << 2);
        v[0] = (oa     <= q) ? va.x : -3.4e38f;
        v[1] = (oa + 1 <= q) ? va.y : -3.4e38f;
        v[2] = (oa + 2 <= q) ? va.z : -3.4e38f;
        v[3] = (oa + 3 <= q) ? va.w : -3.4e38f;
        v[4] = (ob     <= q) ? vb.x : -3.4e38f;
        v[5] = (ob + 1 <= q) ? vb.y : -3.4e38f;
        v[6] = (ob + 2 <= q) ? vb.z : -3.4e38f;
        v[7] = (ob + 3 <= q) ? vb.w : -3.4e38f;
    }
    float mx = v[0];
#pragma unroll
    for (int i = 1; i < 8; i++) mx = fmaxf(mx, v[i]);
#pragma unroll
    for (int o = 16; o; o >>= 1) mx = fmaxf(mx, __shfl_xor_sync(0xffffffffu, mx, o));
    __shared__ float rmax[8], rsum[8];
    if ((t & 31) == 0) rmax[t >> 5] = mx;
    __syncthreads();
    mx = rmax[0];
#pragma unroll
    for (int i = 1; i < 8; i++) mx = fmaxf(mx, rmax[i]);
    float sum = 0.f;
#pragma unroll
    for (int i = 0; i < 8; i++) {
        v[i] = (v[i] > -3.3e38f) ? __expf(v[i] - mx) : 0.f;
        sum += v[i];
    }
#pragma unroll
    for (int o = 16; o; o >>= 1) sum += __shfl_xor_sync(0xffffffffu, sum, o);
    if ((t & 31) == 0) rsum[t >> 5] = sum;
    __syncthreads();
    sum = rsum[0];
#pragma unroll
    for (int i = 1; i < 8; i++) sum += rsum[i];
    float inv = 1.0f / sum;
#pragma unroll
    for (int i = 0; i < 8; i++) v[i] *= inv;

    p4[t]       = make_float4(v[0], v[1], v[2], v[3]);
    p4[t + 256] = make_float4(v[4], v[5], v[6], v[7]);

    // fp16 emission up to kend (multiple of 128 -> quad-aligned)
    {
        int oa = t << 2;
        if (oa < kend) {
            __half h0, h1, h2, h3, l0, l1, l2, l3;
            split_hi_lo(v[0], h0, l0); split_hi_lo(v[1], h1, l1);
            split_hi_lo(v[2], h2, l2); split_hi_lo(v[3], h3, l3);
            *(__half2*)&ph[oa]     = __halves2half2(h0, h1);
            *(__half2*)&ph[oa + 2] = __halves2half2(h2, h3);
            *(__half2*)&pl[oa]     = __halves2half2(l0, l1);
            *(__half2*)&pl[oa + 2] = __halves2half2(l2, l3);
        }
        int ob = 1024 + (t << 2);
        if (ob < kend) {
            __half h0, h1, h2, h3, l0, l1, l2, l3;
            split_hi_lo(v[4], h0, l0); split_hi_lo(v[5], h1, l1);
            split_hi_lo(v[6], h2, l2); split_hi_lo(v[7], h3, l3);
            *(__half2*)&ph[ob]     = __halves2half2(h0, h1);
            *(__half2*)&ph[ob + 2] = __halves2half2(h2, h3);
            *(__half2*)&pl[ob]     = __halves2half2(l0, l1);
            *(__half2*)&pl[ob + 2] = __halves2half2(l2, l3);
        }
    }
}

// ---------------------------------------------------------------------------
extern "C" void kernel_launch(void* const* d_in, const int* in_sizes, int n_in,
                              void* d_out, int out_size)
{
    (void)in_sizes; (void)n_in; (void)out_size;
    const float* hidden = (const float*)d_in[0];
    const float* Wqk    = (const float*)d_in[1];
    const float* bqk    = (const float*)d_in[2];
    const float* Wv     = (const float*)d_in[3];
    const float* bv     = (const float*)d_in[4];
    const float* Wo     = (const float*)d_in[5];
    const float* cosp   = (const float*)d_in[6];
    const float* sinp   = (const float*)d_in[7];

    float* out   = (float*)d_out;
    float* attnw = out + (size_t)BB * SS * DD;

    __half *hh, *hl, *qkh, *vh, *oh;
    __half *qh, *ql, *kh, *kl, *vth, *aoh, *aol, *ph, *pl;
    cudaGetSymbolAddress((void**)&hh,  g_hh);  cudaGetSymbolAddress((void**)&hl,  g_hl);
    cudaGetSymbolAddress((void**)&qkh, g_qkh);
    cudaGetSymbolAddress((void**)&vh,  g_vh);
    cudaGetSymbolAddress((void**)&oh,  g_oh);
    cudaGetSymbolAddress((void**)&qh,  g_qh);  cudaGetSymbolAddress((void**)&ql,  g_ql);
    cudaGetSymbolAddress((void**)&kh,  g_kh);  cudaGetSymbolAddress((void**)&kl,  g_kl);
    cudaGetSymbolAddress((void**)&vth, g_vth);
    cudaGetSymbolAddress((void**)&aoh, g_aoh); cudaGetSymbolAddress((void**)&aol, g_aol);
    cudaGetSymbolAddress((void**)&ph,  g_ph);  cudaGetSymbolAddress((void**)&pl,  g_pl);

    cudaFuncSetAttribute(gemm_tc<0>, cudaFuncAttributeMaxDynamicSharedMemorySize, SMEM_G);
    cudaFuncSetAttribute(gemm_tc<1>, cudaFuncAttributeMaxDynamicSharedMemorySize, SMEM_G);
    cudaFuncSetAttribute(gemm_tc<2>, cudaFuncAttributeMaxDynamicSharedMemorySize, SMEM_G);
    cudaFuncSetAttribute(score_tc,   cudaFuncAttributeMaxDynamicSharedMemorySize, SMEM_S);
    cudaFuncSetAttribute(pv_tc,      cudaFuncAttributeMaxDynamicSharedMemorySize, SMEM_G);

    const int cvblk = (int)((NELT / 4 + 255) / 256);
    const int rope_total = BB * SS * HH * (HD / 2);
    const float scale = 0.088388347648318447f;  // 128^-0.5

    prep_hidden<<<(rope_total + 255) / 256, 256>>>(hidden, hh, hl, qh, ql, cosp, sinp, scale);
    conv_hi<<<cvblk, 256>>>(Wqk, qkh);
    conv_hi<<<cvblk, 256>>>(Wv,  vh);
    conv_hi<<<cvblk, 256>>>(Wo,  oh);

    dim3 gg(DD / 128, (BB * SS) / 128);
    // QK projection with fused bias+RoPE+split
    gemm_tc<1><<<gg, 256, SMEM_G>>>(hh, hl, qkh, bqk, cosp, sinp, nullptr, kh, kl);
    // V projection with fused bias+transpose+split
    gemm_tc<2><<<gg, 256, SMEM_G>>>(hh, hl, vh,  bv,  nullptr, nullptr, nullptr, vth, nullptr);

    score_tc<<<dim3(SS / 128, SS / 128, BB * HH), 256, SMEM_S>>>(qh, ql, kh, kl, attnw);
    softmax_pconv_kernel<<<BB * HH * SS, 256>>>(attnw, ph, pl);
    pv_tc<<<dim3(SS / 128, BB * HH), 256, SMEM_G>>>(ph, pl, vth, aoh, aol);

    gemm_tc<0><<<gg, 256, SMEM_G>>>(aoh, aol, oh, nullptr, nullptr, nullptr, out, nullptr, nullptr);
}

// round 9
// speedup vs baseline: 3.9357x; 1.0479x over previous
#include <cuda_runtime.h>
#include <cuda_fp16.h>
#include <cstdint>
#include <cstddef>

#define BB 2
#define SS 2048
#define DD 4096
#define HH 32
#define HD 128
#define NEG_INF -1000000000.0f

#define NELT ((size_t)BB * SS * DD)          // 16,777,216
#define NP   ((size_t)BB * HH * SS * SS)     // 268,435,456

// ---------------- scratch (device globals; alloc APIs forbidden) ----------
__device__ __half g_hh[NELT],  g_hl[NELT];    // hidden hi/lo
__device__ __half g_qkh[NELT];                // Wqk hi
__device__ __half g_vh[NELT];                 // Wv hi
__device__ __half g_oh[NELT];                 // Wo hi
__device__ __half g_qh[NELT],  g_ql[NELT];    // roped Q hi/lo (b,s,h,hd)
__device__ __half g_kh[NELT],  g_kl[NELT];    // roped K hi/lo (b,s,h,hd)
__device__ __half g_vth[NELT];                // V^T hi (b,h,d,k)
__device__ __half g_aoh[NELT], g_aol[NELT];   // attn-out gathered hi/lo
__device__ __half g_ph[NP];                   // softmax P (fp16 hi only)

// ---------------- helpers ---------------------------------------------------
__device__ __forceinline__ uint32_t smem_u32(const void* p) {
    uint32_t a;
    asm("{ .reg .u64 t; cvta.to.shared.u64 t, %1; cvt.u32.u64 %0, t; }" : "=r"(a) : "l"(p));
    return a;
}
__device__ __forceinline__ void cp_async16(uint32_t dst, const void* src) {
    asm volatile("cp.async.cg.shared.global [%0], [%1], 16;" :: "r"(dst), "l"(src));
}
#define CP_COMMIT() asm volatile("cp.async.commit_group;" ::: "memory")
#define CP_WAIT2()  asm volatile("cp.async.wait_group 2;" ::: "memory")
#define CP_WAIT3()  asm volatile("cp.async.wait_group 3;" ::: "memory")
#define CP_WAIT5()  asm volatile("cp.async.wait_group 5;" ::: "memory")

__device__ __forceinline__ void ldmx4(uint32_t* r, uint32_t addr) {
    asm volatile("ldmatrix.sync.aligned.m8n8.x4.shared.b16 {%0,%1,%2,%3}, [%4];"
                 : "=r"(r[0]), "=r"(r[1]), "=r"(r[2]), "=r"(r[3]) : "r"(addr));
}
__device__ __forceinline__ void mma16816(float* d, const uint32_t* a, const uint32_t* b) {
    asm volatile(
        "mma.sync.aligned.m16n8k16.row.col.f32.f16.f16.f32 "
        "{%0,%1,%2,%3}, {%4,%5,%6,%7}, {%8,%9}, {%0,%1,%2,%3};"
        : "+f"(d[0]), "+f"(d[1]), "+f"(d[2]), "+f"(d[3])
        : "r"(a[0]), "r"(a[1]), "r"(a[2]), "r"(a[3]), "r"(b[0]), "r"(b[1]));
}
__device__ __forceinline__ void split_hi_lo(float f, __half& h, __half& l) {
    h = __float2half_rn(f);
    l = __float2half_rn(f - __half2float(h));
}

// ---- BK=32 tiles ------------------------------------------------------------
#define TILE_B 8192                     // 128 rows x 64B (32 fp16)
#define STAGE2 (3 * TILE_B)             // gemm: Ah, Al, Bh
#define STAGE3 (4 * TILE_B)             // score: Qh, Ql, Kh, Kl
#define STAGE1 (2 * TILE_B)             // pv:    Ph, Vth
#define NSTAGE_G 4
#define NSTAGE_S 3
#define NSTAGE_P 6
#define SMEM_G (NSTAGE_G * STAGE2)      // 98304
#define SMEM_S (NSTAGE_S * STAGE3)      // 98304
#define SMEM_P (NSTAGE_P * STAGE1)      // 98304

__device__ __forceinline__ uint32_t sw_off32(int r, int chunk) {
    return (uint32_t)(r << 6) + (((chunk ^ ((r >> 1) & 3)) << 4));
}

// ---- 2-product K=16 MMA step: A(hi+lo) x B(hi). Tiles: [Ah|Al|Bh] -----------
__device__ __forceinline__ void hmma2(
    uint32_t sb, int ks, int wm, int wn, int lr, int lc, float (&acc)[4][4][4])
{
    const int chunk = ks * 2 + lc;
    uint32_t bh[4][2];
#pragma unroll
    for (int g = 0; g < 2; g++) {
        int r = wn + g * 16 + lr;
        uint32_t rb[4];
        ldmx4(rb, sb + 2 * TILE_B + sw_off32(r, chunk));
        bh[g*2+0][0] = rb[0]; bh[g*2+0][1] = rb[2];
        bh[g*2+1][0] = rb[1]; bh[g*2+1][1] = rb[3];
    }
#pragma unroll
    for (int mi = 0; mi < 4; mi++) {
        int r = wm + mi * 16 + lr;
        uint32_t off = sw_off32(r, chunk);
        uint32_t ah[4], al[4];
        ldmx4(ah, sb + off);
        ldmx4(al, sb + TILE_B + off);
#pragma unroll
        for (int ni = 0; ni < 4; ni++) {
            mma16816(acc[mi][ni], ah, bh[ni]);
            mma16816(acc[mi][ni], al, bh[ni]);
        }
    }
}

// ---- 1-product K=16 MMA step (pv): tiles [Ph|Vth] ---------------------------
__device__ __forceinline__ void hmma1(
    uint32_t sb, int ks, int wm, int wn, int lr, int lc, float (&acc)[4][4][4])
{
    const int chunk = ks * 2 + lc;
    uint32_t bh[4][2];
#pragma unroll
    for (int g = 0; g < 2; g++) {
        int r = wn + g * 16 + lr;
        uint32_t rb[4];
        ldmx4(rb, sb + TILE_B + sw_off32(r, chunk));
        bh[g*2+0][0] = rb[0]; bh[g*2+0][1] = rb[2];
        bh[g*2+1][0] = rb[1]; bh[g*2+1][1] = rb[3];
    }
#pragma unroll
    for (int mi = 0; mi < 4; mi++) {
        int r = wm + mi * 16 + lr;
        uint32_t ah[4];
        ldmx4(ah, sb + sw_off32(r, chunk));
#pragma unroll
        for (int ni = 0; ni < 4; ni++)
            mma16816(acc[mi][ni], ah, bh[ni]);
    }
}

// ---- 3-product K=16 MMA step (score): tiles [Qh|Ql|Kh|Kl] -------------------
__device__ __forceinline__ void hmma3(
    uint32_t sb, int ks, int wm, int wn, int lr, int lc, float (&acc)[4][4][4])
{
    const int chunk = ks * 2 + lc;
    uint32_t bh[4][2], bl[4][2];
#pragma unroll
    for (int g = 0; g < 2; g++) {
        int r = wn + g * 16 + lr;
        uint32_t off = sw_off32(r, chunk);
        uint32_t rb[4];
        ldmx4(rb, sb + 2 * TILE_B + off);
        bh[g*2+0][0] = rb[0]; bh[g*2+0][1] = rb[2];
        bh[g*2+1][0] = rb[1]; bh[g*2+1][1] = rb[3];
        ldmx4(rb, sb + 3 * TILE_B + off);
        bl[g*2+0][0] = rb[0]; bl[g*2+0][1] = rb[2];
        bl[g*2+1][0] = rb[1]; bl[g*2+1][1] = rb[3];
    }
#pragma unroll
    for (int mi = 0; mi < 4; mi++) {
        int r = wm + mi * 16 + lr;
        uint32_t off = sw_off32(r, chunk);
        uint32_t ah[4], al[4];
        ldmx4(ah, sb + off);
        ldmx4(al, sb + TILE_B + off);
#pragma unroll
        for (int ni = 0; ni < 4; ni++) {
            mma16816(acc[mi][ni], ah, bh[ni]);
            mma16816(acc[mi][ni], ah, bl[ni]);
            mma16816(acc[mi][ni], al, bh[ni]);
        }
    }
}

// ---------------------------------------------------------------------------
// HMMA fp16 2-product GEMM with fused epilogues.
//  MODE 0: C = fp32 out (final projection)
//  MODE 1: QK projection -> +bias -> RoPE -> fp16 hi/lo (kh=O1, kl=O2)
//  MODE 2: V projection  -> +bias -> transpose to (b,h,d,s) fp16 hi (O1)
// ---------------------------------------------------------------------------
template<int MODE>
__global__ __launch_bounds__(256, 2) void gemm_tc(
    const __half* __restrict__ Ah, const __half* __restrict__ Al,
    const __half* __restrict__ Bh,
    const float* __restrict__ bias,
    const float* __restrict__ cosp, const float* __restrict__ sinp,
    float* __restrict__ C, __half* __restrict__ O1, __half* __restrict__ O2)
{
    extern __shared__ char smem[];
    const uint32_t sbase = smem_u32(smem);
    const int t = threadIdx.x;
    const int wid = t >> 5, lane = t & 31;
    const int bm = blockIdx.y << 7, bn = blockIdx.x << 7;

    const __half* base0 = Ah + (size_t)bm * DD;
    const __half* base1 = Al + (size_t)bm * DD;
    const __half* base2 = Bh + (size_t)bn * DD;

    auto load_stage = [&](int stg, int kc) {
        uint32_t db = sbase + stg * STAGE2;
#pragma unroll
        for (int i = 0; i < 6; i++) {
            int idx = t + (i << 8);
            int tile = idx >> 9;
            int w = idx & 511;
            int r = w >> 2, c = w & 3;
            const __half* src = (tile == 0 ? base0 : tile == 1 ? base1 : base2)
                                + (size_t)r * DD + kc + (c << 3);
            cp_async16(db + tile * TILE_B + sw_off32(r, c), src);
        }
        CP_COMMIT();
    };

    load_stage(0, 0);
    load_stage(1, 32);
    load_stage(2, 64);
    load_stage(3, 96);

    const int wm = (wid & 1) << 6;
    const int wn = (wid >> 1) << 5;
    const int lr = lane & 15, lc = lane >> 4;

    float acc[4][4][4] = {};
    const int iters = DD / 32;

    for (int it = 0; it < iters; it++) {
        int stg = it % NSTAGE_G;
        CP_WAIT3();
        __syncthreads();
        uint32_t sb = sbase + stg * STAGE2;
        hmma2(sb, 0, wm, wn, lr, lc, acc);
        hmma2(sb, 1, wm, wn, lr, lc, acc);
        __syncthreads();
        if (it + NSTAGE_G < iters) load_stage(stg, (it + NSTAGE_G) * 32);
        else CP_COMMIT();
    }

    const int qr = lane >> 2, qc = (lane & 3) << 1;

    if (MODE == 0) {
#pragma unroll
        for (int mi = 0; mi < 4; mi++) {
#pragma unroll
            for (int ni = 0; ni < 4; ni++) {
                int col = bn + wn + ni * 8 + qc;
                int row0 = bm + wm + mi * 16 + qr;
                float2 v0 = { acc[mi][ni][0], acc[mi][ni][1] };
                float2 v1 = { acc[mi][ni][2], acc[mi][ni][3] };
                *(float2*)&C[(size_t)row0 * DD + col] = v0;
                *(float2*)&C[(size_t)(row0 + 8) * DD + col] = v1;
            }
        }
        return;
    }

    // staged epilogues: write acc (+bias) into padded fp32 smem tile
    __syncthreads();
    const int PAD = (MODE == 1) ? 132 : 133;
    float* eps = (float*)smem;
#pragma unroll
    for (int mi = 0; mi < 4; mi++) {
#pragma unroll
        for (int ni = 0; ni < 4; ni++) {
            int cl = wn + ni * 8 + qc;
            float b0 = bias ? bias[bn + cl] : 0.f;
            float b1 = bias ? bias[bn + cl + 1] : 0.f;
            int r0 = wm + mi * 16 + qr;
            eps[r0 * PAD + cl]           = acc[mi][ni][0] + b0;
            eps[r0 * PAD + cl + 1]       = acc[mi][ni][1] + b1;
            eps[(r0 + 8) * PAD + cl]     = acc[mi][ni][2] + b0;
            eps[(r0 + 8) * PAD + cl + 1] = acc[mi][ni][3] + b1;
        }
    }
    __syncthreads();

    if (MODE == 1) {
        // RoPE within the head tile (N-tile == one head): pairs (d, d+64)
#pragma unroll
        for (int q8 = 0; q8 < 32; q8++) {
            int idx = t + (q8 << 8);          // 0..8191
            int d = idx & 63, r = idx >> 6;
            int m = bm + r;
            size_t cb = (size_t)m * HD;
            float c0 = cosp[cb + d],      s0 = sinp[cb + d];
            float c1 = cosp[cb + d + 64], s1 = sinp[cb + d + 64];
            float x0 = eps[r * 132 + d], x1 = eps[r * 132 + d + 64];
            float y0 = x0 * c0 - x1 * s0;
            float y1 = x1 * c1 + x0 * s1;
            size_t o = (size_t)m * DD + bn + d;
            __half hh, ll;
            split_hi_lo(y0, hh, ll); O1[o] = hh;      O2[o] = ll;
            split_hi_lo(y1, hh, ll); O1[o + 64] = hh; O2[o + 64] = ll;
        }
    } else {
        // MODE 2: transpose tile (s x d) -> Vt (b,h,d,s) fp16 hi
        int bh = ((bm >> 11) << 5) + (bn >> 7);
        int sbase_g = bm & (SS - 1);
#pragma unroll
        for (int q8 = 0; q8 < 16; q8++) {
            int qi = t + (q8 << 8);           // 0..4095 quads
            int d = qi >> 5;
            int sq = (qi & 31) << 2;
            float f0 = eps[(sq + 0) * 133 + d];
            float f1 = eps[(sq + 1) * 133 + d];
            float f2 = eps[(sq + 2) * 133 + d];
            float f3 = eps[(sq + 3) * 133 + d];
            size_t o = ((size_t)bh * HD + d) * SS + sbase_g + sq;
            *(__half2*)&O1[o]     = __halves2half2(__float2half_rn(f0), __float2half_rn(f1));
            *(__half2*)&O1[o + 2] = __halves2half2(__float2half_rn(f2), __float2half_rn(f3));
        }
    }
}

// ---------------------------------------------------------------------------
// score_tc: P = Q.K (fp16 3-product), causal; above-diagonal tiles untouched.
// ---------------------------------------------------------------------------
__global__ __launch_bounds__(256, 2) void score_tc(
    const __half* __restrict__ Qh, const __half* __restrict__ Ql,
    const __half* __restrict__ Kh, const __half* __restrict__ Kl,
    float* __restrict__ P)
{
    extern __shared__ char smem[];
    const int q0 = blockIdx.y << 7, k0 = blockIdx.x << 7;
    if (k0 > q0) return;

    const int bh = blockIdx.z;
    const int b = bh >> 5, h = bh & 31;
    const size_t pbase = ((size_t)bh * SS + q0) * SS + k0;
    const int t = threadIdx.x;
    const uint32_t sbase = smem_u32(smem);
    const int wid = t >> 5, lane = t & 31;

    const __half* base0 = Qh + (size_t)(b * SS + q0) * DD + (h << 7);
    const __half* base1 = Ql + (size_t)(b * SS + q0) * DD + (h << 7);
    const __half* base2 = Kh + (size_t)(b * SS + k0) * DD + (h << 7);
    const __half* base3 = Kl + (size_t)(b * SS + k0) * DD + (h << 7);

    auto load_stage = [&](int stg, int kc) {
        uint32_t db = sbase + stg * STAGE3;
#pragma unroll
        for (int i = 0; i < 8; i++) {
            int idx = t + (i << 8);
            int tile = idx >> 9;
            int w = idx & 511;
            int r = w >> 2, c = w & 3;
            const __half* src = (tile == 0 ? base0 : tile == 1 ? base1 :
                                 tile == 2 ? base2 : base3)
                                + (size_t)r * DD + kc + (c << 3);
            cp_async16(db + tile * TILE_B + sw_off32(r, c), src);
        }
        CP_COMMIT();
    };

    load_stage(0, 0);
    load_stage(1, 32);
    load_stage(2, 64);

    const int wm = (wid & 1) << 6;
    const int wn = (wid >> 1) << 5;
    const int lr = lane & 15, lc = lane >> 4;
    float acc[4][4][4] = {};
    const int iters = HD / 32;

    for (int it = 0; it < iters; it++) {
        int stg = it % NSTAGE_S;
        CP_WAIT2();
        __syncthreads();
        uint32_t sb = sbase + stg * STAGE3;
        hmma3(sb, 0, wm, wn, lr, lc, acc);
        hmma3(sb, 1, wm, wn, lr, lc, acc);
        __syncthreads();
        if (it + NSTAGE_S < iters) load_stage(stg, (it + NSTAGE_S) * 32);
        else CP_COMMIT();
    }

    const int qr = lane >> 2, qc = (lane & 3) << 1;
#pragma unroll
    for (int mi = 0; mi < 4; mi++) {
#pragma unroll
        for (int ni = 0; ni < 4; ni++) {
            int rl = wm + mi * 16 + qr;
            int cl = wn + ni * 8 + qc;
            int k = k0 + cl;
            int qA = q0 + rl, qB = qA + 8;
            float2 v0 = { (k <= qA) ? acc[mi][ni][0] : NEG_INF,
                          (k + 1 <= qA) ? acc[mi][ni][1] : NEG_INF };
            float2 v1 = { (k <= qB) ? acc[mi][ni][2] : NEG_INF,
                          (k + 1 <= qB) ? acc[mi][ni][3] : NEG_INF };
            *(float2*)&P[pbase + (size_t)rl * SS + cl] = v0;
            *(float2*)&P[pbase + (size_t)(rl + 8) * SS + cl] = v1;
        }
    }
}

// ---------------------------------------------------------------------------
// pv_tc: AO = P @ V^T (fp16 1-product), causal k-bound; gathered hi/lo out.
// 6-stage pipeline (2 tiles/stage: Ph, Vth).
// ---------------------------------------------------------------------------
__global__ __launch_bounds__(256, 2) void pv_tc(
    const __half* __restrict__ Ph,
    const __half* __restrict__ Vth,
    __half* __restrict__ AOh, __half* __restrict__ AOl)
{
    extern __shared__ char smem[];
    const uint32_t sbase = smem_u32(smem);
    const int t = threadIdx.x;
    const int wid = t >> 5, lane = t & 31;
    const int q0 = blockIdx.x << 7;
    const int bh = blockIdx.y;
    const int b = bh >> 5, h = bh & 31;

    const __half* base0 = Ph  + ((size_t)bh * SS + q0) * SS;
    const __half* base1 = Vth + (size_t)bh * HD * SS;

    const int iters = (q0 >> 5) + 4;

    auto load_stage = [&](int stg, int kc) {
        uint32_t db = sbase + stg * STAGE1;
#pragma unroll
        for (int i = 0; i < 4; i++) {
            int idx = t + (i << 8);              // 0..1023
            int tile = idx >> 9;                 // 0..1
            int w = idx & 511;
            int r = w >> 2, c = w & 3;
            const __half* src = (tile == 0 ? base0 : base1)
                                + (size_t)r * SS + kc + (c << 3);
            cp_async16(db + tile * TILE_B + sw_off32(r, c), src);
        }
        CP_COMMIT();
    };

#pragma unroll
    for (int s = 0; s < NSTAGE_P; s++) {
        if (s < iters) load_stage(s, s * 32);
        else CP_COMMIT();
    }

    const int wm = (wid & 1) << 6;
    const int wn = (wid >> 1) << 5;
    const int lr = lane & 15, lc = lane >> 4;
    float acc[4][4][4] = {};

    for (int it = 0; it < iters; it++) {
        int stg = it % NSTAGE_P;
        CP_WAIT5();
        __syncthreads();
        uint32_t sb = sbase + stg * STAGE1;
        hmma1(sb, 0, wm, wn, lr, lc, acc);
        hmma1(sb, 1, wm, wn, lr, lc, acc);
        __syncthreads();
        if (it + NSTAGE_P < iters) load_stage(stg, (it + NSTAGE_P) * 32);
        else CP_COMMIT();
    }

    const int qr = lane >> 2, qc = (lane & 3) << 1;
#pragma unroll
    for (int mi = 0; mi < 4; mi++) {
#pragma unroll
        for (int ni = 0; ni < 4; ni++) {
            int row = q0 + wm + mi * 16 + qr;
            int col = (h << 7) + wn + ni * 8 + qc;
            size_t m0 = ((size_t)b * SS + row) * DD + col;
            size_t m1 = m0 + (size_t)8 * DD;
            __half h0, l0, h1, l1;
            split_hi_lo(acc[mi][ni][0], h0, l0);
            split_hi_lo(acc[mi][ni][1], h1, l1);
            *(__half2*)&AOh[m0] = __halves2half2(h0, h1);
            *(__half2*)&AOl[m0] = __halves2half2(l0, l1);
            split_hi_lo(acc[mi][ni][2], h0, l0);
            split_hi_lo(acc[mi][ni][3], h1, l1);
            *(__half2*)&AOh[m1] = __halves2half2(h0, h1);
            *(__half2*)&AOl[m1] = __halves2half2(l0, l1);
        }
    }
}

// ---------------------------------------------------------------------------
// prep_hidden: one pass over hidden -> hh/hl (raw split) + qh/ql (roped Q)
// ---------------------------------------------------------------------------
__global__ void prep_hidden(const float* __restrict__ src,
                            __half* __restrict__ hh, __half* __restrict__ hl,
                            __half* __restrict__ qh, __half* __restrict__ ql,
                            const float* __restrict__ cosp, const float* __restrict__ sinp,
                            float scale)
{
    int idx = blockIdx.x * blockDim.x + threadIdx.x;
    const int total = BB * SS * HH * (HD / 2);
    if (idx >= total) return;
    int d  = idx & 63;
    int h  = (idx >> 6) & (HH - 1);
    int bs = idx >> 11;
    size_t base = (size_t)bs * DD + (h << 7);
    size_t cbase = (size_t)bs * HD;
    float c0 = cosp[cbase + d],      s0 = sinp[cbase + d];
    float c1 = cosp[cbase + d + 64], s1 = sinp[cbase + d + 64];
    float x0 = src[base + d], x1 = src[base + d + 64];
    __half a, b;
    split_hi_lo(x0, a, b); hh[base + d] = a;      hl[base + d] = b;
    split_hi_lo(x1, a, b); hh[base + d + 64] = a; hl[base + d + 64] = b;
    float y0 = (x0 * c0 - x1 * s0) * scale;
    float y1 = (x1 * c1 + x0 * s1) * scale;
    split_hi_lo(y0, a, b); qh[base + d] = a;      ql[base + d] = b;
    split_hi_lo(y1, a, b); qh[base + d + 64] = a; ql[base + d + 64] = b;
}

// fp32 -> fp16 hi only (weights)
__global__ void conv_hi(const float* __restrict__ x, __half* __restrict__ hi)
{
    size_t i = (size_t)blockIdx.x * blockDim.x + threadIdx.x;
    if (i >= NELT / 4) return;
    float4 v = ((const float4*)x)[i];
    ((__half2*)hi)[i * 2]     = __halves2half2(__float2half_rn(v.x), __float2half_rn(v.y));
    ((__half2*)hi)[i * 2 + 1] = __halves2half2(__float2half_rn(v.z), __float2half_rn(v.w));
}

// ---------------------------------------------------------------------------
// Causal softmax in place + fp16 emission (hi only) — float4 vectorized.
// ---------------------------------------------------------------------------
__global__ __launch_bounds__(256) void softmax_pconv_kernel(
    float* __restrict__ P, __half* __restrict__ Ph)
{
    size_t row = blockIdx.x;
    int q = (int)(row & (SS - 1));
    int kend = ((q >> 7) + 1) << 7;
    float4* p4 = (float4*)(P + row * (size_t)SS);
    __half* ph = Ph + row * (size_t)SS;
    int t = threadIdx.x;

    float v[8];
    {
        float4 va = p4[t], vb = p4[t + 256];
        int oa = t << 2, ob = 1024 + (t << 2);
        v[0] = (oa     <= q) ? va.x : -3.4e38f;
        v[1] = (oa + 1 <= q) ? va.y : -3.4e38f;
        v[2] = (oa + 2 <= q) ? va.z : -3.4e38f;
        v[3] = (oa + 3 <= q) ? va.w : -3.4e38f;
        v[4] = (ob     <= q) ? vb.x : -3.4e38f;
        v[5] = (ob + 1 <= q) ? vb.y : -3.4e38f;
        v[6] = (ob + 2 <= q) ? vb.z : -3.4e38f;
        v[7] = (ob + 3 <= q) ? vb.w : -3.4e38f;
    }
    float mx = v[0];
#pragma unroll
    for (int i = 1; i < 8; i++) mx = fmaxf(mx, v[i]);
#pragma unroll
    for (int o = 16; o; o >>= 1) mx = fmaxf(mx, __shfl_xor_sync(0xffffffffu, mx, o));
    __shared__ float rmax[8], rsum[8];
    if ((t & 31) == 0) rmax[t >> 5] = mx;
    __syncthreads();
    mx = rmax[0];
#pragma unroll
    for (int i = 1; i < 8; i++) mx = fmaxf(mx, rmax[i]);
    float sum = 0.f;
#pragma unroll
    for (int i = 0; i < 8; i++) {
        v[i] = (v[i] > -3.3e38f) ? __expf(v[i] - mx) : 0.f;
        sum += v[i];
    }
#pragma unroll
    for (int o = 16; o; o >>= 1) sum += __shfl_xor_sync(0xffffffffu, sum, o);
    if ((t & 31) == 0) rsum[t >> 5] = sum;
    __syncthreads();
    sum = rsum[0];
#pragma unroll
    for (int i = 1; i < 8; i++) sum += rsum[i];
    float inv = 1.0f / sum;
#pragma unroll
    for (int i = 0; i < 8; i++) v[i] *= inv;

    p4[t]       = make_float4(v[0], v[1], v[2], v[3]);
    p4[t + 256] = make_float4(v[4], v[5], v[6], v[7]);

    // fp16 hi emission up to kend (multiple of 128 -> quad-aligned)
    {
        int oa = t << 2;
        if (oa < kend) {
            *(__half2*)&ph[oa]     = __halves2half2(__float2half_rn(v[0]), __float2half_rn(v[1]));
            *(__half2*)&ph[oa + 2] = __halves2half2(__float2half_rn(v[2]), __float2half_rn(v[3]));
        }
        int ob = 1024 + (t << 2);
        if (ob < kend) {
            *(__half2*)&ph[ob]     = __halves2half2(__float2half_rn(v[4]), __float2half_rn(v[5]));
            *(__half2*)&ph[ob + 2] = __halves2half2(__float2half_rn(v[6]), __float2half_rn(v[7]));
        }
    }
}

// ---------------------------------------------------------------------------
extern "C" void kernel_launch(void* const* d_in, const int* in_sizes, int n_in,
                              void* d_out, int out_size)
{
    (void)in_sizes; (void)n_in; (void)out_size;
    const float* hidden = (const float*)d_in[0];
    const float* Wqk    = (const float*)d_in[1];
    const float* bqk    = (const float*)d_in[2];
    const float* Wv     = (const float*)d_in[3];
    const float* bv     = (const float*)d_in[4];
    const float* Wo     = (const float*)d_in[5];
    const float* cosp   = (const float*)d_in[6];
    const float* sinp   = (const float*)d_in[7];

    float* out   = (float*)d_out;
    float* attnw = out + (size_t)BB * SS * DD;

    __half *hh, *hl, *qkh, *vh, *oh;
    __half *qh, *ql, *kh, *kl, *vth, *aoh, *aol, *ph;
    cudaGetSymbolAddress((void**)&hh,  g_hh);  cudaGetSymbolAddress((void**)&hl,  g_hl);
    cudaGetSymbolAddress((void**)&qkh, g_qkh);
    cudaGetSymbolAddress((void**)&vh,  g_vh);
    cudaGetSymbolAddress((void**)&oh,  g_oh);
    cudaGetSymbolAddress((void**)&qh,  g_qh);  cudaGetSymbolAddress((void**)&ql,  g_ql);
    cudaGetSymbolAddress((void**)&kh,  g_kh);  cudaGetSymbolAddress((void**)&kl,  g_kl);
    cudaGetSymbolAddress((void**)&vth, g_vth);
    cudaGetSymbolAddress((void**)&aoh, g_aoh); cudaGetSymbolAddress((void**)&aol, g_aol);
    cudaGetSymbolAddress((void**)&ph,  g_ph);

    cudaFuncSetAttribute(gemm_tc<0>, cudaFuncAttributeMaxDynamicSharedMemorySize, SMEM_G);
    cudaFuncSetAttribute(gemm_tc<1>, cudaFuncAttributeMaxDynamicSharedMemorySize, SMEM_G);
    cudaFuncSetAttribute(gemm_tc<2>, cudaFuncAttributeMaxDynamicSharedMemorySize, SMEM_G);
    cudaFuncSetAttribute(score_tc,   cudaFuncAttributeMaxDynamicSharedMemorySize, SMEM_S);
    cudaFuncSetAttribute(pv_tc,      cudaFuncAttributeMaxDynamicSharedMemorySize, SMEM_P);

    const int cvblk = (int)((NELT / 4 + 255) / 256);
    const int rope_total = BB * SS * HH * (HD / 2);
    const float scale = 0.088388347648318447f;  // 128^-0.5

    prep_hidden<<<(rope_total + 255) / 256, 256>>>(hidden, hh, hl, qh, ql, cosp, sinp, scale);
    conv_hi<<<cvblk, 256>>>(Wqk, qkh);
    conv_hi<<<cvblk, 256>>>(Wv,  vh);
    conv_hi<<<cvblk, 256>>>(Wo,  oh);

    dim3 gg(DD / 128, (BB * SS) / 128);
    // QK projection with fused bias+RoPE+split
    gemm_tc<1><<<gg, 256, SMEM_G>>>(hh, hl, qkh, bqk, cosp, sinp, nullptr, kh, kl);
    // V projection with fused bias+transpose+split
    gemm_tc<2><<<gg, 256, SMEM_G>>>(hh, hl, vh,  bv,  nullptr, nullptr, nullptr, vth, nullptr);

    score_tc<<<dim3(SS / 128, SS / 128, BB * HH), 256, SMEM_S>>>(qh, ql, kh, kl, attnw);
    softmax_pconv_kernel<<<BB * HH * SS, 256>>>(attnw, ph);
    pv_tc<<<dim3(SS / 128, BB * HH), 256, SMEM_P>>>(ph, vth, aoh, aol);

    gemm_tc<0><<<gg, 256, SMEM_G>>>(aoh, aol, oh, nullptr, nullptr, nullptr, out, nullptr, nullptr);
}

// round 10
// speedup vs baseline: 4.4434x; 1.1290x over previous
#include <cuda_runtime.h>
#include <cuda_fp16.h>
#include <cstdint>
#include <cstddef>

#define BB 2
#define SS 2048
#define DD 4096
#define HH 32
#define HD 128
#define NEG_INF -1000000000.0f

#define NELT ((size_t)BB * SS * DD)          // 16,777,216
#define NP   ((size_t)BB * HH * SS * SS)     // 268,435,456

// ---------------- scratch (device globals; alloc APIs forbidden) ----------
__device__ __half g_hh[NELT],  g_hl[NELT];    // hidden hi/lo
__device__ __half g_qkh[NELT];                // Wqk hi
__device__ __half g_vh[NELT];                 // Wv hi
__device__ __half g_oh[NELT];                 // Wo hi
__device__ __half g_qh[NELT],  g_ql[NELT];    // roped Q hi/lo (b,s,h,hd)
__device__ __half g_kh[NELT],  g_kl[NELT];    // roped K hi/lo (b,s,h,hd)
__device__ __half g_vth[NELT];                // V^T hi (b,h,d,k)
__device__ __half g_aoh[NELT];                // attn-out gathered (fp16 hi only)
__device__ __half g_ph[NP];                   // softmax P (fp16 hi only)

// ---------------- helpers ---------------------------------------------------
__device__ __forceinline__ uint32_t smem_u32(const void* p) {
    uint32_t a;
    asm("{ .reg .u64 t; cvta.to.shared.u64 t, %1; cvt.u32.u64 %0, t; }" : "=r"(a) : "l"(p));
    return a;
}
__device__ __forceinline__ void cp_async16(uint32_t dst, const void* src) {
    asm volatile("cp.async.cg.shared.global [%0], [%1], 16;" :: "r"(dst), "l"(src));
}
#define CP_COMMIT() asm volatile("cp.async.commit_group;" ::: "memory")
#define CP_WAIT2()  asm volatile("cp.async.wait_group 2;" ::: "memory")
#define CP_WAIT3()  asm volatile("cp.async.wait_group 3;" ::: "memory")
#define CP_WAIT5()  asm volatile("cp.async.wait_group 5;" ::: "memory")

__device__ __forceinline__ void ldmx4(uint32_t* r, uint32_t addr) {
    asm volatile("ldmatrix.sync.aligned.m8n8.x4.shared.b16 {%0,%1,%2,%3}, [%4];"
                 : "=r"(r[0]), "=r"(r[1]), "=r"(r[2]), "=r"(r[3]) : "r"(addr));
}
__device__ __forceinline__ void mma16816(float* d, const uint32_t* a, const uint32_t* b) {
    asm volatile(
        "mma.sync.aligned.m16n8k16.row.col.f32.f16.f16.f32 "
        "{%0,%1,%2,%3}, {%4,%5,%6,%7}, {%8,%9}, {%0,%1,%2,%3};"
        : "+f"(d[0]), "+f"(d[1]), "+f"(d[2]), "+f"(d[3])
        : "r"(a[0]), "r"(a[1]), "r"(a[2]), "r"(a[3]), "r"(b[0]), "r"(b[1]));
}
__device__ __forceinline__ void split_hi_lo(float f, __half& h, __half& l) {
    h = __float2half_rn(f);
    l = __float2half_rn(f - __half2float(h));
}

// ---- BK=32 tiles ------------------------------------------------------------
#define TILE_B 8192                     // 128 rows x 64B (32 fp16)
#define STAGE2 (3 * TILE_B)             // gemm(proj): Ah, Al, Bh
#define STAGE3 (4 * TILE_B)             // score: Qh, Ql, Kh, Kl
#define STAGE1 (2 * TILE_B)             // pv / final gemm: 2 tiles
#define NSTAGE_G 4
#define NSTAGE_S 3
#define NSTAGE_P 6
#define SMEM_G (NSTAGE_G * STAGE2)      // 98304
#define SMEM_S (NSTAGE_S * STAGE3)      // 98304
#define SMEM_P (NSTAGE_P * STAGE1)      // 98304

__device__ __forceinline__ uint32_t sw_off32(int r, int chunk) {
    return (uint32_t)(r << 6) + (((chunk ^ ((r >> 1) & 3)) << 4));
}

// ---- 2-product K=16 MMA step: A(hi+lo) x B(hi). Tiles: [Ah|Al|Bh] -----------
__device__ __forceinline__ void hmma2(
    uint32_t sb, int ks, int wm, int wn, int lr, int lc, float (&acc)[4][4][4])
{
    const int chunk = ks * 2 + lc;
    uint32_t bh[4][2];
#pragma unroll
    for (int g = 0; g < 2; g++) {
        int r = wn + g * 16 + lr;
        uint32_t rb[4];
        ldmx4(rb, sb + 2 * TILE_B + sw_off32(r, chunk));
        bh[g*2+0][0] = rb[0]; bh[g*2+0][1] = rb[2];
        bh[g*2+1][0] = rb[1]; bh[g*2+1][1] = rb[3];
    }
#pragma unroll
    for (int mi = 0; mi < 4; mi++) {
        int r = wm + mi * 16 + lr;
        uint32_t off = sw_off32(r, chunk);
        uint32_t ah[4], al[4];
        ldmx4(ah, sb + off);
        ldmx4(al, sb + TILE_B + off);
#pragma unroll
        for (int ni = 0; ni < 4; ni++) {
            mma16816(acc[mi][ni], ah, bh[ni]);
            mma16816(acc[mi][ni], al, bh[ni]);
        }
    }
}

// ---- 1-product K=16 MMA step: tiles [Ah|Bh] ---------------------------------
__device__ __forceinline__ void hmma1(
    uint32_t sb, int ks, int wm, int wn, int lr, int lc, float (&acc)[4][4][4])
{
    const int chunk = ks * 2 + lc;
    uint32_t bh[4][2];
#pragma unroll
    for (int g = 0; g < 2; g++) {
        int r = wn + g * 16 + lr;
        uint32_t rb[4];
        ldmx4(rb, sb + TILE_B + sw_off32(r, chunk));
        bh[g*2+0][0] = rb[0]; bh[g*2+0][1] = rb[2];
        bh[g*2+1][0] = rb[1]; bh[g*2+1][1] = rb[3];
    }
#pragma unroll
    for (int mi = 0; mi < 4; mi++) {
        int r = wm + mi * 16 + lr;
        uint32_t ah[4];
        ldmx4(ah, sb + sw_off32(r, chunk));
#pragma unroll
        for (int ni = 0; ni < 4; ni++)
            mma16816(acc[mi][ni], ah, bh[ni]);
    }
}

// ---- 3-product K=16 MMA step (score): tiles [Qh|Ql|Kh|Kl] -------------------
__device__ __forceinline__ void hmma3(
    uint32_t sb, int ks, int wm, int wn, int lr, int lc, float (&acc)[4][4][4])
{
    const int chunk = ks * 2 + lc;
    uint32_t bh[4][2], bl[4][2];
#pragma unroll
    for (int g = 0; g < 2; g++) {
        int r = wn + g * 16 + lr;
        uint32_t off = sw_off32(r, chunk);
        uint32_t rb[4];
        ldmx4(rb, sb + 2 * TILE_B + off);
        bh[g*2+0][0] = rb[0]; bh[g*2+0][1] = rb[2];
        bh[g*2+1][0] = rb[1]; bh[g*2+1][1] = rb[3];
        ldmx4(rb, sb + 3 * TILE_B + off);
        bl[g*2+0][0] = rb[0]; bl[g*2+0][1] = rb[2];
        bl[g*2+1][0] = rb[1]; bl[g*2+1][1] = rb[3];
    }
#pragma unroll
    for (int mi = 0; mi < 4; mi++) {
        int r = wm + mi * 16 + lr;
        uint32_t off = sw_off32(r, chunk);
        uint32_t ah[4], al[4];
        ldmx4(ah, sb + off);
        ldmx4(al, sb + TILE_B + off);
#pragma unroll
        for (int ni = 0; ni < 4; ni++) {
            mma16816(acc[mi][ni], ah, bh[ni]);
            mma16816(acc[mi][ni], ah, bl[ni]);
            mma16816(acc[mi][ni], al, bh[ni]);
        }
    }
}

// ---------------------------------------------------------------------------
// HMMA fp16 2-product GEMM with fused epilogues (projections).
//  MODE 1: QK projection -> +bias -> RoPE -> fp16 hi/lo (kh=O1, kl=O2)
//  MODE 2: V projection  -> +bias -> transpose to (b,h,d,s) fp16 hi (O1)
// ---------------------------------------------------------------------------
template<int MODE>
__global__ __launch_bounds__(256, 2) void gemm_tc(
    const __half* __restrict__ Ah, const __half* __restrict__ Al,
    const __half* __restrict__ Bh,
    const float* __restrict__ bias,
    const float* __restrict__ cosp, const float* __restrict__ sinp,
    __half* __restrict__ O1, __half* __restrict__ O2)
{
    extern __shared__ char smem[];
    const uint32_t sbase = smem_u32(smem);
    const int t = threadIdx.x;
    const int wid = t >> 5, lane = t & 31;
    const int bm = blockIdx.y << 7, bn = blockIdx.x << 7;

    const __half* base0 = Ah + (size_t)bm * DD;
    const __half* base1 = Al + (size_t)bm * DD;
    const __half* base2 = Bh + (size_t)bn * DD;

    auto load_stage = [&](int stg, int kc) {
        uint32_t db = sbase + stg * STAGE2;
#pragma unroll
        for (int i = 0; i < 6; i++) {
            int idx = t + (i << 8);
            int tile = idx >> 9;
            int w = idx & 511;
            int r = w >> 2, c = w & 3;
            const __half* src = (tile == 0 ? base0 : tile == 1 ? base1 : base2)
                                + (size_t)r * DD + kc + (c << 3);
            cp_async16(db + tile * TILE_B + sw_off32(r, c), src);
        }
        CP_COMMIT();
    };

    load_stage(0, 0);
    load_stage(1, 32);
    load_stage(2, 64);
    load_stage(3, 96);

    const int wm = (wid & 1) << 6;
    const int wn = (wid >> 1) << 5;
    const int lr = lane & 15, lc = lane >> 4;

    float acc[4][4][4] = {};
    const int iters = DD / 32;

    for (int it = 0; it < iters; it++) {
        int stg = it % NSTAGE_G;
        CP_WAIT3();
        __syncthreads();
        uint32_t sb = sbase + stg * STAGE2;
        hmma2(sb, 0, wm, wn, lr, lc, acc);
        hmma2(sb, 1, wm, wn, lr, lc, acc);
        __syncthreads();
        if (it + NSTAGE_G < iters) load_stage(stg, (it + NSTAGE_G) * 32);
        else CP_COMMIT();
    }

    const int qr = lane >> 2, qc = (lane & 3) << 1;

    // staged epilogues: write acc (+bias) into padded fp32 smem tile
    __syncthreads();
    const int PAD = (MODE == 1) ? 132 : 133;
    float* eps = (float*)smem;
#pragma unroll
    for (int mi = 0; mi < 4; mi++) {
#pragma unroll
        for (int ni = 0; ni < 4; ni++) {
            int cl = wn + ni * 8 + qc;
            float b0 = bias ? bias[bn + cl] : 0.f;
            float b1 = bias ? bias[bn + cl + 1] : 0.f;
            int r0 = wm + mi * 16 + qr;
            eps[r0 * PAD + cl]           = acc[mi][ni][0] + b0;
            eps[r0 * PAD + cl + 1]       = acc[mi][ni][1] + b1;
            eps[(r0 + 8) * PAD + cl]     = acc[mi][ni][2] + b0;
            eps[(r0 + 8) * PAD + cl + 1] = acc[mi][ni][3] + b1;
        }
    }
    __syncthreads();

    if (MODE == 1) {
        // RoPE within the head tile (N-tile == one head): pairs (d, d+64)
#pragma unroll
        for (int q8 = 0; q8 < 32; q8++) {
            int idx = t + (q8 << 8);          // 0..8191
            int d = idx & 63, r = idx >> 6;
            int m = bm + r;
            size_t cb = (size_t)m * HD;
            float c0 = cosp[cb + d],      s0 = sinp[cb + d];
            float c1 = cosp[cb + d + 64], s1 = sinp[cb + d + 64];
            float x0 = eps[r * 132 + d], x1 = eps[r * 132 + d + 64];
            float y0 = x0 * c0 - x1 * s0;
            float y1 = x1 * c1 + x0 * s1;
            size_t o = (size_t)m * DD + bn + d;
            __half hh, ll;
            split_hi_lo(y0, hh, ll); O1[o] = hh;      O2[o] = ll;
            split_hi_lo(y1, hh, ll); O1[o + 64] = hh; O2[o + 64] = ll;
        }
    } else {
        // MODE 2: transpose tile (s x d) -> Vt (b,h,d,s) fp16 hi
        int bh = ((bm >> 11) << 5) + (bn >> 7);
        int sbase_g = bm & (SS - 1);
#pragma unroll
        for (int q8 = 0; q8 < 16; q8++) {
            int qi = t + (q8 << 8);           // 0..4095 quads
            int d = qi >> 5;
            int sq = (qi & 31) << 2;
            float f0 = eps[(sq + 0) * 133 + d];
            float f1 = eps[(sq + 1) * 133 + d];
            float f2 = eps[(sq + 2) * 133 + d];
            float f3 = eps[(sq + 3) * 133 + d];
            size_t o = ((size_t)bh * HD + d) * SS + sbase_g + sq;
            *(__half2*)&O1[o]     = __halves2half2(__float2half_rn(f0), __float2half_rn(f1));
            *(__half2*)&O1[o + 2] = __halves2half2(__float2half_rn(f2), __float2half_rn(f3));
        }
    }
}

// ---------------------------------------------------------------------------
// gemm1_tc: final projection, fp16 1-product: out = AOh @ Wo_hi^T (fp32 out).
// 6-stage pipeline, 2 tiles/stage.
// ---------------------------------------------------------------------------
__global__ __launch_bounds__(256, 2) void gemm1_tc(
    const __half* __restrict__ Ah, const __half* __restrict__ Bh,
    float* __restrict__ C)
{
    extern __shared__ char smem[];
    const uint32_t sbase = smem_u32(smem);
    const int t = threadIdx.x;
    const int wid = t >> 5, lane = t & 31;
    const int bm = blockIdx.y << 7, bn = blockIdx.x << 7;

    const __half* base0 = Ah + (size_t)bm * DD;
    const __half* base1 = Bh + (size_t)bn * DD;

    auto load_stage = [&](int stg, int kc) {
        uint32_t db = sbase + stg * STAGE1;
#pragma unroll
        for (int i = 0; i < 4; i++) {
            int idx = t + (i << 8);              // 0..1023
            int tile = idx >> 9;                 // 0..1
            int w = idx & 511;
            int r = w >> 2, c = w & 3;
            const __half* src = (tile == 0 ? base0 : base1)
                                + (size_t)r * DD + kc + (c << 3);
            cp_async16(db + tile * TILE_B + sw_off32(r, c), src);
        }
        CP_COMMIT();
    };

#pragma unroll
    for (int s = 0; s < NSTAGE_P; s++) load_stage(s, s * 32);

    const int wm = (wid & 1) << 6;
    const int wn = (wid >> 1) << 5;
    const int lr = lane & 15, lc = lane >> 4;
    float acc[4][4][4] = {};
    const int iters = DD / 32;

    for (int it = 0; it < iters; it++) {
        int stg = it % NSTAGE_P;
        CP_WAIT5();
        __syncthreads();
        uint32_t sb = sbase + stg * STAGE1;
        hmma1(sb, 0, wm, wn, lr, lc, acc);
        hmma1(sb, 1, wm, wn, lr, lc, acc);
        __syncthreads();
        if (it + NSTAGE_P < iters) load_stage(stg, (it + NSTAGE_P) * 32);
        else CP_COMMIT();
    }

    const int qr = lane >> 2, qc = (lane & 3) << 1;
#pragma unroll
    for (int mi = 0; mi < 4; mi++) {
#pragma unroll
        for (int ni = 0; ni < 4; ni++) {
            int col = bn + wn + ni * 8 + qc;
            int row0 = bm + wm + mi * 16 + qr;
            float2 v0 = { acc[mi][ni][0], acc[mi][ni][1] };
            float2 v1 = { acc[mi][ni][2], acc[mi][ni][3] };
            *(float2*)&C[(size_t)row0 * DD + col] = v0;
            *(float2*)&C[(size_t)(row0 + 8) * DD + col] = v1;
        }
    }
}

// ---------------------------------------------------------------------------
// score_tc: P = Q.K (fp16 3-product), causal; above-diagonal tiles untouched.
// ---------------------------------------------------------------------------
__global__ __launch_bounds__(256, 2) void score_tc(
    const __half* __restrict__ Qh, const __half* __restrict__ Ql,
    const __half* __restrict__ Kh, const __half* __restrict__ Kl,
    float* __restrict__ P)
{
    extern __shared__ char smem[];
    const int q0 = blockIdx.y << 7, k0 = blockIdx.x << 7;
    if (k0 > q0) return;

    const int bh = blockIdx.z;
    const int b = bh >> 5, h = bh & 31;
    const size_t pbase = ((size_t)bh * SS + q0) * SS + k0;
    const int t = threadIdx.x;
    const uint32_t sbase = smem_u32(smem);
    const int wid = t >> 5, lane = t & 31;

    const __half* base0 = Qh + (size_t)(b * SS + q0) * DD + (h << 7);
    const __half* base1 = Ql + (size_t)(b * SS + q0) * DD + (h << 7);
    const __half* base2 = Kh + (size_t)(b * SS + k0) * DD + (h << 7);
    const __half* base3 = Kl + (size_t)(b * SS + k0) * DD + (h << 7);

    auto load_stage = [&](int stg, int kc) {
        uint32_t db = sbase + stg * STAGE3;
#pragma unroll
        for (int i = 0; i < 8; i++) {
            int idx = t + (i << 8);
            int tile = idx >> 9;
            int w = idx & 511;
            int r = w >> 2, c = w & 3;
            const __half* src = (tile == 0 ? base0 : tile == 1 ? base1 :
                                 tile == 2 ? base2 : base3)
                                + (size_t)r * DD + kc + (c << 3);
            cp_async16(db + tile * TILE_B + sw_off32(r, c), src);
        }
        CP_COMMIT();
    };

    load_stage(0, 0);
    load_stage(1, 32);
    load_stage(2, 64);

    const int wm = (wid & 1) << 6;
    const int wn = (wid >> 1) << 5;
    const int lr = lane & 15, lc = lane >> 4;
    float acc[4][4][4] = {};
    const int iters = HD / 32;

    for (int it = 0; it < iters; it++) {
        int stg = it % NSTAGE_S;
        CP_WAIT2();
        __syncthreads();
        uint32_t sb = sbase + stg * STAGE3;
        hmma3(sb, 0, wm, wn, lr, lc, acc);
        hmma3(sb, 1, wm, wn, lr, lc, acc);
        __syncthreads();
        if (it + NSTAGE_S < iters) load_stage(stg, (it + NSTAGE_S) * 32);
        else CP_COMMIT();
    }

    const int qr = lane >> 2, qc = (lane & 3) << 1;
#pragma unroll
    for (int mi = 0; mi < 4; mi++) {
#pragma unroll
        for (int ni = 0; ni < 4; ni++) {
            int rl = wm + mi * 16 + qr;
            int cl = wn + ni * 8 + qc;
            int k = k0 + cl;
            int qA = q0 + rl, qB = qA + 8;
            float2 v0 = { (k <= qA) ? acc[mi][ni][0] : NEG_INF,
                          (k + 1 <= qA) ? acc[mi][ni][1] : NEG_INF };
            float2 v1 = { (k <= qB) ? acc[mi][ni][2] : NEG_INF,
                          (k + 1 <= qB) ? acc[mi][ni][3] : NEG_INF };
            *(float2*)&P[pbase + (size_t)rl * SS + cl] = v0;
            *(float2*)&P[pbase + (size_t)(rl + 8) * SS + cl] = v1;
        }
    }
}

// ---------------------------------------------------------------------------
// pv_tc: AO = P @ V^T (fp16 1-product), causal k-bound; gathered fp16 hi out.
// ---------------------------------------------------------------------------
__global__ __launch_bounds__(256, 2) void pv_tc(
    const __half* __restrict__ Ph,
    const __half* __restrict__ Vth,
    __half* __restrict__ AOh)
{
    extern __shared__ char smem[];
    const uint32_t sbase = smem_u32(smem);
    const int t = threadIdx.x;
    const int wid = t >> 5, lane = t & 31;
    const int q0 = blockIdx.x << 7;
    const int bh = blockIdx.y;
    const int b = bh >> 5, h = bh & 31;

    const __half* base0 = Ph  + ((size_t)bh * SS + q0) * SS;
    const __half* base1 = Vth + (size_t)bh * HD * SS;

    const int iters = (q0 >> 5) + 4;

    auto load_stage = [&](int stg, int kc) {
        uint32_t db = sbase + stg * STAGE1;
#pragma unroll
        for (int i = 0; i < 4; i++) {
            int idx = t + (i << 8);
            int tile = idx >> 9;
            int w = idx & 511;
            int r = w >> 2, c = w & 3;
            const __half* src = (tile == 0 ? base0 : base1)
                                + (size_t)r * SS + kc + (c << 3);
            cp_async16(db + tile * TILE_B + sw_off32(r, c), src);
        }
        CP_COMMIT();
    };

#pragma unroll
    for (int s = 0; s < NSTAGE_P; s++) {
        if (s < iters) load_stage(s, s * 32);
        else CP_COMMIT();
    }

    const int wm = (wid & 1) << 6;
    const int wn = (wid >> 1) << 5;
    const int lr = lane & 15, lc = lane >> 4;
    float acc[4][4][4] = {};

    for (int it = 0; it < iters; it++) {
        int stg = it % NSTAGE_P;
        CP_WAIT5();
        __syncthreads();
        uint32_t sb = sbase + stg * STAGE1;
        hmma1(sb, 0, wm, wn, lr, lc, acc);
        hmma1(sb, 1, wm, wn, lr, lc, acc);
        __syncthreads();
        if (it + NSTAGE_P < iters) load_stage(stg, (it + NSTAGE_P) * 32);
        else CP_COMMIT();
    }

    const int qr = lane >> 2, qc = (lane & 3) << 1;
#pragma unroll
    for (int mi = 0; mi < 4; mi++) {
#pragma unroll
        for (int ni = 0; ni < 4; ni++) {
            int row = q0 + wm + mi * 16 + qr;
            int col = (h << 7) + wn + ni * 8 + qc;
            size_t m0 = ((size_t)b * SS + row) * DD + col;
            size_t m1 = m0 + (size_t)8 * DD;
            *(__half2*)&AOh[m0] = __halves2half2(__float2half_rn(acc[mi][ni][0]),
                                                 __float2half_rn(acc[mi][ni][1]));
            *(__half2*)&AOh[m1] = __halves2half2(__float2half_rn(acc[mi][ni][2]),
                                                 __float2half_rn(acc[mi][ni][3]));
        }
    }
}

// ---------------------------------------------------------------------------
// prep_hidden: one pass over hidden -> hh/hl (raw split) + qh/ql (roped Q)
// ---------------------------------------------------------------------------
__global__ void prep_hidden(const float* __restrict__ src,
                            __half* __restrict__ hh, __half* __restrict__ hl,
                            __half* __restrict__ qh, __half* __restrict__ ql,
                            const float* __restrict__ cosp, const float* __restrict__ sinp,
                            float scale)
{
    int idx = blockIdx.x * blockDim.x + threadIdx.x;
    const int total = BB * SS * HH * (HD / 2);
    if (idx >= total) return;
    int d  = idx & 63;
    int h  = (idx >> 6) & (HH - 1);
    int bs = idx >> 11;
    size_t base = (size_t)bs * DD + (h << 7);
    size_t cbase = (size_t)bs * HD;
    float c0 = cosp[cbase + d],      s0 = sinp[cbase + d];
    float c1 = cosp[cbase + d + 64], s1 = sinp[cbase + d + 64];
    float x0 = src[base + d], x1 = src[base + d + 64];
    __half a, b;
    split_hi_lo(x0, a, b); hh[base + d] = a;      hl[base + d] = b;
    split_hi_lo(x1, a, b); hh[base + d + 64] = a; hl[base + d + 64] = b;
    float y0 = (x0 * c0 - x1 * s0) * scale;
    float y1 = (x1 * c1 + x0 * s1) * scale;
    split_hi_lo(y0, a, b); qh[base + d] = a;      ql[base + d] = b;
    split_hi_lo(y1, a, b); qh[base + d + 64] = a; ql[base + d + 64] = b;
}

// fp32 -> fp16 hi only (weights)
__global__ void conv_hi(const float* __restrict__ x, __half* __restrict__ hi)
{
    size_t i = (size_t)blockIdx.x * blockDim.x + threadIdx.x;
    if (i >= NELT / 4) return;
    float4 v = ((const float4*)x)[i];
    ((__half2*)hi)[i * 2]     = __halves2half2(__float2half_rn(v.x), __float2half_rn(v.y));
    ((__half2*)hi)[i * 2 + 1] = __halves2half2(__float2half_rn(v.z), __float2half_rn(v.w));
}

// ---------------------------------------------------------------------------
// Causal softmax in place + fp16 emission (hi only) — float4 vectorized.
// ---------------------------------------------------------------------------
__global__ __launch_bounds__(256) void softmax_pconv_kernel(
    float* __restrict__ P, __half* __restrict__ Ph)
{
    size_t row = blockIdx.x;
    int q = (int)(row & (SS - 1));
    int kend = ((q >> 7) + 1) << 7;
    float4* p4 = (float4*)(P + row * (size_t)SS);
    __half* ph = Ph + row * (size_t)SS;
    int t = threadIdx.x;

    float v[8];
    {
        float4 va = p4[t], vb = p4[t + 256];
        int oa = t << 2, ob = 1024 + (t << 2);
        v[0] = (oa     <= q) ? va.x : -3.4e38f;
        v[1] = (oa + 1 <= q) ? va.y : -3.4e38f;
        v[2] = (oa + 2 <= q) ? va.z : -3.4e38f;
        v[3] = (oa + 3 <= q) ? va.w : -3.4e38f;
        v[4] = (ob     <= q) ? vb.x : -3.4e38f;
        v[5] = (ob + 1 <= q) ? vb.y : -3.4e38f;
        v[6] = (ob + 2 <= q) ? vb.z : -3.4e38f;
        v[7] = (ob + 3 <= q) ? vb.w : -3.4e38f;
    }
    float mx = v[0];
#pragma unroll
    for (int i = 1; i < 8; i++) mx = fmaxf(mx, v[i]);
#pragma unroll
    for (int o = 16; o; o >>= 1) mx = fmaxf(mx, __shfl_xor_sync(0xffffffffu, mx, o));
    __shared__ float rmax[8], rsum[8];
    if ((t & 31) == 0) rmax[t >> 5] = mx;
    __syncthreads();
    mx = rmax[0];
#pragma unroll
    for (int i = 1; i < 8; i++) mx = fmaxf(mx, rmax[i]);
    float sum = 0.f;
#pragma unroll
    for (int i = 0; i < 8; i++) {
        v[i] = (v[i] > -3.3e38f) ? __expf(v[i] - mx) : 0.f;
        sum += v[i];
    }
#pragma unroll
    for (int o = 16; o; o >>= 1) sum += __shfl_xor_sync(0xffffffffu, sum, o);
    if ((t & 31) == 0) rsum[t >> 5] = sum;
    __syncthreads();
    sum = rsum[0];
#pragma unroll
    for (int i = 1; i < 8; i++) sum += rsum[i];
    float inv = 1.0f / sum;
#pragma unroll
    for (int i = 0; i < 8; i++) v[i] *= inv;

    p4[t]       = make_float4(v[0], v[1], v[2], v[3]);
    p4[t + 256] = make_float4(v[4], v[5], v[6], v[7]);

    {
        int oa = t << 2;
        if (oa < kend) {
            *(__half2*)&ph[oa]     = __halves2half2(__float2half_rn(v[0]), __float2half_rn(v[1]));
            *(__half2*)&ph[oa + 2] = __halves2half2(__float2half_rn(v[2]), __float2half_rn(v[3]));
        }
        int ob = 1024 + (t << 2);
        if (ob < kend) {
            *(__half2*)&ph[ob]     = __halves2half2(__float2half_rn(v[4]), __float2half_rn(v[5]));
            *(__half2*)&ph[ob + 2] = __halves2half2(__float2half_rn(v[6]), __float2half_rn(v[7]));
        }
    }
}

// ---------------------------------------------------------------------------
extern "C" void kernel_launch(void* const* d_in, const int* in_sizes, int n_in,
                              void* d_out, int out_size)
{
    (void)in_sizes; (void)n_in; (void)out_size;
    const float* hidden = (const float*)d_in[0];
    const float* Wqk    = (const float*)d_in[1];
    const float* bqk    = (const float*)d_in[2];
    const float* Wv     = (const float*)d_in[3];
    const float* bv     = (const float*)d_in[4];
    const float* Wo     = (const float*)d_in[5];
    const float* cosp   = (const float*)d_in[6];
    const float* sinp   = (const float*)d_in[7];

    float* out   = (float*)d_out;
    float* attnw = out + (size_t)BB * SS * DD;

    __half *hh, *hl, *qkh, *vh, *oh;
    __half *qh, *ql, *kh, *kl, *vth, *aoh, *ph;
    cudaGetSymbolAddress((void**)&hh,  g_hh);  cudaGetSymbolAddress((void**)&hl,  g_hl);
    cudaGetSymbolAddress((void**)&qkh, g_qkh);
    cudaGetSymbolAddress((void**)&vh,  g_vh);
    cudaGetSymbolAddress((void**)&oh,  g_oh);
    cudaGetSymbolAddress((void**)&qh,  g_qh);  cudaGetSymbolAddress((void**)&ql,  g_ql);
    cudaGetSymbolAddress((void**)&kh,  g_kh);  cudaGetSymbolAddress((void**)&kl,  g_kl);
    cudaGetSymbolAddress((void**)&vth, g_vth);
    cudaGetSymbolAddress((void**)&aoh, g_aoh);
    cudaGetSymbolAddress((void**)&ph,  g_ph);

    cudaFuncSetAttribute(gemm_tc<1>, cudaFuncAttributeMaxDynamicSharedMemorySize, SMEM_G);
    cudaFuncSetAttribute(gemm_tc<2>, cudaFuncAttributeMaxDynamicSharedMemorySize, SMEM_G);
    cudaFuncSetAttribute(gemm1_tc,   cudaFuncAttributeMaxDynamicSharedMemorySize, SMEM_P);
    cudaFuncSetAttribute(score_tc,   cudaFuncAttributeMaxDynamicSharedMemorySize, SMEM_S);
    cudaFuncSetAttribute(pv_tc,      cudaFuncAttributeMaxDynamicSharedMemorySize, SMEM_P);

    const int cvblk = (int)((NELT / 4 + 255) / 256);
    const int rope_total = BB * SS * HH * (HD / 2);
    const float scale = 0.088388347648318447f;  // 128^-0.5

    prep_hidden<<<(rope_total + 255) / 256, 256>>>(hidden, hh, hl, qh, ql, cosp, sinp, scale);
    conv_hi<<<cvblk, 256>>>(Wqk, qkh);
    conv_hi<<<cvblk, 256>>>(Wv,  vh);
    conv_hi<<<cvblk, 256>>>(Wo,  oh);

    dim3 gg(DD / 128, (BB * SS) / 128);
    // QK projection with fused bias+RoPE+split
    gemm_tc<1><<<gg, 256, SMEM_G>>>(hh, hl, qkh, bqk, cosp, sinp, kh, kl);
    // V projection with fused bias+transpose+split
    gemm_tc<2><<<gg, 256, SMEM_G>>>(hh, hl, vh,  bv,  nullptr, nullptr, vth, nullptr);

    score_tc<<<dim3(SS / 128, SS / 128, BB * HH), 256, SMEM_S>>>(qh, ql, kh, kl, attnw);
    softmax_pconv_kernel<<<BB * HH * SS, 256>>>(attnw, ph);
    pv_tc<<<dim3(SS / 128, BB * HH), 256, SMEM_P>>>(ph, vth, aoh);

    // final projection: fp16 1-product
    gemm1_tc<<<gg, 256, SMEM_P>>>(aoh, oh, out);
}

// round 11
// speedup vs baseline: 5.1577x; 1.1607x over previous
#include <cuda_runtime.h>
#include <cuda_fp16.h>
#include <cstdint>
#include <cstddef>

#define BB 2
#define SS 2048
#define DD 4096
#define HH 32
#define HD 128
#define NEG_INF -1000000000.0f

#define NELT ((size_t)BB * SS * DD)          // 16,777,216
#define NP   ((size_t)BB * HH * SS * SS)     // 268,435,456

// ---------------- scratch (device globals; alloc APIs forbidden) ----------
__device__ __half g_hh[NELT],  g_hl[NELT];    // hidden hi/lo
__device__ __half g_qkh[NELT];                // Wqk hi
__device__ __half g_vh[NELT];                 // Wv hi
__device__ __half g_oh[NELT];                 // Wo hi
__device__ __half g_qh[NELT],  g_ql[NELT];    // roped Q hi/lo (b,s,h,hd)
__device__ __half g_kh[NELT],  g_kl[NELT];    // roped K hi/lo (b,s,h,hd)
__device__ __half g_vth[NELT];                // V^T hi (b,h,d,k)
__device__ __half g_aoh[NELT];                // attn-out gathered (fp16 hi only)
__device__ __half g_ph[NP];                   // softmax P (fp16 hi only)

// ---------------- helpers ---------------------------------------------------
__device__ __forceinline__ uint32_t smem_u32(const void* p) {
    uint32_t a;
    asm("{ .reg .u64 t; cvta.to.shared.u64 t, %1; cvt.u32.u64 %0, t; }" : "=r"(a) : "l"(p));
    return a;
}
__device__ __forceinline__ void cp_async16(uint32_t dst, const void* src) {
    asm volatile("cp.async.cg.shared.global [%0], [%1], 16;" :: "r"(dst), "l"(src));
}
#define CP_COMMIT() asm volatile("cp.async.commit_group;" ::: "memory")
#define CP_WAIT2()  asm volatile("cp.async.wait_group 2;" ::: "memory")
#define CP_WAIT3()  asm volatile("cp.async.wait_group 3;" ::: "memory")
#define CP_WAIT5()  asm volatile("cp.async.wait_group 5;" ::: "memory")

__device__ __forceinline__ void ldmx4(uint32_t* r, uint32_t addr) {
    asm volatile("ldmatrix.sync.aligned.m8n8.x4.shared.b16 {%0,%1,%2,%3}, [%4];"
                 : "=r"(r[0]), "=r"(r[1]), "=r"(r[2]), "=r"(r[3]) : "r"(addr));
}
__device__ __forceinline__ void mma16816(float* d, const uint32_t* a, const uint32_t* b) {
    asm volatile(
        "mma.sync.aligned.m16n8k16.row.col.f32.f16.f16.f32 "
        "{%0,%1,%2,%3}, {%4,%5,%6,%7}, {%8,%9}, {%0,%1,%2,%3};"
        : "+f"(d[0]), "+f"(d[1]), "+f"(d[2]), "+f"(d[3])
        : "r"(a[0]), "r"(a[1]), "r"(a[2]), "r"(a[3]), "r"(b[0]), "r"(b[1]));
}
__device__ __forceinline__ void split_hi_lo(float f, __half& h, __half& l) {
    h = __float2half_rn(f);
    l = __float2half_rn(f - __half2float(h));
}

// ---- BK=32 tiles ------------------------------------------------------------
#define TILE_B 8192                     // 128 rows x 64B (32 fp16)
#define STAGE2 (3 * TILE_B)             // QK gemm: Ah, Al, Bh
#define STAGE3 (4 * TILE_B)             // score: Qh, Ql, Kh, Kl
#define STAGE1 (2 * TILE_B)             // 1-product kernels: 2 tiles
#define NSTAGE_G 4
#define NSTAGE_S 3
#define NSTAGE_P 6
#define SMEM_G (NSTAGE_G * STAGE2)      // 98304
#define SMEM_S (NSTAGE_S * STAGE3)      // 98304
#define SMEM_P (NSTAGE_P * STAGE1)      // 98304

__device__ __forceinline__ uint32_t sw_off32(int r, int chunk) {
    return (uint32_t)(r << 6) + (((chunk ^ ((r >> 1) & 3)) << 4));
}

// ---- 2-product K=16 MMA step: A(hi+lo) x B(hi). Tiles: [Ah|Al|Bh] -----------
__device__ __forceinline__ void hmma2(
    uint32_t sb, int ks, int wm, int wn, int lr, int lc, float (&acc)[4][4][4])
{
    const int chunk = ks * 2 + lc;
    uint32_t bh[4][2];
#pragma unroll
    for (int g = 0; g < 2; g++) {
        int r = wn + g * 16 + lr;
        uint32_t rb[4];
        ldmx4(rb, sb + 2 * TILE_B + sw_off32(r, chunk));
        bh[g*2+0][0] = rb[0]; bh[g*2+0][1] = rb[2];
        bh[g*2+1][0] = rb[1]; bh[g*2+1][1] = rb[3];
    }
#pragma unroll
    for (int mi = 0; mi < 4; mi++) {
        int r = wm + mi * 16 + lr;
        uint32_t off = sw_off32(r, chunk);
        uint32_t ah[4], al[4];
        ldmx4(ah, sb + off);
        ldmx4(al, sb + TILE_B + off);
#pragma unroll
        for (int ni = 0; ni < 4; ni++) {
            mma16816(acc[mi][ni], ah, bh[ni]);
            mma16816(acc[mi][ni], al, bh[ni]);
        }
    }
}

// ---- 1-product K=16 MMA step: tiles [Ah|Bh] ---------------------------------
__device__ __forceinline__ void hmma1(
    uint32_t sb, int ks, int wm, int wn, int lr, int lc, float (&acc)[4][4][4])
{
    const int chunk = ks * 2 + lc;
    uint32_t bh[4][2];
#pragma unroll
    for (int g = 0; g < 2; g++) {
        int r = wn + g * 16 + lr;
        uint32_t rb[4];
        ldmx4(rb, sb + TILE_B + sw_off32(r, chunk));
        bh[g*2+0][0] = rb[0]; bh[g*2+0][1] = rb[2];
        bh[g*2+1][0] = rb[1]; bh[g*2+1][1] = rb[3];
    }
#pragma unroll
    for (int mi = 0; mi < 4; mi++) {
        int r = wm + mi * 16 + lr;
        uint32_t ah[4];
        ldmx4(ah, sb + sw_off32(r, chunk));
#pragma unroll
        for (int ni = 0; ni < 4; ni++)
            mma16816(acc[mi][ni], ah, bh[ni]);
    }
}

// ---- 3-product K=16 MMA step (score): tiles [Qh|Ql|Kh|Kl] -------------------
__device__ __forceinline__ void hmma3(
    uint32_t sb, int ks, int wm, int wn, int lr, int lc, float (&acc)[4][4][4])
{
    const int chunk = ks * 2 + lc;
    uint32_t bh[4][2], bl[4][2];
#pragma unroll
    for (int g = 0; g < 2; g++) {
        int r = wn + g * 16 + lr;
        uint32_t off = sw_off32(r, chunk);
        uint32_t rb[4];
        ldmx4(rb, sb + 2 * TILE_B + off);
        bh[g*2+0][0] = rb[0]; bh[g*2+0][1] = rb[2];
        bh[g*2+1][0] = rb[1]; bh[g*2+1][1] = rb[3];
        ldmx4(rb, sb + 3 * TILE_B + off);
        bl[g*2+0][0] = rb[0]; bl[g*2+0][1] = rb[2];
        bl[g*2+1][0] = rb[1]; bl[g*2+1][1] = rb[3];
    }
#pragma unroll
    for (int mi = 0; mi < 4; mi++) {
        int r = wm + mi * 16 + lr;
        uint32_t off = sw_off32(r, chunk);
        uint32_t ah[4], al[4];
        ldmx4(ah, sb + off);
        ldmx4(al, sb + TILE_B + off);
#pragma unroll
        for (int ni = 0; ni < 4; ni++) {
            mma16816(acc[mi][ni], ah, bh[ni]);
            mma16816(acc[mi][ni], ah, bl[ni]);
            mma16816(acc[mi][ni], al, bh[ni]);
        }
    }
}

// ---------------------------------------------------------------------------
// gemm_rope_tc: QK projection, fp16 2-product, fused bias+RoPE+hi/lo split.
// ---------------------------------------------------------------------------
__global__ __launch_bounds__(256, 2) void gemm_rope_tc(
    const __half* __restrict__ Ah, const __half* __restrict__ Al,
    const __half* __restrict__ Bh,
    const float* __restrict__ bias,
    const float* __restrict__ cosp, const float* __restrict__ sinp,
    __half* __restrict__ O1, __half* __restrict__ O2)
{
    extern __shared__ char smem[];
    const uint32_t sbase = smem_u32(smem);
    const int t = threadIdx.x;
    const int wid = t >> 5, lane = t & 31;
    const int bm = blockIdx.y << 7, bn = blockIdx.x << 7;

    const __half* base0 = Ah + (size_t)bm * DD;
    const __half* base1 = Al + (size_t)bm * DD;
    const __half* base2 = Bh + (size_t)bn * DD;

    auto load_stage = [&](int stg, int kc) {
        uint32_t db = sbase + stg * STAGE2;
#pragma unroll
        for (int i = 0; i < 6; i++) {
            int idx = t + (i << 8);
            int tile = idx >> 9;
            int w = idx & 511;
            int r = w >> 2, c = w & 3;
            const __half* src = (tile == 0 ? base0 : tile == 1 ? base1 : base2)
                                + (size_t)r * DD + kc + (c << 3);
            cp_async16(db + tile * TILE_B + sw_off32(r, c), src);
        }
        CP_COMMIT();
    };

    load_stage(0, 0);
    load_stage(1, 32);
    load_stage(2, 64);
    load_stage(3, 96);

    const int wm = (wid & 1) << 6;
    const int wn = (wid >> 1) << 5;
    const int lr = lane & 15, lc = lane >> 4;

    float acc[4][4][4] = {};
    const int iters = DD / 32;

    for (int it = 0; it < iters; it++) {
        int stg = it % NSTAGE_G;
        CP_WAIT3();
        __syncthreads();
        uint32_t sb = sbase + stg * STAGE2;
        hmma2(sb, 0, wm, wn, lr, lc, acc);
        hmma2(sb, 1, wm, wn, lr, lc, acc);
        __syncthreads();
        if (it + NSTAGE_G < iters) load_stage(stg, (it + NSTAGE_G) * 32);
        else CP_COMMIT();
    }

    const int qr = lane >> 2, qc = (lane & 3) << 1;

    // stage acc (+bias) into padded fp32 smem tile, then RoPE + split
    __syncthreads();
    float* eps = (float*)smem;
#pragma unroll
    for (int mi = 0; mi < 4; mi++) {
#pragma unroll
        for (int ni = 0; ni < 4; ni++) {
            int cl = wn + ni * 8 + qc;
            float b0 = bias[bn + cl];
            float b1 = bias[bn + cl + 1];
            int r0 = wm + mi * 16 + qr;
            eps[r0 * 132 + cl]           = acc[mi][ni][0] + b0;
            eps[r0 * 132 + cl + 1]       = acc[mi][ni][1] + b1;
            eps[(r0 + 8) * 132 + cl]     = acc[mi][ni][2] + b0;
            eps[(r0 + 8) * 132 + cl + 1] = acc[mi][ni][3] + b1;
        }
    }
    __syncthreads();

#pragma unroll
    for (int q8 = 0; q8 < 32; q8++) {
        int idx = t + (q8 << 8);          // 0..8191
        int d = idx & 63, r = idx >> 6;
        int m = bm + r;
        size_t cb = (size_t)m * HD;
        float c0 = cosp[cb + d],      s0 = sinp[cb + d];
        float c1 = cosp[cb + d + 64], s1 = sinp[cb + d + 64];
        float x0 = eps[r * 132 + d], x1 = eps[r * 132 + d + 64];
        float y0 = x0 * c0 - x1 * s0;
        float y1 = x1 * c1 + x0 * s1;
        size_t o = (size_t)m * DD + bn + d;
        __half hh, ll;
        split_hi_lo(y0, hh, ll); O1[o] = hh;      O2[o] = ll;
        split_hi_lo(y1, hh, ll); O1[o + 64] = hh; O2[o + 64] = ll;
    }
}

// ---------------------------------------------------------------------------
// gemm1_tc: fp16 1-product GEMM over K=4096.
//  MODE 0: fp32 out (final projection, no bias)
//  MODE 2: V projection -> +bias -> transpose to (b,h,d,s) fp16 hi (O1)
// 6-stage pipeline, 2 tiles/stage.
// ---------------------------------------------------------------------------
template<int MODE>
__global__ __launch_bounds__(256, 2) void gemm1_tc(
    const __half* __restrict__ Ah, const __half* __restrict__ Bh,
    const float* __restrict__ bias,
    float* __restrict__ C, __half* __restrict__ O1)
{
    extern __shared__ char smem[];
    const uint32_t sbase = smem_u32(smem);
    const int t = threadIdx.x;
    const int wid = t >> 5, lane = t & 31;
    const int bm = blockIdx.y << 7, bn = blockIdx.x << 7;

    const __half* base0 = Ah + (size_t)bm * DD;
    const __half* base1 = Bh + (size_t)bn * DD;

    auto load_stage = [&](int stg, int kc) {
        uint32_t db = sbase + stg * STAGE1;
#pragma unroll
        for (int i = 0; i < 4; i++) {
            int idx = t + (i << 8);              // 0..1023
            int tile = idx >> 9;                 // 0..1
            int w = idx & 511;
            int r = w >> 2, c = w & 3;
            const __half* src = (tile == 0 ? base0 : base1)
                                + (size_t)r * DD + kc + (c << 3);
            cp_async16(db + tile * TILE_B + sw_off32(r, c), src);
        }
        CP_COMMIT();
    };

#pragma unroll
    for (int s = 0; s < NSTAGE_P; s++) load_stage(s, s * 32);

    const int wm = (wid & 1) << 6;
    const int wn = (wid >> 1) << 5;
    const int lr = lane & 15, lc = lane >> 4;
    float acc[4][4][4] = {};
    const int iters = DD / 32;

    for (int it = 0; it < iters; it++) {
        int stg = it % NSTAGE_P;
        CP_WAIT5();
        __syncthreads();
        uint32_t sb = sbase + stg * STAGE1;
        hmma1(sb, 0, wm, wn, lr, lc, acc);
        hmma1(sb, 1, wm, wn, lr, lc, acc);
        __syncthreads();
        if (it + NSTAGE_P < iters) load_stage(stg, (it + NSTAGE_P) * 32);
        else CP_COMMIT();
    }

    const int qr = lane >> 2, qc = (lane & 3) << 1;

    if (MODE == 0) {
#pragma unroll
        for (int mi = 0; mi < 4; mi++) {
#pragma unroll
            for (int ni = 0; ni < 4; ni++) {
                int col = bn + wn + ni * 8 + qc;
                int row0 = bm + wm + mi * 16 + qr;
                float2 v0 = { acc[mi][ni][0], acc[mi][ni][1] };
                float2 v1 = { acc[mi][ni][2], acc[mi][ni][3] };
                *(float2*)&C[(size_t)row0 * DD + col] = v0;
                *(float2*)&C[(size_t)(row0 + 8) * DD + col] = v1;
            }
        }
        return;
    }

    // MODE 2: stage (+bias) into padded smem tile, transpose -> Vt fp16 hi
    __syncthreads();
    float* eps = (float*)smem;
#pragma unroll
    for (int mi = 0; mi < 4; mi++) {
#pragma unroll
        for (int ni = 0; ni < 4; ni++) {
            int cl = wn + ni * 8 + qc;
            float b0 = bias[bn + cl];
            float b1 = bias[bn + cl + 1];
            int r0 = wm + mi * 16 + qr;
            eps[r0 * 133 + cl]           = acc[mi][ni][0] + b0;
            eps[r0 * 133 + cl + 1]       = acc[mi][ni][1] + b1;
            eps[(r0 + 8) * 133 + cl]     = acc[mi][ni][2] + b0;
            eps[(r0 + 8) * 133 + cl + 1] = acc[mi][ni][3] + b1;
        }
    }
    __syncthreads();

    int bh = ((bm >> 11) << 5) + (bn >> 7);
    int sbase_g = bm & (SS - 1);
#pragma unroll
    for (int q8 = 0; q8 < 16; q8++) {
        int qi = t + (q8 << 8);           // 0..4095 quads
        int d = qi >> 5;
        int sq = (qi & 31) << 2;
        float f0 = eps[(sq + 0) * 133 + d];
        float f1 = eps[(sq + 1) * 133 + d];
        float f2 = eps[(sq + 2) * 133 + d];
        float f3 = eps[(sq + 3) * 133 + d];
        size_t o = ((size_t)bh * HD + d) * SS + sbase_g + sq;
        *(__half2*)&O1[o]     = __halves2half2(__float2half_rn(f0), __float2half_rn(f1));
        *(__half2*)&O1[o + 2] = __halves2half2(__float2half_rn(f2), __float2half_rn(f3));
    }
}

// ---------------------------------------------------------------------------
// score_tc: P = Q.K (fp16 3-product), causal; above-diagonal tiles untouched.
// ---------------------------------------------------------------------------
__global__ __launch_bounds__(256, 2) void score_tc(
    const __half* __restrict__ Qh, const __half* __restrict__ Ql,
    const __half* __restrict__ Kh, const __half* __restrict__ Kl,
    float* __restrict__ P)
{
    extern __shared__ char smem[];
    const int q0 = blockIdx.y << 7, k0 = blockIdx.x << 7;
    if (k0 > q0) return;

    const int bh = blockIdx.z;
    const int b = bh >> 5, h = bh & 31;
    const size_t pbase = ((size_t)bh * SS + q0) * SS + k0;
    const int t = threadIdx.x;
    const uint32_t sbase = smem_u32(smem);
    const int wid = t >> 5, lane = t & 31;

    const __half* base0 = Qh + (size_t)(b * SS + q0) * DD + (h << 7);
    const __half* base1 = Ql + (size_t)(b * SS + q0) * DD + (h << 7);
    const __half* base2 = Kh + (size_t)(b * SS + k0) * DD + (h << 7);
    const __half* base3 = Kl + (size_t)(b * SS + k0) * DD + (h << 7);

    auto load_stage = [&](int stg, int kc) {
        uint32_t db = sbase + stg * STAGE3;
#pragma unroll
        for (int i = 0; i < 8; i++) {
            int idx = t + (i << 8);
            int tile = idx >> 9;
            int w = idx & 511;
            int r = w >> 2, c = w & 3;
            const __half* src = (tile == 0 ? base0 : tile == 1 ? base1 :
                                 tile == 2 ? base2 : base3)
                                + (size_t)r * DD + kc + (c << 3);
            cp_async16(db + tile * TILE_B + sw_off32(r, c), src);
        }
        CP_COMMIT();
    };

    load_stage(0, 0);
    load_stage(1, 32);
    load_stage(2, 64);

    const int wm = (wid & 1) << 6;
    const int wn = (wid >> 1) << 5;
    const int lr = lane & 15, lc = lane >> 4;
    float acc[4][4][4] = {};
    const int iters = HD / 32;

    for (int it = 0; it < iters; it++) {
        int stg = it % NSTAGE_S;
        CP_WAIT2();
        __syncthreads();
        uint32_t sb = sbase + stg * STAGE3;
        hmma3(sb, 0, wm, wn, lr, lc, acc);
        hmma3(sb, 1, wm, wn, lr, lc, acc);
        __syncthreads();
        if (it + NSTAGE_S < iters) load_stage(stg, (it + NSTAGE_S) * 32);
        else CP_COMMIT();
    }

    const int qr = lane >> 2, qc = (lane & 3) << 1;
#pragma unroll
    for (int mi = 0; mi < 4; mi++) {
#pragma unroll
        for (int ni = 0; ni < 4; ni++) {
            int rl = wm + mi * 16 + qr;
            int cl = wn + ni * 8 + qc;
            int k = k0 + cl;
            int qA = q0 + rl, qB = qA + 8;
            float2 v0 = { (k <= qA) ? acc[mi][ni][0] : NEG_INF,
                          (k + 1 <= qA) ? acc[mi][ni][1] : NEG_INF };
            float2 v1 = { (k <= qB) ? acc[mi][ni][2] : NEG_INF,
                          (k + 1 <= qB) ? acc[mi][ni][3] : NEG_INF };
            *(float2*)&P[pbase + (size_t)rl * SS + cl] = v0;
            *(float2*)&P[pbase + (size_t)(rl + 8) * SS + cl] = v1;
        }
    }
}

// ---------------------------------------------------------------------------
// pv_tc: AO = P @ V^T (fp16 1-product), causal k-bound; gathered fp16 hi out.
// ---------------------------------------------------------------------------
__global__ __launch_bounds__(256, 2) void pv_tc(
    const __half* __restrict__ Ph,
    const __half* __restrict__ Vth,
    __half* __restrict__ AOh)
{
    extern __shared__ char smem[];
    const uint32_t sbase = smem_u32(smem);
    const int t = threadIdx.x;
    const int wid = t >> 5, lane = t & 31;
    const int q0 = blockIdx.x << 7;
    const int bh = blockIdx.y;
    const int b = bh >> 5, h = bh & 31;

    const __half* base0 = Ph  + ((size_t)bh * SS + q0) * SS;
    const __half* base1 = Vth + (size_t)bh * HD * SS;

    const int iters = (q0 >> 5) + 4;

    auto load_stage = [&](int stg, int kc) {
        uint32_t db = sbase + stg * STAGE1;
#pragma unroll
        for (int i = 0; i < 4; i++) {
            int idx = t + (i << 8);
            int tile = idx >> 9;
            int w = idx & 511;
            int r = w >> 2, c = w & 3;
            const __half* src = (tile == 0 ? base0 : base1)
                                + (size_t)r * SS + kc + (c << 3);
            cp_async16(db + tile * TILE_B + sw_off32(r, c), src);
        }
        CP_COMMIT();
    };

#pragma unroll
    for (int s = 0; s < NSTAGE_P; s++) {
        if (s < iters) load_stage(s, s * 32);
        else CP_COMMIT();
    }

    const int wm = (wid & 1) << 6;
    const int wn = (wid >> 1) << 5;
    const int lr = lane & 15, lc = lane >> 4;
    float acc[4][4][4] = {};

    for (int it = 0; it < iters; it++) {
        int stg = it % NSTAGE_P;
        CP_WAIT5();
        __syncthreads();
        uint32_t sb = sbase + stg * STAGE1;
        hmma1(sb, 0, wm, wn, lr, lc, acc);
        hmma1(sb, 1, wm, wn, lr, lc, acc);
        __syncthreads();
        if (it + NSTAGE_P < iters) load_stage(stg, (it + NSTAGE_P) * 32);
        else CP_COMMIT();
    }

    const int qr = lane >> 2, qc = (lane & 3) << 1;
#pragma unroll
    for (int mi = 0; mi < 4; mi++) {
#pragma unroll
        for (int ni = 0; ni < 4; ni++) {
            int row = q0 + wm + mi * 16 + qr;
            int col = (h << 7) + wn + ni * 8 + qc;
            size_t m0 = ((size_t)b * SS + row) * DD + col;
            size_t m1 = m0 + (size_t)8 * DD;
            *(__half2*)&AOh[m0] = __halves2half2(__float2half_rn(acc[mi][ni][0]),
                                                 __float2half_rn(acc[mi][ni][1]));
            *(__half2*)&AOh[m1] = __halves2half2(__float2half_rn(acc[mi][ni][2]),
                                                 __float2half_rn(acc[mi][ni][3]));
        }
    }
}

// ---------------------------------------------------------------------------
// prep_hidden: one pass over hidden -> hh/hl (raw split) + qh/ql (roped Q)
// ---------------------------------------------------------------------------
__global__ void prep_hidden(const float* __restrict__ src,
                            __half* __restrict__ hh, __half* __restrict__ hl,
                            __half* __restrict__ qh, __half* __restrict__ ql,
                            const float* __restrict__ cosp, const float* __restrict__ sinp,
                            float scale)
{
    int idx = blockIdx.x * blockDim.x + threadIdx.x;
    const int total = BB * SS * HH * (HD / 2);
    if (idx >= total) return;
    int d  = idx & 63;
    int h  = (idx >> 6) & (HH - 1);
    int bs = idx >> 11;
    size_t base = (size_t)bs * DD + (h << 7);
    size_t cbase = (size_t)bs * HD;
    float c0 = cosp[cbase + d],      s0 = sinp[cbase + d];
    float c1 = cosp[cbase + d + 64], s1 = sinp[cbase + d + 64];
    float x0 = src[base + d], x1 = src[base + d + 64];
    __half a, b;
    split_hi_lo(x0, a, b); hh[base + d] = a;      hl[base + d] = b;
    split_hi_lo(x1, a, b); hh[base + d + 64] = a; hl[base + d + 64] = b;
    float y0 = (x0 * c0 - x1 * s0) * scale;
    float y1 = (x1 * c1 + x0 * s1) * scale;
    split_hi_lo(y0, a, b); qh[base + d] = a;      ql[base + d] = b;
    split_hi_lo(y1, a, b); qh[base + d + 64] = a; ql[base + d + 64] = b;
}

// fp32 -> fp16 hi only (weights)
__global__ void conv_hi(const float* __restrict__ x, __half* __restrict__ hi)
{
    size_t i = (size_t)blockIdx.x * blockDim.x + threadIdx.x;
    if (i >= NELT / 4) return;
    float4 v = ((const float4*)x)[i];
    ((__half2*)hi)[i * 2]     = __halves2half2(__float2half_rn(v.x), __float2half_rn(v.y));
    ((__half2*)hi)[i * 2 + 1] = __halves2half2(__float2half_rn(v.z), __float2half_rn(v.w));
}

// ---------------------------------------------------------------------------
// Causal softmax in place + fp16 emission (hi only) — float4 vectorized.
// Reads only the causal half (second 1024-col chunk skipped when kend<=1024).
// ---------------------------------------------------------------------------
__global__ __launch_bounds__(256) void softmax_pconv_kernel(
    float* __restrict__ P, __half* __restrict__ Ph)
{
    size_t row = blockIdx.x;
    int q = (int)(row & (SS - 1));
    int kend = ((q >> 7) + 1) << 7;
    float4* p4 = (float4*)(P + row * (size_t)SS);
    __half* ph = Ph + row * (size_t)SS;
    int t = threadIdx.x;

    float v[8];
    {
        float4 va = p4[t];
        int oa = t << 2;
        v[0] = (oa     <= q) ? va.x : -3.4e38f;
        v[1] = (oa + 1 <= q) ? va.y : -3.4e38f;
        v[2] = (oa + 2 <= q) ? va.z : -3.4e38f;
        v[3] = (oa + 3 <= q) ? va.w : -3.4e38f;
        if (kend > 1024) {
            float4 vb = p4[t + 256];
            int ob = 1024 + (t << 2);
            v[4] = (ob     <= q) ? vb.x : -3.4e38f;
            v[5] = (ob + 1 <= q) ? vb.y : -3.4e38f;
            v[6] = (ob + 2 <= q) ? vb.z : -3.4e38f;
            v[7] = (ob + 3 <= q) ? vb.w : -3.4e38f;
        } else {
            v[4] = v[5] = v[6] = v[7] = -3.4e38f;
        }
    }
    float mx = v[0];
#pragma unroll
    for (int i = 1; i < 8; i++) mx = fmaxf(mx, v[i]);
#pragma unroll
    for (int o = 16; o; o >>= 1) mx = fmaxf(mx, __shfl_xor_sync(0xffffffffu, mx, o));
    __shared__ float rmax[8], rsum[8];
    if ((t & 31) == 0) rmax[t >> 5] = mx;
    __syncthreads();
    mx = rmax[0];
#pragma unroll
    for (int i = 1; i < 8; i++) mx = fmaxf(mx, rmax[i]);
    float sum = 0.f;
#pragma unroll
    for (int i = 0; i < 8; i++) {
        v[i] = (v[i] > -3.3e38f) ? __expf(v[i] - mx) : 0.f;
        sum += v[i];
    }
#pragma unroll
    for (int o = 16; o; o >>= 1) sum += __shfl_xor_sync(0xffffffffu, sum, o);
    if ((t & 31) == 0) rsum[t >> 5] = sum;
    __syncthreads();
    sum = rsum[0];
#pragma unroll
    for (int i = 1; i < 8; i++) sum += rsum[i];
    float inv = 1.0f / sum;
#pragma unroll
    for (int i = 0; i < 8; i++) v[i] *= inv;

    p4[t]       = make_float4(v[0], v[1], v[2], v[3]);
    p4[t + 256] = make_float4(v[4], v[5], v[6], v[7]);

    {
        int oa = t << 2;
        if (oa < kend) {
            *(__half2*)&ph[oa]     = __halves2half2(__float2half_rn(v[0]), __float2half_rn(v[1]));
            *(__half2*)&ph[oa + 2] = __halves2half2(__float2half_rn(v[2]), __float2half_rn(v[3]));
        }
        int ob = 1024 + (t << 2);
        if (ob < kend) {
            *(__half2*)&ph[ob]     = __halves2half2(__float2half_rn(v[4]), __float2half_rn(v[5]));
            *(__half2*)&ph[ob + 2] = __halves2half2(__float2half_rn(v[6]), __float2half_rn(v[7]));
        }
    }
}

// ---------------------------------------------------------------------------
extern "C" void kernel_launch(void* const* d_in, const int* in_sizes, int n_in,
                              void* d_out, int out_size)
{
    (void)in_sizes; (void)n_in; (void)out_size;
    const float* hidden = (const float*)d_in[0];
    const float* Wqk    = (const float*)d_in[1];
    const float* bqk    = (const float*)d_in[2];
    const float* Wv     = (const float*)d_in[3];
    const float* bv     = (const float*)d_in[4];
    const float* Wo     = (const float*)d_in[5];
    const float* cosp   = (const float*)d_in[6];
    const float* sinp   = (const float*)d_in[7];

    float* out   = (float*)d_out;
    float* attnw = out + (size_t)BB * SS * DD;

    __half *hh, *hl, *qkh, *vh, *oh;
    __half *qh, *ql, *kh, *kl, *vth, *aoh, *ph;
    cudaGetSymbolAddress((void**)&hh,  g_hh);  cudaGetSymbolAddress((void**)&hl,  g_hl);
    cudaGetSymbolAddress((void**)&qkh, g_qkh);
    cudaGetSymbolAddress((void**)&vh,  g_vh);
    cudaGetSymbolAddress((void**)&oh,  g_oh);
    cudaGetSymbolAddress((void**)&qh,  g_qh);  cudaGetSymbolAddress((void**)&ql,  g_ql);
    cudaGetSymbolAddress((void**)&kh,  g_kh);  cudaGetSymbolAddress((void**)&kl,  g_kl);
    cudaGetSymbolAddress((void**)&vth, g_vth);
    cudaGetSymbolAddress((void**)&aoh, g_aoh);
    cudaGetSymbolAddress((void**)&ph,  g_ph);

    cudaFuncSetAttribute(gemm_rope_tc, cudaFuncAttributeMaxDynamicSharedMemorySize, SMEM_G);
    cudaFuncSetAttribute(gemm1_tc<0>,  cudaFuncAttributeMaxDynamicSharedMemorySize, SMEM_P);
    cudaFuncSetAttribute(gemm1_tc<2>,  cudaFuncAttributeMaxDynamicSharedMemorySize, SMEM_P);
    cudaFuncSetAttribute(score_tc,     cudaFuncAttributeMaxDynamicSharedMemorySize, SMEM_S);
    cudaFuncSetAttribute(pv_tc,        cudaFuncAttributeMaxDynamicSharedMemorySize, SMEM_P);

    const int cvblk = (int)((NELT / 4 + 255) / 256);
    const int rope_total = BB * SS * HH * (HD / 2);
    const float scale = 0.088388347648318447f;  // 128^-0.5

    prep_hidden<<<(rope_total + 255) / 256, 256>>>(hidden, hh, hl, qh, ql, cosp, sinp, scale);
    conv_hi<<<cvblk, 256>>>(Wqk, qkh);
    conv_hi<<<cvblk, 256>>>(Wv,  vh);
    conv_hi<<<cvblk, 256>>>(Wo,  oh);

    dim3 gg(DD / 128, (BB * SS) / 128);
    // QK projection (2-product) with fused bias+RoPE+split — feeds attnw path
    gemm_rope_tc<<<gg, 256, SMEM_G>>>(hh, hl, qkh, bqk, cosp, sinp, kh, kl);
    // V projection (1-product) with fused bias+transpose+split
    gemm1_tc<2><<<gg, 256, SMEM_P>>>(hh, vh, bv, nullptr, vth);

    score_tc<<<dim3(SS / 128, SS / 128, BB * HH), 256, SMEM_S>>>(qh, ql, kh, kl, attnw);
    softmax_pconv_kernel<<<BB * HH * SS, 256>>>(attnw, ph);
    pv_tc<<<dim3(SS / 128, BB * HH), 256, SMEM_P>>>(ph, vth, aoh);

    // final projection: fp16 1-product
    gemm1_tc<0><<<gg, 256, SMEM_P>>>(aoh, oh, nullptr, out, nullptr);
}

// round 12
// speedup vs baseline: 5.3791x; 1.0429x over previous
#include <cuda_runtime.h>
#include <cuda_fp16.h>
#include <cstdint>
#include <cstddef>

#define BB 2
#define SS 2048
#define DD 4096
#define HH 32
#define HD 128
#define NEG_INF -1000000000.0f

#define NELT ((size_t)BB * SS * DD)          // 16,777,216
#define NP   ((size_t)BB * HH * SS * SS)     // 268,435,456

// ---------------- scratch (device globals; alloc APIs forbidden) ----------
__device__ __half g_hh[NELT],  g_hl[NELT];    // hidden hi/lo
__device__ __half g_qkh[NELT];                // Wqk hi
__device__ __half g_vh[NELT];                 // Wv hi
__device__ __half g_oh[NELT];                 // Wo hi
__device__ __half g_qh[NELT],  g_ql[NELT];    // roped Q hi/lo (b,s,h,hd)
__device__ __half g_kh[NELT];                 // roped K hi (b,s,h,hd)
__device__ __half g_vth[NELT];                // V^T hi (b,h,d,k)
__device__ __half g_aoh[NELT];                // attn-out gathered (fp16 hi only)
__device__ __half g_ph[NP];                   // softmax P (fp16 hi only)

// ---------------- helpers ---------------------------------------------------
__device__ __forceinline__ uint32_t smem_u32(const void* p) {
    uint32_t a;
    asm("{ .reg .u64 t; cvta.to.shared.u64 t, %1; cvt.u32.u64 %0, t; }" : "=r"(a) : "l"(p));
    return a;
}
__device__ __forceinline__ void cp_async16(uint32_t dst, const void* src) {
    asm volatile("cp.async.cg.shared.global [%0], [%1], 16;" :: "r"(dst), "l"(src));
}
#define CP_COMMIT() asm volatile("cp.async.commit_group;" ::: "memory")
#define CP_WAIT3()  asm volatile("cp.async.wait_group 3;" ::: "memory")
#define CP_WAIT5()  asm volatile("cp.async.wait_group 5;" ::: "memory")

__device__ __forceinline__ void ldmx4(uint32_t* r, uint32_t addr) {
    asm volatile("ldmatrix.sync.aligned.m8n8.x4.shared.b16 {%0,%1,%2,%3}, [%4];"
                 : "=r"(r[0]), "=r"(r[1]), "=r"(r[2]), "=r"(r[3]) : "r"(addr));
}
__device__ __forceinline__ void mma16816(float* d, const uint32_t* a, const uint32_t* b) {
    asm volatile(
        "mma.sync.aligned.m16n8k16.row.col.f32.f16.f16.f32 "
        "{%0,%1,%2,%3}, {%4,%5,%6,%7}, {%8,%9}, {%0,%1,%2,%3};"
        : "+f"(d[0]), "+f"(d[1]), "+f"(d[2]), "+f"(d[3])
        : "r"(a[0]), "r"(a[1]), "r"(a[2]), "r"(a[3]), "r"(b[0]), "r"(b[1]));
}
__device__ __forceinline__ void split_hi_lo(float f, __half& h, __half& l) {
    h = __float2half_rn(f);
    l = __float2half_rn(f - __half2float(h));
}

// ---- BK=32 tiles ------------------------------------------------------------
#define TILE_B 8192                     // 128 rows x 64B (32 fp16)
#define STAGE2 (3 * TILE_B)             // 2-product kernels: Ah, Al, Bh
#define STAGE1 (2 * TILE_B)             // 1-product kernels: 2 tiles
#define NSTAGE_G 4
#define NSTAGE_P 6
#define SMEM_G (NSTAGE_G * STAGE2)      // 98304
#define SMEM_P (NSTAGE_P * STAGE1)      // 98304

__device__ __forceinline__ uint32_t sw_off32(int r, int chunk) {
    return (uint32_t)(r << 6) + (((chunk ^ ((r >> 1) & 3)) << 4));
}

// ---- 2-product K=16 MMA step: A(hi+lo) x B(hi). Tiles: [Ah|Al|Bh] -----------
__device__ __forceinline__ void hmma2(
    uint32_t sb, int ks, int wm, int wn, int lr, int lc, float (&acc)[4][4][4])
{
    const int chunk = ks * 2 + lc;
    uint32_t bh[4][2];
#pragma unroll
    for (int g = 0; g < 2; g++) {
        int r = wn + g * 16 + lr;
        uint32_t rb[4];
        ldmx4(rb, sb + 2 * TILE_B + sw_off32(r, chunk));
        bh[g*2+0][0] = rb[0]; bh[g*2+0][1] = rb[2];
        bh[g*2+1][0] = rb[1]; bh[g*2+1][1] = rb[3];
    }
#pragma unroll
    for (int mi = 0; mi < 4; mi++) {
        int r = wm + mi * 16 + lr;
        uint32_t off = sw_off32(r, chunk);
        uint32_t ah[4], al[4];
        ldmx4(ah, sb + off);
        ldmx4(al, sb + TILE_B + off);
#pragma unroll
        for (int ni = 0; ni < 4; ni++) {
            mma16816(acc[mi][ni], ah, bh[ni]);
            mma16816(acc[mi][ni], al, bh[ni]);
        }
    }
}

// ---- 1-product K=16 MMA step: tiles [Ah|Bh] ---------------------------------
__device__ __forceinline__ void hmma1(
    uint32_t sb, int ks, int wm, int wn, int lr, int lc, float (&acc)[4][4][4])
{
    const int chunk = ks * 2 + lc;
    uint32_t bh[4][2];
#pragma unroll
    for (int g = 0; g < 2; g++) {
        int r = wn + g * 16 + lr;
        uint32_t rb[4];
        ldmx4(rb, sb + TILE_B + sw_off32(r, chunk));
        bh[g*2+0][0] = rb[0]; bh[g*2+0][1] = rb[2];
        bh[g*2+1][0] = rb[1]; bh[g*2+1][1] = rb[3];
    }
#pragma unroll
    for (int mi = 0; mi < 4; mi++) {
        int r = wm + mi * 16 + lr;
        uint32_t ah[4];
        ldmx4(ah, sb + sw_off32(r, chunk));
#pragma unroll
        for (int ni = 0; ni < 4; ni++)
            mma16816(acc[mi][ni], ah, bh[ni]);
    }
}

// ---------------------------------------------------------------------------
// gemm_rope_tc: QK projection, fp16 2-product, fused bias+RoPE -> K hi only.
// ---------------------------------------------------------------------------
__global__ __launch_bounds__(256, 2) void gemm_rope_tc(
    const __half* __restrict__ Ah, const __half* __restrict__ Al,
    const __half* __restrict__ Bh,
    const float* __restrict__ bias,
    const float* __restrict__ cosp, const float* __restrict__ sinp,
    __half* __restrict__ O1)
{
    extern __shared__ char smem[];
    const uint32_t sbase = smem_u32(smem);
    const int t = threadIdx.x;
    const int wid = t >> 5, lane = t & 31;
    const int bm = blockIdx.y << 7, bn = blockIdx.x << 7;

    const __half* base0 = Ah + (size_t)bm * DD;
    const __half* base1 = Al + (size_t)bm * DD;
    const __half* base2 = Bh + (size_t)bn * DD;

    auto load_stage = [&](int stg, int kc) {
        uint32_t db = sbase + stg * STAGE2;
#pragma unroll
        for (int i = 0; i < 6; i++) {
            int idx = t + (i << 8);
            int tile = idx >> 9;
            int w = idx & 511;
            int r = w >> 2, c = w & 3;
            const __half* src = (tile == 0 ? base0 : tile == 1 ? base1 : base2)
                                + (size_t)r * DD + kc + (c << 3);
            cp_async16(db + tile * TILE_B + sw_off32(r, c), src);
        }
        CP_COMMIT();
    };

    load_stage(0, 0);
    load_stage(1, 32);
    load_stage(2, 64);
    load_stage(3, 96);

    const int wm = (wid & 1) << 6;
    const int wn = (wid >> 1) << 5;
    const int lr = lane & 15, lc = lane >> 4;

    float acc[4][4][4] = {};
    const int iters = DD / 32;

    for (int it = 0; it < iters; it++) {
        int stg = it % NSTAGE_G;
        CP_WAIT3();
        __syncthreads();
        uint32_t sb = sbase + stg * STAGE2;
        hmma2(sb, 0, wm, wn, lr, lc, acc);
        hmma2(sb, 1, wm, wn, lr, lc, acc);
        __syncthreads();
        if (it + NSTAGE_G < iters) load_stage(stg, (it + NSTAGE_G) * 32);
        else CP_COMMIT();
    }

    const int qr = lane >> 2, qc = (lane & 3) << 1;

    // stage acc (+bias) into padded fp32 smem tile, then RoPE -> K hi
    __syncthreads();
    float* eps = (float*)smem;
#pragma unroll
    for (int mi = 0; mi < 4; mi++) {
#pragma unroll
        for (int ni = 0; ni < 4; ni++) {
            int cl = wn + ni * 8 + qc;
            float b0 = bias[bn + cl];
            float b1 = bias[bn + cl + 1];
            int r0 = wm + mi * 16 + qr;
            eps[r0 * 132 + cl]           = acc[mi][ni][0] + b0;
            eps[r0 * 132 + cl + 1]       = acc[mi][ni][1] + b1;
            eps[(r0 + 8) * 132 + cl]     = acc[mi][ni][2] + b0;
            eps[(r0 + 8) * 132 + cl + 1] = acc[mi][ni][3] + b1;
        }
    }
    __syncthreads();

#pragma unroll
    for (int q8 = 0; q8 < 32; q8++) {
        int idx = t + (q8 << 8);          // 0..8191
        int d = idx & 63, r = idx >> 6;
        int m = bm + r;
        size_t cb = (size_t)m * HD;
        float c0 = cosp[cb + d],      s0 = sinp[cb + d];
        float c1 = cosp[cb + d + 64], s1 = sinp[cb + d + 64];
        float x0 = eps[r * 132 + d], x1 = eps[r * 132 + d + 64];
        float y0 = x0 * c0 - x1 * s0;
        float y1 = x1 * c1 + x0 * s1;
        size_t o = (size_t)m * DD + bn + d;
        O1[o]      = __float2half_rn(y0);
        O1[o + 64] = __float2half_rn(y1);
    }
}

// ---------------------------------------------------------------------------
// gemm1_tc: fp16 1-product GEMM over K=4096.
//  MODE 0: fp32 out (final projection, no bias)
//  MODE 2: V projection -> +bias -> transpose to (b,h,d,s) fp16 hi (O1)
// ---------------------------------------------------------------------------
template<int MODE>
__global__ __launch_bounds__(256, 2) void gemm1_tc(
    const __half* __restrict__ Ah, const __half* __restrict__ Bh,
    const float* __restrict__ bias,
    float* __restrict__ C, __half* __restrict__ O1)
{
    extern __shared__ char smem[];
    const uint32_t sbase = smem_u32(smem);
    const int t = threadIdx.x;
    const int wid = t >> 5, lane = t & 31;
    const int bm = blockIdx.y << 7, bn = blockIdx.x << 7;

    const __half* base0 = Ah + (size_t)bm * DD;
    const __half* base1 = Bh + (size_t)bn * DD;

    auto load_stage = [&](int stg, int kc) {
        uint32_t db = sbase + stg * STAGE1;
#pragma unroll
        for (int i = 0; i < 4; i++) {
            int idx = t + (i << 8);              // 0..1023
            int tile = idx >> 9;                 // 0..1
            int w = idx & 511;
            int r = w >> 2, c = w & 3;
            const __half* src = (tile == 0 ? base0 : base1)
                                + (size_t)r * DD + kc + (c << 3);
            cp_async16(db + tile * TILE_B + sw_off32(r, c), src);
        }
        CP_COMMIT();
    };

#pragma unroll
    for (int s = 0; s < NSTAGE_P; s++) load_stage(s, s * 32);

    const int wm = (wid & 1) << 6;
    const int wn = (wid >> 1) << 5;
    const int lr = lane & 15, lc = lane >> 4;
    float acc[4][4][4] = {};
    const int iters = DD / 32;

    for (int it = 0; it < iters; it++) {
        int stg = it % NSTAGE_P;
        CP_WAIT5();
        __syncthreads();
        uint32_t sb = sbase + stg * STAGE1;
        hmma1(sb, 0, wm, wn, lr, lc, acc);
        hmma1(sb, 1, wm, wn, lr, lc, acc);
        __syncthreads();
        if (it + NSTAGE_P < iters) load_stage(stg, (it + NSTAGE_P) * 32);
        else CP_COMMIT();
    }

    const int qr = lane >> 2, qc = (lane & 3) << 1;

    if (MODE == 0) {
#pragma unroll
        for (int mi = 0; mi < 4; mi++) {
#pragma unroll
            for (int ni = 0; ni < 4; ni++) {
                int col = bn + wn + ni * 8 + qc;
                int row0 = bm + wm + mi * 16 + qr;
                float2 v0 = { acc[mi][ni][0], acc[mi][ni][1] };
                float2 v1 = { acc[mi][ni][2], acc[mi][ni][3] };
                *(float2*)&C[(size_t)row0 * DD + col] = v0;
                *(float2*)&C[(size_t)(row0 + 8) * DD + col] = v1;
            }
        }
        return;
    }

    // MODE 2: stage (+bias) into padded smem tile, transpose -> Vt fp16 hi
    __syncthreads();
    float* eps = (float*)smem;
#pragma unroll
    for (int mi = 0; mi < 4; mi++) {
#pragma unroll
        for (int ni = 0; ni < 4; ni++) {
            int cl = wn + ni * 8 + qc;
            float b0 = bias[bn + cl];
            float b1 = bias[bn + cl + 1];
            int r0 = wm + mi * 16 + qr;
            eps[r0 * 133 + cl]           = acc[mi][ni][0] + b0;
            eps[r0 * 133 + cl + 1]       = acc[mi][ni][1] + b1;
            eps[(r0 + 8) * 133 + cl]     = acc[mi][ni][2] + b0;
            eps[(r0 + 8) * 133 + cl + 1] = acc[mi][ni][3] + b1;
        }
    }
    __syncthreads();

    int bh = ((bm >> 11) << 5) + (bn >> 7);
    int sbase_g = bm & (SS - 1);
#pragma unroll
    for (int q8 = 0; q8 < 16; q8++) {
        int qi = t + (q8 << 8);           // 0..4095 quads
        int d = qi >> 5;
        int sq = (qi & 31) << 2;
        float f0 = eps[(sq + 0) * 133 + d];
        float f1 = eps[(sq + 1) * 133 + d];
        float f2 = eps[(sq + 2) * 133 + d];
        float f3 = eps[(sq + 3) * 133 + d];
        size_t o = ((size_t)bh * HD + d) * SS + sbase_g + sq;
        *(__half2*)&O1[o]     = __halves2half2(__float2half_rn(f0), __float2half_rn(f1));
        *(__half2*)&O1[o + 2] = __halves2half2(__float2half_rn(f2), __float2half_rn(f3));
    }
}

// ---------------------------------------------------------------------------
// score_tc: P = Q.K (fp16 2-product: (Qh+Ql)·Kh), causal.
// Above-diagonal tiles write fp32 zeros (overlaps with tensor-bound blocks;
// softmax then only writes up to the causal bound).
// ---------------------------------------------------------------------------
__global__ __launch_bounds__(256, 2) void score_tc(
    const __half* __restrict__ Qh, const __half* __restrict__ Ql,
    const __half* __restrict__ Kh,
    float* __restrict__ P)
{
    extern __shared__ char smem[];
    const int q0 = blockIdx.y << 7, k0 = blockIdx.x << 7;
    const int bh = blockIdx.z;
    const size_t pbase = ((size_t)bh * SS + q0) * SS + k0;
    const int t = threadIdx.x;

    if (k0 > q0) {                 // fully-masked tile -> exact zeros
        const float4 z = { 0.f, 0.f, 0.f, 0.f };
#pragma unroll
        for (int q8 = 0; q8 < 16; q8++) {
            int i = t + (q8 << 8);             // 0..4095 float4 slots
            int r = i >> 5, c4 = (i & 31) << 2;
            *(float4*)&P[pbase + (size_t)r * SS + c4] = z;
        }
        return;
    }

    const int b = bh >> 5, h = bh & 31;
    const uint32_t sbase = smem_u32(smem);
    const int wid = t >> 5, lane = t & 31;

    const __half* base0 = Qh + (size_t)(b * SS + q0) * DD + (h << 7);
    const __half* base1 = Ql + (size_t)(b * SS + q0) * DD + (h << 7);
    const __half* base2 = Kh + (size_t)(b * SS + k0) * DD + (h << 7);

    auto load_stage = [&](int stg, int kc) {
        uint32_t db = sbase + stg * STAGE2;
#pragma unroll
        for (int i = 0; i < 6; i++) {
            int idx = t + (i << 8);
            int tile = idx >> 9;
            int w = idx & 511;
            int r = w >> 2, c = w & 3;
            const __half* src = (tile == 0 ? base0 : tile == 1 ? base1 : base2)
                                + (size_t)r * DD + kc + (c << 3);
            cp_async16(db + tile * TILE_B + sw_off32(r, c), src);
        }
        CP_COMMIT();
    };

    load_stage(0, 0);
    load_stage(1, 32);
    load_stage(2, 64);
    load_stage(3, 96);

    const int wm = (wid & 1) << 6;
    const int wn = (wid >> 1) << 5;
    const int lr = lane & 15, lc = lane >> 4;
    float acc[4][4][4] = {};
    const int iters = HD / 32;     // 4

    for (int it = 0; it < iters; it++) {
        int stg = it % NSTAGE_G;
        CP_WAIT3();
        __syncthreads();
        uint32_t sb = sbase + stg * STAGE2;
        hmma2(sb, 0, wm, wn, lr, lc, acc);
        hmma2(sb, 1, wm, wn, lr, lc, acc);
        __syncthreads();
        CP_COMMIT();               // keep group count in step (no more loads)
    }

    const int qr = lane >> 2, qc = (lane & 3) << 1;
#pragma unroll
    for (int mi = 0; mi < 4; mi++) {
#pragma unroll
        for (int ni = 0; ni < 4; ni++) {
            int rl = wm + mi * 16 + qr;
            int cl = wn + ni * 8 + qc;
            int k = k0 + cl;
            int qA = q0 + rl, qB = qA + 8;
            float2 v0 = { (k <= qA) ? acc[mi][ni][0] : NEG_INF,
                          (k + 1 <= qA) ? acc[mi][ni][1] : NEG_INF };
            float2 v1 = { (k <= qB) ? acc[mi][ni][2] : NEG_INF,
                          (k + 1 <= qB) ? acc[mi][ni][3] : NEG_INF };
            *(float2*)&P[pbase + (size_t)rl * SS + cl] = v0;
            *(float2*)&P[pbase + (size_t)(rl + 8) * SS + cl] = v1;
        }
    }
}

// ---------------------------------------------------------------------------
// pv_tc: AO = P @ V^T (fp16 1-product), causal k-bound; gathered fp16 hi out.
// ---------------------------------------------------------------------------
__global__ __launch_bounds__(256, 2) void pv_tc(
    const __half* __restrict__ Ph,
    const __half* __restrict__ Vth,
    __half* __restrict__ AOh)
{
    extern __shared__ char smem[];
    const uint32_t sbase = smem_u32(smem);
    const int t = threadIdx.x;
    const int wid = t >> 5, lane = t & 31;
    const int q0 = blockIdx.x << 7;
    const int bh = blockIdx.y;
    const int b = bh >> 5, h = bh & 31;

    const __half* base0 = Ph  + ((size_t)bh * SS + q0) * SS;
    const __half* base1 = Vth + (size_t)bh * HD * SS;

    const int iters = (q0 >> 5) + 4;

    auto load_stage = [&](int stg, int kc) {
        uint32_t db = sbase + stg * STAGE1;
#pragma unroll
        for (int i = 0; i < 4; i++) {
            int idx = t + (i << 8);
            int tile = idx >> 9;
            int w = idx & 511;
            int r = w >> 2, c = w & 3;
            const __half* src = (tile == 0 ? base0 : base1)
                                + (size_t)r * SS + kc + (c << 3);
            cp_async16(db + tile * TILE_B + sw_off32(r, c), src);
        }
        CP_COMMIT();
    };

#pragma unroll
    for (int s = 0; s < NSTAGE_P; s++) {
        if (s < iters) load_stage(s, s * 32);
        else CP_COMMIT();
    }

    const int wm = (wid & 1) << 6;
    const int wn = (wid >> 1) << 5;
    const int lr = lane & 15, lc = lane >> 4;
    float acc[4][4][4] = {};

    for (int it = 0; it < iters; it++) {
        int stg = it % NSTAGE_P;
        CP_WAIT5();
        __syncthreads();
        uint32_t sb = sbase + stg * STAGE1;
        hmma1(sb, 0, wm, wn, lr, lc, acc);
        hmma1(sb, 1, wm, wn, lr, lc, acc);
        __syncthreads();
        if (it + NSTAGE_P < iters) load_stage(stg, (it + NSTAGE_P) * 32);
        else CP_COMMIT();
    }

    const int qr = lane >> 2, qc = (lane & 3) << 1;
#pragma unroll
    for (int mi = 0; mi < 4; mi++) {
#pragma unroll
        for (int ni = 0; ni < 4; ni++) {
            int row = q0 + wm + mi * 16 + qr;
            int col = (h << 7) + wn + ni * 8 + qc;
            size_t m0 = ((size_t)b * SS + row) * DD + col;
            size_t m1 = m0 + (size_t)8 * DD;
            *(__half2*)&AOh[m0] = __halves2half2(__float2half_rn(acc[mi][ni][0]),
                                                 __float2half_rn(acc[mi][ni][1]));
            *(__half2*)&AOh[m1] = __halves2half2(__float2half_rn(acc[mi][ni][2]),
                                                 __float2half_rn(acc[mi][ni][3]));
        }
    }
}

// ---------------------------------------------------------------------------
// prep_hidden: one pass over hidden -> hh/hl (raw split) + qh/ql (roped Q)
// ---------------------------------------------------------------------------
__global__ void prep_hidden(const float* __restrict__ src,
                            __half* __restrict__ hh, __half* __restrict__ hl,
                            __half* __restrict__ qh, __half* __restrict__ ql,
                            const float* __restrict__ cosp, const float* __restrict__ sinp,
                            float scale)
{
    int idx = blockIdx.x * blockDim.x + threadIdx.x;
    const int total = BB * SS * HH * (HD / 2);
    if (idx >= total) return;
    int d  = idx & 63;
    int h  = (idx >> 6) & (HH - 1);
    int bs = idx >> 11;
    size_t base = (size_t)bs * DD + (h << 7);
    size_t cbase = (size_t)bs * HD;
    float c0 = cosp[cbase + d],      s0 = sinp[cbase + d];
    float c1 = cosp[cbase + d + 64], s1 = sinp[cbase + d + 64];
    float x0 = src[base + d], x1 = src[base + d + 64];
    __half a, b;
    split_hi_lo(x0, a, b); hh[base + d] = a;      hl[base + d] = b;
    split_hi_lo(x1, a, b); hh[base + d + 64] = a; hl[base + d + 64] = b;
    float y0 = (x0 * c0 - x1 * s0) * scale;
    float y1 = (x1 * c1 + x0 * s1) * scale;
    split_hi_lo(y0, a, b); qh[base + d] = a;      ql[base + d] = b;
    split_hi_lo(y1, a, b); qh[base + d + 64] = a; ql[base + d + 64] = b;
}

// fp32 -> fp16 hi only (weights)
__global__ void conv_hi(const float* __restrict__ x, __half* __restrict__ hi)
{
    size_t i = (size_t)blockIdx.x * blockDim.x + threadIdx.x;
    if (i >= NELT / 4) return;
    float4 v = ((const float4*)x)[i];
    ((__half2*)hi)[i * 2]     = __halves2half2(__float2half_rn(v.x), __float2half_rn(v.y));
    ((__half2*)hi)[i * 2 + 1] = __halves2half2(__float2half_rn(v.z), __float2half_rn(v.w));
}

// ---------------------------------------------------------------------------
// Causal softmax + fp16 emission. Reads AND writes only the causal region
// (cols >= kend already zeroed by score's masked blocks).
// ---------------------------------------------------------------------------
__global__ __launch_bounds__(256) void softmax_pconv_kernel(
    float* __restrict__ P, __half* __restrict__ Ph)
{
    size_t row = blockIdx.x;
    int q = (int)(row & (SS - 1));
    int kend = ((q >> 7) + 1) << 7;
    float4* p4 = (float4*)(P + row * (size_t)SS);
    __half* ph = Ph + row * (size_t)SS;
    int t = threadIdx.x;

    float v[8];
    {
        float4 va = p4[t];
        int oa = t << 2;
        v[0] = (oa     <= q) ? va.x : -3.4e38f;
        v[1] = (oa + 1 <= q) ? va.y : -3.4e38f;
        v[2] = (oa + 2 <= q) ? va.z : -3.4e38f;
        v[3] = (oa + 3 <= q) ? va.w : -3.4e38f;
        if (kend > 1024) {
            float4 vb = p4[t + 256];
            int ob = 1024 + (t << 2);
            v[4] = (ob     <= q) ? vb.x : -3.4e38f;
            v[5] = (ob + 1 <= q) ? vb.y : -3.4e38f;
            v[6] = (ob + 2 <= q) ? vb.z : -3.4e38f;
            v[7] = (ob + 3 <= q) ? vb.w : -3.4e38f;
        } else {
            v[4] = v[5] = v[6] = v[7] = -3.4e38f;
        }
    }
    float mx = v[0];
#pragma unroll
    for (int i = 1; i < 8; i++) mx = fmaxf(mx, v[i]);
#pragma unroll
    for (int o = 16; o; o >>= 1) mx = fmaxf(mx, __shfl_xor_sync(0xffffffffu, mx, o));
    __shared__ float rmax[8], rsum[8];
    if ((t & 31) == 0) rmax[t >> 5] = mx;
    __syncthreads();
    mx = rmax[0];
#pragma unroll
    for (int i = 1; i < 8; i++) mx = fmaxf(mx, rmax[i]);
    float sum = 0.f;
#pragma unroll
    for (int i = 0; i < 8; i++) {
        v[i] = (v[i] > -3.3e38f) ? __expf(v[i] - mx) : 0.f;
        sum += v[i];
    }
#pragma unroll
    for (int o = 16; o; o >>= 1) sum += __shfl_xor_sync(0xffffffffu, sum, o);
    if ((t & 31) == 0) rsum[t >> 5] = sum;
    __syncthreads();
    sum = rsum[0];
#pragma unroll
    for (int i = 1; i < 8; i++) sum += rsum[i];
    float inv = 1.0f / sum;
#pragma unroll
    for (int i = 0; i < 8; i++) v[i] *= inv;

    // fp32 + fp16 writes only inside the causal bound (kend multiple of 128)
    {
        int oa = t << 2;
        if (oa < kend) {
            p4[t] = make_float4(v[0], v[1], v[2], v[3]);
            *(__half2*)&ph[oa]     = __halves2half2(__float2half_rn(v[0]), __float2half_rn(v[1]));
            *(__half2*)&ph[oa + 2] = __halves2half2(__float2half_rn(v[2]), __float2half_rn(v[3]));
        }
        int ob = 1024 + (t << 2);
        if (ob < kend) {
            p4[t + 256] = make_float4(v[4], v[5], v[6], v[7]);
            *(__half2*)&ph[ob]     = __halves2half2(__float2half_rn(v[4]), __float2half_rn(v[5]));
            *(__half2*)&ph[ob + 2] = __halves2half2(__float2half_rn(v[6]), __float2half_rn(v[7]));
        }
    }
}

// ---------------------------------------------------------------------------
extern "C" void kernel_launch(void* const* d_in, const int* in_sizes, int n_in,
                              void* d_out, int out_size)
{
    (void)in_sizes; (void)n_in; (void)out_size;
    const float* hidden = (const float*)d_in[0];
    const float* Wqk    = (const float*)d_in[1];
    const float* bqk    = (const float*)d_in[2];
    const float* Wv     = (const float*)d_in[3];
    const float* bv     = (const float*)d_in[4];
    const float* Wo     = (const float*)d_in[5];
    const float* cosp   = (const float*)d_in[6];
    const float* sinp   = (const float*)d_in[7];

    float* out   = (float*)d_out;
    float* attnw = out + (size_t)BB * SS * DD;

    __half *hh, *hl, *qkh, *vh, *oh;
    __half *qh, *ql, *kh, *vth, *aoh, *ph;
    cudaGetSymbolAddress((void**)&hh,  g_hh);  cudaGetSymbolAddress((void**)&hl,  g_hl);
    cudaGetSymbolAddress((void**)&qkh, g_qkh);
    cudaGetSymbolAddress((void**)&vh,  g_vh);
    cudaGetSymbolAddress((void**)&oh,  g_oh);
    cudaGetSymbolAddress((void**)&qh,  g_qh);  cudaGetSymbolAddress((void**)&ql,  g_ql);
    cudaGetSymbolAddress((void**)&kh,  g_kh);
    cudaGetSymbolAddress((void**)&vth, g_vth);
    cudaGetSymbolAddress((void**)&aoh, g_aoh);
    cudaGetSymbolAddress((void**)&ph,  g_ph);

    cudaFuncSetAttribute(gemm_rope_tc, cudaFuncAttributeMaxDynamicSharedMemorySize, SMEM_G);
    cudaFuncSetAttribute(gemm1_tc<0>,  cudaFuncAttributeMaxDynamicSharedMemorySize, SMEM_P);
    cudaFuncSetAttribute(gemm1_tc<2>,  cudaFuncAttributeMaxDynamicSharedMemorySize, SMEM_P);
    cudaFuncSetAttribute(score_tc,     cudaFuncAttributeMaxDynamicSharedMemorySize, SMEM_G);
    cudaFuncSetAttribute(pv_tc,        cudaFuncAttributeMaxDynamicSharedMemorySize, SMEM_P);

    const int cvblk = (int)((NELT / 4 + 255) / 256);
    const int rope_total = BB * SS * HH * (HD / 2);
    const float scale = 0.088388347648318447f;  // 128^-0.5

    prep_hidden<<<(rope_total + 255) / 256, 256>>>(hidden, hh, hl, qh, ql, cosp, sinp, scale);
    conv_hi<<<cvblk, 256>>>(Wqk, qkh);
    conv_hi<<<cvblk, 256>>>(Wv,  vh);
    conv_hi<<<cvblk, 256>>>(Wo,  oh);

    dim3 gg(DD / 128, (BB * SS) / 128);
    // QK projection (2-product), fused bias+RoPE -> K hi
    gemm_rope_tc<<<gg, 256, SMEM_G>>>(hh, hl, qkh, bqk, cosp, sinp, kh);
    // V projection (1-product), fused bias+transpose
    gemm1_tc<2><<<gg, 256, SMEM_P>>>(hh, vh, bv, nullptr, vth);

    score_tc<<<dim3(SS / 128, SS / 128, BB * HH), 256, SMEM_G>>>(qh, ql, kh, attnw);
    softmax_pconv_kernel<<<BB * HH * SS, 256>>>(attnw, ph);
    pv_tc<<<dim3(SS / 128, BB * HH), 256, SMEM_P>>>(ph, vth, aoh);

    // final projection: fp16 1-product
    gemm1_tc<0><<<gg, 256, SMEM_P>>>(aoh, oh, nullptr, out, nullptr);
}

// round 13
// speedup vs baseline: 6.6160x; 1.2300x over previous
#include <cuda_runtime.h>
#include <cuda_fp16.h>
#include <cstdint>
#include <cstddef>

#define BB 2
#define SS 2048
#define DD 4096
#define HH 32
#define HD 128
#define NEG_INF -1000000000.0f

#define NELT ((size_t)BB * SS * DD)          // 16,777,216
#define NP   ((size_t)BB * HH * SS * SS)     // 268,435,456

// ---------------- scratch (device globals; alloc APIs forbidden) ----------
__device__ __half g_hh[NELT];                 // hidden hi
__device__ __half g_qkh[NELT];                // Wqk hi
__device__ __half g_vh[NELT];                 // Wv hi
__device__ __half g_oh[NELT];                 // Wo hi
__device__ __half g_qh[NELT];                 // roped Q hi (b,s,h,hd)
__device__ __half g_kh[NELT];                 // roped K hi (b,s,h,hd)
__device__ __half g_vth[NELT];                // V^T hi (b,h,d,k)
__device__ __half g_aoh[NELT];                // attn-out gathered fp16
__device__ __half g_ph[NP];                   // softmax P fp16

// ---------------- helpers ---------------------------------------------------
__device__ __forceinline__ uint32_t smem_u32(const void* p) {
    uint32_t a;
    asm("{ .reg .u64 t; cvta.to.shared.u64 t, %1; cvt.u32.u64 %0, t; }" : "=r"(a) : "l"(p));
    return a;
}
__device__ __forceinline__ void cp_async16(uint32_t dst, const void* src) {
    asm volatile("cp.async.cg.shared.global [%0], [%1], 16;" :: "r"(dst), "l"(src));
}
#define CP_COMMIT() asm volatile("cp.async.commit_group;" ::: "memory")
#define CP_WAIT3()  asm volatile("cp.async.wait_group 3;" ::: "memory")
#define CP_WAIT5()  asm volatile("cp.async.wait_group 5;" ::: "memory")

__device__ __forceinline__ void ldmx4(uint32_t* r, uint32_t addr) {
    asm volatile("ldmatrix.sync.aligned.m8n8.x4.shared.b16 {%0,%1,%2,%3}, [%4];"
                 : "=r"(r[0]), "=r"(r[1]), "=r"(r[2]), "=r"(r[3]) : "r"(addr));
}
__device__ __forceinline__ void mma16816(float* d, const uint32_t* a, const uint32_t* b) {
    asm volatile(
        "mma.sync.aligned.m16n8k16.row.col.f32.f16.f16.f32 "
        "{%0,%1,%2,%3}, {%4,%5,%6,%7}, {%8,%9}, {%0,%1,%2,%3};"
        : "+f"(d[0]), "+f"(d[1]), "+f"(d[2]), "+f"(d[3])
        : "r"(a[0]), "r"(a[1]), "r"(a[2]), "r"(a[3]), "r"(b[0]), "r"(b[1]));
}

// ---- BK=32 tiles ------------------------------------------------------------
#define TILE_B 8192                     // 128 rows x 64B (32 fp16)
#define STAGE1 (2 * TILE_B)             // all kernels: 2 tiles/stage
#define NSTAGE_P 6
#define NSTAGE_S 4
#define SMEM_P (NSTAGE_P * STAGE1)      // 98304
#define SMEM_S (NSTAGE_S * STAGE1)      // 65536

__device__ __forceinline__ uint32_t sw_off32(int r, int chunk) {
    return (uint32_t)(r << 6) + (((chunk ^ ((r >> 1) & 3)) << 4));
}

// ---- 1-product K=16 MMA step: tiles [Ah|Bh] ---------------------------------
__device__ __forceinline__ void hmma1(
    uint32_t sb, int ks, int wm, int wn, int lr, int lc, float (&acc)[4][4][4])
{
    const int chunk = ks * 2 + lc;
    uint32_t bh[4][2];
#pragma unroll
    for (int g = 0; g < 2; g++) {
        int r = wn + g * 16 + lr;
        uint32_t rb[4];
        ldmx4(rb, sb + TILE_B + sw_off32(r, chunk));
        bh[g*2+0][0] = rb[0]; bh[g*2+0][1] = rb[2];
        bh[g*2+1][0] = rb[1]; bh[g*2+1][1] = rb[3];
    }
#pragma unroll
    for (int mi = 0; mi < 4; mi++) {
        int r = wm + mi * 16 + lr;
        uint32_t ah[4];
        ldmx4(ah, sb + sw_off32(r, chunk));
#pragma unroll
        for (int ni = 0; ni < 4; ni++)
            mma16816(acc[mi][ni], ah, bh[ni]);
    }
}

// ---------------------------------------------------------------------------
// gemm1_tc: fp16 1-product GEMM over K=4096, 6-stage pipeline.
//  MODE 0: fp32 out (final projection, no bias)
//  MODE 1: QK projection -> +bias -> RoPE -> fp16 hi (O1)
//  MODE 2: V projection  -> +bias -> transpose to (b,h,d,s) fp16 hi (O1)
// ---------------------------------------------------------------------------
template<int MODE>
__global__ __launch_bounds__(256, 2) void gemm1_tc(
    const __half* __restrict__ Ah, const __half* __restrict__ Bh,
    const float* __restrict__ bias,
    const float* __restrict__ cosp, const float* __restrict__ sinp,
    float* __restrict__ C, __half* __restrict__ O1)
{
    extern __shared__ char smem[];
    const uint32_t sbase = smem_u32(smem);
    const int t = threadIdx.x;
    const int wid = t >> 5, lane = t & 31;
    const int bm = blockIdx.y << 7, bn = blockIdx.x << 7;

    const __half* base0 = Ah + (size_t)bm * DD;
    const __half* base1 = Bh + (size_t)bn * DD;

    auto load_stage = [&](int stg, int kc) {
        uint32_t db = sbase + stg * STAGE1;
#pragma unroll
        for (int i = 0; i < 4; i++) {
            int idx = t + (i << 8);              // 0..1023
            int tile = idx >> 9;                 // 0..1
            int w = idx & 511;
            int r = w >> 2, c = w & 3;
            const __half* src = (tile == 0 ? base0 : base1)
                                + (size_t)r * DD + kc + (c << 3);
            cp_async16(db + tile * TILE_B + sw_off32(r, c), src);
        }
        CP_COMMIT();
    };

#pragma unroll
    for (int s = 0; s < NSTAGE_P; s++) load_stage(s, s * 32);

    const int wm = (wid & 1) << 6;
    const int wn = (wid >> 1) << 5;
    const int lr = lane & 15, lc = lane >> 4;
    float acc[4][4][4] = {};
    const int iters = DD / 32;

    for (int it = 0; it < iters; it++) {
        int stg = it % NSTAGE_P;
        CP_WAIT5();
        __syncthreads();
        uint32_t sb = sbase + stg * STAGE1;
        hmma1(sb, 0, wm, wn, lr, lc, acc);
        hmma1(sb, 1, wm, wn, lr, lc, acc);
        __syncthreads();
        if (it + NSTAGE_P < iters) load_stage(stg, (it + NSTAGE_P) * 32);
        else CP_COMMIT();
    }

    const int qr = lane >> 2, qc = (lane & 3) << 1;

    if (MODE == 0) {
#pragma unroll
        for (int mi = 0; mi < 4; mi++) {
#pragma unroll
            for (int ni = 0; ni < 4; ni++) {
                int col = bn + wn + ni * 8 + qc;
                int row0 = bm + wm + mi * 16 + qr;
                float2 v0 = { acc[mi][ni][0], acc[mi][ni][1] };
                float2 v1 = { acc[mi][ni][2], acc[mi][ni][3] };
                *(float2*)&C[(size_t)row0 * DD + col] = v0;
                *(float2*)&C[(size_t)(row0 + 8) * DD + col] = v1;
            }
        }
        return;
    }

    // stage acc (+bias) into padded fp32 smem tile
    __syncthreads();
    const int PAD = (MODE == 1) ? 132 : 133;
    float* eps = (float*)smem;
#pragma unroll
    for (int mi = 0; mi < 4; mi++) {
#pragma unroll
        for (int ni = 0; ni < 4; ni++) {
            int cl = wn + ni * 8 + qc;
            float b0 = bias[bn + cl];
            float b1 = bias[bn + cl + 1];
            int r0 = wm + mi * 16 + qr;
            eps[r0 * PAD + cl]           = acc[mi][ni][0] + b0;
            eps[r0 * PAD + cl + 1]       = acc[mi][ni][1] + b1;
            eps[(r0 + 8) * PAD + cl]     = acc[mi][ni][2] + b0;
            eps[(r0 + 8) * PAD + cl + 1] = acc[mi][ni][3] + b1;
        }
    }
    __syncthreads();

    if (MODE == 1) {
        // RoPE within the head tile (N-tile == one head): pairs (d, d+64)
#pragma unroll
        for (int q8 = 0; q8 < 32; q8++) {
            int idx = t + (q8 << 8);          // 0..8191
            int d = idx & 63, r = idx >> 6;
            int m = bm + r;
            size_t cb = (size_t)m * HD;
            float c0 = cosp[cb + d],      s0 = sinp[cb + d];
            float c1 = cosp[cb + d + 64], s1 = sinp[cb + d + 64];
            float x0 = eps[r * 132 + d], x1 = eps[r * 132 + d + 64];
            float y0 = x0 * c0 - x1 * s0;
            float y1 = x1 * c1 + x0 * s1;
            size_t o = (size_t)m * DD + bn + d;
            O1[o]      = __float2half_rn(y0);
            O1[o + 64] = __float2half_rn(y1);
        }
    } else {
        // MODE 2: transpose tile (s x d) -> Vt (b,h,d,s) fp16 hi
        int bh = ((bm >> 11) << 5) + (bn >> 7);
        int sbase_g = bm & (SS - 1);
#pragma unroll
        for (int q8 = 0; q8 < 16; q8++) {
            int qi = t + (q8 << 8);           // 0..4095 quads
            int d = qi >> 5;
            int sq = (qi & 31) << 2;
            float f0 = eps[(sq + 0) * 133 + d];
            float f1 = eps[(sq + 1) * 133 + d];
            float f2 = eps[(sq + 2) * 133 + d];
            float f3 = eps[(sq + 3) * 133 + d];
            size_t o = ((size_t)bh * HD + d) * SS + sbase_g + sq;
            *(__half2*)&O1[o]     = __halves2half2(__float2half_rn(f0), __float2half_rn(f1));
            *(__half2*)&O1[o + 2] = __halves2half2(__float2half_rn(f2), __float2half_rn(f3));
        }
    }
}

// ---------------------------------------------------------------------------
// score_tc: P = Qh.Kh (fp16 1-product), causal. 4-stage, 2 tiles/stage.
// Above-diagonal tiles write fp32 zeros; softmax writes only causal region.
// ---------------------------------------------------------------------------
__global__ __launch_bounds__(256, 2) void score_tc(
    const __half* __restrict__ Qh, const __half* __restrict__ Kh,
    float* __restrict__ P)
{
    extern __shared__ char smem[];
    const int q0 = blockIdx.y << 7, k0 = blockIdx.x << 7;
    const int bh = blockIdx.z;
    const size_t pbase = ((size_t)bh * SS + q0) * SS + k0;
    const int t = threadIdx.x;

    if (k0 > q0) {                 // fully-masked tile -> exact zeros
        const float4 z = { 0.f, 0.f, 0.f, 0.f };
#pragma unroll
        for (int q8 = 0; q8 < 16; q8++) {
            int i = t + (q8 << 8);
            int r = i >> 5, c4 = (i & 31) << 2;
            *(float4*)&P[pbase + (size_t)r * SS + c4] = z;
        }
        return;
    }

    const int b = bh >> 5, h = bh & 31;
    const uint32_t sbase = smem_u32(smem);
    const int wid = t >> 5, lane = t & 31;

    const __half* base0 = Qh + (size_t)(b * SS + q0) * DD + (h << 7);
    const __half* base1 = Kh + (size_t)(b * SS + k0) * DD + (h << 7);

    auto load_stage = [&](int stg, int kc) {
        uint32_t db = sbase + stg * STAGE1;
#pragma unroll
        for (int i = 0; i < 4; i++) {
            int idx = t + (i << 8);
            int tile = idx >> 9;
            int w = idx & 511;
            int r = w >> 2, c = w & 3;
            const __half* src = (tile == 0 ? base0 : base1)
                                + (size_t)r * DD + kc + (c << 3);
            cp_async16(db + tile * TILE_B + sw_off32(r, c), src);
        }
        CP_COMMIT();
    };

    load_stage(0, 0);
    load_stage(1, 32);
    load_stage(2, 64);
    load_stage(3, 96);

    const int wm = (wid & 1) << 6;
    const int wn = (wid >> 1) << 5;
    const int lr = lane & 15, lc = lane >> 4;
    float acc[4][4][4] = {};
    const int iters = HD / 32;     // 4 == NSTAGE_S

    for (int it = 0; it < iters; it++) {
        int stg = it % NSTAGE_S;
        CP_WAIT3();
        __syncthreads();
        uint32_t sb = sbase + stg * STAGE1;
        hmma1(sb, 0, wm, wn, lr, lc, acc);
        hmma1(sb, 1, wm, wn, lr, lc, acc);
        __syncthreads();
        CP_COMMIT();               // keep group count in step
    }

    const int qr = lane >> 2, qc = (lane & 3) << 1;
#pragma unroll
    for (int mi = 0; mi < 4; mi++) {
#pragma unroll
        for (int ni = 0; ni < 4; ni++) {
            int rl = wm + mi * 16 + qr;
            int cl = wn + ni * 8 + qc;
            int k = k0 + cl;
            int qA = q0 + rl, qB = qA + 8;
            float2 v0 = { (k <= qA) ? acc[mi][ni][0] : NEG_INF,
                          (k + 1 <= qA) ? acc[mi][ni][1] : NEG_INF };
            float2 v1 = { (k <= qB) ? acc[mi][ni][2] : NEG_INF,
                          (k + 1 <= qB) ? acc[mi][ni][3] : NEG_INF };
            *(float2*)&P[pbase + (size_t)rl * SS + cl] = v0;
            *(float2*)&P[pbase + (size_t)(rl + 8) * SS + cl] = v1;
        }
    }
}

// ---------------------------------------------------------------------------
// pv_tc: AO = P @ V^T (fp16 1-product), causal k-bound; gathered fp16 out.
// ---------------------------------------------------------------------------
__global__ __launch_bounds__(256, 2) void pv_tc(
    const __half* __restrict__ Ph,
    const __half* __restrict__ Vth,
    __half* __restrict__ AOh)
{
    extern __shared__ char smem[];
    const uint32_t sbase = smem_u32(smem);
    const int t = threadIdx.x;
    const int wid = t >> 5, lane = t & 31;
    const int q0 = blockIdx.x << 7;
    const int bh = blockIdx.y;
    const int b = bh >> 5, h = bh & 31;

    const __half* base0 = Ph  + ((size_t)bh * SS + q0) * SS;
    const __half* base1 = Vth + (size_t)bh * HD * SS;

    const int iters = (q0 >> 5) + 4;

    auto load_stage = [&](int stg, int kc) {
        uint32_t db = sbase + stg * STAGE1;
#pragma unroll
        for (int i = 0; i < 4; i++) {
            int idx = t + (i << 8);
            int tile = idx >> 9;
            int w = idx & 511;
            int r = w >> 2, c = w & 3;
            const __half* src = (tile == 0 ? base0 : base1)
                                + (size_t)r * SS + kc + (c << 3);
            cp_async16(db + tile * TILE_B + sw_off32(r, c), src);
        }
        CP_COMMIT();
    };

#pragma unroll
    for (int s = 0; s < NSTAGE_P; s++) {
        if (s < iters) load_stage(s, s * 32);
        else CP_COMMIT();
    }

    const int wm = (wid & 1) << 6;
    const int wn = (wid >> 1) << 5;
    const int lr = lane & 15, lc = lane >> 4;
    float acc[4][4][4] = {};

    for (int it = 0; it < iters; it++) {
        int stg = it % NSTAGE_P;
        CP_WAIT5();
        __syncthreads();
        uint32_t sb = sbase + stg * STAGE1;
        hmma1(sb, 0, wm, wn, lr, lc, acc);
        hmma1(sb, 1, wm, wn, lr, lc, acc);
        __syncthreads();
        if (it + NSTAGE_P < iters) load_stage(stg, (it + NSTAGE_P) * 32);
        else CP_COMMIT();
    }

    const int qr = lane >> 2, qc = (lane & 3) << 1;
#pragma unroll
    for (int mi = 0; mi < 4; mi++) {
#pragma unroll
        for (int ni = 0; ni < 4; ni++) {
            int row = q0 + wm + mi * 16 + qr;
            int col = (h << 7) + wn + ni * 8 + qc;
            size_t m0 = ((size_t)b * SS + row) * DD + col;
            size_t m1 = m0 + (size_t)8 * DD;
            *(__half2*)&AOh[m0] = __halves2half2(__float2half_rn(acc[mi][ni][0]),
                                                 __float2half_rn(acc[mi][ni][1]));
            *(__half2*)&AOh[m1] = __halves2half2(__float2half_rn(acc[mi][ni][2]),
                                                 __float2half_rn(acc[mi][ni][3]));
        }
    }
}

// ---------------------------------------------------------------------------
// prep_hidden: hidden -> hh (fp16 hi) + qh (roped+scaled Q, fp16 hi)
// ---------------------------------------------------------------------------
__global__ void prep_hidden(const float* __restrict__ src,
                            __half* __restrict__ hh, __half* __restrict__ qh,
                            const float* __restrict__ cosp, const float* __restrict__ sinp,
                            float scale)
{
    int idx = blockIdx.x * blockDim.x + threadIdx.x;
    const int total = BB * SS * HH * (HD / 2);
    if (idx >= total) return;
    int d  = idx & 63;
    int h  = (idx >> 6) & (HH - 1);
    int bs = idx >> 11;
    size_t base = (size_t)bs * DD + (h << 7);
    size_t cbase = (size_t)bs * HD;
    float c0 = cosp[cbase + d],      s0 = sinp[cbase + d];
    float c1 = cosp[cbase + d + 64], s1 = sinp[cbase + d + 64];
    float x0 = src[base + d], x1 = src[base + d + 64];
    hh[base + d]      = __float2half_rn(x0);
    hh[base + d + 64] = __float2half_rn(x1);
    float y0 = (x0 * c0 - x1 * s0) * scale;
    float y1 = (x1 * c1 + x0 * s1) * scale;
    qh[base + d]      = __float2half_rn(y0);
    qh[base + d + 64] = __float2half_rn(y1);
}

// fp32 -> fp16 hi only (weights)
__global__ void conv_hi(const float* __restrict__ x, __half* __restrict__ hi)
{
    size_t i = (size_t)blockIdx.x * blockDim.x + threadIdx.x;
    if (i >= NELT / 4) return;
    float4 v = ((const float4*)x)[i];
    ((__half2*)hi)[i * 2]     = __halves2half2(__float2half_rn(v.x), __float2half_rn(v.y));
    ((__half2*)hi)[i * 2 + 1] = __halves2half2(__float2half_rn(v.z), __float2half_rn(v.w));
}

// ---------------------------------------------------------------------------
// Causal softmax + fp16 emission. Reads/writes only the causal region
// (cols >= kend already zeroed by score's masked blocks).
// ---------------------------------------------------------------------------
__global__ __launch_bounds__(256) void softmax_pconv_kernel(
    float* __restrict__ P, __half* __restrict__ Ph)
{
    size_t row = blockIdx.x;
    int q = (int)(row & (SS - 1));
    int kend = ((q >> 7) + 1) << 7;
    float4* p4 = (float4*)(P + row * (size_t)SS);
    __half* ph = Ph + row * (size_t)SS;
    int t = threadIdx.x;

    float v[8];
    {
        float4 va = p4[t];
        int oa = t << 2;
        v[0] = (oa     <= q) ? va.x : -3.4e38f;
        v[1] = (oa + 1 <= q) ? va.y : -3.4e38f;
        v[2] = (oa + 2 <= q) ? va.z : -3.4e38f;
        v[3] = (oa + 3 <= q) ? va.w : -3.4e38f;
        if (kend > 1024) {
            float4 vb = p4[t + 256];
            int ob = 1024 + (t << 2);
            v[4] = (ob     <= q) ? vb.x : -3.4e38f;
            v[5] = (ob + 1 <= q) ? vb.y : -3.4e38f;
            v[6] = (ob + 2 <= q) ? vb.z : -3.4e38f;
            v[7] = (ob + 3 <= q) ? vb.w : -3.4e38f;
        } else {
            v[4] = v[5] = v[6] = v[7] = -3.4e38f;
        }
    }
    float mx = v[0];
#pragma unroll
    for (int i = 1; i < 8; i++) mx = fmaxf(mx, v[i]);
#pragma unroll
    for (int o = 16; o; o >>= 1) mx = fmaxf(mx, __shfl_xor_sync(0xffffffffu, mx, o));
    __shared__ float rmax[8], rsum[8];
    if ((t & 31) == 0) rmax[t >> 5] = mx;
    __syncthreads();
    mx = rmax[0];
#pragma unroll
    for (int i = 1; i < 8; i++) mx = fmaxf(mx, rmax[i]);
    float sum = 0.f;
#pragma unroll
    for (int i = 0; i < 8; i++) {
        v[i] = (v[i] > -3.3e38f) ? __expf(v[i] - mx) : 0.f;
        sum += v[i];
    }
#pragma unroll
    for (int o = 16; o; o >>= 1) sum += __shfl_xor_sync(0xffffffffu, sum, o);
    if ((t & 31) == 0) rsum[t >> 5] = sum;
    __syncthreads();
    sum = rsum[0];
#pragma unroll
    for (int i = 1; i < 8; i++) sum += rsum[i];
    float inv = 1.0f / sum;
#pragma unroll
    for (int i = 0; i < 8; i++) v[i] *= inv;

    {
        int oa = t << 2;
        if (oa < kend) {
            p4[t] = make_float4(v[0], v[1], v[2], v[3]);
            *(__half2*)&ph[oa]     = __halves2half2(__float2half_rn(v[0]), __float2half_rn(v[1]));
            *(__half2*)&ph[oa + 2] = __halves2half2(__float2half_rn(v[2]), __float2half_rn(v[3]));
        }
        int ob = 1024 + (t << 2);
        if (ob < kend) {
            p4[t + 256] = make_float4(v[4], v[5], v[6], v[7]);
            *(__half2*)&ph[ob]     = __halves2half2(__float2half_rn(v[4]), __float2half_rn(v[5]));
            *(__half2*)&ph[ob + 2] = __halves2half2(__float2half_rn(v[6]), __float2half_rn(v[7]));
        }
    }
}

// ---------------------------------------------------------------------------
extern "C" void kernel_launch(void* const* d_in, const int* in_sizes, int n_in,
                              void* d_out, int out_size)
{
    (void)in_sizes; (void)n_in; (void)out_size;
    const float* hidden = (const float*)d_in[0];
    const float* Wqk    = (const float*)d_in[1];
    const float* bqk    = (const float*)d_in[2];
    const float* Wv     = (const float*)d_in[3];
    const float* bv     = (const float*)d_in[4];
    const float* Wo     = (const float*)d_in[5];
    const float* cosp   = (const float*)d_in[6];
    const float* sinp   = (const float*)d_in[7];

    float* out   = (float*)d_out;
    float* attnw = out + (size_t)BB * SS * DD;

    __half *hh, *qkh, *vh, *oh, *qh, *kh, *vth, *aoh, *ph;
    cudaGetSymbolAddress((void**)&hh,  g_hh);
    cudaGetSymbolAddress((void**)&qkh, g_qkh);
    cudaGetSymbolAddress((void**)&vh,  g_vh);
    cudaGetSymbolAddress((void**)&oh,  g_oh);
    cudaGetSymbolAddress((void**)&qh,  g_qh);
    cudaGetSymbolAddress((void**)&kh,  g_kh);
    cudaGetSymbolAddress((void**)&vth, g_vth);
    cudaGetSymbolAddress((void**)&aoh, g_aoh);
    cudaGetSymbolAddress((void**)&ph,  g_ph);

    cudaFuncSetAttribute(gemm1_tc<0>, cudaFuncAttributeMaxDynamicSharedMemorySize, SMEM_P);
    cudaFuncSetAttribute(gemm1_tc<1>, cudaFuncAttributeMaxDynamicSharedMemorySize, SMEM_P);
    cudaFuncSetAttribute(gemm1_tc<2>, cudaFuncAttributeMaxDynamicSharedMemorySize, SMEM_P);
    cudaFuncSetAttribute(score_tc,    cudaFuncAttributeMaxDynamicSharedMemorySize, SMEM_S);
    cudaFuncSetAttribute(pv_tc,       cudaFuncAttributeMaxDynamicSharedMemorySize, SMEM_P);

    const int cvblk = (int)((NELT / 4 + 255) / 256);
    const int rope_total = BB * SS * HH * (HD / 2);
    const float scale = 0.088388347648318447f;  // 128^-0.5

    prep_hidden<<<(rope_total + 255) / 256, 256>>>(hidden, hh, qh, cosp, sinp, scale);
    conv_hi<<<cvblk, 256>>>(Wqk, qkh);
    conv_hi<<<cvblk, 256>>>(Wv,  vh);
    conv_hi<<<cvblk, 256>>>(Wo,  oh);

    dim3 gg(DD / 128, (BB * SS) / 128);
    // QK projection (1-product), fused bias+RoPE -> K hi
    gemm1_tc<1><<<gg, 256, SMEM_P>>>(hh, qkh, bqk, cosp, sinp, nullptr, kh);
    // V projection (1-product), fused bias+transpose
    gemm1_tc<2><<<gg, 256, SMEM_P>>>(hh, vh, bv, nullptr, nullptr, nullptr, vth);

    score_tc<<<dim3(SS / 128, SS / 128, BB * HH), 256, SMEM_S>>>(qh, kh, attnw);
    softmax_pconv_kernel<<<BB * HH * SS, 256>>>(attnw, ph);
    pv_tc<<<dim3(SS / 128, BB * HH), 256, SMEM_P>>>(ph, vth, aoh);

    // final projection (1-product)
    gemm1_tc<0><<<gg, 256, SMEM_P>>>(aoh, oh, nullptr, nullptr, nullptr, out, nullptr);
}

// round 14
// speedup vs baseline: 6.6959x; 1.0121x over previous
#include <cuda_runtime.h>
#include <cuda_fp16.h>
#include <cstdint>
#include <cstddef>

#define BB 2
#define SS 2048
#define DD 4096
#define HH 32
#define HD 128
#define NEG_INF -1000000000.0f

#define NELT ((size_t)BB * SS * DD)          // 16,777,216
#define NP   ((size_t)BB * HH * SS * SS)     // 268,435,456

// ---------------- scratch (device globals; alloc APIs forbidden) ----------
__device__ __half g_hh[NELT];                 // hidden hi
__device__ __half g_qkh[NELT];                // Wqk hi
__device__ __half g_vh[NELT];                 // Wv hi
__device__ __half g_oh[NELT];                 // Wo hi
__device__ __half g_qh[NELT];                 // roped Q hi (b,s,h,hd)
__device__ __half g_kh[NELT];                 // roped K hi (b,s,h,hd)
__device__ __half g_vth[NELT];                // V^T hi (b,h,d,k)
__device__ __half g_aoh[NELT];                // attn-out gathered fp16
__device__ __half g_ph[NP];                   // softmax P fp16

// ---------------- helpers ---------------------------------------------------
__device__ __forceinline__ uint32_t smem_u32(const void* p) {
    uint32_t a;
    asm("{ .reg .u64 t; cvta.to.shared.u64 t, %1; cvt.u32.u64 %0, t; }" : "=r"(a) : "l"(p));
    return a;
}
__device__ __forceinline__ void cp_async16(uint32_t dst, const void* src) {
    asm volatile("cp.async.cg.shared.global [%0], [%1], 16;" :: "r"(dst), "l"(src));
}
#define CP_COMMIT() asm volatile("cp.async.commit_group;" ::: "memory")
#define CP_WAIT2()  asm volatile("cp.async.wait_group 2;" ::: "memory")
#define CP_WAIT4()  asm volatile("cp.async.wait_group 4;" ::: "memory")

__device__ __forceinline__ void ldmx4(uint32_t* r, uint32_t addr) {
    asm volatile("ldmatrix.sync.aligned.m8n8.x4.shared.b16 {%0,%1,%2,%3}, [%4];"
                 : "=r"(r[0]), "=r"(r[1]), "=r"(r[2]), "=r"(r[3]) : "r"(addr));
}
__device__ __forceinline__ void mma16816(float* d, const uint32_t* a, const uint32_t* b) {
    asm volatile(
        "mma.sync.aligned.m16n8k16.row.col.f32.f16.f16.f32 "
        "{%0,%1,%2,%3}, {%4,%5,%6,%7}, {%8,%9}, {%0,%1,%2,%3};"
        : "+f"(d[0]), "+f"(d[1]), "+f"(d[2]), "+f"(d[3])
        : "r"(a[0]), "r"(a[1]), "r"(a[2]), "r"(a[3]), "r"(b[0]), "r"(b[1]));
}

// ---- BK=32 tiles ------------------------------------------------------------
#define TILE_B 8192                     // 128 rows x 64B (32 fp16)
#define STAGE1 (2 * TILE_B)             // all kernels: 2 tiles/stage
#define NSTAGE_P 6
#define NSTAGE_S 4
#define SMEM_P (NSTAGE_P * STAGE1)      // 98304
#define SMEM_S (NSTAGE_S * STAGE1)      // 65536

__device__ __forceinline__ uint32_t sw_off32(int r, int chunk) {
    return (uint32_t)(r << 6) + (((chunk ^ ((r >> 1) & 3)) << 4));
}

// ---- 1-product K=16 MMA step: tiles [Ah|Bh] ---------------------------------
__device__ __forceinline__ void hmma1(
    uint32_t sb, int ks, int wm, int wn, int lr, int lc, float (&acc)[4][4][4])
{
    const int chunk = ks * 2 + lc;
    uint32_t bh[4][2];
#pragma unroll
    for (int g = 0; g < 2; g++) {
        int r = wn + g * 16 + lr;
        uint32_t rb[4];
        ldmx4(rb, sb + TILE_B + sw_off32(r, chunk));
        bh[g*2+0][0] = rb[0]; bh[g*2+0][1] = rb[2];
        bh[g*2+1][0] = rb[1]; bh[g*2+1][1] = rb[3];
    }
#pragma unroll
    for (int mi = 0; mi < 4; mi++) {
        int r = wm + mi * 16 + lr;
        uint32_t ah[4];
        ldmx4(ah, sb + sw_off32(r, chunk));
#pragma unroll
        for (int ni = 0; ni < 4; ni++)
            mma16816(acc[mi][ni], ah, bh[ni]);
    }
}

// ---------------------------------------------------------------------------
// gemm1_tc: fp16 1-product GEMM over K=4096. One-barrier 6-stage pipeline:
// prefetch distance NSTAGE-1, so the stage being written was consumed one
// iteration ago (ordered by the top-of-iteration barrier).
//  MODE 0: fp32 out (final projection, no bias)
//  MODE 1: QK projection -> +bias -> RoPE -> fp16 hi (O1)
//  MODE 2: V projection  -> +bias -> transpose to (b,h,d,s) fp16 hi (O1)
// ---------------------------------------------------------------------------
template<int MODE>
__global__ __launch_bounds__(256, 2) void gemm1_tc(
    const __half* __restrict__ Ah, const __half* __restrict__ Bh,
    const float* __restrict__ bias,
    const float* __restrict__ cosp, const float* __restrict__ sinp,
    float* __restrict__ C, __half* __restrict__ O1)
{
    extern __shared__ char smem[];
    const uint32_t sbase = smem_u32(smem);
    const int t = threadIdx.x;
    const int wid = t >> 5, lane = t & 31;
    const int bm = blockIdx.y << 7, bn = blockIdx.x << 7;

    const __half* base0 = Ah + (size_t)bm * DD;
    const __half* base1 = Bh + (size_t)bn * DD;

    auto load_stage = [&](int stg, int kc) {
        uint32_t db = sbase + stg * STAGE1;
#pragma unroll
        for (int i = 0; i < 4; i++) {
            int idx = t + (i << 8);              // 0..1023
            int tile = idx >> 9;                 // 0..1
            int w = idx & 511;
            int r = w >> 2, c = w & 3;
            const __half* src = (tile == 0 ? base0 : base1)
                                + (size_t)r * DD + kc + (c << 3);
            cp_async16(db + tile * TILE_B + sw_off32(r, c), src);
        }
        CP_COMMIT();
    };

#pragma unroll
    for (int s = 0; s < NSTAGE_P - 1; s++) load_stage(s, s * 32);   // 5 groups

    const int wm = (wid & 1) << 6;
    const int wn = (wid >> 1) << 5;
    const int lr = lane & 15, lc = lane >> 4;
    float acc[4][4][4] = {};
    const int iters = DD / 32;

    for (int it = 0; it < iters; it++) {
        int stg = it % NSTAGE_P;
        CP_WAIT4();
        __syncthreads();
        uint32_t sb = sbase + stg * STAGE1;
        hmma1(sb, 0, wm, wn, lr, lc, acc);
        hmma1(sb, 1, wm, wn, lr, lc, acc);
        int nx = it + NSTAGE_P - 1;
        if (nx < iters) load_stage(nx % NSTAGE_P, nx * 32);
        else CP_COMMIT();
    }

    const int qr = lane >> 2, qc = (lane & 3) << 1;

    if (MODE == 0) {
#pragma unroll
        for (int mi = 0; mi < 4; mi++) {
#pragma unroll
            for (int ni = 0; ni < 4; ni++) {
                int col = bn + wn + ni * 8 + qc;
                int row0 = bm + wm + mi * 16 + qr;
                float2 v0 = { acc[mi][ni][0], acc[mi][ni][1] };
                float2 v1 = { acc[mi][ni][2], acc[mi][ni][3] };
                *(float2*)&C[(size_t)row0 * DD + col] = v0;
                *(float2*)&C[(size_t)(row0 + 8) * DD + col] = v1;
            }
        }
        return;
    }

    // stage acc (+bias) into padded fp32 smem tile
    __syncthreads();
    const int PAD = (MODE == 1) ? 132 : 133;
    float* eps = (float*)smem;
#pragma unroll
    for (int mi = 0; mi < 4; mi++) {
#pragma unroll
        for (int ni = 0; ni < 4; ni++) {
            int cl = wn + ni * 8 + qc;
            float b0 = bias[bn + cl];
            float b1 = bias[bn + cl + 1];
            int r0 = wm + mi * 16 + qr;
            eps[r0 * PAD + cl]           = acc[mi][ni][0] + b0;
            eps[r0 * PAD + cl + 1]       = acc[mi][ni][1] + b1;
            eps[(r0 + 8) * PAD + cl]     = acc[mi][ni][2] + b0;
            eps[(r0 + 8) * PAD + cl + 1] = acc[mi][ni][3] + b1;
        }
    }
    __syncthreads();

    if (MODE == 1) {
        // RoPE within the head tile (N-tile == one head): pairs (d, d+64)
#pragma unroll
        for (int q8 = 0; q8 < 32; q8++) {
            int idx = t + (q8 << 8);          // 0..8191
            int d = idx & 63, r = idx >> 6;
            int m = bm + r;
            size_t cb = (size_t)m * HD;
            float c0 = cosp[cb + d],      s0 = sinp[cb + d];
            float c1 = cosp[cb + d + 64], s1 = sinp[cb + d + 64];
            float x0 = eps[r * 132 + d], x1 = eps[r * 132 + d + 64];
            float y0 = x0 * c0 - x1 * s0;
            float y1 = x1 * c1 + x0 * s1;
            size_t o = (size_t)m * DD + bn + d;
            O1[o]      = __float2half_rn(y0);
            O1[o + 64] = __float2half_rn(y1);
        }
    } else {
        // MODE 2: transpose tile (s x d) -> Vt (b,h,d,s) fp16 hi
        int bh = ((bm >> 11) << 5) + (bn >> 7);
        int sbase_g = bm & (SS - 1);
#pragma unroll
        for (int q8 = 0; q8 < 16; q8++) {
            int qi = t + (q8 << 8);           // 0..4095 quads
            int d = qi >> 5;
            int sq = (qi & 31) << 2;
            float f0 = eps[(sq + 0) * 133 + d];
            float f1 = eps[(sq + 1) * 133 + d];
            float f2 = eps[(sq + 2) * 133 + d];
            float f3 = eps[(sq + 3) * 133 + d];
            size_t o = ((size_t)bh * HD + d) * SS + sbase_g + sq;
            *(__half2*)&O1[o]     = __halves2half2(__float2half_rn(f0), __float2half_rn(f1));
            *(__half2*)&O1[o + 2] = __halves2half2(__float2half_rn(f2), __float2half_rn(f3));
        }
    }
}

// ---------------------------------------------------------------------------
// score_tc: P = Qh.Kh (fp16 1-product), causal. One-barrier 4-stage pipeline.
// Above-diagonal tiles write fp32 zeros; softmax writes only causal region.
// ---------------------------------------------------------------------------
__global__ __launch_bounds__(256, 2) void score_tc(
    const __half* __restrict__ Qh, const __half* __restrict__ Kh,
    float* __restrict__ P)
{
    extern __shared__ char smem[];
    const int q0 = blockIdx.y << 7, k0 = blockIdx.x << 7;
    const int bh = blockIdx.z;
    const size_t pbase = ((size_t)bh * SS + q0) * SS + k0;
    const int t = threadIdx.x;

    if (k0 > q0) {                 // fully-masked tile -> exact zeros
        const float4 z = { 0.f, 0.f, 0.f, 0.f };
#pragma unroll
        for (int q8 = 0; q8 < 16; q8++) {
            int i = t + (q8 << 8);
            int r = i >> 5, c4 = (i & 31) << 2;
            *(float4*)&P[pbase + (size_t)r * SS + c4] = z;
        }
        return;
    }

    const int b = bh >> 5, h = bh & 31;
    const uint32_t sbase = smem_u32(smem);
    const int wid = t >> 5, lane = t & 31;

    const __half* base0 = Qh + (size_t)(b * SS + q0) * DD + (h << 7);
    const __half* base1 = Kh + (size_t)(b * SS + k0) * DD + (h << 7);

    auto load_stage = [&](int stg, int kc) {
        uint32_t db = sbase + stg * STAGE1;
#pragma unroll
        for (int i = 0; i < 4; i++) {
            int idx = t + (i << 8);
            int tile = idx >> 9;
            int w = idx & 511;
            int r = w >> 2, c = w & 3;
            const __half* src = (tile == 0 ? base0 : base1)
                                + (size_t)r * DD + kc + (c << 3);
            cp_async16(db + tile * TILE_B + sw_off32(r, c), src);
        }
        CP_COMMIT();
    };

    load_stage(0, 0);
    load_stage(1, 32);
    load_stage(2, 64);             // 3 groups (prefetch distance 3)

    const int wm = (wid & 1) << 6;
    const int wn = (wid >> 1) << 5;
    const int lr = lane & 15, lc = lane >> 4;
    float acc[4][4][4] = {};
    const int iters = HD / 32;     // 4 == NSTAGE_S

    for (int it = 0; it < iters; it++) {
        int stg = it % NSTAGE_S;
        CP_WAIT2();
        __syncthreads();
        uint32_t sb = sbase + stg * STAGE1;
        hmma1(sb, 0, wm, wn, lr, lc, acc);
        hmma1(sb, 1, wm, wn, lr, lc, acc);
        int nx = it + NSTAGE_S - 1;
        if (nx < iters) load_stage(nx % NSTAGE_S, nx * 32);
        else CP_COMMIT();
    }

    const int qr = lane >> 2, qc = (lane & 3) << 1;
#pragma unroll
    for (int mi = 0; mi < 4; mi++) {
#pragma unroll
        for (int ni = 0; ni < 4; ni++) {
            int rl = wm + mi * 16 + qr;
            int cl = wn + ni * 8 + qc;
            int k = k0 + cl;
            int qA = q0 + rl, qB = qA + 8;
            float2 v0 = { (k <= qA) ? acc[mi][ni][0] : NEG_INF,
                          (k + 1 <= qA) ? acc[mi][ni][1] : NEG_INF };
            float2 v1 = { (k <= qB) ? acc[mi][ni][2] : NEG_INF,
                          (k + 1 <= qB) ? acc[mi][ni][3] : NEG_INF };
            *(float2*)&P[pbase + (size_t)rl * SS + cl] = v0;
            *(float2*)&P[pbase + (size_t)(rl + 8) * SS + cl] = v1;
        }
    }
}

// ---------------------------------------------------------------------------
// pv_tc: AO = P @ V^T (fp16 1-product), causal k-bound. One-barrier pipeline.
// ---------------------------------------------------------------------------
__global__ __launch_bounds__(256, 2) void pv_tc(
    const __half* __restrict__ Ph,
    const __half* __restrict__ Vth,
    __half* __restrict__ AOh)
{
    extern __shared__ char smem[];
    const uint32_t sbase = smem_u32(smem);
    const int t = threadIdx.x;
    const int wid = t >> 5, lane = t & 31;
    const int q0 = blockIdx.x << 7;
    const int bh = blockIdx.y;
    const int b = bh >> 5, h = bh & 31;

    const __half* base0 = Ph  + ((size_t)bh * SS + q0) * SS;
    const __half* base1 = Vth + (size_t)bh * HD * SS;

    const int iters = (q0 >> 5) + 4;

    auto load_stage = [&](int stg, int kc) {
        uint32_t db = sbase + stg * STAGE1;
#pragma unroll
        for (int i = 0; i < 4; i++) {
            int idx = t + (i << 8);
            int tile = idx >> 9;
            int w = idx & 511;
            int r = w >> 2, c = w & 3;
            const __half* src = (tile == 0 ? base0 : base1)
                                + (size_t)r * SS + kc + (c << 3);
            cp_async16(db + tile * TILE_B + sw_off32(r, c), src);
        }
        CP_COMMIT();
    };

#pragma unroll
    for (int s = 0; s < NSTAGE_P - 1; s++) {
        if (s < iters) load_stage(s, s * 32);
        else CP_COMMIT();
    }

    const int wm = (wid & 1) << 6;
    const int wn = (wid >> 1) << 5;
    const int lr = lane & 15, lc = lane >> 4;
    float acc[4][4][4] = {};

    for (int it = 0; it < iters; it++) {
        int stg = it % NSTAGE_P;
        CP_WAIT4();
        __syncthreads();
        uint32_t sb = sbase + stg * STAGE1;
        hmma1(sb, 0, wm, wn, lr, lc, acc);
        hmma1(sb, 1, wm, wn, lr, lc, acc);
        int nx = it + NSTAGE_P - 1;
        if (nx < iters) load_stage(nx % NSTAGE_P, nx * 32);
        else CP_COMMIT();
    }

    const int qr = lane >> 2, qc = (lane & 3) << 1;
#pragma unroll
    for (int mi = 0; mi < 4; mi++) {
#pragma unroll
        for (int ni = 0; ni < 4; ni++) {
            int row = q0 + wm + mi * 16 + qr;
            int col = (h << 7) + wn + ni * 8 + qc;
            size_t m0 = ((size_t)b * SS + row) * DD + col;
            size_t m1 = m0 + (size_t)8 * DD;
            *(__half2*)&AOh[m0] = __halves2half2(__float2half_rn(acc[mi][ni][0]),
                                                 __float2half_rn(acc[mi][ni][1]));
            *(__half2*)&AOh[m1] = __halves2half2(__float2half_rn(acc[mi][ni][2]),
                                                 __float2half_rn(acc[mi][ni][3]));
        }
    }
}

// ---------------------------------------------------------------------------
// prep_hidden: hidden -> hh (fp16 hi) + qh (roped+scaled Q, fp16 hi)
// ---------------------------------------------------------------------------
__global__ void prep_hidden(const float* __restrict__ src,
                            __half* __restrict__ hh, __half* __restrict__ qh,
                            const float* __restrict__ cosp, const float* __restrict__ sinp,
                            float scale)
{
    int idx = blockIdx.x * blockDim.x + threadIdx.x;
    const int total = BB * SS * HH * (HD / 2);
    if (idx >= total) return;
    int d  = idx & 63;
    int h  = (idx >> 6) & (HH - 1);
    int bs = idx >> 11;
    size_t base = (size_t)bs * DD + (h << 7);
    size_t cbase = (size_t)bs * HD;
    float c0 = cosp[cbase + d],      s0 = sinp[cbase + d];
    float c1 = cosp[cbase + d + 64], s1 = sinp[cbase + d + 64];
    float x0 = src[base + d], x1 = src[base + d + 64];
    hh[base + d]      = __float2half_rn(x0);
    hh[base + d + 64] = __float2half_rn(x1);
    float y0 = (x0 * c0 - x1 * s0) * scale;
    float y1 = (x1 * c1 + x0 * s1) * scale;
    qh[base + d]      = __float2half_rn(y0);
    qh[base + d + 64] = __float2half_rn(y1);
}

// fp32 -> fp16 hi, 3 weight tensors in one launch (blockIdx.y selects)
__global__ void conv_hi3(const float* __restrict__ x0, __half* __restrict__ h0,
                         const float* __restrict__ x1, __half* __restrict__ h1,
                         const float* __restrict__ x2, __half* __restrict__ h2)
{
    size_t i = (size_t)blockIdx.x * blockDim.x + threadIdx.x;
    if (i >= NELT / 4) return;
    const float* x = (blockIdx.y == 0) ? x0 : (blockIdx.y == 1) ? x1 : x2;
    __half* hi = (blockIdx.y == 0) ? h0 : (blockIdx.y == 1) ? h1 : h2;
    float4 v = ((const float4*)x)[i];
    ((__half2*)hi)[i * 2]     = __halves2half2(__float2half_rn(v.x), __float2half_rn(v.y));
    ((__half2*)hi)[i * 2 + 1] = __halves2half2(__float2half_rn(v.z), __float2half_rn(v.w));
}

// ---------------------------------------------------------------------------
// Causal softmax + fp16 emission. Reads/writes only the causal region
// (cols >= kend already zeroed by score's masked blocks).
// ---------------------------------------------------------------------------
__global__ __launch_bounds__(256) void softmax_pconv_kernel(
    float* __restrict__ P, __half* __restrict__ Ph)
{
    size_t row = blockIdx.x;
    int q = (int)(row & (SS - 1));
    int kend = ((q >> 7) + 1) << 7;
    float4* p4 = (float4*)(P + row * (size_t)SS);
    __half* ph = Ph + row * (size_t)SS;
    int t = threadIdx.x;

    float v[8];
    {
        float4 va = p4[t];
        int oa = t << 2;
        v[0] = (oa     <= q) ? va.x : -3.4e38f;
        v[1] = (oa + 1 <= q) ? va.y : -3.4e38f;
        v[2] = (oa + 2 <= q) ? va.z : -3.4e38f;
        v[3] = (oa + 3 <= q) ? va.w : -3.4e38f;
        if (kend > 1024) {
            float4 vb = p4[t + 256];
            int ob = 1024 + (t << 2);
            v[4] = (ob     <= q) ? vb.x : -3.4e38f;
            v[5] = (ob + 1 <= q) ? vb.y : -3.4e38f;
            v[6] = (ob + 2 <= q) ? vb.z : -3.4e38f;
            v[7] = (ob + 3 <= q) ? vb.w : -3.4e38f;
        } else {
            v[4] = v[5] = v[6] = v[7] = -3.4e38f;
        }
    }
    float mx = v[0];
#pragma unroll
    for (int i = 1; i < 8; i++) mx = fmaxf(mx, v[i]);
#pragma unroll
    for (int o = 16; o; o >>= 1) mx = fmaxf(mx, __shfl_xor_sync(0xffffffffu, mx, o));
    __shared__ float rmax[8], rsum[8];
    if ((t & 31) == 0) rmax[t >> 5] = mx;
    __syncthreads();
    mx = rmax[0];
#pragma unroll
    for (int i = 1; i < 8; i++) mx = fmaxf(mx, rmax[i]);
    float sum = 0.f;
#pragma unroll
    for (int i = 0; i < 8; i++) {
        v[i] = (v[i] > -3.3e38f) ? __expf(v[i] - mx) : 0.f;
        sum += v[i];
    }
#pragma unroll
    for (int o = 16; o; o >>= 1) sum += __shfl_xor_sync(0xffffffffu, sum, o);
    if ((t & 31) == 0) rsum[t >> 5] = sum;
    __syncthreads();
    sum = rsum[0];
#pragma unroll
    for (int i = 1; i < 8; i++) sum += rsum[i];
    float inv = 1.0f / sum;
#pragma unroll
    for (int i = 0; i < 8; i++) v[i] *= inv;

    {
        int oa = t << 2;
        if (oa < kend) {
            p4[t] = make_float4(v[0], v[1], v[2], v[3]);
            *(__half2*)&ph[oa]     = __halves2half2(__float2half_rn(v[0]), __float2half_rn(v[1]));
            *(__half2*)&ph[oa + 2] = __halves2half2(__float2half_rn(v[2]), __float2half_rn(v[3]));
        }
        int ob = 1024 + (t << 2);
        if (ob < kend) {
            p4[t + 256] = make_float4(v[4], v[5], v[6], v[7]);
            *(__half2*)&ph[ob]     = __halves2half2(__float2half_rn(v[4]), __float2half_rn(v[5]));
            *(__half2*)&ph[ob + 2] = __halves2half2(__float2half_rn(v[6]), __float2half_rn(v[7]));
        }
    }
}

// ---------------------------------------------------------------------------
extern "C" void kernel_launch(void* const* d_in, const int* in_sizes, int n_in,
                              void* d_out, int out_size)
{
    (void)in_sizes; (void)n_in; (void)out_size;
    const float* hidden = (const float*)d_in[0];
    const float* Wqk    = (const float*)d_in[1];
    const float* bqk    = (const float*)d_in[2];
    const float* Wv     = (const float*)d_in[3];
    const float* bv     = (const float*)d_in[4];
    const float* Wo     = (const float*)d_in[5];
    const float* cosp   = (const float*)d_in[6];
    const float* sinp   = (const float*)d_in[7];

    float* out   = (float*)d_out;
    float* attnw = out + (size_t)BB * SS * DD;

    __half *hh, *qkh, *vh, *oh, *qh, *kh, *vth, *aoh, *ph;
    cudaGetSymbolAddress((void**)&hh,  g_hh);
    cudaGetSymbolAddress((void**)&qkh, g_qkh);
    cudaGetSymbolAddress((void**)&vh,  g_vh);
    cudaGetSymbolAddress((void**)&oh,  g_oh);
    cudaGetSymbolAddress((void**)&qh,  g_qh);
    cudaGetSymbolAddress((void**)&kh,  g_kh);
    cudaGetSymbolAddress((void**)&vth, g_vth);
    cudaGetSymbolAddress((void**)&aoh, g_aoh);
    cudaGetSymbolAddress((void**)&ph,  g_ph);

    cudaFuncSetAttribute(gemm1_tc<0>, cudaFuncAttributeMaxDynamicSharedMemorySize, SMEM_P);
    cudaFuncSetAttribute(gemm1_tc<1>, cudaFuncAttributeMaxDynamicSharedMemorySize, SMEM_P);
    cudaFuncSetAttribute(gemm1_tc<2>, cudaFuncAttributeMaxDynamicSharedMemorySize, SMEM_P);
    cudaFuncSetAttribute(score_tc,    cudaFuncAttributeMaxDynamicSharedMemorySize, SMEM_S);
    cudaFuncSetAttribute(pv_tc,       cudaFuncAttributeMaxDynamicSharedMemorySize, SMEM_P);

    const int cvblk = (int)((NELT / 4 + 255) / 256);
    const int rope_total = BB * SS * HH * (HD / 2);
    const float scale = 0.088388347648318447f;  // 128^-0.5

    prep_hidden<<<(rope_total + 255) / 256, 256>>>(hidden, hh, qh, cosp, sinp, scale);
    conv_hi3<<<dim3(cvblk, 3), 256>>>(Wqk, qkh, Wv, vh, Wo, oh);

    dim3 gg(DD / 128, (BB * SS) / 128);
    // QK projection (1-product), fused bias+RoPE -> K hi
    gemm1_tc<1><<<gg, 256, SMEM_P>>>(hh, qkh, bqk, cosp, sinp, nullptr, kh);
    // V projection (1-product), fused bias+transpose
    gemm1_tc<2><<<gg, 256, SMEM_P>>>(hh, vh, bv, nullptr, nullptr, nullptr, vth);

    score_tc<<<dim3(SS / 128, SS / 128, BB * HH), 256, SMEM_S>>>(qh, kh, attnw);
    softmax_pconv_kernel<<<BB * HH * SS, 256>>>(attnw, ph);
    pv_tc<<<dim3(SS / 128, BB * HH), 256, SMEM_P>>>(ph, vth, aoh);

    // final projection (1-product)
    gemm1_tc<0><<<gg, 256, SMEM_P>>>(aoh, oh, nullptr, nullptr, nullptr, out, nullptr);
}

// round 15
// speedup vs baseline: 7.1448x; 1.0670x over previous
#include <cuda_runtime.h>
#include <cuda_fp16.h>
#include <cstdint>
#include <cstddef>

#define BB 2
#define SS 2048
#define DD 4096
#define HH 32
#define HD 128
#define NEG_INF -1000000000.0f

#define NELT ((size_t)BB * SS * DD)          // 16,777,216
#define NP   ((size_t)BB * HH * SS * SS)     // 268,435,456

// ---------------- scratch (device globals; alloc APIs forbidden) ----------
__device__ __half g_hh[NELT];                 // hidden hi
__device__ __half g_qkh[NELT];                // Wqk hi
__device__ __half g_vh[NELT];                 // Wv hi
__device__ __half g_oh[NELT];                 // Wo hi
__device__ __half g_qh[NELT];                 // roped Q hi (b,s,h,hd)
__device__ __half g_kh[NELT];                 // roped K hi (b,s,h,hd)
__device__ __half g_vth[NELT];                // V^T hi (b,h,d,k)
__device__ __half g_aoh[NELT];                // attn-out gathered fp16
__device__ __half g_ph[NP];                   // softmax P fp16

// ---------------- helpers ---------------------------------------------------
__device__ __forceinline__ uint32_t smem_u32(const void* p) {
    uint32_t a;
    asm("{ .reg .u64 t; cvta.to.shared.u64 t, %1; cvt.u32.u64 %0, t; }" : "=r"(a) : "l"(p));
    return a;
}
__device__ __forceinline__ void cp_async16(uint32_t dst, const void* src) {
    asm volatile("cp.async.cg.shared.global [%0], [%1], 16;" :: "r"(dst), "l"(src));
}
#define CP_COMMIT() asm volatile("cp.async.commit_group;" ::: "memory")
#define CP_WAIT0()  asm volatile("cp.async.wait_group 0;" ::: "memory")
#define CP_WAIT1()  asm volatile("cp.async.wait_group 1;" ::: "memory")

__device__ __forceinline__ void ldmx4(uint32_t* r, uint32_t addr) {
    asm volatile("ldmatrix.sync.aligned.m8n8.x4.shared.b16 {%0,%1,%2,%3}, [%4];"
                 : "=r"(r[0]), "=r"(r[1]), "=r"(r[2]), "=r"(r[3]) : "r"(addr));
}
__device__ __forceinline__ void mma16816(float* d, const uint32_t* a, const uint32_t* b) {
    asm volatile(
        "mma.sync.aligned.m16n8k16.row.col.f32.f16.f16.f32 "
        "{%0,%1,%2,%3}, {%4,%5,%6,%7}, {%8,%9}, {%0,%1,%2,%3};"
        : "+f"(d[0]), "+f"(d[1]), "+f"(d[2]), "+f"(d[3])
        : "r"(a[0]), "r"(a[1]), "r"(a[2]), "r"(a[3]), "r"(b[0]), "r"(b[1]));
}

// ---- BK=64 tiles ------------------------------------------------------------
#define TILE64 16384                    // 128 rows x 128B (64 fp16)
#define STG (2 * TILE64)                // 2 tiles (A, B) per stage = 32KB
#define NST 3
#define SMEM_P (NST * STG)              // 98304 (gemm / pv)
#define SMEM_S (2 * STG)                // 65536 (score: HD fits in 2 stages)

// swizzled byte offset within a 128x64-fp16 tile (128B rows); chunk 0..7
__device__ __forceinline__ uint32_t sw64(int r, int chunk) {
    return (uint32_t)(r << 7) + (((chunk ^ (r & 7)) << 4));
}

// ---- 1-product K=16 MMA step within a BK=64 stage; ks in 0..3 ---------------
__device__ __forceinline__ void hmma64(
    uint32_t sb, int ks, int wm, int wn, int lr, int lc, float (&acc)[4][4][4])
{
    const int chunk = ks * 2 + lc;
    uint32_t bh[4][2];
#pragma unroll
    for (int g = 0; g < 2; g++) {
        int r = wn + g * 16 + lr;
        uint32_t rb[4];
        ldmx4(rb, sb + TILE64 + sw64(r, chunk));
        bh[g*2+0][0] = rb[0]; bh[g*2+0][1] = rb[2];
        bh[g*2+1][0] = rb[1]; bh[g*2+1][1] = rb[3];
    }
#pragma unroll
    for (int mi = 0; mi < 4; mi++) {
        int r = wm + mi * 16 + lr;
        uint32_t ah[4];
        ldmx4(ah, sb + sw64(r, chunk));
#pragma unroll
        for (int ni = 0; ni < 4; ni++)
            mma16816(acc[mi][ni], ah, bh[ni]);
    }
}

// stage loader: 2 tiles of 128x64 fp16, 2048 cp.async over 256 threads
__device__ __forceinline__ void load_stage64(
    uint32_t db, const __half* base0, const __half* base1, int ld, int kc, int t)
{
#pragma unroll
    for (int i = 0; i < 8; i++) {
        int idx = t + (i << 8);              // 0..2047
        int tile = idx >> 10;                // 0..1
        int w = idx & 1023;
        int r = w >> 3, c = w & 7;
        const __half* src = (tile == 0 ? base0 : base1)
                            + (size_t)r * ld + kc + (c << 3);
        cp_async16(db + tile * TILE64 + sw64(r, c), src);
    }
    CP_COMMIT();
}

// ---------------------------------------------------------------------------
// gemm1_tc: fp16 1-product GEMM over K=4096. BK=64, 3-stage, one barrier/iter.
//  MODE 0: fp32 out (final projection, no bias)
//  MODE 1: QK projection -> +bias -> RoPE -> fp16 hi (O1)
//  MODE 2: V projection  -> +bias -> transpose to (b,h,d,s) fp16 hi (O1)
// ---------------------------------------------------------------------------
template<int MODE>
__global__ __launch_bounds__(256, 2) void gemm1_tc(
    const __half* __restrict__ Ah, const __half* __restrict__ Bh,
    const float* __restrict__ bias,
    const float* __restrict__ cosp, const float* __restrict__ sinp,
    float* __restrict__ C, __half* __restrict__ O1)
{
    extern __shared__ char smem[];
    const uint32_t sbase = smem_u32(smem);
    const int t = threadIdx.x;
    const int wid = t >> 5, lane = t & 31;
    const int bm = blockIdx.y << 7, bn = blockIdx.x << 7;

    const __half* base0 = Ah + (size_t)bm * DD;
    const __half* base1 = Bh + (size_t)bn * DD;

    load_stage64(sbase,       base0, base1, DD, 0,  t);
    load_stage64(sbase + STG, base0, base1, DD, 64, t);

    const int wm = (wid & 1) << 6;
    const int wn = (wid >> 1) << 5;
    const int lr = lane & 15, lc = lane >> 4;
    float acc[4][4][4] = {};
    const int iters = DD / 64;     // 64

    for (int it = 0; it < iters; it++) {
        int stg = it % NST;
        CP_WAIT1();
        __syncthreads();
        uint32_t sb = sbase + stg * STG;
        hmma64(sb, 0, wm, wn, lr, lc, acc);
        hmma64(sb, 1, wm, wn, lr, lc, acc);
        hmma64(sb, 2, wm, wn, lr, lc, acc);
        hmma64(sb, 3, wm, wn, lr, lc, acc);
        int nx = it + 2;
        if (nx < iters) load_stage64(sbase + (nx % NST) * STG, base0, base1, DD, nx * 64, t);
        else CP_COMMIT();
    }

    const int qr = lane >> 2, qc = (lane & 3) << 1;

    if (MODE == 0) {
#pragma unroll
        for (int mi = 0; mi < 4; mi++) {
#pragma unroll
            for (int ni = 0; ni < 4; ni++) {
                int col = bn + wn + ni * 8 + qc;
                int row0 = bm + wm + mi * 16 + qr;
                float2 v0 = { acc[mi][ni][0], acc[mi][ni][1] };
                float2 v1 = { acc[mi][ni][2], acc[mi][ni][3] };
                *(float2*)&C[(size_t)row0 * DD + col] = v0;
                *(float2*)&C[(size_t)(row0 + 8) * DD + col] = v1;
            }
        }
        return;
    }

    // stage acc (+bias) into padded fp32 smem tile
    __syncthreads();
    const int PAD = (MODE == 1) ? 132 : 133;
    float* eps = (float*)smem;
#pragma unroll
    for (int mi = 0; mi < 4; mi++) {
#pragma unroll
        for (int ni = 0; ni < 4; ni++) {
            int cl = wn + ni * 8 + qc;
            float b0 = bias[bn + cl];
            float b1 = bias[bn + cl + 1];
            int r0 = wm + mi * 16 + qr;
            eps[r0 * PAD + cl]           = acc[mi][ni][0] + b0;
            eps[r0 * PAD + cl + 1]       = acc[mi][ni][1] + b1;
            eps[(r0 + 8) * PAD + cl]     = acc[mi][ni][2] + b0;
            eps[(r0 + 8) * PAD + cl + 1] = acc[mi][ni][3] + b1;
        }
    }
    __syncthreads();

    if (MODE == 1) {
        // RoPE within the head tile (N-tile == one head): pairs (d, d+64)
#pragma unroll
        for (int q8 = 0; q8 < 32; q8++) {
            int idx = t + (q8 << 8);          // 0..8191
            int d = idx & 63, r = idx >> 6;
            int m = bm + r;
            size_t cb = (size_t)m * HD;
            float c0 = cosp[cb + d],      s0 = sinp[cb + d];
            float c1 = cosp[cb + d + 64], s1 = sinp[cb + d + 64];
            float x0 = eps[r * 132 + d], x1 = eps[r * 132 + d + 64];
            float y0 = x0 * c0 - x1 * s0;
            float y1 = x1 * c1 + x0 * s1;
            size_t o = (size_t)m * DD + bn + d;
            O1[o]      = __float2half_rn(y0);
            O1[o + 64] = __float2half_rn(y1);
        }
    } else {
        // MODE 2: transpose tile (s x d) -> Vt (b,h,d,s) fp16 hi
        int bh = ((bm >> 11) << 5) + (bn >> 7);
        int sbase_g = bm & (SS - 1);
#pragma unroll
        for (int q8 = 0; q8 < 16; q8++) {
            int qi = t + (q8 << 8);           // 0..4095 quads
            int d = qi >> 5;
            int sq = (qi & 31) << 2;
            float f0 = eps[(sq + 0) * 133 + d];
            float f1 = eps[(sq + 1) * 133 + d];
            float f2 = eps[(sq + 2) * 133 + d];
            float f3 = eps[(sq + 3) * 133 + d];
            size_t o = ((size_t)bh * HD + d) * SS + sbase_g + sq;
            *(__half2*)&O1[o]     = __halves2half2(__float2half_rn(f0), __float2half_rn(f1));
            *(__half2*)&O1[o + 2] = __halves2half2(__float2half_rn(f2), __float2half_rn(f3));
        }
    }
}

// ---------------------------------------------------------------------------
// score_tc: P = Qh.Kh (fp16 1-product), causal. HD=128 fully preloaded:
// one wait + one barrier, then 8 uninterrupted MMA chunks.
// Above-diagonal tiles write fp32 zeros; softmax writes only causal region.
// ---------------------------------------------------------------------------
__global__ __launch_bounds__(256, 2) void score_tc(
    const __half* __restrict__ Qh, const __half* __restrict__ Kh,
    float* __restrict__ P)
{
    extern __shared__ char smem[];
    const int q0 = blockIdx.y << 7, k0 = blockIdx.x << 7;
    const int bh = blockIdx.z;
    const size_t pbase = ((size_t)bh * SS + q0) * SS + k0;
    const int t = threadIdx.x;

    if (k0 > q0) {                 // fully-masked tile -> exact zeros
        const float4 z = { 0.f, 0.f, 0.f, 0.f };
#pragma unroll
        for (int q8 = 0; q8 < 16; q8++) {
            int i = t + (q8 << 8);
            int r = i >> 5, c4 = (i & 31) << 2;
            *(float4*)&P[pbase + (size_t)r * SS + c4] = z;
        }
        return;
    }

    const int b = bh >> 5, h = bh & 31;
    const uint32_t sbase = smem_u32(smem);
    const int wid = t >> 5, lane = t & 31;

    const __half* base0 = Qh + (size_t)(b * SS + q0) * DD + (h << 7);
    const __half* base1 = Kh + (size_t)(b * SS + k0) * DD + (h << 7);

    load_stage64(sbase,       base0, base1, DD, 0,  t);
    load_stage64(sbase + STG, base0, base1, DD, 64, t);
    CP_WAIT0();
    __syncthreads();

    const int wm = (wid & 1) << 6;
    const int wn = (wid >> 1) << 5;
    const int lr = lane & 15, lc = lane >> 4;
    float acc[4][4][4] = {};

#pragma unroll
    for (int st = 0; st < 2; st++) {
        uint32_t sb = sbase + st * STG;
        hmma64(sb, 0, wm, wn, lr, lc, acc);
        hmma64(sb, 1, wm, wn, lr, lc, acc);
        hmma64(sb, 2, wm, wn, lr, lc, acc);
        hmma64(sb, 3, wm, wn, lr, lc, acc);
    }

    const int qr = lane >> 2, qc = (lane & 3) << 1;
#pragma unroll
    for (int mi = 0; mi < 4; mi++) {
#pragma unroll
        for (int ni = 0; ni < 4; ni++) {
            int rl = wm + mi * 16 + qr;
            int cl = wn + ni * 8 + qc;
            int k = k0 + cl;
            int qA = q0 + rl, qB = qA + 8;
            float2 v0 = { (k <= qA) ? acc[mi][ni][0] : NEG_INF,
                          (k + 1 <= qA) ? acc[mi][ni][1] : NEG_INF };
            float2 v1 = { (k <= qB) ? acc[mi][ni][2] : NEG_INF,
                          (k + 1 <= qB) ? acc[mi][ni][3] : NEG_INF };
            *(float2*)&P[pbase + (size_t)rl * SS + cl] = v0;
            *(float2*)&P[pbase + (size_t)(rl + 8) * SS + cl] = v1;
        }
    }
}

// ---------------------------------------------------------------------------
// pv_tc: AO = P @ V^T (fp16 1-product), causal k-bound. BK=64, 3-stage.
// ---------------------------------------------------------------------------
__global__ __launch_bounds__(256, 2) void pv_tc(
    const __half* __restrict__ Ph,
    const __half* __restrict__ Vth,
    __half* __restrict__ AOh)
{
    extern __shared__ char smem[];
    const uint32_t sbase = smem_u32(smem);
    const int t = threadIdx.x;
    const int wid = t >> 5, lane = t & 31;
    const int q0 = blockIdx.x << 7;
    const int bh = blockIdx.y;
    const int b = bh >> 5, h = bh & 31;

    const __half* base0 = Ph  + ((size_t)bh * SS + q0) * SS;
    const __half* base1 = Vth + (size_t)bh * HD * SS;

    const int iters = (q0 >> 6) + 2;   // kend/64, kend = q0+128

    load_stage64(sbase,       base0, base1, SS, 0,  t);
    load_stage64(sbase + STG, base0, base1, SS, 64, t);

    const int wm = (wid & 1) << 6;
    const int wn = (wid >> 1) << 5;
    const int lr = lane & 15, lc = lane >> 4;
    float acc[4][4][4] = {};

    for (int it = 0; it < iters; it++) {
        int stg = it % NST;
        CP_WAIT1();
        __syncthreads();
        uint32_t sb = sbase + stg * STG;
        hmma64(sb, 0, wm, wn, lr, lc, acc);
        hmma64(sb, 1, wm, wn, lr, lc, acc);
        hmma64(sb, 2, wm, wn, lr, lc, acc);
        hmma64(sb, 3, wm, wn, lr, lc, acc);
        int nx = it + 2;
        if (nx < iters) load_stage64(sbase + (nx % NST) * STG, base0, base1, SS, nx * 64, t);
        else CP_COMMIT();
    }

    const int qr = lane >> 2, qc = (lane & 3) << 1;
#pragma unroll
    for (int mi = 0; mi < 4; mi++) {
#pragma unroll
        for (int ni = 0; ni < 4; ni++) {
            int row = q0 + wm + mi * 16 + qr;
            int col = (h << 7) + wn + ni * 8 + qc;
            size_t m0 = ((size_t)b * SS + row) * DD + col;
            size_t m1 = m0 + (size_t)8 * DD;
            *(__half2*)&AOh[m0] = __halves2half2(__float2half_rn(acc[mi][ni][0]),
                                                 __float2half_rn(acc[mi][ni][1]));
            *(__half2*)&AOh[m1] = __halves2half2(__float2half_rn(acc[mi][ni][2]),
                                                 __float2half_rn(acc[mi][ni][3]));
        }
    }
}

// ---------------------------------------------------------------------------
// prep_hidden: hidden -> hh (fp16 hi) + qh (roped+scaled Q, fp16 hi)
// ---------------------------------------------------------------------------
__global__ void prep_hidden(const float* __restrict__ src,
                            __half* __restrict__ hh, __half* __restrict__ qh,
                            const float* __restrict__ cosp, const float* __restrict__ sinp,
                            float scale)
{
    int idx = blockIdx.x * blockDim.x + threadIdx.x;
    const int total = BB * SS * HH * (HD / 2);
    if (idx >= total) return;
    int d  = idx & 63;
    int h  = (idx >> 6) & (HH - 1);
    int bs = idx >> 11;
    size_t base = (size_t)bs * DD + (h << 7);
    size_t cbase = (size_t)bs * HD;
    float c0 = cosp[cbase + d],      s0 = sinp[cbase + d];
    float c1 = cosp[cbase + d + 64], s1 = sinp[cbase + d + 64];
    float x0 = src[base + d], x1 = src[base + d + 64];
    hh[base + d]      = __float2half_rn(x0);
    hh[base + d + 64] = __float2half_rn(x1);
    float y0 = (x0 * c0 - x1 * s0) * scale;
    float y1 = (x1 * c1 + x0 * s1) * scale;
    qh[base + d]      = __float2half_rn(y0);
    qh[base + d + 64] = __float2half_rn(y1);
}

// fp32 -> fp16 hi, 3 weight tensors in one launch (blockIdx.y selects)
__global__ void conv_hi3(const float* __restrict__ x0, __half* __restrict__ h0,
                         const float* __restrict__ x1, __half* __restrict__ h1,
                         const float* __restrict__ x2, __half* __restrict__ h2)
{
    size_t i = (size_t)blockIdx.x * blockDim.x + threadIdx.x;
    if (i >= NELT / 4) return;
    const float* x = (blockIdx.y == 0) ? x0 : (blockIdx.y == 1) ? x1 : x2;
    __half* hi = (blockIdx.y == 0) ? h0 : (blockIdx.y == 1) ? h1 : h2;
    float4 v = ((const float4*)x)[i];
    ((__half2*)hi)[i * 2]     = __halves2half2(__float2half_rn(v.x), __float2half_rn(v.y));
    ((__half2*)hi)[i * 2 + 1] = __halves2half2(__float2half_rn(v.z), __float2half_rn(v.w));
}

// ---------------------------------------------------------------------------
// Causal softmax + fp16 emission. Reads/writes only the causal region
// (cols >= kend already zeroed by score's masked blocks).
// ---------------------------------------------------------------------------
__global__ __launch_bounds__(256) void softmax_pconv_kernel(
    float* __restrict__ P, __half* __restrict__ Ph)
{
    size_t row = blockIdx.x;
    int q = (int)(row & (SS - 1));
    int kend = ((q >> 7) + 1) << 7;
    float4* p4 = (float4*)(P + row * (size_t)SS);
    __half* ph = Ph + row * (size_t)SS;
    int t = threadIdx.x;

    float v[8];
    {
        float4 va = p4[t];
        int oa = t << 2;
        v[0] = (oa     <= q) ? va.x : -3.4e38f;
        v[1] = (oa + 1 <= q) ? va.y : -3.4e38f;
        v[2] = (oa + 2 <= q) ? va.z : -3.4e38f;
        v[3] = (oa + 3 <= q) ? va.w : -3.4e38f;
        if (kend > 1024) {
            float4 vb = p4[t + 256];
            int ob = 1024 + (t << 2);
            v[4] = (ob     <= q) ? vb.x : -3.4e38f;
            v[5] = (ob + 1 <= q) ? vb.y : -3.4e38f;
            v[6] = (ob + 2 <= q) ? vb.z : -3.4e38f;
            v[7] = (ob + 3 <= q) ? vb.w : -3.4e38f;
        } else {
            v[4] = v[5] = v[6] = v[7] = -3.4e38f;
        }
    }
    float mx = v[0];
#pragma unroll
    for (int i = 1; i < 8; i++) mx = fmaxf(mx, v[i]);
#pragma unroll
    for (int o = 16; o; o >>= 1) mx = fmaxf(mx, __shfl_xor_sync(0xffffffffu, mx, o));
    __shared__ float rmax[8], rsum[8];
    if ((t & 31) == 0) rmax[t >> 5] = mx;
    __syncthreads();
    mx = rmax[0];
#pragma unroll
    for (int i = 1; i < 8; i++) mx = fmaxf(mx, rmax[i]);
    float sum = 0.f;
#pragma unroll
    for (int i = 0; i < 8; i++) {
        v[i] = (v[i] > -3.3e38f) ? __expf(v[i] - mx) : 0.f;
        sum += v[i];
    }
#pragma unroll
    for (int o = 16; o; o >>= 1) sum += __shfl_xor_sync(0xffffffffu, sum, o);
    if ((t & 31) == 0) rsum[t >> 5] = sum;
    __syncthreads();
    sum = rsum[0];
#pragma unroll
    for (int i = 1; i < 8; i++) sum += rsum[i];
    float inv = 1.0f / sum;
#pragma unroll
    for (int i = 0; i < 8; i++) v[i] *= inv;

    {
        int oa = t << 2;
        if (oa < kend) {
            p4[t] = make_float4(v[0], v[1], v[2], v[3]);
            *(__half2*)&ph[oa]     = __halves2half2(__float2half_rn(v[0]), __float2half_rn(v[1]));
            *(__half2*)&ph[oa + 2] = __halves2half2(__float2half_rn(v[2]), __float2half_rn(v[3]));
        }
        int ob = 1024 + (t << 2);
        if (ob < kend) {
            p4[t + 256] = make_float4(v[4], v[5], v[6], v[7]);
            *(__half2*)&ph[ob]     = __halves2half2(__float2half_rn(v[4]), __float2half_rn(v[5]));
            *(__half2*)&ph[ob + 2] = __halves2half2(__float2half_rn(v[6]), __float2half_rn(v[7]));
        }
    }
}

// ---------------------------------------------------------------------------
extern "C" void kernel_launch(void* const* d_in, const int* in_sizes, int n_in,
                              void* d_out, int out_size)
{
    (void)in_sizes; (void)n_in; (void)out_size;
    const float* hidden = (const float*)d_in[0];
    const float* Wqk    = (const float*)d_in[1];
    const float* bqk    = (const float*)d_in[2];
    const float* Wv     = (const float*)d_in[3];
    const float* bv     = (const float*)d_in[4];
    const float* Wo     = (const float*)d_in[5];
    const float* cosp   = (const float*)d_in[6];
    const float* sinp   = (const float*)d_in[7];

    float* out   = (float*)d_out;
    float* attnw = out + (size_t)BB * SS * DD;

    __half *hh, *qkh, *vh, *oh, *qh, *kh, *vth, *aoh, *ph;
    cudaGetSymbolAddress((void**)&hh,  g_hh);
    cudaGetSymbolAddress((void**)&qkh, g_qkh);
    cudaGetSymbolAddress((void**)&vh,  g_vh);
    cudaGetSymbolAddress((void**)&oh,  g_oh);
    cudaGetSymbolAddress((void**)&qh,  g_qh);
    cudaGetSymbolAddress((void**)&kh,  g_kh);
    cudaGetSymbolAddress((void**)&vth, g_vth);
    cudaGetSymbolAddress((void**)&aoh, g_aoh);
    cudaGetSymbolAddress((void**)&ph,  g_ph);

    cudaFuncSetAttribute(gemm1_tc<0>, cudaFuncAttributeMaxDynamicSharedMemorySize, SMEM_P);
    cudaFuncSetAttribute(gemm1_tc<1>, cudaFuncAttributeMaxDynamicSharedMemorySize, SMEM_P);
    cudaFuncSetAttribute(gemm1_tc<2>, cudaFuncAttributeMaxDynamicSharedMemorySize, SMEM_P);
    cudaFuncSetAttribute(score_tc,    cudaFuncAttributeMaxDynamicSharedMemorySize, SMEM_S);
    cudaFuncSetAttribute(pv_tc,       cudaFuncAttributeMaxDynamicSharedMemorySize, SMEM_P);

    const int cvblk = (int)((NELT / 4 + 255) / 256);
    const int rope_total = BB * SS * HH * (HD / 2);
    const float scale = 0.088388347648318447f;  // 128^-0.5

    prep_hidden<<<(rope_total + 255) / 256, 256>>>(hidden, hh, qh, cosp, sinp, scale);
    conv_hi3<<<dim3(cvblk, 3), 256>>>(Wqk, qkh, Wv, vh, Wo, oh);

    dim3 gg(DD / 128, (BB * SS) / 128);
    // QK projection (1-product), fused bias+RoPE -> K hi
    gemm1_tc<1><<<gg, 256, SMEM_P>>>(hh, qkh, bqk, cosp, sinp, nullptr, kh);
    // V projection (1-product), fused bias+transpose
    gemm1_tc<2><<<gg, 256, SMEM_P>>>(hh, vh, bv, nullptr, nullptr, nullptr, vth);

    score_tc<<<dim3(SS / 128, SS / 128, BB * HH), 256, SMEM_S>>>(qh, kh, attnw);
    softmax_pconv_kernel<<<BB * HH * SS, 256>>>(attnw, ph);
    pv_tc<<<dim3(SS / 128, BB * HH), 256, SMEM_P>>>(ph, vth, aoh);

    // final projection (1-product)
    gemm1_tc<0><<<gg, 256, SMEM_P>>>(aoh, oh, nullptr, nullptr, nullptr, out, nullptr);
}

// round 16
// speedup vs baseline: 7.2484x; 1.0145x over previous
#include <cuda_runtime.h>
#include <cuda_fp16.h>
#include <cstdint>
#include <cstddef>

#define BB 2
#define SS 2048
#define DD 4096
#define HH 32
#define HD 128
#define NEG_INF -1000000000.0f

#define NELT ((size_t)BB * SS * DD)          // 16,777,216
#define NP   ((size_t)BB * HH * SS * SS)     // 268,435,456

// ---------------- scratch (device globals; alloc APIs forbidden) ----------
__device__ __half g_hh[NELT];                 // hidden hi
__device__ __half g_qkh[NELT];                // Wqk hi
__device__ __half g_vh[NELT];                 // Wv hi
__device__ __half g_oh[NELT];                 // Wo hi
__device__ __half g_qh[NELT];                 // roped Q hi (b,s,h,hd)
__device__ __half g_kh[NELT];                 // roped K hi (b,s,h,hd)
__device__ __half g_vth[NELT];                // V^T hi (b,h,d,k)
__device__ __half g_aoh[NELT];                // attn-out gathered fp16
__device__ __half g_ph[NP];                   // softmax P fp16

// ---------------- helpers ---------------------------------------------------
__device__ __forceinline__ uint32_t smem_u32(const void* p) {
    uint32_t a;
    asm("{ .reg .u64 t; cvta.to.shared.u64 t, %1; cvt.u32.u64 %0, t; }" : "=r"(a) : "l"(p));
    return a;
}
__device__ __forceinline__ void cp_async16(uint32_t dst, const void* src) {
    asm volatile("cp.async.cg.shared.global [%0], [%1], 16;" :: "r"(dst), "l"(src));
}
#define CP_COMMIT() asm volatile("cp.async.commit_group;" ::: "memory")
#define CP_WAIT0()  asm volatile("cp.async.wait_group 0;" ::: "memory")
#define CP_WAIT1()  asm volatile("cp.async.wait_group 1;" ::: "memory")

__device__ __forceinline__ void ldmx4(uint32_t* r, uint32_t addr) {
    asm volatile("ldmatrix.sync.aligned.m8n8.x4.shared.b16 {%0,%1,%2,%3}, [%4];"
                 : "=r"(r[0]), "=r"(r[1]), "=r"(r[2]), "=r"(r[3]) : "r"(addr));
}
__device__ __forceinline__ void mma16816(float* d, const uint32_t* a, const uint32_t* b) {
    asm volatile(
        "mma.sync.aligned.m16n8k16.row.col.f32.f16.f16.f32 "
        "{%0,%1,%2,%3}, {%4,%5,%6,%7}, {%8,%9}, {%0,%1,%2,%3};"
        : "+f"(d[0]), "+f"(d[1]), "+f"(d[2]), "+f"(d[3])
        : "r"(a[0]), "r"(a[1]), "r"(a[2]), "r"(a[3]), "r"(b[0]), "r"(b[1]));
}

// ---- BK=64 tiles ------------------------------------------------------------
#define TILE64 16384                    // 128 rows x 128B (64 fp16)
#define STG (2 * TILE64)                // 2 tiles (A, B) per stage = 32KB
#define NST 3
#define SMEM_P (NST * STG)              // 98304 (gemm / pv)
#define SMEM_S (2 * STG)                // 65536 (score: HD fits in 2 stages)

// swizzled byte offset within a 128x64-fp16 tile (128B rows); chunk 0..7
__device__ __forceinline__ uint32_t sw64(int r, int chunk) {
    return (uint32_t)(r << 7) + (((chunk ^ (r & 7)) << 4));
}

// ---- 1-product K=16 MMA step within a BK=64 stage; ks in 0..3 ---------------
__device__ __forceinline__ void hmma64(
    uint32_t sb, int ks, int wm, int wn, int lr, int lc, float (&acc)[4][4][4])
{
    const int chunk = ks * 2 + lc;
    uint32_t bh[4][2];
#pragma unroll
    for (int g = 0; g < 2; g++) {
        int r = wn + g * 16 + lr;
        uint32_t rb[4];
        ldmx4(rb, sb + TILE64 + sw64(r, chunk));
        bh[g*2+0][0] = rb[0]; bh[g*2+0][1] = rb[2];
        bh[g*2+1][0] = rb[1]; bh[g*2+1][1] = rb[3];
    }
#pragma unroll
    for (int mi = 0; mi < 4; mi++) {
        int r = wm + mi * 16 + lr;
        uint32_t ah[4];
        ldmx4(ah, sb + sw64(r, chunk));
#pragma unroll
        for (int ni = 0; ni < 4; ni++)
            mma16816(acc[mi][ni], ah, bh[ni]);
    }
}

// stage loader: 2 tiles of 128x64 fp16, 2048 cp.async over 256 threads
__device__ __forceinline__ void load_stage64(
    uint32_t db, const __half* base0, const __half* base1, int ld, int kc, int t)
{
#pragma unroll
    for (int i = 0; i < 8; i++) {
        int idx = t + (i << 8);              // 0..2047
        int tile = idx >> 10;                // 0..1
        int w = idx & 1023;
        int r = w >> 3, c = w & 7;
        const __half* src = (tile == 0 ? base0 : base1)
                            + (size_t)r * ld + kc + (c << 3);
        cp_async16(db + tile * TILE64 + sw64(r, c), src);
    }
    CP_COMMIT();
}

// ---------------------------------------------------------------------------
// gemm_qkv_tc: fused QK + V projections (blockIdx.z selects), fp16 1-product,
// BK=64, 3-stage, one barrier/iter. z=0: bias+RoPE -> K hi. z=1: bias+transpose.
// ---------------------------------------------------------------------------
__global__ __launch_bounds__(256, 2) void gemm_qkv_tc(
    const __half* __restrict__ Ah,
    const __half* __restrict__ Wqk, const __half* __restrict__ Wv,
    const float* __restrict__ bqk, const float* __restrict__ bv,
    const float* __restrict__ cosp, const float* __restrict__ sinp,
    __half* __restrict__ Kh, __half* __restrict__ Vth)
{
    extern __shared__ char smem[];
    const uint32_t sbase = smem_u32(smem);
    const int t = threadIdx.x;
    const int wid = t >> 5, lane = t & 31;
    const int bm = blockIdx.y << 7, bn = blockIdx.x << 7;
    const int zv = blockIdx.z;               // 0 = QK, 1 = V

    const __half* base0 = Ah + (size_t)bm * DD;
    const __half* base1 = (zv ? Wv : Wqk) + (size_t)bn * DD;
    const float* bias = zv ? bv : bqk;

    load_stage64(sbase,       base0, base1, DD, 0,  t);
    load_stage64(sbase + STG, base0, base1, DD, 64, t);

    const int wm = (wid & 1) << 6;
    const int wn = (wid >> 1) << 5;
    const int lr = lane & 15, lc = lane >> 4;
    float acc[4][4][4] = {};
    const int iters = DD / 64;     // 64

    for (int it = 0; it < iters; it++) {
        int stg = it % NST;
        CP_WAIT1();
        __syncthreads();
        uint32_t sb = sbase + stg * STG;
        hmma64(sb, 0, wm, wn, lr, lc, acc);
        hmma64(sb, 1, wm, wn, lr, lc, acc);
        hmma64(sb, 2, wm, wn, lr, lc, acc);
        hmma64(sb, 3, wm, wn, lr, lc, acc);
        int nx = it + 2;
        if (nx < iters) load_stage64(sbase + (nx % NST) * STG, base0, base1, DD, nx * 64, t);
        else CP_COMMIT();
    }

    const int qr = lane >> 2, qc = (lane & 3) << 1;

    // stage acc (+bias) into padded fp32 smem tile
    __syncthreads();
    const int PAD = zv ? 133 : 132;
    float* eps = (float*)smem;
#pragma unroll
    for (int mi = 0; mi < 4; mi++) {
#pragma unroll
        for (int ni = 0; ni < 4; ni++) {
            int cl = wn + ni * 8 + qc;
            float b0 = bias[bn + cl];
            float b1 = bias[bn + cl + 1];
            int r0 = wm + mi * 16 + qr;
            eps[r0 * PAD + cl]           = acc[mi][ni][0] + b0;
            eps[r0 * PAD + cl + 1]       = acc[mi][ni][1] + b1;
            eps[(r0 + 8) * PAD + cl]     = acc[mi][ni][2] + b0;
            eps[(r0 + 8) * PAD + cl + 1] = acc[mi][ni][3] + b1;
        }
    }
    __syncthreads();

    if (!zv) {
        // RoPE within the head tile (N-tile == one head): pairs (d, d+64)
#pragma unroll
        for (int q8 = 0; q8 < 32; q8++) {
            int idx = t + (q8 << 8);          // 0..8191
            int d = idx & 63, r = idx >> 6;
            int m = bm + r;
            size_t cb = (size_t)m * HD;
            float c0 = cosp[cb + d],      s0 = sinp[cb + d];
            float c1 = cosp[cb + d + 64], s1 = sinp[cb + d + 64];
            float x0 = eps[r * 132 + d], x1 = eps[r * 132 + d + 64];
            float y0 = x0 * c0 - x1 * s0;
            float y1 = x1 * c1 + x0 * s1;
            size_t o = (size_t)m * DD + bn + d;
            Kh[o]      = __float2half_rn(y0);
            Kh[o + 64] = __float2half_rn(y1);
        }
    } else {
        // transpose tile (s x d) -> Vt (b,h,d,s) fp16 hi
        int bh = ((bm >> 11) << 5) + (bn >> 7);
        int sbase_g = bm & (SS - 1);
#pragma unroll
        for (int q8 = 0; q8 < 16; q8++) {
            int qi = t + (q8 << 8);           // 0..4095 quads
            int d = qi >> 5;
            int sq = (qi & 31) << 2;
            float f0 = eps[(sq + 0) * 133 + d];
            float f1 = eps[(sq + 1) * 133 + d];
            float f2 = eps[(sq + 2) * 133 + d];
            float f3 = eps[(sq + 3) * 133 + d];
            size_t o = ((size_t)bh * HD + d) * SS + sbase_g + sq;
            *(__half2*)&Vth[o]     = __halves2half2(__float2half_rn(f0), __float2half_rn(f1));
            *(__half2*)&Vth[o + 2] = __halves2half2(__float2half_rn(f2), __float2half_rn(f3));
        }
    }
}

// ---------------------------------------------------------------------------
// gemm1_tc: final projection, fp16 1-product, fp32 out. BK=64, 3-stage.
// ---------------------------------------------------------------------------
__global__ __launch_bounds__(256, 2) void gemm1_tc(
    const __half* __restrict__ Ah, const __half* __restrict__ Bh,
    float* __restrict__ C)
{
    extern __shared__ char smem[];
    const uint32_t sbase = smem_u32(smem);
    const int t = threadIdx.x;
    const int wid = t >> 5, lane = t & 31;
    const int bm = blockIdx.y << 7, bn = blockIdx.x << 7;

    const __half* base0 = Ah + (size_t)bm * DD;
    const __half* base1 = Bh + (size_t)bn * DD;

    load_stage64(sbase,       base0, base1, DD, 0,  t);
    load_stage64(sbase + STG, base0, base1, DD, 64, t);

    const int wm = (wid & 1) << 6;
    const int wn = (wid >> 1) << 5;
    const int lr = lane & 15, lc = lane >> 4;
    float acc[4][4][4] = {};
    const int iters = DD / 64;

    for (int it = 0; it < iters; it++) {
        int stg = it % NST;
        CP_WAIT1();
        __syncthreads();
        uint32_t sb = sbase + stg * STG;
        hmma64(sb, 0, wm, wn, lr, lc, acc);
        hmma64(sb, 1, wm, wn, lr, lc, acc);
        hmma64(sb, 2, wm, wn, lr, lc, acc);
        hmma64(sb, 3, wm, wn, lr, lc, acc);
        int nx = it + 2;
        if (nx < iters) load_stage64(sbase + (nx % NST) * STG, base0, base1, DD, nx * 64, t);
        else CP_COMMIT();
    }

    const int qr = lane >> 2, qc = (lane & 3) << 1;
#pragma unroll
    for (int mi = 0; mi < 4; mi++) {
#pragma unroll
        for (int ni = 0; ni < 4; ni++) {
            int col = bn + wn + ni * 8 + qc;
            int row0 = bm + wm + mi * 16 + qr;
            float2 v0 = { acc[mi][ni][0], acc[mi][ni][1] };
            float2 v1 = { acc[mi][ni][2], acc[mi][ni][3] };
            *(float2*)&C[(size_t)row0 * DD + col] = v0;
            *(float2*)&C[(size_t)(row0 + 8) * DD + col] = v1;
        }
    }
}

// ---------------------------------------------------------------------------
// score_tc: P = Qh.Kh (fp16 1-product), causal. HD=128 fully preloaded:
// one wait + one barrier, then 8 uninterrupted MMA chunks.
// Above-diagonal tiles write fp32 zeros; softmax writes only causal region.
// ---------------------------------------------------------------------------
__global__ __launch_bounds__(256, 2) void score_tc(
    const __half* __restrict__ Qh, const __half* __restrict__ Kh,
    float* __restrict__ P)
{
    extern __shared__ char smem[];
    const int q0 = blockIdx.y << 7, k0 = blockIdx.x << 7;
    const int bh = blockIdx.z;
    const size_t pbase = ((size_t)bh * SS + q0) * SS + k0;
    const int t = threadIdx.x;

    if (k0 > q0) {                 // fully-masked tile -> exact zeros
        const float4 z = { 0.f, 0.f, 0.f, 0.f };
#pragma unroll
        for (int q8 = 0; q8 < 16; q8++) {
            int i = t + (q8 << 8);
            int r = i >> 5, c4 = (i & 31) << 2;
            *(float4*)&P[pbase + (size_t)r * SS + c4] = z;
        }
        return;
    }

    const int b = bh >> 5, h = bh & 31;
    const uint32_t sbase = smem_u32(smem);
    const int wid = t >> 5, lane = t & 31;

    const __half* base0 = Qh + (size_t)(b * SS + q0) * DD + (h << 7);
    const __half* base1 = Kh + (size_t)(b * SS + k0) * DD + (h << 7);

    load_stage64(sbase,       base0, base1, DD, 0,  t);
    load_stage64(sbase + STG, base0, base1, DD, 64, t);
    CP_WAIT0();
    __syncthreads();

    const int wm = (wid & 1) << 6;
    const int wn = (wid >> 1) << 5;
    const int lr = lane & 15, lc = lane >> 4;
    float acc[4][4][4] = {};

#pragma unroll
    for (int st = 0; st < 2; st++) {
        uint32_t sb = sbase + st * STG;
        hmma64(sb, 0, wm, wn, lr, lc, acc);
        hmma64(sb, 1, wm, wn, lr, lc, acc);
        hmma64(sb, 2, wm, wn, lr, lc, acc);
        hmma64(sb, 3, wm, wn, lr, lc, acc);
    }

    const int qr = lane >> 2, qc = (lane & 3) << 1;
#pragma unroll
    for (int mi = 0; mi < 4; mi++) {
#pragma unroll
        for (int ni = 0; ni < 4; ni++) {
            int rl = wm + mi * 16 + qr;
            int cl = wn + ni * 8 + qc;
            int k = k0 + cl;
            int qA = q0 + rl, qB = qA + 8;
            float2 v0 = { (k <= qA) ? acc[mi][ni][0] : NEG_INF,
                          (k + 1 <= qA) ? acc[mi][ni][1] : NEG_INF };
            float2 v1 = { (k <= qB) ? acc[mi][ni][2] : NEG_INF,
                          (k + 1 <= qB) ? acc[mi][ni][3] : NEG_INF };
            *(float2*)&P[pbase + (size_t)rl * SS + cl] = v0;
            *(float2*)&P[pbase + (size_t)(rl + 8) * SS + cl] = v1;
        }
    }
}

// ---------------------------------------------------------------------------
// pv_tc: AO = P @ V^T (fp16 1-product), causal k-bound. BK=64, 3-stage.
// ---------------------------------------------------------------------------
__global__ __launch_bounds__(256, 2) void pv_tc(
    const __half* __restrict__ Ph,
    const __half* __restrict__ Vth,
    __half* __restrict__ AOh)
{
    extern __shared__ char smem[];
    const uint32_t sbase = smem_u32(smem);
    const int t = threadIdx.x;
    const int wid = t >> 5, lane = t & 31;
    const int q0 = blockIdx.x << 7;
    const int bh = blockIdx.y;
    const int b = bh >> 5, h = bh & 31;

    const __half* base0 = Ph  + ((size_t)bh * SS + q0) * SS;
    const __half* base1 = Vth + (size_t)bh * HD * SS;

    const int iters = (q0 >> 6) + 2;   // kend/64, kend = q0+128

    load_stage64(sbase,       base0, base1, SS, 0,  t);
    load_stage64(sbase + STG, base0, base1, SS, 64, t);

    const int wm = (wid & 1) << 6;
    const int wn = (wid >> 1) << 5;
    const int lr = lane & 15, lc = lane >> 4;
    float acc[4][4][4] = {};

    for (int it = 0; it < iters; it++) {
        int stg = it % NST;
        CP_WAIT1();
        __syncthreads();
        uint32_t sb = sbase + stg * STG;
        hmma64(sb, 0, wm, wn, lr, lc, acc);
        hmma64(sb, 1, wm, wn, lr, lc, acc);
        hmma64(sb, 2, wm, wn, lr, lc, acc);
        hmma64(sb, 3, wm, wn, lr, lc, acc);
        int nx = it + 2;
        if (nx < iters) load_stage64(sbase + (nx % NST) * STG, base0, base1, SS, nx * 64, t);
        else CP_COMMIT();
    }

    const int qr = lane >> 2, qc = (lane & 3) << 1;
#pragma unroll
    for (int mi = 0; mi < 4; mi++) {
#pragma unroll
        for (int ni = 0; ni < 4; ni++) {
            int row = q0 + wm + mi * 16 + qr;
            int col = (h << 7) + wn + ni * 8 + qc;
            size_t m0 = ((size_t)b * SS + row) * DD + col;
            size_t m1 = m0 + (size_t)8 * DD;
            *(__half2*)&AOh[m0] = __halves2half2(__float2half_rn(acc[mi][ni][0]),
                                                 __float2half_rn(acc[mi][ni][1]));
            *(__half2*)&AOh[m1] = __halves2half2(__float2half_rn(acc[mi][ni][2]),
                                                 __float2half_rn(acc[mi][ni][3]));
        }
    }
}

// ---------------------------------------------------------------------------
// prep_hidden: hidden -> hh (fp16 hi) + qh (roped+scaled Q, fp16 hi)
// ---------------------------------------------------------------------------
__global__ void prep_hidden(const float* __restrict__ src,
                            __half* __restrict__ hh, __half* __restrict__ qh,
                            const float* __restrict__ cosp, const float* __restrict__ sinp,
                            float scale)
{
    int idx = blockIdx.x * blockDim.x + threadIdx.x;
    const int total = BB * SS * HH * (HD / 2);
    if (idx >= total) return;
    int d  = idx & 63;
    int h  = (idx >> 6) & (HH - 1);
    int bs = idx >> 11;
    size_t base = (size_t)bs * DD + (h << 7);
    size_t cbase = (size_t)bs * HD;
    float c0 = cosp[cbase + d],      s0 = sinp[cbase + d];
    float c1 = cosp[cbase + d + 64], s1 = sinp[cbase + d + 64];
    float x0 = src[base + d], x1 = src[base + d + 64];
    hh[base + d]      = __float2half_rn(x0);
    hh[base + d + 64] = __float2half_rn(x1);
    float y0 = (x0 * c0 - x1 * s0) * scale;
    float y1 = (x1 * c1 + x0 * s1) * scale;
    qh[base + d]      = __float2half_rn(y0);
    qh[base + d + 64] = __float2half_rn(y1);
}

// fp32 -> fp16 hi, 3 weight tensors in one launch (blockIdx.y selects)
__global__ void conv_hi3(const float* __restrict__ x0, __half* __restrict__ h0,
                         const float* __restrict__ x1, __half* __restrict__ h1,
                         const float* __restrict__ x2, __half* __restrict__ h2)
{
    size_t i = (size_t)blockIdx.x * blockDim.x + threadIdx.x;
    if (i >= NELT / 4) return;
    const float* x = (blockIdx.y == 0) ? x0 : (blockIdx.y == 1) ? x1 : x2;
    __half* hi = (blockIdx.y == 0) ? h0 : (blockIdx.y == 1) ? h1 : h2;
    float4 v = ((const float4*)x)[i];
    ((__half2*)hi)[i * 2]     = __halves2half2(__float2half_rn(v.x), __float2half_rn(v.y));
    ((__half2*)hi)[i * 2 + 1] = __halves2half2(__float2half_rn(v.z), __float2half_rn(v.w));
}

// ---------------------------------------------------------------------------
// Causal softmax + fp16 emission. Reads/writes only the causal region
// (cols >= kend already zeroed by score's masked blocks).
// ---------------------------------------------------------------------------
__global__ __launch_bounds__(256) void softmax_pconv_kernel(
    float* __restrict__ P, __half* __restrict__ Ph)
{
    size_t row = blockIdx.x;
    int q = (int)(row & (SS - 1));
    int kend = ((q >> 7) + 1) << 7;
    float4* p4 = (float4*)(P + row * (size_t)SS);
    __half* ph = Ph + row * (size_t)SS;
    int t = threadIdx.x;

    float v[8];
    {
        float4 va = p4[t];
        int oa = t << 2;
        v[0] = (oa     <= q) ? va.x : -3.4e38f;
        v[1] = (oa + 1 <= q) ? va.y : -3.4e38f;
        v[2] = (oa + 2 <= q) ? va.z : -3.4e38f;
        v[3] = (oa + 3 <= q) ? va.w : -3.4e38f;
        if (kend > 1024) {
            float4 vb = p4[t + 256];
            int ob = 1024 + (t << 2);
            v[4] = (ob     <= q) ? vb.x : -3.4e38f;
            v[5] = (ob + 1 <= q) ? vb.y : -3.4e38f;
            v[6] = (ob + 2 <= q) ? vb.z : -3.4e38f;
            v[7] = (ob + 3 <= q) ? vb.w : -3.4e38f;
        } else {
            v[4] = v[5] = v[6] = v[7] = -3.4e38f;
        }
    }
    float mx = v[0];
#pragma unroll
    for (int i = 1; i < 8; i++) mx = fmaxf(mx, v[i]);
#pragma unroll
    for (int o = 16; o; o >>= 1) mx = fmaxf(mx, __shfl_xor_sync(0xffffffffu, mx, o));
    __shared__ float rmax[8], rsum[8];
    if ((t & 31) == 0) rmax[t >> 5] = mx;
    __syncthreads();
    mx = rmax[0];
#pragma unroll
    for (int i = 1; i < 8; i++) mx = fmaxf(mx, rmax[i]);
    float sum = 0.f;
#pragma unroll
    for (int i = 0; i < 8; i++) {
        v[i] = (v[i] > -3.3e38f) ? __expf(v[i] - mx) : 0.f;
        sum += v[i];
    }
#pragma unroll
    for (int o = 16; o; o >>= 1) sum += __shfl_xor_sync(0xffffffffu, sum, o);
    if ((t & 31) == 0) rsum[t >> 5] = sum;
    __syncthreads();
    sum = rsum[0];
#pragma unroll
    for (int i = 1; i < 8; i++) sum += rsum[i];
    float inv = 1.0f / sum;
#pragma unroll
    for (int i = 0; i < 8; i++) v[i] *= inv;

    {
        int oa = t << 2;
        if (oa < kend) {
            p4[t] = make_float4(v[0], v[1], v[2], v[3]);
            *(__half2*)&ph[oa]     = __halves2half2(__float2half_rn(v[0]), __float2half_rn(v[1]));
            *(__half2*)&ph[oa + 2] = __halves2half2(__float2half_rn(v[2]), __float2half_rn(v[3]));
        }
        int ob = 1024 + (t << 2);
        if (ob < kend) {
            p4[t + 256] = make_float4(v[4], v[5], v[6], v[7]);
            *(__half2*)&ph[ob]     = __halves2half2(__float2half_rn(v[4]), __float2half_rn(v[5]));
            *(__half2*)&ph[ob + 2] = __halves2half2(__float2half_rn(v[6]), __float2half_rn(v[7]));
        }
    }
}

// ---------------------------------------------------------------------------
extern "C" void kernel_launch(void* const* d_in, const int* in_sizes, int n_in,
                              void* d_out, int out_size)
{
    (void)in_sizes; (void)n_in; (void)out_size;
    const float* hidden = (const float*)d_in[0];
    const float* Wqk    = (const float*)d_in[1];
    const float* bqk    = (const float*)d_in[2];
    const float* Wv     = (const float*)d_in[3];
    const float* bv     = (const float*)d_in[4];
    const float* Wo     = (const float*)d_in[5];
    const float* cosp   = (const float*)d_in[6];
    const float* sinp   = (const float*)d_in[7];

    float* out   = (float*)d_out;
    float* attnw = out + (size_t)BB * SS * DD;

    __half *hh, *qkh, *vh, *oh, *qh, *kh, *vth, *aoh, *ph;
    cudaGetSymbolAddress((void**)&hh,  g_hh);
    cudaGetSymbolAddress((void**)&qkh, g_qkh);
    cudaGetSymbolAddress((void**)&vh,  g_vh);
    cudaGetSymbolAddress((void**)&oh,  g_oh);
    cudaGetSymbolAddress((void**)&qh,  g_qh);
    cudaGetSymbolAddress((void**)&kh,  g_kh);
    cudaGetSymbolAddress((void**)&vth, g_vth);
    cudaGetSymbolAddress((void**)&aoh, g_aoh);
    cudaGetSymbolAddress((void**)&ph,  g_ph);

    cudaFuncSetAttribute(gemm_qkv_tc, cudaFuncAttributeMaxDynamicSharedMemorySize, SMEM_P);
    cudaFuncSetAttribute(gemm1_tc,    cudaFuncAttributeMaxDynamicSharedMemorySize, SMEM_P);
    cudaFuncSetAttribute(score_tc,    cudaFuncAttributeMaxDynamicSharedMemorySize, SMEM_S);
    cudaFuncSetAttribute(pv_tc,       cudaFuncAttributeMaxDynamicSharedMemorySize, SMEM_P);

    const int cvblk = (int)((NELT / 4 + 255) / 256);
    const int rope_total = BB * SS * HH * (HD / 2);
    const float scale = 0.088388347648318447f;  // 128^-0.5

    prep_hidden<<<(rope_total + 255) / 256, 256>>>(hidden, hh, qh, cosp, sinp, scale);
    conv_hi3<<<dim3(cvblk, 3), 256>>>(Wqk, qkh, Wv, vh, Wo, oh);

    // fused QK + V projections in one launch (tail waves merged)
    gemm_qkv_tc<<<dim3(DD / 128, (BB * SS) / 128, 2), 256, SMEM_P>>>(
        hh, qkh, vh, bqk, bv, cosp, sinp, kh, vth);

    score_tc<<<dim3(SS / 128, SS / 128, BB * HH), 256, SMEM_S>>>(qh, kh, attnw);
    softmax_pconv_kernel<<<BB * HH * SS, 256>>>(attnw, ph);
    pv_tc<<<dim3(SS / 128, BB * HH), 256, SMEM_P>>>(ph, vth, aoh);

    // final projection (1-product)
    gemm1_tc<<<dim3(DD / 128, (BB * SS) / 128), 256, SMEM_P>>>(aoh, oh, out);
}